// round 3
// baseline (speedup 1.0000x reference)
#include <cuda_runtime.h>
#include <cstdint>
#include <cstddef>

// Problem constants
#define CB 8
#define CS 512
#define CE 512
#define CH 8
#define CD 64
#define CP 64
#define CF 2048
#define CNR 129            // 2P+1
#define CSR 192            // padded stride for bins / pos_emb (3 chunks of 64)
#define CBH (CB*CH)        // 64
#define CM (CB*CS)         // 4096

// ---------------- device scratch (zero-initialized .bss) ----------------------
__device__ __align__(16) float g_q[CBH*CS*CD];
__device__ __align__(16) float g_k[CBH*CS*CD];
__device__ __align__(16) float g_v[CBH*CS*CD];
__device__ __align__(16) float g_qz[CBH*CS*CNR];
__device__ __align__(16) float g_w[CBH*CS*CS];          // scores -> aw (in place)
__device__ __align__(16) float g_s[CBH*CS*CSR];         // softmax bins (padded)
__device__ __align__(16) float g_pe[CSR*CD];            // padded pos_emb
__device__ __align__(16) float g_concat[CM*CE];
__device__ __align__(16) float g_t1[CM*CE];
__device__ __align__(16) float g_attnout[CM*CE];
__device__ __align__(16) float g_hidden[CM*CF];
__device__ __align__(16) float g_t2[CM*CE];
__device__ __align__(16) float g_wqkv[CE*3*CE];         // packed [512][1536]
__device__ __align__(16) float g_bqkv[3*CE];

enum { EPI_QKV = 0, EPI_RESID = 1, EPI_RELU = 2 };

__device__ __forceinline__ uint32_t f2tf(float f) {
    uint32_t u;
    asm("cvt.rna.tf32.f32 %0, %1;" : "=r"(u) : "f"(f));
    return u;
}

__device__ __forceinline__ void split_tf32(float x, uint32_t& hi, uint32_t& lo) {
    hi = f2tf(x);
    lo = f2tf(x - __uint_as_float(hi));
}

__device__ __forceinline__ void mma_tf32(float c[4], const uint32_t a[4],
                                         const uint32_t b[2]) {
    asm volatile(
        "mma.sync.aligned.m16n8k8.row.col.f32.tf32.tf32.f32 "
        "{%0,%1,%2,%3}, {%4,%5,%6,%7}, {%8,%9}, {%0,%1,%2,%3};\n"
        : "+f"(c[0]), "+f"(c[1]), "+f"(c[2]), "+f"(c[3])
        : "r"(a[0]), "r"(a[1]), "r"(a[2]), "r"(a[3]), "r"(b[0]), "r"(b[1]));
}

// ---------------- TF32 tensor-core GEMM: C = A(MxK)@B(KxN) + epilogue ---------
// Block tile 128xBN, BK=16, 8 warps (4x2).
#define APITCH 20

template<int BN>
__global__ __launch_bounds__(256) void mma_gemm_kernel(
    const float* __restrict__ A, const float* __restrict__ Bm,
    float* __restrict__ C, float* __restrict__ C2, float* __restrict__ C3,
    int M, int N, int K,
    const float* __restrict__ bias, const float* __restrict__ resid, int mode)
{
    constexpr int BPITCH = BN + 4;
    constexpr int NT = BN / 16;            // n fragments per warp
    __shared__ uint32_t As[2][128 * APITCH];
    __shared__ uint32_t Bs[2][16 * BPITCH];

    const int tid = threadIdx.x;
    const int warp = tid >> 5;
    const int lane = tid & 31;
    const int gid = lane >> 2;
    const int tig = lane & 3;
    const int wy = warp >> 1;     // 0..3 (M)
    const int wx = warp & 1;      // 0..1 (N)
    const int bm = blockIdx.y * 128;
    const int bn = blockIdx.x * BN;

    const int ar = tid >> 1;                 // A row in tile (0..127)
    const int ak = (tid & 1) << 3;           // A k base (0 or 8)
    const int br = tid >> 4;                 // B k row in tile (0..15)
    const int bc = (tid & 15) << 2;          // B col base

    const float* Ap = A + (size_t)(bm + ar) * K + ak;
    const float* Bp = Bm + (size_t)br * N + bn + bc;

    float acc[2][NT][4];
#pragma unroll
    for (int mt = 0; mt < 2; mt++)
#pragma unroll
        for (int nt = 0; nt < NT; nt++)
#pragma unroll
            for (int r = 0; r < 4; r++) acc[mt][nt][r] = 0.0f;

    // prologue: stage 0
    {
        float4 a0 = *(const float4*)(Ap + 0);
        float4 a1 = *(const float4*)(Ap + 4);
        uint4 ua0 = {f2tf(a0.x), f2tf(a0.y), f2tf(a0.z), f2tf(a0.w)};
        uint4 ua1 = {f2tf(a1.x), f2tf(a1.y), f2tf(a1.z), f2tf(a1.w)};
        *(uint4*)&As[0][ar * APITCH + ak] = ua0;
        *(uint4*)&As[0][ar * APITCH + ak + 4] = ua1;
        float4 b0 = *(const float4*)(Bp + 0);
        uint4 ub0 = {f2tf(b0.x), f2tf(b0.y), f2tf(b0.z), f2tf(b0.w)};
        *(uint4*)&Bs[0][br * BPITCH + bc] = ub0;
        if (BN == 128) {
            float4 b1 = *(const float4*)(Bp + 64);
            uint4 ub1 = {f2tf(b1.x), f2tf(b1.y), f2tf(b1.z), f2tf(b1.w)};
            *(uint4*)&Bs[0][br * BPITCH + bc + 64] = ub1;
        }
    }
    __syncthreads();

    for (int k0 = 0; k0 < K; k0 += 16) {
        const int buf = (k0 >> 4) & 1;
        const bool has_next = (k0 + 16) < K;
        float4 ra0, ra1, rb0, rb1;
        if (has_next) {
            ra0 = *(const float4*)(Ap + k0 + 16);
            ra1 = *(const float4*)(Ap + k0 + 20);
            rb0 = *(const float4*)(Bp + (size_t)(k0 + 16) * N);
            if (BN == 128) rb1 = *(const float4*)(Bp + (size_t)(k0 + 16) * N + 64);
        }

#pragma unroll
        for (int ks = 0; ks < 16; ks += 8) {
            uint32_t af[2][4];
#pragma unroll
            for (int mt = 0; mt < 2; mt++) {
                const int mrow = wy * 32 + mt * 16 + gid;
                af[mt][0] = As[buf][mrow * APITCH + ks + tig];
                af[mt][1] = As[buf][(mrow + 8) * APITCH + ks + tig];
                af[mt][2] = As[buf][mrow * APITCH + ks + tig + 4];
                af[mt][3] = As[buf][(mrow + 8) * APITCH + ks + tig + 4];
            }
            uint32_t bf[NT][2];
#pragma unroll
            for (int nt = 0; nt < NT; nt++) {
                const int nc = wx * (BN / 2) + nt * 8 + gid;
                bf[nt][0] = Bs[buf][(ks + tig) * BPITCH + nc];
                bf[nt][1] = Bs[buf][(ks + tig + 4) * BPITCH + nc];
            }
#pragma unroll
            for (int mt = 0; mt < 2; mt++)
#pragma unroll
                for (int nt = 0; nt < NT; nt++)
                    mma_tf32(acc[mt][nt], af[mt], bf[nt]);
        }

        if (has_next) {
            const int nb = buf ^ 1;
            uint4 ua0 = {f2tf(ra0.x), f2tf(ra0.y), f2tf(ra0.z), f2tf(ra0.w)};
            uint4 ua1 = {f2tf(ra1.x), f2tf(ra1.y), f2tf(ra1.z), f2tf(ra1.w)};
            *(uint4*)&As[nb][ar * APITCH + ak] = ua0;
            *(uint4*)&As[nb][ar * APITCH + ak + 4] = ua1;
            uint4 ub0 = {f2tf(rb0.x), f2tf(rb0.y), f2tf(rb0.z), f2tf(rb0.w)};
            *(uint4*)&Bs[nb][br * BPITCH + bc] = ub0;
            if (BN == 128) {
                uint4 ub1 = {f2tf(rb1.x), f2tf(rb1.y), f2tf(rb1.z), f2tf(rb1.w)};
                *(uint4*)&Bs[nb][br * BPITCH + bc + 64] = ub1;
            }
        }
        __syncthreads();
    }

    // epilogue
#pragma unroll
    for (int mt = 0; mt < 2; mt++) {
#pragma unroll
        for (int nt = 0; nt < NT; nt++) {
            const int col = bn + wx * (BN / 2) + nt * 8 + 2 * tig;
            float bv0 = 0.0f, bv1 = 0.0f;
            if (bias) { bv0 = bias[col]; bv1 = bias[col + 1]; }
#pragma unroll
            for (int half = 0; half < 2; half++) {
                const int row = bm + wy * 32 + mt * 16 + gid + half * 8;
                float v0 = acc[mt][nt][half * 2 + 0] + bv0;
                float v1 = acc[mt][nt][half * 2 + 1] + bv1;
                if (mode == EPI_RESID) {
                    v0 += resid[(size_t)row * N + col];
                    v1 += resid[(size_t)row * N + col + 1];
                } else if (mode == EPI_RELU) {
                    v0 = fmaxf(v0, 0.0f);
                    v1 = fmaxf(v1, 0.0f);
                }
                float2 vv = {v0, v1};
                if (mode == EPI_QKV) {
                    const int b = row >> 9, ii = row & 511;
                    const int which = col >> 9;
                    const int cc = col & 511;
                    const int h = cc >> 6, d = cc & 63;
                    float* base = (which == 0) ? C : (which == 1) ? C2 : C3;
                    *(float2*)(base + (((size_t)(b * CH + h) * CS) + ii) * CD + d) = vv;
                } else {
                    *(float2*)(C + (size_t)row * N + col) = vv;
                }
            }
        }
    }
}

// ---------------- pack QKV weights/biases --------------------------------------
__global__ void pack_qkv_kernel(const float* __restrict__ wq, const float* __restrict__ wk,
                                const float* __restrict__ wv, const float* __restrict__ bq,
                                const float* __restrict__ bk, const float* __restrict__ bv)
{
    int idx = blockIdx.x * 256 + threadIdx.x;
    if (idx < CE * CE) {
        int r = idx >> 9, c = idx & 511;
        g_wqkv[(size_t)r * 1536 + c] = wq[idx];
        g_wqkv[(size_t)r * 1536 + 512 + c] = wk[idx];
        g_wqkv[(size_t)r * 1536 + 1024 + c] = wv[idx];
    }
    if (idx < CE) {
        g_bqkv[idx] = bq[idx];
        g_bqkv[512 + idx] = bk[idx];
        g_bqkv[1024 + idx] = bv[idx];
    }
}

// ---------------- pad pos_emb into g_pe ---------------------------------------
__global__ void pe_copy_kernel(const float* __restrict__ pe)
{
    int t = blockIdx.x * 256 + threadIdx.x;
    if (t < CNR * CD) g_pe[t] = pe[t];
}

// ---------------- qz table: (BH*S, 129) = Q2d(32768x64) @ pos_emb^T -----------
__global__ __launch_bounds__(256) void qz_kernel(const float* __restrict__ pe)
{
    const int m0 = blockIdx.x << 5;  // 32 q rows
    __shared__ float Qs[32 * 64];
    __shared__ float PEs[CNR * 64];
    const int tid = threadIdx.x;

    const float4* qsrc = (const float4*)(g_q + (size_t)m0 * CD);
    float4* qdst = (float4*)Qs;
    for (int t = tid; t < 32 * 16; t += 256) qdst[t] = qsrc[t];
    const float4* psrc = (const float4*)pe;
    float4* pdst = (float4*)PEs;
    for (int t = tid; t < CNR * 16; t += 256) pdst[t] = psrc[t];
    __syncthreads();

    for (int o = tid; o < 32 * CNR; o += 256) {
        const int i = o / CNR;
        const int r = o - i * CNR;
        const float* qq = Qs + i * 64;
        const float* pp = PEs + r * 64;
        float s = 0.0f;
#pragma unroll
        for (int d = 0; d < 64; d++) s = fmaf(qq[d], pp[d], s);
        g_qz[(size_t)(m0 + i) * CNR + r] = s;
    }
}

// ---------------- scores (tensor, tf32x3): 128x128 tile -----------------------
// dynamic smem layout (uint32 units):
//   QH[128*68], QL[128*68], KH[64*132], KL[64*132], then int dti[128], dtj[128], mj[128]
#define SC_QH 0
#define SC_QL (128*68)
#define SC_KH (2*128*68)
#define SC_KL (2*128*68 + 64*132)
#define SC_INT (2*128*68 + 2*64*132)
#define SC_SMEM_BYTES ((SC_INT + 3*128) * 4)

__global__ __launch_bounds__(256) void scores_mma_kernel(
    const float* __restrict__ dist, const int* __restrict__ dt,
    const int* __restrict__ mask)
{
    extern __shared__ uint32_t sm[];
    uint32_t* QH = sm + SC_QH;
    uint32_t* QL = sm + SC_QL;
    uint32_t* KH = sm + SC_KH;
    uint32_t* KL = sm + SC_KL;
    int* dti_s = (int*)(sm + SC_INT);
    int* dtj_s = dti_s + 128;
    int* mj_s = dtj_s + 128;

    const int bh = blockIdx.z;
    const int b = bh >> 3;
    const int i0 = blockIdx.y << 7;
    const int j0 = blockIdx.x << 7;
    const int tid = threadIdx.x;
    const int warp = tid >> 5;
    const int lane = tid & 31;
    const int gid = lane >> 2;
    const int tig = lane & 3;
    const int wy = warp >> 1;
    const int wx = warp & 1;

    const float* qb = g_q + (size_t)bh * CS * CD;
    const float* kb = g_k + (size_t)bh * CS * CD;

    // stage Q (row-major) and K (transposed [d][j]) with hi/lo split
#pragma unroll
    for (int l = 0; l < 8; l++) {
        const int idx = tid + (l << 8);
        const int r = idx >> 4;
        const int c = (idx & 15) << 2;
        float4 qv = *(const float4*)(qb + (size_t)(i0 + r) * CD + c);
        float4 kv = *(const float4*)(kb + (size_t)(j0 + r) * CD + c);
        uint32_t h0, l0;
        split_tf32(qv.x, h0, l0); QH[r*68 + c + 0] = h0; QL[r*68 + c + 0] = l0;
        split_tf32(qv.y, h0, l0); QH[r*68 + c + 1] = h0; QL[r*68 + c + 1] = l0;
        split_tf32(qv.z, h0, l0); QH[r*68 + c + 2] = h0; QL[r*68 + c + 2] = l0;
        split_tf32(qv.w, h0, l0); QH[r*68 + c + 3] = h0; QL[r*68 + c + 3] = l0;
        split_tf32(kv.x, h0, l0); KH[(c+0)*132 + r] = h0; KL[(c+0)*132 + r] = l0;
        split_tf32(kv.y, h0, l0); KH[(c+1)*132 + r] = h0; KL[(c+1)*132 + r] = l0;
        split_tf32(kv.z, h0, l0); KH[(c+2)*132 + r] = h0; KL[(c+2)*132 + r] = l0;
        split_tf32(kv.w, h0, l0); KH[(c+3)*132 + r] = h0; KL[(c+3)*132 + r] = l0;
    }
    if (tid < 128) {
        dti_s[tid] = dt[b * CS + i0 + tid];
        dtj_s[tid] = dt[b * CS + j0 + tid];
        mj_s[tid] = mask[b * CS + j0 + tid];
    }
    __syncthreads();

    float acc[2][8][4];
#pragma unroll
    for (int mt = 0; mt < 2; mt++)
#pragma unroll
        for (int nt = 0; nt < 8; nt++)
#pragma unroll
            for (int r = 0; r < 4; r++) acc[mt][nt][r] = 0.0f;

#pragma unroll
    for (int ks = 0; ks < 64; ks += 8) {
        uint32_t ah[2][4], al[2][4];
#pragma unroll
        for (int mt = 0; mt < 2; mt++) {
            const int mrow = wy * 32 + mt * 16 + gid;
            ah[mt][0] = QH[mrow*68 + ks + tig];
            ah[mt][1] = QH[(mrow+8)*68 + ks + tig];
            ah[mt][2] = QH[mrow*68 + ks + tig + 4];
            ah[mt][3] = QH[(mrow+8)*68 + ks + tig + 4];
            al[mt][0] = QL[mrow*68 + ks + tig];
            al[mt][1] = QL[(mrow+8)*68 + ks + tig];
            al[mt][2] = QL[mrow*68 + ks + tig + 4];
            al[mt][3] = QL[(mrow+8)*68 + ks + tig + 4];
        }
        uint32_t bhf[8][2], blf[8][2];
#pragma unroll
        for (int nt = 0; nt < 8; nt++) {
            const int nc = wx * 64 + nt * 8 + gid;
            bhf[nt][0] = KH[(ks + tig)*132 + nc];
            bhf[nt][1] = KH[(ks + tig + 4)*132 + nc];
            blf[nt][0] = KL[(ks + tig)*132 + nc];
            blf[nt][1] = KL[(ks + tig + 4)*132 + nc];
        }
#pragma unroll
        for (int mt = 0; mt < 2; mt++)
#pragma unroll
            for (int nt = 0; nt < 8; nt++) {
                mma_tf32(acc[mt][nt], ah[mt], blf[nt]);
                mma_tf32(acc[mt][nt], al[mt], bhf[nt]);
                mma_tf32(acc[mt][nt], ah[mt], bhf[nt]);
            }
    }

    // epilogue: qz gather + dist + mask
#pragma unroll
    for (int mt = 0; mt < 2; mt++) {
#pragma unroll
        for (int half = 0; half < 2; half++) {
            const int il = wy * 32 + mt * 16 + gid + half * 8;
            const int i = i0 + il;
            const int di = dti_s[il];
            const size_t qzrow = ((size_t)bh * CS + i) * CNR;
            const size_t drow = ((size_t)b * CS + i) * CS;
            const size_t wrow = ((size_t)bh * CS + i) * CS;
#pragma unroll
            for (int nt = 0; nt < 8; nt++) {
                const int jl = wx * 64 + nt * 8 + 2 * tig;
                float ov[2];
#pragma unroll
                for (int u = 0; u < 2; u++) {
                    const int jloc = jl + u;
                    int rel = min(max(dtj_s[jloc] - di, -CP), CP) + CP;
                    float v = (acc[mt][nt][half*2+u] + g_qz[qzrow + rel]) * 0.125f
                            + 0.6f * dist[drow + j0 + jloc];
                    if (mj_s[jloc] == 0) v = -1e9f;
                    ov[u] = v;
                }
                float2 st = {ov[0], ov[1]};
                *(float2*)&g_w[wrow + j0 + jl] = st;
            }
        }
    }
}

// ---------------- softmax + 129-bin histogram ---------------------------------
__global__ __launch_bounds__(256) void softmax_kernel(const int* __restrict__ dt)
{
    const int row = blockIdx.x;           // bh*S + i
    const int bh = row >> 9;
    const int i = row & 511;
    const int b = bh >> 3;
    float* wr = g_w + (size_t)row * CS;
    const int tid = threadIdx.x;

    __shared__ float red[256];
    __shared__ float bins[CNR];

    float v0 = wr[tid], v1 = wr[tid + 256];
    red[tid] = fmaxf(v0, v1);
    __syncthreads();
    for (int s = 128; s > 0; s >>= 1) {
        if (tid < s) red[tid] = fmaxf(red[tid], red[tid + s]);
        __syncthreads();
    }
    const float mx = red[0];
    __syncthreads();

    const float e0 = __expf(v0 - mx);
    const float e1 = __expf(v1 - mx);
    red[tid] = e0 + e1;
    __syncthreads();
    for (int s = 128; s > 0; s >>= 1) {
        if (tid < s) red[tid] += red[tid + s];
        __syncthreads();
    }
    const float inv = 1.0f / red[0];
    if (tid < CNR) bins[tid] = 0.0f;
    __syncthreads();

    const float a0 = e0 * inv, a1 = e1 * inv;
    wr[tid] = a0;
    wr[tid + 256] = a1;

    const int di = dt[b * CS + i];
    int r0 = min(max(dt[b * CS + tid] - di, -CP), CP) + CP;
    int r1 = min(max(dt[b * CS + tid + 256] - di, -CP), CP) + CP;
    atomicAdd(&bins[r0], a0);
    atomicAdd(&bins[r1], a1);
    __syncthreads();
    if (tid < CNR) g_s[(size_t)row * CSR + tid] = bins[tid];
}

// ---------------- attn (tensor, tf32x3): out = aw@v + bins@pe, 128x64 tile ----
// dynamic smem (uint32): AH[128*68], AL[128*68], BH[64*68], BL[64*68]
#define AT_AH 0
#define AT_AL (128*68)
#define AT_BH (2*128*68)
#define AT_BL (2*128*68 + 64*68)
#define AT_SMEM_BYTES ((2*128*68 + 2*64*68) * 4)

__global__ __launch_bounds__(256) void attn_mma_kernel()
{
    extern __shared__ uint32_t sm[];
    uint32_t* AH = sm + AT_AH;
    uint32_t* AL = sm + AT_AL;
    uint32_t* BH = sm + AT_BH;
    uint32_t* BL = sm + AT_BL;

    const int bh = blockIdx.y;
    const int b = bh >> 3, h = bh & 7;
    const int i0 = blockIdx.x << 7;
    const int tid = threadIdx.x;
    const int warp = tid >> 5;
    const int lane = tid & 31;
    const int gid = lane >> 2;
    const int tig = lane & 3;
    const int wy = warp >> 1;
    const int wx = warp & 1;

    const float* awb = g_w + (size_t)bh * CS * CS;
    const float* sb = g_s + (size_t)bh * CS * CSR;
    const float* vb = g_v + (size_t)bh * CS * CD;

    float acc[2][4][4];
#pragma unroll
    for (int mt = 0; mt < 2; mt++)
#pragma unroll
        for (int nt = 0; nt < 4; nt++)
#pragma unroll
            for (int r = 0; r < 4; r++) acc[mt][nt][r] = 0.0f;

    for (int c = 0; c < 11; c++) {
        // stage A: 128 x 64
#pragma unroll
        for (int l = 0; l < 8; l++) {
            const int idx = tid + (l << 8);
            const int r = idx >> 4;
            const int cc = (idx & 15) << 2;
            float4 av;
            if (c < 8) av = *(const float4*)(awb + (size_t)(i0 + r) * CS + (c << 6) + cc);
            else       av = *(const float4*)(sb + (size_t)(i0 + r) * CSR + ((c - 8) << 6) + cc);
            uint32_t hh, ll;
            split_tf32(av.x, hh, ll); AH[r*68 + cc + 0] = hh; AL[r*68 + cc + 0] = ll;
            split_tf32(av.y, hh, ll); AH[r*68 + cc + 1] = hh; AL[r*68 + cc + 1] = ll;
            split_tf32(av.z, hh, ll); AH[r*68 + cc + 2] = hh; AL[r*68 + cc + 2] = ll;
            split_tf32(av.w, hh, ll); AH[r*68 + cc + 3] = hh; AL[r*68 + cc + 3] = ll;
        }
        // stage B: 64 x 64 (row = k, col = d) — already the layout mma needs
#pragma unroll
        for (int l = 0; l < 4; l++) {
            const int idx = tid + (l << 8);
            const int r = idx >> 4;
            const int cc = (idx & 15) << 2;
            float4 vv;
            if (c < 8) vv = *(const float4*)(vb + (size_t)((c << 6) + r) * CD + cc);
            else       vv = *(const float4*)(g_pe + (size_t)(((c - 8) << 6) + r) * CD + cc);
            uint32_t hh, ll;
            split_tf32(vv.x, hh, ll); BH[r*68 + cc + 0] = hh; BL[r*68 + cc + 0] = ll;
            split_tf32(vv.y, hh, ll); BH[r*68 + cc + 1] = hh; BL[r*68 + cc + 1] = ll;
            split_tf32(vv.z, hh, ll); BH[r*68 + cc + 2] = hh; BL[r*68 + cc + 2] = ll;
            split_tf32(vv.w, hh, ll); BH[r*68 + cc + 3] = hh; BL[r*68 + cc + 3] = ll;
        }
        __syncthreads();

#pragma unroll
        for (int ks = 0; ks < 64; ks += 8) {
            uint32_t ah[2][4], al[2][4];
#pragma unroll
            for (int mt = 0; mt < 2; mt++) {
                const int mrow = wy * 32 + mt * 16 + gid;
                ah[mt][0] = AH[mrow*68 + ks + tig];
                ah[mt][1] = AH[(mrow+8)*68 + ks + tig];
                ah[mt][2] = AH[mrow*68 + ks + tig + 4];
                ah[mt][3] = AH[(mrow+8)*68 + ks + tig + 4];
                al[mt][0] = AL[mrow*68 + ks + tig];
                al[mt][1] = AL[(mrow+8)*68 + ks + tig];
                al[mt][2] = AL[mrow*68 + ks + tig + 4];
                al[mt][3] = AL[(mrow+8)*68 + ks + tig + 4];
            }
            uint32_t bhf[4][2], blf[4][2];
#pragma unroll
            for (int nt = 0; nt < 4; nt++) {
                const int nc = wx * 32 + nt * 8 + gid;
                bhf[nt][0] = BH[(ks + tig)*68 + nc];
                bhf[nt][1] = BH[(ks + tig + 4)*68 + nc];
                blf[nt][0] = BL[(ks + tig)*68 + nc];
                blf[nt][1] = BL[(ks + tig + 4)*68 + nc];
            }
#pragma unroll
            for (int mt = 0; mt < 2; mt++)
#pragma unroll
                for (int nt = 0; nt < 4; nt++) {
                    mma_tf32(acc[mt][nt], ah[mt], blf[nt]);
                    mma_tf32(acc[mt][nt], al[mt], bhf[nt]);
                    mma_tf32(acc[mt][nt], ah[mt], bhf[nt]);
                }
        }
        __syncthreads();
    }

#pragma unroll
    for (int mt = 0; mt < 2; mt++)
#pragma unroll
        for (int nt = 0; nt < 4; nt++) {
            const int col = wx * 32 + nt * 8 + 2 * tig;
#pragma unroll
            for (int half = 0; half < 2; half++) {
                const int row = wy * 32 + mt * 16 + gid + half * 8;
                float2 vv = {acc[mt][nt][half*2+0], acc[mt][nt][half*2+1]};
                *(float2*)&g_concat[(size_t)(b * CS + i0 + row) * CE + h * CD + col] = vv;
            }
        }
}

// ---------------- layernorm (row = 512) ---------------------------------------
__global__ __launch_bounds__(256) void ln_kernel(
    const float* __restrict__ in, float* __restrict__ out,
    const float* __restrict__ gg, const float* __restrict__ bb)
{
    const int row = blockIdx.x;
    const float* xr = in + (size_t)row * CE;
    const int tid = threadIdx.x;
    __shared__ float red[256];

    float v0 = xr[tid], v1 = xr[tid + 256];
    red[tid] = v0 + v1;
    __syncthreads();
    for (int s = 128; s > 0; s >>= 1) {
        if (tid < s) red[tid] += red[tid + s];
        __syncthreads();
    }
    const float mu = red[0] * (1.0f / CE);
    __syncthreads();
    const float d0 = v0 - mu, d1 = v1 - mu;
    red[tid] = d0 * d0 + d1 * d1;
    __syncthreads();
    for (int s = 128; s > 0; s >>= 1) {
        if (tid < s) red[tid] += red[tid + s];
        __syncthreads();
    }
    const float rstd = rsqrtf(red[0] * (1.0f / CE) + 1e-5f);
    out[(size_t)row * CE + tid] = d0 * rstd * gg[tid] + bb[tid];
    out[(size_t)row * CE + tid + 256] = d1 * rstd * gg[tid + 256] + bb[tid + 256];
}

// ---------------- launch -------------------------------------------------------
extern "C" void kernel_launch(void* const* d_in, const int* in_sizes, int n_in,
                              void* d_out, int out_size)
{
    const float* x    = (const float*)d_in[0];
    const float* dist = (const float*)d_in[1];
    const int*   dt   = (const int*)d_in[2];
    const int*   mask = (const int*)d_in[3];
    const float* wq_w = (const float*)d_in[4];
    const float* wq_b = (const float*)d_in[5];
    const float* wk_w = (const float*)d_in[6];
    const float* wk_b = (const float*)d_in[7];
    const float* wv_w = (const float*)d_in[8];
    const float* wv_b = (const float*)d_in[9];
    const float* wo_w = (const float*)d_in[10];
    const float* wo_b = (const float*)d_in[11];
    const float* pe   = (const float*)d_in[12];
    const float* w1   = (const float*)d_in[13];
    const float* b1   = (const float*)d_in[14];
    const float* w2   = (const float*)d_in[15];
    const float* b2   = (const float*)d_in[16];
    const float* ln1g = (const float*)d_in[17];
    const float* ln1b = (const float*)d_in[18];
    const float* ln2g = (const float*)d_in[19];
    const float* ln2b = (const float*)d_in[20];
    float* out = (float*)d_out;

    void *pq, *pk, *pv, *pcc, *pt1, *pao, *phid, *pt2, *pwqkv, *pbqkv;
    cudaGetSymbolAddress(&pq, g_q);
    cudaGetSymbolAddress(&pk, g_k);
    cudaGetSymbolAddress(&pv, g_v);
    cudaGetSymbolAddress(&pcc, g_concat);
    cudaGetSymbolAddress(&pt1, g_t1);
    cudaGetSymbolAddress(&pao, g_attnout);
    cudaGetSymbolAddress(&phid, g_hidden);
    cudaGetSymbolAddress(&pt2, g_t2);
    cudaGetSymbolAddress(&pwqkv, g_wqkv);
    cudaGetSymbolAddress(&pbqkv, g_bqkv);

    cudaFuncSetAttribute(scores_mma_kernel,
                         cudaFuncAttributeMaxDynamicSharedMemorySize, SC_SMEM_BYTES);
    cudaFuncSetAttribute(attn_mma_kernel,
                         cudaFuncAttributeMaxDynamicSharedMemorySize, AT_SMEM_BYTES);

    pe_copy_kernel<<<(CNR * CD + 255) / 256, 256>>>(pe);
    pack_qkv_kernel<<<(CE * CE + 255) / 256, 256>>>(wq_w, wk_w, wv_w, wq_b, wk_b, wv_b);

    // fused QKV: M=4096, N=1536, K=512
    dim3 gq(1536 / 128, CM / 128);
    mma_gemm_kernel<128><<<gq, 256>>>(x, (const float*)pwqkv, (float*)pq, (float*)pk, (float*)pv,
                                      CM, 1536, CE, (const float*)pbqkv, nullptr, EPI_QKV);

    qz_kernel<<<(CBH * CS) / 32, 256>>>(pe);

    dim3 gsc(CS / 128, CS / 128, CBH);
    scores_mma_kernel<<<gsc, 256, SC_SMEM_BYTES>>>(dist, dt, mask);

    softmax_kernel<<<CBH * CS, 256>>>(dt);

    dim3 gat(CS / 128, CBH);
    attn_mma_kernel<<<gat, 256, AT_SMEM_BYTES>>>();

    dim3 gwo(CE / 64, CM / 128);
    mma_gemm_kernel<64><<<gwo, 256>>>((const float*)pcc, wo_w, (float*)pt1, nullptr, nullptr,
                                      CM, CE, CE, wo_b, x, EPI_RESID);
    ln_kernel<<<CM, 256>>>((const float*)pt1, (float*)pao, ln1g, ln1b);

    dim3 gf1(CF / 128, CM / 128);
    mma_gemm_kernel<128><<<gf1, 256>>>((const float*)pao, w1, (float*)phid, nullptr, nullptr,
                                       CM, CF, CE, b1, nullptr, EPI_RELU);
    dim3 gf2(CE / 64, CM / 128);
    mma_gemm_kernel<64><<<gf2, 256>>>((const float*)phid, w2, (float*)pt2, nullptr, nullptr,
                                      CM, CE, CF, b2, (const float*)pao, EPI_RESID);
    ln_kernel<<<CM, 256>>>((const float*)pt2, out, ln2g, ln2b);
}

// round 4
// speedup vs baseline: 1.2658x; 1.2658x over previous
#include <cuda_runtime.h>
#include <cstdint>
#include <cstddef>

// Problem constants
#define CB 8
#define CS 512
#define CE 512
#define CH 8
#define CD 64
#define CP 64
#define CF 2048
#define CNR 129            // 2P+1
#define QZP 144            // padded qz row stride
#define CSR 192            // padded stride for bins / pos_emb (3 chunks of 64)
#define CBH (CB*CH)        // 64
#define CM (CB*CS)         // 4096

// ---------------- device scratch (zero-initialized .bss) ----------------------
__device__ __align__(16) float g_q[CBH*CS*CD];
__device__ __align__(16) float g_k[CBH*CS*CD];
__device__ __align__(16) float g_v[CBH*CS*CD];
__device__ __align__(16) float g_qz[(size_t)CBH*CS*QZP];
__device__ __align__(16) float g_w[CBH*CS*CS];          // scores -> aw (in place)
__device__ __align__(16) float g_s[CBH*CS*CSR];         // softmax bins (padded)
__device__ __align__(16) float g_pe[CSR*CD];            // padded pos_emb
__device__ __align__(16) float g_concat[CM*CE];
__device__ __align__(16) float g_t1[CM*CE];
__device__ __align__(16) float g_attnout[CM*CE];
__device__ __align__(16) float g_hidden[CM*CF];
__device__ __align__(16) float g_t2[CM*CE];
__device__ __align__(16) float g_wqkv[CE*3*CE];         // packed [512][1536]
__device__ __align__(16) float g_bqkv[3*CE];

enum { EPI_QKV = 0, EPI_RESID = 1, EPI_RELU = 2 };

__device__ __forceinline__ uint32_t f2tf(float f) {
    uint32_t u;
    asm("cvt.rna.tf32.f32 %0, %1;" : "=r"(u) : "f"(f));
    return u;
}

__device__ __forceinline__ void split_tf32(float x, uint32_t& hi, uint32_t& lo) {
    hi = f2tf(x);
    lo = f2tf(x - __uint_as_float(hi));
}

__device__ __forceinline__ void mma_tf32(float c[4], const uint32_t a[4],
                                         const uint32_t b[2]) {
    asm volatile(
        "mma.sync.aligned.m16n8k8.row.col.f32.tf32.tf32.f32 "
        "{%0,%1,%2,%3}, {%4,%5,%6,%7}, {%8,%9}, {%0,%1,%2,%3};\n"
        : "+f"(c[0]), "+f"(c[1]), "+f"(c[2]), "+f"(c[3])
        : "r"(a[0]), "r"(a[1]), "r"(a[2]), "r"(a[3]), "r"(b[0]), "r"(b[1]));
}

// ---------------- TF32 tensor-core GEMM: C = A(MxK)@B(KxN) + epilogue ---------
// Block tile 128xBN, BK=16, 8 warps (4x2).
#define APITCH 20

template<int BN>
__global__ __launch_bounds__(256) void mma_gemm_kernel(
    const float* __restrict__ A, const float* __restrict__ Bm,
    float* __restrict__ C, float* __restrict__ C2, float* __restrict__ C3,
    int M, int N, int K,
    const float* __restrict__ bias, const float* __restrict__ resid, int mode)
{
    constexpr int BPITCH = BN + 4;
    constexpr int NT = BN / 16;            // n fragments per warp
    __shared__ uint32_t As[2][128 * APITCH];
    __shared__ uint32_t Bs[2][16 * BPITCH];

    const int tid = threadIdx.x;
    const int warp = tid >> 5;
    const int lane = tid & 31;
    const int gid = lane >> 2;
    const int tig = lane & 3;
    const int wy = warp >> 1;     // 0..3 (M)
    const int wx = warp & 1;      // 0..1 (N)
    const int bm = blockIdx.y * 128;
    const int bn = blockIdx.x * BN;

    const int ar = tid >> 1;                 // A row in tile (0..127)
    const int ak = (tid & 1) << 3;           // A k base (0 or 8)
    const int br = tid >> 4;                 // B k row in tile (0..15)
    const int bc = (tid & 15) << 2;          // B col base

    const float* Ap = A + (size_t)(bm + ar) * K + ak;
    const float* Bp = Bm + (size_t)br * N + bn + bc;

    float acc[2][NT][4];
#pragma unroll
    for (int mt = 0; mt < 2; mt++)
#pragma unroll
        for (int nt = 0; nt < NT; nt++)
#pragma unroll
            for (int r = 0; r < 4; r++) acc[mt][nt][r] = 0.0f;

    // prologue: stage 0
    {
        float4 a0 = *(const float4*)(Ap + 0);
        float4 a1 = *(const float4*)(Ap + 4);
        uint4 ua0 = {f2tf(a0.x), f2tf(a0.y), f2tf(a0.z), f2tf(a0.w)};
        uint4 ua1 = {f2tf(a1.x), f2tf(a1.y), f2tf(a1.z), f2tf(a1.w)};
        *(uint4*)&As[0][ar * APITCH + ak] = ua0;
        *(uint4*)&As[0][ar * APITCH + ak + 4] = ua1;
        float4 b0 = *(const float4*)(Bp + 0);
        uint4 ub0 = {f2tf(b0.x), f2tf(b0.y), f2tf(b0.z), f2tf(b0.w)};
        *(uint4*)&Bs[0][br * BPITCH + bc] = ub0;
        if (BN == 128) {
            float4 b1 = *(const float4*)(Bp + 64);
            uint4 ub1 = {f2tf(b1.x), f2tf(b1.y), f2tf(b1.z), f2tf(b1.w)};
            *(uint4*)&Bs[0][br * BPITCH + bc + 64] = ub1;
        }
    }
    __syncthreads();

    for (int k0 = 0; k0 < K; k0 += 16) {
        const int buf = (k0 >> 4) & 1;
        const bool has_next = (k0 + 16) < K;
        float4 ra0, ra1, rb0, rb1;
        if (has_next) {
            ra0 = *(const float4*)(Ap + k0 + 16);
            ra1 = *(const float4*)(Ap + k0 + 20);
            rb0 = *(const float4*)(Bp + (size_t)(k0 + 16) * N);
            if (BN == 128) rb1 = *(const float4*)(Bp + (size_t)(k0 + 16) * N + 64);
        }

#pragma unroll
        for (int ks = 0; ks < 16; ks += 8) {
            uint32_t af[2][4];
#pragma unroll
            for (int mt = 0; mt < 2; mt++) {
                const int mrow = wy * 32 + mt * 16 + gid;
                af[mt][0] = As[buf][mrow * APITCH + ks + tig];
                af[mt][1] = As[buf][(mrow + 8) * APITCH + ks + tig];
                af[mt][2] = As[buf][mrow * APITCH + ks + tig + 4];
                af[mt][3] = As[buf][(mrow + 8) * APITCH + ks + tig + 4];
            }
            uint32_t bf[NT][2];
#pragma unroll
            for (int nt = 0; nt < NT; nt++) {
                const int nc = wx * (BN / 2) + nt * 8 + gid;
                bf[nt][0] = Bs[buf][(ks + tig) * BPITCH + nc];
                bf[nt][1] = Bs[buf][(ks + tig + 4) * BPITCH + nc];
            }
#pragma unroll
            for (int mt = 0; mt < 2; mt++)
#pragma unroll
                for (int nt = 0; nt < NT; nt++)
                    mma_tf32(acc[mt][nt], af[mt], bf[nt]);
        }

        if (has_next) {
            const int nb = buf ^ 1;
            uint4 ua0 = {f2tf(ra0.x), f2tf(ra0.y), f2tf(ra0.z), f2tf(ra0.w)};
            uint4 ua1 = {f2tf(ra1.x), f2tf(ra1.y), f2tf(ra1.z), f2tf(ra1.w)};
            *(uint4*)&As[nb][ar * APITCH + ak] = ua0;
            *(uint4*)&As[nb][ar * APITCH + ak + 4] = ua1;
            uint4 ub0 = {f2tf(rb0.x), f2tf(rb0.y), f2tf(rb0.z), f2tf(rb0.w)};
            *(uint4*)&Bs[nb][br * BPITCH + bc] = ub0;
            if (BN == 128) {
                uint4 ub1 = {f2tf(rb1.x), f2tf(rb1.y), f2tf(rb1.z), f2tf(rb1.w)};
                *(uint4*)&Bs[nb][br * BPITCH + bc + 64] = ub1;
            }
        }
        __syncthreads();
    }

    // epilogue
#pragma unroll
    for (int mt = 0; mt < 2; mt++) {
#pragma unroll
        for (int nt = 0; nt < NT; nt++) {
            const int col = bn + wx * (BN / 2) + nt * 8 + 2 * tig;
            float bv0 = 0.0f, bv1 = 0.0f;
            if (bias) { bv0 = bias[col]; bv1 = bias[col + 1]; }
#pragma unroll
            for (int half = 0; half < 2; half++) {
                const int row = bm + wy * 32 + mt * 16 + gid + half * 8;
                float v0 = acc[mt][nt][half * 2 + 0] + bv0;
                float v1 = acc[mt][nt][half * 2 + 1] + bv1;
                if (mode == EPI_RESID) {
                    v0 += resid[(size_t)row * N + col];
                    v1 += resid[(size_t)row * N + col + 1];
                } else if (mode == EPI_RELU) {
                    v0 = fmaxf(v0, 0.0f);
                    v1 = fmaxf(v1, 0.0f);
                }
                float2 vv = {v0, v1};
                if (mode == EPI_QKV) {
                    const int b = row >> 9, ii = row & 511;
                    const int which = col >> 9;
                    const int cc = col & 511;
                    const int h = cc >> 6, d = cc & 63;
                    float* base = (which == 0) ? C : (which == 1) ? C2 : C3;
                    *(float2*)(base + (((size_t)(b * CH + h) * CS) + ii) * CD + d) = vv;
                } else {
                    *(float2*)(C + (size_t)row * N + col) = vv;
                }
            }
        }
    }
}

// ---------------- pack QKV weights/biases --------------------------------------
__global__ void pack_qkv_kernel(const float* __restrict__ wq, const float* __restrict__ wk,
                                const float* __restrict__ wv, const float* __restrict__ bq,
                                const float* __restrict__ bk, const float* __restrict__ bv)
{
    int idx = blockIdx.x * 256 + threadIdx.x;
    if (idx < CE * CE) {
        int r = idx >> 9, c = idx & 511;
        g_wqkv[(size_t)r * 1536 + c] = wq[idx];
        g_wqkv[(size_t)r * 1536 + 512 + c] = wk[idx];
        g_wqkv[(size_t)r * 1536 + 1024 + c] = wv[idx];
    }
    if (idx < CE) {
        g_bqkv[idx] = bq[idx];
        g_bqkv[512 + idx] = bk[idx];
        g_bqkv[1024 + idx] = bv[idx];
    }
}

// ---------------- pad pos_emb into g_pe ---------------------------------------
__global__ void pe_copy_kernel(const float* __restrict__ pe)
{
    int t = blockIdx.x * 256 + threadIdx.x;
    if (t < CNR * CD) g_pe[t] = pe[t];
}

// ---------------- qz (tensor, tf32x3): (32768x64) @ (64x129->144) --------------
// dynamic smem (uint32): AH[128*68], AL[128*68], BH[64*148], BL[64*148]
#define QZ_AH 0
#define QZ_AL (128*68)
#define QZ_BH (2*128*68)
#define QZ_BL (2*128*68 + 64*148)
#define QZ_SMEM_BYTES ((2*128*68 + 2*64*148) * 4)

__global__ __launch_bounds__(256) void qz_mma_kernel(const float* __restrict__ pe)
{
    extern __shared__ uint32_t sm[];
    uint32_t* AH = sm + QZ_AH;
    uint32_t* AL = sm + QZ_AL;
    uint32_t* BH = sm + QZ_BH;
    uint32_t* BL = sm + QZ_BL;

    const int m0 = blockIdx.x << 7;     // 128 q rows
    const int tid = threadIdx.x;
    const int warp = tid >> 5;
    const int lane = tid & 31;
    const int gid = lane >> 2;
    const int tig = lane & 3;
    const int wy = warp >> 1;
    const int wx = warp & 1;

    // zero B pads
    for (int t = tid; t < 64 * 148; t += 256) { BH[t] = 0u; BL[t] = 0u; }
    __syncthreads();

    // stage A: q rows [m0, m0+128), hi/lo split, row-major pitch 68
#pragma unroll
    for (int l = 0; l < 8; l++) {
        const int idx = tid + (l << 8);
        const int r = idx >> 4;
        const int c = (idx & 15) << 2;
        float4 qv = *(const float4*)(g_q + (size_t)(m0 + r) * CD + c);
        uint32_t hh, ll;
        split_tf32(qv.x, hh, ll); AH[r*68 + c + 0] = hh; AL[r*68 + c + 0] = ll;
        split_tf32(qv.y, hh, ll); AH[r*68 + c + 1] = hh; AL[r*68 + c + 1] = ll;
        split_tf32(qv.z, hh, ll); AH[r*68 + c + 2] = hh; AL[r*68 + c + 2] = ll;
        split_tf32(qv.w, hh, ll); AH[r*68 + c + 3] = hh; AL[r*68 + c + 3] = ll;
    }
    // stage B transposed: BH[k*148 + n] = pe[n*64 + k], n < 129
    for (int t = tid; t < CNR * 16; t += 256) {
        const int n = t >> 4;
        const int k = (t & 15) << 2;
        float4 pv = *(const float4*)(pe + (size_t)n * CD + k);
        uint32_t hh, ll;
        split_tf32(pv.x, hh, ll); BH[(k+0)*148 + n] = hh; BL[(k+0)*148 + n] = ll;
        split_tf32(pv.y, hh, ll); BH[(k+1)*148 + n] = hh; BL[(k+1)*148 + n] = ll;
        split_tf32(pv.z, hh, ll); BH[(k+2)*148 + n] = hh; BL[(k+2)*148 + n] = ll;
        split_tf32(pv.w, hh, ll); BH[(k+3)*148 + n] = hh; BL[(k+3)*148 + n] = ll;
    }
    __syncthreads();

    float acc[2][9][4];
#pragma unroll
    for (int mt = 0; mt < 2; mt++)
#pragma unroll
        for (int nt = 0; nt < 9; nt++)
#pragma unroll
            for (int r = 0; r < 4; r++) acc[mt][nt][r] = 0.0f;

#pragma unroll
    for (int ks = 0; ks < 64; ks += 8) {
        uint32_t ah[2][4], al[2][4];
#pragma unroll
        for (int mt = 0; mt < 2; mt++) {
            const int mrow = wy * 32 + mt * 16 + gid;
            ah[mt][0] = AH[mrow*68 + ks + tig];
            ah[mt][1] = AH[(mrow+8)*68 + ks + tig];
            ah[mt][2] = AH[mrow*68 + ks + tig + 4];
            ah[mt][3] = AH[(mrow+8)*68 + ks + tig + 4];
            al[mt][0] = AL[mrow*68 + ks + tig];
            al[mt][1] = AL[(mrow+8)*68 + ks + tig];
            al[mt][2] = AL[mrow*68 + ks + tig + 4];
            al[mt][3] = AL[(mrow+8)*68 + ks + tig + 4];
        }
        uint32_t bhf[9][2], blf[9][2];
#pragma unroll
        for (int nt = 0; nt < 9; nt++) {
            const int nc = wx * 72 + nt * 8 + gid;
            bhf[nt][0] = BH[(ks + tig)*148 + nc];
            bhf[nt][1] = BH[(ks + tig + 4)*148 + nc];
            blf[nt][0] = BL[(ks + tig)*148 + nc];
            blf[nt][1] = BL[(ks + tig + 4)*148 + nc];
        }
#pragma unroll
        for (int mt = 0; mt < 2; mt++)
#pragma unroll
            for (int nt = 0; nt < 9; nt++) {
                mma_tf32(acc[mt][nt], ah[mt], blf[nt]);
                mma_tf32(acc[mt][nt], al[mt], bhf[nt]);
                mma_tf32(acc[mt][nt], ah[mt], bhf[nt]);
            }
    }

#pragma unroll
    for (int mt = 0; mt < 2; mt++)
#pragma unroll
        for (int nt = 0; nt < 9; nt++) {
            const int col = wx * 72 + nt * 8 + 2 * tig;
#pragma unroll
            for (int half = 0; half < 2; half++) {
                const int row = m0 + wy * 32 + mt * 16 + gid + half * 8;
                float2 vv = {acc[mt][nt][half*2+0], acc[mt][nt][half*2+1]};
                *(float2*)&g_qz[(size_t)row * QZP + col] = vv;
            }
        }
}

// ---------------- scores (tensor, tf32x3): 128x128 tile -----------------------
#define SC_QH 0
#define SC_QL (128*68)
#define SC_KH (2*128*68)
#define SC_KL (2*128*68 + 64*132)
#define SC_INT (2*128*68 + 2*64*132)
#define SC_SMEM_BYTES ((SC_INT + 3*128) * 4)

__global__ __launch_bounds__(256) void scores_mma_kernel(
    const float* __restrict__ dist, const int* __restrict__ dt,
    const int* __restrict__ mask)
{
    extern __shared__ uint32_t sm[];
    uint32_t* QH = sm + SC_QH;
    uint32_t* QL = sm + SC_QL;
    uint32_t* KH = sm + SC_KH;
    uint32_t* KL = sm + SC_KL;
    int* dti_s = (int*)(sm + SC_INT);
    int* dtj_s = dti_s + 128;
    int* mj_s = dtj_s + 128;

    const int bh = blockIdx.z;
    const int b = bh >> 3;
    const int i0 = blockIdx.y << 7;
    const int j0 = blockIdx.x << 7;
    const int tid = threadIdx.x;
    const int warp = tid >> 5;
    const int lane = tid & 31;
    const int gid = lane >> 2;
    const int tig = lane & 3;
    const int wy = warp >> 1;
    const int wx = warp & 1;

    const float* qb = g_q + (size_t)bh * CS * CD;
    const float* kb = g_k + (size_t)bh * CS * CD;

#pragma unroll
    for (int l = 0; l < 8; l++) {
        const int idx = tid + (l << 8);
        const int r = idx >> 4;
        const int c = (idx & 15) << 2;
        float4 qv = *(const float4*)(qb + (size_t)(i0 + r) * CD + c);
        float4 kv = *(const float4*)(kb + (size_t)(j0 + r) * CD + c);
        uint32_t h0, l0;
        split_tf32(qv.x, h0, l0); QH[r*68 + c + 0] = h0; QL[r*68 + c + 0] = l0;
        split_tf32(qv.y, h0, l0); QH[r*68 + c + 1] = h0; QL[r*68 + c + 1] = l0;
        split_tf32(qv.z, h0, l0); QH[r*68 + c + 2] = h0; QL[r*68 + c + 2] = l0;
        split_tf32(qv.w, h0, l0); QH[r*68 + c + 3] = h0; QL[r*68 + c + 3] = l0;
        split_tf32(kv.x, h0, l0); KH[(c+0)*132 + r] = h0; KL[(c+0)*132 + r] = l0;
        split_tf32(kv.y, h0, l0); KH[(c+1)*132 + r] = h0; KL[(c+1)*132 + r] = l0;
        split_tf32(kv.z, h0, l0); KH[(c+2)*132 + r] = h0; KL[(c+2)*132 + r] = l0;
        split_tf32(kv.w, h0, l0); KH[(c+3)*132 + r] = h0; KL[(c+3)*132 + r] = l0;
    }
    if (tid < 128) {
        dti_s[tid] = dt[b * CS + i0 + tid];
        dtj_s[tid] = dt[b * CS + j0 + tid];
        mj_s[tid] = mask[b * CS + j0 + tid];
    }
    __syncthreads();

    float acc[2][8][4];
#pragma unroll
    for (int mt = 0; mt < 2; mt++)
#pragma unroll
        for (int nt = 0; nt < 8; nt++)
#pragma unroll
            for (int r = 0; r < 4; r++) acc[mt][nt][r] = 0.0f;

#pragma unroll
    for (int ks = 0; ks < 64; ks += 8) {
        uint32_t ah[2][4], al[2][4];
#pragma unroll
        for (int mt = 0; mt < 2; mt++) {
            const int mrow = wy * 32 + mt * 16 + gid;
            ah[mt][0] = QH[mrow*68 + ks + tig];
            ah[mt][1] = QH[(mrow+8)*68 + ks + tig];
            ah[mt][2] = QH[mrow*68 + ks + tig + 4];
            ah[mt][3] = QH[(mrow+8)*68 + ks + tig + 4];
            al[mt][0] = QL[mrow*68 + ks + tig];
            al[mt][1] = QL[(mrow+8)*68 + ks + tig];
            al[mt][2] = QL[mrow*68 + ks + tig + 4];
            al[mt][3] = QL[(mrow+8)*68 + ks + tig + 4];
        }
        uint32_t bhf[8][2], blf[8][2];
#pragma unroll
        for (int nt = 0; nt < 8; nt++) {
            const int nc = wx * 64 + nt * 8 + gid;
            bhf[nt][0] = KH[(ks + tig)*132 + nc];
            bhf[nt][1] = KH[(ks + tig + 4)*132 + nc];
            blf[nt][0] = KL[(ks + tig)*132 + nc];
            blf[nt][1] = KL[(ks + tig + 4)*132 + nc];
        }
#pragma unroll
        for (int mt = 0; mt < 2; mt++)
#pragma unroll
            for (int nt = 0; nt < 8; nt++) {
                mma_tf32(acc[mt][nt], ah[mt], blf[nt]);
                mma_tf32(acc[mt][nt], al[mt], bhf[nt]);
                mma_tf32(acc[mt][nt], ah[mt], bhf[nt]);
            }
    }

    // epilogue: qz gather + dist + mask
#pragma unroll
    for (int mt = 0; mt < 2; mt++) {
#pragma unroll
        for (int half = 0; half < 2; half++) {
            const int il = wy * 32 + mt * 16 + gid + half * 8;
            const int i = i0 + il;
            const int di = dti_s[il];
            const size_t qzrow = ((size_t)bh * CS + i) * QZP;
            const size_t drow = ((size_t)b * CS + i) * CS;
            const size_t wrow = ((size_t)bh * CS + i) * CS;
#pragma unroll
            for (int nt = 0; nt < 8; nt++) {
                const int jl = wx * 64 + nt * 8 + 2 * tig;
                float ov[2];
#pragma unroll
                for (int u = 0; u < 2; u++) {
                    const int jloc = jl + u;
                    int rel = min(max(dtj_s[jloc] - di, -CP), CP) + CP;
                    float v = (acc[mt][nt][half*2+u] + g_qz[qzrow + rel]) * 0.125f
                            + 0.6f * dist[drow + j0 + jloc];
                    if (mj_s[jloc] == 0) v = -1e9f;
                    ov[u] = v;
                }
                float2 st = {ov[0], ov[1]};
                *(float2*)&g_w[wrow + j0 + jl] = st;
            }
        }
    }
}

// ---------------- softmax + 129-bin histogram ---------------------------------
__global__ __launch_bounds__(256) void softmax_kernel(const int* __restrict__ dt)
{
    const int row = blockIdx.x;           // bh*S + i
    const int bh = row >> 9;
    const int i = row & 511;
    const int b = bh >> 3;
    float* wr = g_w + (size_t)row * CS;
    const int tid = threadIdx.x;

    __shared__ float red[256];
    __shared__ float bins[CNR];

    float v0 = wr[tid], v1 = wr[tid + 256];
    red[tid] = fmaxf(v0, v1);
    __syncthreads();
    for (int s = 128; s > 0; s >>= 1) {
        if (tid < s) red[tid] = fmaxf(red[tid], red[tid + s]);
        __syncthreads();
    }
    const float mx = red[0];
    __syncthreads();

    const float e0 = __expf(v0 - mx);
    const float e1 = __expf(v1 - mx);
    red[tid] = e0 + e1;
    __syncthreads();
    for (int s = 128; s > 0; s >>= 1) {
        if (tid < s) red[tid] += red[tid + s];
        __syncthreads();
    }
    const float inv = 1.0f / red[0];
    if (tid < CNR) bins[tid] = 0.0f;
    __syncthreads();

    const float a0 = e0 * inv, a1 = e1 * inv;
    wr[tid] = a0;
    wr[tid + 256] = a1;

    const int di = dt[b * CS + i];
    int r0 = min(max(dt[b * CS + tid] - di, -CP), CP) + CP;
    int r1 = min(max(dt[b * CS + tid + 256] - di, -CP), CP) + CP;
    atomicAdd(&bins[r0], a0);
    atomicAdd(&bins[r1], a1);
    __syncthreads();
    if (tid < CNR) g_s[(size_t)row * CSR + tid] = bins[tid];
}

// ---------------- attn (tensor, tf32x3): out = aw@v + bins@pe, 128x64 tile ----
#define AT_AH 0
#define AT_AL (128*68)
#define AT_BH (2*128*68)
#define AT_BL (2*128*68 + 64*68)
#define AT_SMEM_BYTES ((2*128*68 + 2*64*68) * 4)

__global__ __launch_bounds__(256) void attn_mma_kernel()
{
    extern __shared__ uint32_t sm[];
    uint32_t* AH = sm + AT_AH;
    uint32_t* AL = sm + AT_AL;
    uint32_t* BH = sm + AT_BH;
    uint32_t* BL = sm + AT_BL;

    const int bh = blockIdx.y;
    const int b = bh >> 3, h = bh & 7;
    const int i0 = blockIdx.x << 7;
    const int tid = threadIdx.x;
    const int warp = tid >> 5;
    const int lane = tid & 31;
    const int gid = lane >> 2;
    const int tig = lane & 3;
    const int wy = warp >> 1;
    const int wx = warp & 1;

    const float* awb = g_w + (size_t)bh * CS * CS;
    const float* sb = g_s + (size_t)bh * CS * CSR;
    const float* vb = g_v + (size_t)bh * CS * CD;

    float acc[2][4][4];
#pragma unroll
    for (int mt = 0; mt < 2; mt++)
#pragma unroll
        for (int nt = 0; nt < 4; nt++)
#pragma unroll
            for (int r = 0; r < 4; r++) acc[mt][nt][r] = 0.0f;

    for (int c = 0; c < 11; c++) {
#pragma unroll
        for (int l = 0; l < 8; l++) {
            const int idx = tid + (l << 8);
            const int r = idx >> 4;
            const int cc = (idx & 15) << 2;
            float4 av;
            if (c < 8) av = *(const float4*)(awb + (size_t)(i0 + r) * CS + (c << 6) + cc);
            else       av = *(const float4*)(sb + (size_t)(i0 + r) * CSR + ((c - 8) << 6) + cc);
            uint32_t hh, ll;
            split_tf32(av.x, hh, ll); AH[r*68 + cc + 0] = hh; AL[r*68 + cc + 0] = ll;
            split_tf32(av.y, hh, ll); AH[r*68 + cc + 1] = hh; AL[r*68 + cc + 1] = ll;
            split_tf32(av.z, hh, ll); AH[r*68 + cc + 2] = hh; AL[r*68 + cc + 2] = ll;
            split_tf32(av.w, hh, ll); AH[r*68 + cc + 3] = hh; AL[r*68 + cc + 3] = ll;
        }
#pragma unroll
        for (int l = 0; l < 4; l++) {
            const int idx = tid + (l << 8);
            const int r = idx >> 4;
            const int cc = (idx & 15) << 2;
            float4 vv;
            if (c < 8) vv = *(const float4*)(vb + (size_t)((c << 6) + r) * CD + cc);
            else       vv = *(const float4*)(g_pe + (size_t)(((c - 8) << 6) + r) * CD + cc);
            uint32_t hh, ll;
            split_tf32(vv.x, hh, ll); BH[r*68 + cc + 0] = hh; BL[r*68 + cc + 0] = ll;
            split_tf32(vv.y, hh, ll); BH[r*68 + cc + 1] = hh; BL[r*68 + cc + 1] = ll;
            split_tf32(vv.z, hh, ll); BH[r*68 + cc + 2] = hh; BL[r*68 + cc + 2] = ll;
            split_tf32(vv.w, hh, ll); BH[r*68 + cc + 3] = hh; BL[r*68 + cc + 3] = ll;
        }
        __syncthreads();

#pragma unroll
        for (int ks = 0; ks < 64; ks += 8) {
            uint32_t ah[2][4], al[2][4];
#pragma unroll
            for (int mt = 0; mt < 2; mt++) {
                const int mrow = wy * 32 + mt * 16 + gid;
                ah[mt][0] = AH[mrow*68 + ks + tig];
                ah[mt][1] = AH[(mrow+8)*68 + ks + tig];
                ah[mt][2] = AH[mrow*68 + ks + tig + 4];
                ah[mt][3] = AH[(mrow+8)*68 + ks + tig + 4];
                al[mt][0] = AL[mrow*68 + ks + tig];
                al[mt][1] = AL[(mrow+8)*68 + ks + tig];
                al[mt][2] = AL[mrow*68 + ks + tig + 4];
                al[mt][3] = AL[(mrow+8)*68 + ks + tig + 4];
            }
            uint32_t bhf[4][2], blf[4][2];
#pragma unroll
            for (int nt = 0; nt < 4; nt++) {
                const int nc = wx * 32 + nt * 8 + gid;
                bhf[nt][0] = BH[(ks + tig)*68 + nc];
                bhf[nt][1] = BH[(ks + tig + 4)*68 + nc];
                blf[nt][0] = BL[(ks + tig)*68 + nc];
                blf[nt][1] = BL[(ks + tig + 4)*68 + nc];
            }
#pragma unroll
            for (int mt = 0; mt < 2; mt++)
#pragma unroll
                for (int nt = 0; nt < 4; nt++) {
                    mma_tf32(acc[mt][nt], ah[mt], blf[nt]);
                    mma_tf32(acc[mt][nt], al[mt], bhf[nt]);
                    mma_tf32(acc[mt][nt], ah[mt], bhf[nt]);
                }
        }
        __syncthreads();
    }

#pragma unroll
    for (int mt = 0; mt < 2; mt++)
#pragma unroll
        for (int nt = 0; nt < 4; nt++) {
            const int col = wx * 32 + nt * 8 + 2 * tig;
#pragma unroll
            for (int half = 0; half < 2; half++) {
                const int row = wy * 32 + mt * 16 + gid + half * 8;
                float2 vv = {acc[mt][nt][half*2+0], acc[mt][nt][half*2+1]};
                *(float2*)&g_concat[(size_t)(b * CS + i0 + row) * CE + h * CD + col] = vv;
            }
        }
}

// ---------------- layernorm (row = 512) ---------------------------------------
__global__ __launch_bounds__(256) void ln_kernel(
    const float* __restrict__ in, float* __restrict__ out,
    const float* __restrict__ gg, const float* __restrict__ bb)
{
    const int row = blockIdx.x;
    const float* xr = in + (size_t)row * CE;
    const int tid = threadIdx.x;
    __shared__ float red[256];

    float v0 = xr[tid], v1 = xr[tid + 256];
    red[tid] = v0 + v1;
    __syncthreads();
    for (int s = 128; s > 0; s >>= 1) {
        if (tid < s) red[tid] += red[tid + s];
        __syncthreads();
    }
    const float mu = red[0] * (1.0f / CE);
    __syncthreads();
    const float d0 = v0 - mu, d1 = v1 - mu;
    red[tid] = d0 * d0 + d1 * d1;
    __syncthreads();
    for (int s = 128; s > 0; s >>= 1) {
        if (tid < s) red[tid] += red[tid + s];
        __syncthreads();
    }
    const float rstd = rsqrtf(red[0] * (1.0f / CE) + 1e-5f);
    out[(size_t)row * CE + tid] = d0 * rstd * gg[tid] + bb[tid];
    out[(size_t)row * CE + tid + 256] = d1 * rstd * gg[tid + 256] + bb[tid + 256];
}

// ---------------- launch -------------------------------------------------------
extern "C" void kernel_launch(void* const* d_in, const int* in_sizes, int n_in,
                              void* d_out, int out_size)
{
    const float* x    = (const float*)d_in[0];
    const float* dist = (const float*)d_in[1];
    const int*   dt   = (const int*)d_in[2];
    const int*   mask = (const int*)d_in[3];
    const float* wq_w = (const float*)d_in[4];
    const float* wq_b = (const float*)d_in[5];
    const float* wk_w = (const float*)d_in[6];
    const float* wk_b = (const float*)d_in[7];
    const float* wv_w = (const float*)d_in[8];
    const float* wv_b = (const float*)d_in[9];
    const float* wo_w = (const float*)d_in[10];
    const float* wo_b = (const float*)d_in[11];
    const float* pe   = (const float*)d_in[12];
    const float* w1   = (const float*)d_in[13];
    const float* b1   = (const float*)d_in[14];
    const float* w2   = (const float*)d_in[15];
    const float* b2   = (const float*)d_in[16];
    const float* ln1g = (const float*)d_in[17];
    const float* ln1b = (const float*)d_in[18];
    const float* ln2g = (const float*)d_in[19];
    const float* ln2b = (const float*)d_in[20];
    float* out = (float*)d_out;

    void *pq, *pk, *pv, *pcc, *pt1, *pao, *phid, *pt2, *pwqkv, *pbqkv;
    cudaGetSymbolAddress(&pq, g_q);
    cudaGetSymbolAddress(&pk, g_k);
    cudaGetSymbolAddress(&pv, g_v);
    cudaGetSymbolAddress(&pcc, g_concat);
    cudaGetSymbolAddress(&pt1, g_t1);
    cudaGetSymbolAddress(&pao, g_attnout);
    cudaGetSymbolAddress(&phid, g_hidden);
    cudaGetSymbolAddress(&pt2, g_t2);
    cudaGetSymbolAddress(&pwqkv, g_wqkv);
    cudaGetSymbolAddress(&pbqkv, g_bqkv);

    cudaFuncSetAttribute(scores_mma_kernel,
                         cudaFuncAttributeMaxDynamicSharedMemorySize, SC_SMEM_BYTES);
    cudaFuncSetAttribute(attn_mma_kernel,
                         cudaFuncAttributeMaxDynamicSharedMemorySize, AT_SMEM_BYTES);
    cudaFuncSetAttribute(qz_mma_kernel,
                         cudaFuncAttributeMaxDynamicSharedMemorySize, QZ_SMEM_BYTES);

    pe_copy_kernel<<<(CNR * CD + 255) / 256, 256>>>(pe);
    pack_qkv_kernel<<<(CE * CE + 255) / 256, 256>>>(wq_w, wk_w, wv_w, wq_b, wk_b, wv_b);

    // fused QKV: M=4096, N=1536, K=512
    dim3 gq(1536 / 128, CM / 128);
    mma_gemm_kernel<128><<<gq, 256>>>(x, (const float*)pwqkv, (float*)pq, (float*)pk, (float*)pv,
                                      CM, 1536, CE, (const float*)pbqkv, nullptr, EPI_QKV);

    qz_mma_kernel<<<(CBH * CS) / 128, 256, QZ_SMEM_BYTES>>>(pe);

    dim3 gsc(CS / 128, CS / 128, CBH);
    scores_mma_kernel<<<gsc, 256, SC_SMEM_BYTES>>>(dist, dt, mask);

    softmax_kernel<<<CBH * CS, 256>>>(dt);

    dim3 gat(CS / 128, CBH);
    attn_mma_kernel<<<gat, 256, AT_SMEM_BYTES>>>();

    dim3 gwo(CE / 64, CM / 128);
    mma_gemm_kernel<64><<<gwo, 256>>>((const float*)pcc, wo_w, (float*)pt1, nullptr, nullptr,
                                      CM, CE, CE, wo_b, x, EPI_RESID);
    ln_kernel<<<CM, 256>>>((const float*)pt1, (float*)pao, ln1g, ln1b);

    dim3 gf1(CF / 128, CM / 128);
    mma_gemm_kernel<128><<<gf1, 256>>>((const float*)pao, w1, (float*)phid, nullptr, nullptr,
                                       CM, CF, CE, b1, nullptr, EPI_RELU);
    dim3 gf2(CE / 64, CM / 128);
    mma_gemm_kernel<64><<<gf2, 256>>>((const float*)phid, w2, (float*)pt2, nullptr, nullptr,
                                      CM, CE, CF, b2, (const float*)pao, EPI_RESID);
    ln_kernel<<<CM, 256>>>((const float*)pt2, out, ln2g, ln2b);
}

// round 5
// speedup vs baseline: 1.3577x; 1.0726x over previous
#include <cuda_runtime.h>
#include <cstdint>
#include <cstddef>

// Problem constants
#define CB 8
#define CS 512
#define CE 512
#define CH 8
#define CD 64
#define CP 64
#define CF 2048
#define CNR 129            // 2P+1
#define QZP 144            // padded qz row stride
#define CSR 192            // padded stride for bins / pos_emb (3 chunks of 64)
#define CBH (CB*CH)        // 64
#define CM (CB*CS)         // 4096

// ---------------- device scratch (zero-initialized .bss) ----------------------
__device__ __align__(16) float g_q[CBH*CS*CD];
__device__ __align__(16) float g_k[CBH*CS*CD];
__device__ __align__(16) float g_v[CBH*CS*CD];
__device__ __align__(16) float g_qz[(size_t)CBH*CS*QZP];
__device__ __align__(16) float g_w[CBH*CS*CS];          // scores -> aw (in place)
__device__ __align__(16) float g_s[CBH*CS*CSR];         // softmax bins (padded)
__device__ __align__(16) float g_pe[CSR*CD];            // padded pos_emb
__device__ __align__(16) float g_concat[CM*CE];
__device__ __align__(16) float g_t1[CM*CE];
__device__ __align__(16) float g_attnout[CM*CE];
__device__ __align__(16) float g_hidden[CM*CF];
__device__ __align__(16) float g_t2[CM*CE];
__device__ __align__(16) float g_wqkv[CE*3*CE];         // packed [512][1536]
__device__ __align__(16) float g_bqkv[3*CE];

enum { EPI_QKV = 0, EPI_RESID = 1, EPI_RELU = 2 };

__device__ __forceinline__ uint32_t f2tf(float f) {
    uint32_t u;
    asm("cvt.rna.tf32.f32 %0, %1;" : "=r"(u) : "f"(f));
    return u;
}

__device__ __forceinline__ void split_tf32(float x, uint32_t& hi, uint32_t& lo) {
    hi = f2tf(x);
    lo = f2tf(x - __uint_as_float(hi));
}

__device__ __forceinline__ void mma_tf32(float c[4], const uint32_t a[4],
                                         const uint32_t b[2]) {
    asm volatile(
        "mma.sync.aligned.m16n8k8.row.col.f32.tf32.tf32.f32 "
        "{%0,%1,%2,%3}, {%4,%5,%6,%7}, {%8,%9}, {%0,%1,%2,%3};\n"
        : "+f"(c[0]), "+f"(c[1]), "+f"(c[2]), "+f"(c[3])
        : "r"(a[0]), "r"(a[1]), "r"(a[2]), "r"(a[3]), "r"(b[0]), "r"(b[1]));
}

// ---------------- TF32 tensor-core GEMM: C = A(MxK)@B(KxN) + epilogue ---------
// Block tile 128xBN, BK=16, 8 warps (4x2).
#define APITCH 20

template<int BN>
__global__ __launch_bounds__(256, 2) void mma_gemm_kernel(
    const float* __restrict__ A, const float* __restrict__ Bm,
    float* __restrict__ C, float* __restrict__ C2, float* __restrict__ C3,
    int M, int N, int K,
    const float* __restrict__ bias, const float* __restrict__ resid, int mode)
{
    constexpr int BPITCH = BN + 4;
    constexpr int NT = BN / 16;            // n fragments per warp
    __shared__ uint32_t As[2][128 * APITCH];
    __shared__ uint32_t Bs[2][16 * BPITCH];

    const int tid = threadIdx.x;
    const int warp = tid >> 5;
    const int lane = tid & 31;
    const int gid = lane >> 2;
    const int tig = lane & 3;
    const int wy = warp >> 1;     // 0..3 (M)
    const int wx = warp & 1;      // 0..1 (N)
    const int bm = blockIdx.y * 128;
    const int bn = blockIdx.x * BN;

    const int ar = tid >> 1;                 // A row in tile (0..127)
    const int ak = (tid & 1) << 3;           // A k base (0 or 8)
    const int br = tid >> 4;                 // B k row in tile (0..15)
    const int bc = (tid & 15) << 2;          // B col base

    const float* Ap = A + (size_t)(bm + ar) * K + ak;
    const float* Bp = Bm + (size_t)br * N + bn + bc;

    float acc[2][NT][4];
#pragma unroll
    for (int mt = 0; mt < 2; mt++)
#pragma unroll
        for (int nt = 0; nt < NT; nt++)
#pragma unroll
            for (int r = 0; r < 4; r++) acc[mt][nt][r] = 0.0f;

    // prologue: stage 0
    {
        float4 a0 = *(const float4*)(Ap + 0);
        float4 a1 = *(const float4*)(Ap + 4);
        uint4 ua0 = {f2tf(a0.x), f2tf(a0.y), f2tf(a0.z), f2tf(a0.w)};
        uint4 ua1 = {f2tf(a1.x), f2tf(a1.y), f2tf(a1.z), f2tf(a1.w)};
        *(uint4*)&As[0][ar * APITCH + ak] = ua0;
        *(uint4*)&As[0][ar * APITCH + ak + 4] = ua1;
        float4 b0 = *(const float4*)(Bp + 0);
        uint4 ub0 = {f2tf(b0.x), f2tf(b0.y), f2tf(b0.z), f2tf(b0.w)};
        *(uint4*)&Bs[0][br * BPITCH + bc] = ub0;
        if (BN == 128) {
            float4 b1 = *(const float4*)(Bp + 64);
            uint4 ub1 = {f2tf(b1.x), f2tf(b1.y), f2tf(b1.z), f2tf(b1.w)};
            *(uint4*)&Bs[0][br * BPITCH + bc + 64] = ub1;
        }
    }
    __syncthreads();

    for (int k0 = 0; k0 < K; k0 += 16) {
        const int buf = (k0 >> 4) & 1;
        const bool has_next = (k0 + 16) < K;
        float4 ra0, ra1, rb0, rb1;
        if (has_next) {
            ra0 = *(const float4*)(Ap + k0 + 16);
            ra1 = *(const float4*)(Ap + k0 + 20);
            rb0 = *(const float4*)(Bp + (size_t)(k0 + 16) * N);
            if (BN == 128) rb1 = *(const float4*)(Bp + (size_t)(k0 + 16) * N + 64);
        }

#pragma unroll
        for (int ks = 0; ks < 16; ks += 8) {
            uint32_t af[2][4];
#pragma unroll
            for (int mt = 0; mt < 2; mt++) {
                const int mrow = wy * 32 + mt * 16 + gid;
                af[mt][0] = As[buf][mrow * APITCH + ks + tig];
                af[mt][1] = As[buf][(mrow + 8) * APITCH + ks + tig];
                af[mt][2] = As[buf][mrow * APITCH + ks + tig + 4];
                af[mt][3] = As[buf][(mrow + 8) * APITCH + ks + tig + 4];
            }
            uint32_t bf[NT][2];
#pragma unroll
            for (int nt = 0; nt < NT; nt++) {
                const int nc = wx * (BN / 2) + nt * 8 + gid;
                bf[nt][0] = Bs[buf][(ks + tig) * BPITCH + nc];
                bf[nt][1] = Bs[buf][(ks + tig + 4) * BPITCH + nc];
            }
#pragma unroll
            for (int mt = 0; mt < 2; mt++)
#pragma unroll
                for (int nt = 0; nt < NT; nt++)
                    mma_tf32(acc[mt][nt], af[mt], bf[nt]);
        }

        if (has_next) {
            const int nb = buf ^ 1;
            uint4 ua0 = {f2tf(ra0.x), f2tf(ra0.y), f2tf(ra0.z), f2tf(ra0.w)};
            uint4 ua1 = {f2tf(ra1.x), f2tf(ra1.y), f2tf(ra1.z), f2tf(ra1.w)};
            *(uint4*)&As[nb][ar * APITCH + ak] = ua0;
            *(uint4*)&As[nb][ar * APITCH + ak + 4] = ua1;
            uint4 ub0 = {f2tf(rb0.x), f2tf(rb0.y), f2tf(rb0.z), f2tf(rb0.w)};
            *(uint4*)&Bs[nb][br * BPITCH + bc] = ub0;
            if (BN == 128) {
                uint4 ub1 = {f2tf(rb1.x), f2tf(rb1.y), f2tf(rb1.z), f2tf(rb1.w)};
                *(uint4*)&Bs[nb][br * BPITCH + bc + 64] = ub1;
            }
        }
        __syncthreads();
    }

    // epilogue
#pragma unroll
    for (int mt = 0; mt < 2; mt++) {
#pragma unroll
        for (int nt = 0; nt < NT; nt++) {
            const int col = bn + wx * (BN / 2) + nt * 8 + 2 * tig;
            float bv0 = 0.0f, bv1 = 0.0f;
            if (bias) { bv0 = bias[col]; bv1 = bias[col + 1]; }
#pragma unroll
            for (int half = 0; half < 2; half++) {
                const int row = bm + wy * 32 + mt * 16 + gid + half * 8;
                float v0 = acc[mt][nt][half * 2 + 0] + bv0;
                float v1 = acc[mt][nt][half * 2 + 1] + bv1;
                if (mode == EPI_RESID) {
                    v0 += resid[(size_t)row * N + col];
                    v1 += resid[(size_t)row * N + col + 1];
                } else if (mode == EPI_RELU) {
                    v0 = fmaxf(v0, 0.0f);
                    v1 = fmaxf(v1, 0.0f);
                }
                float2 vv = {v0, v1};
                if (mode == EPI_QKV) {
                    const int b = row >> 9, ii = row & 511;
                    const int which = col >> 9;
                    const int cc = col & 511;
                    const int h = cc >> 6, d = cc & 63;
                    float* base = (which == 0) ? C : (which == 1) ? C2 : C3;
                    *(float2*)(base + (((size_t)(b * CH + h) * CS) + ii) * CD + d) = vv;
                } else {
                    *(float2*)(C + (size_t)row * N + col) = vv;
                }
            }
        }
    }
}

// ---------------- pack QKV weights/biases --------------------------------------
__global__ void pack_qkv_kernel(const float* __restrict__ wq, const float* __restrict__ wk,
                                const float* __restrict__ wv, const float* __restrict__ bq,
                                const float* __restrict__ bk, const float* __restrict__ bv)
{
    int idx = blockIdx.x * 256 + threadIdx.x;
    if (idx < CE * CE) {
        int r = idx >> 9, c = idx & 511;
        g_wqkv[(size_t)r * 1536 + c] = wq[idx];
        g_wqkv[(size_t)r * 1536 + 512 + c] = wk[idx];
        g_wqkv[(size_t)r * 1536 + 1024 + c] = wv[idx];
    }
    if (idx < CE) {
        g_bqkv[idx] = bq[idx];
        g_bqkv[512 + idx] = bk[idx];
        g_bqkv[1024 + idx] = bv[idx];
    }
}

// ---------------- pad pos_emb into g_pe ---------------------------------------
__global__ void pe_copy_kernel(const float* __restrict__ pe)
{
    int t = blockIdx.x * 256 + threadIdx.x;
    if (t < CNR * CD) g_pe[t] = pe[t];
}

// ---------------- qz (tensor, tf32x3): (32768x64) @ (64x129->144) --------------
#define QZ_AH 0
#define QZ_AL (128*68)
#define QZ_BH (2*128*68)
#define QZ_BL (2*128*68 + 64*148)
#define QZ_SMEM_BYTES ((2*128*68 + 2*64*148) * 4)

__global__ __launch_bounds__(256) void qz_mma_kernel(const float* __restrict__ pe)
{
    extern __shared__ uint32_t sm[];
    uint32_t* AH = sm + QZ_AH;
    uint32_t* AL = sm + QZ_AL;
    uint32_t* BH = sm + QZ_BH;
    uint32_t* BL = sm + QZ_BL;

    const int m0 = blockIdx.x << 7;     // 128 q rows
    const int tid = threadIdx.x;
    const int warp = tid >> 5;
    const int lane = tid & 31;
    const int gid = lane >> 2;
    const int tig = lane & 3;
    const int wy = warp >> 1;
    const int wx = warp & 1;

    for (int t = tid; t < 64 * 148; t += 256) { BH[t] = 0u; BL[t] = 0u; }
    __syncthreads();

#pragma unroll
    for (int l = 0; l < 8; l++) {
        const int idx = tid + (l << 8);
        const int r = idx >> 4;
        const int c = (idx & 15) << 2;
        float4 qv = *(const float4*)(g_q + (size_t)(m0 + r) * CD + c);
        uint32_t hh, ll;
        split_tf32(qv.x, hh, ll); AH[r*68 + c + 0] = hh; AL[r*68 + c + 0] = ll;
        split_tf32(qv.y, hh, ll); AH[r*68 + c + 1] = hh; AL[r*68 + c + 1] = ll;
        split_tf32(qv.z, hh, ll); AH[r*68 + c + 2] = hh; AL[r*68 + c + 2] = ll;
        split_tf32(qv.w, hh, ll); AH[r*68 + c + 3] = hh; AL[r*68 + c + 3] = ll;
    }
    for (int t = tid; t < CNR * 16; t += 256) {
        const int n = t >> 4;
        const int k = (t & 15) << 2;
        float4 pv = *(const float4*)(pe + (size_t)n * CD + k);
        uint32_t hh, ll;
        split_tf32(pv.x, hh, ll); BH[(k+0)*148 + n] = hh; BL[(k+0)*148 + n] = ll;
        split_tf32(pv.y, hh, ll); BH[(k+1)*148 + n] = hh; BL[(k+1)*148 + n] = ll;
        split_tf32(pv.z, hh, ll); BH[(k+2)*148 + n] = hh; BL[(k+2)*148 + n] = ll;
        split_tf32(pv.w, hh, ll); BH[(k+3)*148 + n] = hh; BL[(k+3)*148 + n] = ll;
    }
    __syncthreads();

    float acc[2][9][4];
#pragma unroll
    for (int mt = 0; mt < 2; mt++)
#pragma unroll
        for (int nt = 0; nt < 9; nt++)
#pragma unroll
            for (int r = 0; r < 4; r++) acc[mt][nt][r] = 0.0f;

#pragma unroll
    for (int ks = 0; ks < 64; ks += 8) {
        uint32_t ah[2][4], al[2][4];
#pragma unroll
        for (int mt = 0; mt < 2; mt++) {
            const int mrow = wy * 32 + mt * 16 + gid;
            ah[mt][0] = AH[mrow*68 + ks + tig];
            ah[mt][1] = AH[(mrow+8)*68 + ks + tig];
            ah[mt][2] = AH[mrow*68 + ks + tig + 4];
            ah[mt][3] = AH[(mrow+8)*68 + ks + tig + 4];
            al[mt][0] = AL[mrow*68 + ks + tig];
            al[mt][1] = AL[(mrow+8)*68 + ks + tig];
            al[mt][2] = AL[mrow*68 + ks + tig + 4];
            al[mt][3] = AL[(mrow+8)*68 + ks + tig + 4];
        }
        uint32_t bhf[9][2], blf[9][2];
#pragma unroll
        for (int nt = 0; nt < 9; nt++) {
            const int nc = wx * 72 + nt * 8 + gid;
            bhf[nt][0] = BH[(ks + tig)*148 + nc];
            bhf[nt][1] = BH[(ks + tig + 4)*148 + nc];
            blf[nt][0] = BL[(ks + tig)*148 + nc];
            blf[nt][1] = BL[(ks + tig + 4)*148 + nc];
        }
#pragma unroll
        for (int mt = 0; mt < 2; mt++)
#pragma unroll
            for (int nt = 0; nt < 9; nt++) {
                mma_tf32(acc[mt][nt], ah[mt], blf[nt]);
                mma_tf32(acc[mt][nt], al[mt], bhf[nt]);
                mma_tf32(acc[mt][nt], ah[mt], bhf[nt]);
            }
    }

#pragma unroll
    for (int mt = 0; mt < 2; mt++)
#pragma unroll
        for (int nt = 0; nt < 9; nt++) {
            const int col = wx * 72 + nt * 8 + 2 * tig;
#pragma unroll
            for (int half = 0; half < 2; half++) {
                const int row = m0 + wy * 32 + mt * 16 + gid + half * 8;
                float2 vv = {acc[mt][nt][half*2+0], acc[mt][nt][half*2+1]};
                *(float2*)&g_qz[(size_t)row * QZP + col] = vv;
            }
        }
}

// ---------------- scores (tensor, tf32x3): 128x128 tile -----------------------
#define SC_QH 0
#define SC_QL (128*68)
#define SC_KH (2*128*68)
#define SC_KL (2*128*68 + 64*132)
#define SC_INT (2*128*68 + 2*64*132)
#define SC_SMEM_BYTES ((SC_INT + 3*128) * 4)

__global__ __launch_bounds__(256) void scores_mma_kernel(
    const float* __restrict__ dist, const int* __restrict__ dt,
    const int* __restrict__ mask)
{
    extern __shared__ uint32_t sm[];
    uint32_t* QH = sm + SC_QH;
    uint32_t* QL = sm + SC_QL;
    uint32_t* KH = sm + SC_KH;
    uint32_t* KL = sm + SC_KL;
    int* dti_s = (int*)(sm + SC_INT);
    int* dtj_s = dti_s + 128;
    int* mj_s = dtj_s + 128;

    const int bh = blockIdx.z;
    const int b = bh >> 3;
    const int i0 = blockIdx.y << 7;
    const int j0 = blockIdx.x << 7;
    const int tid = threadIdx.x;
    const int warp = tid >> 5;
    const int lane = tid & 31;
    const int gid = lane >> 2;
    const int tig = lane & 3;
    const int wy = warp >> 1;
    const int wx = warp & 1;

    const float* qb = g_q + (size_t)bh * CS * CD;
    const float* kb = g_k + (size_t)bh * CS * CD;

#pragma unroll
    for (int l = 0; l < 8; l++) {
        const int idx = tid + (l << 8);
        const int r = idx >> 4;
        const int c = (idx & 15) << 2;
        float4 qv = *(const float4*)(qb + (size_t)(i0 + r) * CD + c);
        float4 kv = *(const float4*)(kb + (size_t)(j0 + r) * CD + c);
        uint32_t h0, l0;
        split_tf32(qv.x, h0, l0); QH[r*68 + c + 0] = h0; QL[r*68 + c + 0] = l0;
        split_tf32(qv.y, h0, l0); QH[r*68 + c + 1] = h0; QL[r*68 + c + 1] = l0;
        split_tf32(qv.z, h0, l0); QH[r*68 + c + 2] = h0; QL[r*68 + c + 2] = l0;
        split_tf32(qv.w, h0, l0); QH[r*68 + c + 3] = h0; QL[r*68 + c + 3] = l0;
        split_tf32(kv.x, h0, l0); KH[(c+0)*132 + r] = h0; KL[(c+0)*132 + r] = l0;
        split_tf32(kv.y, h0, l0); KH[(c+1)*132 + r] = h0; KL[(c+1)*132 + r] = l0;
        split_tf32(kv.z, h0, l0); KH[(c+2)*132 + r] = h0; KL[(c+2)*132 + r] = l0;
        split_tf32(kv.w, h0, l0); KH[(c+3)*132 + r] = h0; KL[(c+3)*132 + r] = l0;
    }
    if (tid < 128) {
        dti_s[tid] = dt[b * CS + i0 + tid];
        dtj_s[tid] = dt[b * CS + j0 + tid];
        mj_s[tid] = mask[b * CS + j0 + tid];
    }
    __syncthreads();

    float acc[2][8][4];
#pragma unroll
    for (int mt = 0; mt < 2; mt++)
#pragma unroll
        for (int nt = 0; nt < 8; nt++)
#pragma unroll
            for (int r = 0; r < 4; r++) acc[mt][nt][r] = 0.0f;

#pragma unroll
    for (int ks = 0; ks < 64; ks += 8) {
        uint32_t ah[2][4], al[2][4];
#pragma unroll
        for (int mt = 0; mt < 2; mt++) {
            const int mrow = wy * 32 + mt * 16 + gid;
            ah[mt][0] = QH[mrow*68 + ks + tig];
            ah[mt][1] = QH[(mrow+8)*68 + ks + tig];
            ah[mt][2] = QH[mrow*68 + ks + tig + 4];
            ah[mt][3] = QH[(mrow+8)*68 + ks + tig + 4];
            al[mt][0] = QL[mrow*68 + ks + tig];
            al[mt][1] = QL[(mrow+8)*68 + ks + tig];
            al[mt][2] = QL[mrow*68 + ks + tig + 4];
            al[mt][3] = QL[(mrow+8)*68 + ks + tig + 4];
        }
        uint32_t bhf[8][2], blf[8][2];
#pragma unroll
        for (int nt = 0; nt < 8; nt++) {
            const int nc = wx * 64 + nt * 8 + gid;
            bhf[nt][0] = KH[(ks + tig)*132 + nc];
            bhf[nt][1] = KH[(ks + tig + 4)*132 + nc];
            blf[nt][0] = KL[(ks + tig)*132 + nc];
            blf[nt][1] = KL[(ks + tig + 4)*132 + nc];
        }
#pragma unroll
        for (int mt = 0; mt < 2; mt++)
#pragma unroll
            for (int nt = 0; nt < 8; nt++) {
                mma_tf32(acc[mt][nt], ah[mt], blf[nt]);
                mma_tf32(acc[mt][nt], al[mt], bhf[nt]);
                mma_tf32(acc[mt][nt], ah[mt], bhf[nt]);
            }
    }

    // epilogue: qz gather + dist + mask
#pragma unroll
    for (int mt = 0; mt < 2; mt++) {
#pragma unroll
        for (int half = 0; half < 2; half++) {
            const int il = wy * 32 + mt * 16 + gid + half * 8;
            const int i = i0 + il;
            const int di = dti_s[il];
            const size_t qzrow = ((size_t)bh * CS + i) * QZP;
            const size_t drow = ((size_t)b * CS + i) * CS;
            const size_t wrow = ((size_t)bh * CS + i) * CS;
#pragma unroll
            for (int nt = 0; nt < 8; nt++) {
                const int jl = wx * 64 + nt * 8 + 2 * tig;
                float ov[2];
#pragma unroll
                for (int u = 0; u < 2; u++) {
                    const int jloc = jl + u;
                    int rel = min(max(dtj_s[jloc] - di, -CP), CP) + CP;
                    float v = (acc[mt][nt][half*2+u] + g_qz[qzrow + rel]) * 0.125f
                            + 0.6f * dist[drow + j0 + jloc];
                    if (mj_s[jloc] == 0) v = -1e9f;
                    ov[u] = v;
                }
                float2 st = {ov[0], ov[1]};
                *(float2*)&g_w[wrow + j0 + jl] = st;
            }
        }
    }
}

// ---------------- softmax + 129-bin histogram ---------------------------------
__global__ __launch_bounds__(256) void softmax_kernel(const int* __restrict__ dt)
{
    const int row = blockIdx.x;           // bh*S + i
    const int bh = row >> 9;
    const int i = row & 511;
    const int b = bh >> 3;
    float* wr = g_w + (size_t)row * CS;
    const int tid = threadIdx.x;

    __shared__ float red[256];
    __shared__ float bins[CNR];

    float v0 = wr[tid], v1 = wr[tid + 256];
    red[tid] = fmaxf(v0, v1);
    __syncthreads();
    for (int s = 128; s > 0; s >>= 1) {
        if (tid < s) red[tid] = fmaxf(red[tid], red[tid + s]);
        __syncthreads();
    }
    const float mx = red[0];
    __syncthreads();

    const float e0 = __expf(v0 - mx);
    const float e1 = __expf(v1 - mx);
    red[tid] = e0 + e1;
    __syncthreads();
    for (int s = 128; s > 0; s >>= 1) {
        if (tid < s) red[tid] += red[tid + s];
        __syncthreads();
    }
    const float inv = 1.0f / red[0];
    if (tid < CNR) bins[tid] = 0.0f;
    __syncthreads();

    const float a0 = e0 * inv, a1 = e1 * inv;
    wr[tid] = a0;
    wr[tid + 256] = a1;

    const int di = dt[b * CS + i];
    int r0 = min(max(dt[b * CS + tid] - di, -CP), CP) + CP;
    int r1 = min(max(dt[b * CS + tid + 256] - di, -CP), CP) + CP;
    atomicAdd(&bins[r0], a0);
    atomicAdd(&bins[r1], a1);
    __syncthreads();
    if (tid < CNR) g_s[(size_t)row * CSR + tid] = bins[tid];
}

// ---------------- attn (tensor, single-pass tf32): 128x64 tile -----------------
// dynamic smem (uint32): A[128*68], B[64*68]
#define AT_A 0
#define AT_B (128*68)
#define AT_SMEM_BYTES ((128*68 + 64*68) * 4)

__global__ __launch_bounds__(256, 2) void attn_mma_kernel()
{
    extern __shared__ uint32_t sm[];
    uint32_t* Asm = sm + AT_A;
    uint32_t* Bsm = sm + AT_B;

    const int bh = blockIdx.y;
    const int b = bh >> 3, h = bh & 7;
    const int i0 = blockIdx.x << 7;
    const int tid = threadIdx.x;
    const int warp = tid >> 5;
    const int lane = tid & 31;
    const int gid = lane >> 2;
    const int tig = lane & 3;
    const int wy = warp >> 1;
    const int wx = warp & 1;

    const float* awb = g_w + (size_t)bh * CS * CS;
    const float* sb = g_s + (size_t)bh * CS * CSR;
    const float* vb = g_v + (size_t)bh * CS * CD;

    float acc[2][4][4];
#pragma unroll
    for (int mt = 0; mt < 2; mt++)
#pragma unroll
        for (int nt = 0; nt < 4; nt++)
#pragma unroll
            for (int r = 0; r < 4; r++) acc[mt][nt][r] = 0.0f;

    for (int c = 0; c < 11; c++) {
        // stage A: 128 x 64 (single tf32)
#pragma unroll
        for (int l = 0; l < 8; l++) {
            const int idx = tid + (l << 8);
            const int r = idx >> 4;
            const int cc = (idx & 15) << 2;
            float4 av;
            if (c < 8) av = *(const float4*)(awb + (size_t)(i0 + r) * CS + (c << 6) + cc);
            else       av = *(const float4*)(sb + (size_t)(i0 + r) * CSR + ((c - 8) << 6) + cc);
            uint4 ua = {f2tf(av.x), f2tf(av.y), f2tf(av.z), f2tf(av.w)};
            *(uint4*)&Asm[r*68 + cc] = ua;
        }
        // stage B: 64 x 64 (row = k, col = d)
#pragma unroll
        for (int l = 0; l < 4; l++) {
            const int idx = tid + (l << 8);
            const int r = idx >> 4;
            const int cc = (idx & 15) << 2;
            float4 vv;
            if (c < 8) vv = *(const float4*)(vb + (size_t)((c << 6) + r) * CD + cc);
            else       vv = *(const float4*)(g_pe + (size_t)(((c - 8) << 6) + r) * CD + cc);
            uint4 ub = {f2tf(vv.x), f2tf(vv.y), f2tf(vv.z), f2tf(vv.w)};
            *(uint4*)&Bsm[r*68 + cc] = ub;
        }
        __syncthreads();

#pragma unroll
        for (int ks = 0; ks < 64; ks += 8) {
            uint32_t af[2][4];
#pragma unroll
            for (int mt = 0; mt < 2; mt++) {
                const int mrow = wy * 32 + mt * 16 + gid;
                af[mt][0] = Asm[mrow*68 + ks + tig];
                af[mt][1] = Asm[(mrow+8)*68 + ks + tig];
                af[mt][2] = Asm[mrow*68 + ks + tig + 4];
                af[mt][3] = Asm[(mrow+8)*68 + ks + tig + 4];
            }
            uint32_t bf[4][2];
#pragma unroll
            for (int nt = 0; nt < 4; nt++) {
                const int nc = wx * 32 + nt * 8 + gid;
                bf[nt][0] = Bsm[(ks + tig)*68 + nc];
                bf[nt][1] = Bsm[(ks + tig + 4)*68 + nc];
            }
#pragma unroll
            for (int mt = 0; mt < 2; mt++)
#pragma unroll
                for (int nt = 0; nt < 4; nt++)
                    mma_tf32(acc[mt][nt], af[mt], bf[nt]);
        }
        __syncthreads();
    }

#pragma unroll
    for (int mt = 0; mt < 2; mt++)
#pragma unroll
        for (int nt = 0; nt < 4; nt++) {
            const int col = wx * 32 + nt * 8 + 2 * tig;
#pragma unroll
            for (int half = 0; half < 2; half++) {
                const int row = wy * 32 + mt * 16 + gid + half * 8;
                float2 vv = {acc[mt][nt][half*2+0], acc[mt][nt][half*2+1]};
                *(float2*)&g_concat[(size_t)(b * CS + i0 + row) * CE + h * CD + col] = vv;
            }
        }
}

// ---------------- layernorm (row = 512) ---------------------------------------
__global__ __launch_bounds__(256) void ln_kernel(
    const float* __restrict__ in, float* __restrict__ out,
    const float* __restrict__ gg, const float* __restrict__ bb)
{
    const int row = blockIdx.x;
    const float* xr = in + (size_t)row * CE;
    const int tid = threadIdx.x;
    __shared__ float red[256];

    float v0 = xr[tid], v1 = xr[tid + 256];
    red[tid] = v0 + v1;
    __syncthreads();
    for (int s = 128; s > 0; s >>= 1) {
        if (tid < s) red[tid] += red[tid + s];
        __syncthreads();
    }
    const float mu = red[0] * (1.0f / CE);
    __syncthreads();
    const float d0 = v0 - mu, d1 = v1 - mu;
    red[tid] = d0 * d0 + d1 * d1;
    __syncthreads();
    for (int s = 128; s > 0; s >>= 1) {
        if (tid < s) red[tid] += red[tid + s];
        __syncthreads();
    }
    const float rstd = rsqrtf(red[0] * (1.0f / CE) + 1e-5f);
    out[(size_t)row * CE + tid] = d0 * rstd * gg[tid] + bb[tid];
    out[(size_t)row * CE + tid + 256] = d1 * rstd * gg[tid + 256] + bb[tid + 256];
}

// ---------------- launch -------------------------------------------------------
extern "C" void kernel_launch(void* const* d_in, const int* in_sizes, int n_in,
                              void* d_out, int out_size)
{
    const float* x    = (const float*)d_in[0];
    const float* dist = (const float*)d_in[1];
    const int*   dt   = (const int*)d_in[2];
    const int*   mask = (const int*)d_in[3];
    const float* wq_w = (const float*)d_in[4];
    const float* wq_b = (const float*)d_in[5];
    const float* wk_w = (const float*)d_in[6];
    const float* wk_b = (const float*)d_in[7];
    const float* wv_w = (const float*)d_in[8];
    const float* wv_b = (const float*)d_in[9];
    const float* wo_w = (const float*)d_in[10];
    const float* wo_b = (const float*)d_in[11];
    const float* pe   = (const float*)d_in[12];
    const float* w1   = (const float*)d_in[13];
    const float* b1   = (const float*)d_in[14];
    const float* w2   = (const float*)d_in[15];
    const float* b2   = (const float*)d_in[16];
    const float* ln1g = (const float*)d_in[17];
    const float* ln1b = (const float*)d_in[18];
    const float* ln2g = (const float*)d_in[19];
    const float* ln2b = (const float*)d_in[20];
    float* out = (float*)d_out;

    void *pq, *pk, *pv, *pcc, *pt1, *pao, *phid, *pt2, *pwqkv, *pbqkv;
    cudaGetSymbolAddress(&pq, g_q);
    cudaGetSymbolAddress(&pk, g_k);
    cudaGetSymbolAddress(&pv, g_v);
    cudaGetSymbolAddress(&pcc, g_concat);
    cudaGetSymbolAddress(&pt1, g_t1);
    cudaGetSymbolAddress(&pao, g_attnout);
    cudaGetSymbolAddress(&phid, g_hidden);
    cudaGetSymbolAddress(&pt2, g_t2);
    cudaGetSymbolAddress(&pwqkv, g_wqkv);
    cudaGetSymbolAddress(&pbqkv, g_bqkv);

    cudaFuncSetAttribute(scores_mma_kernel,
                         cudaFuncAttributeMaxDynamicSharedMemorySize, SC_SMEM_BYTES);
    cudaFuncSetAttribute(attn_mma_kernel,
                         cudaFuncAttributeMaxDynamicSharedMemorySize, AT_SMEM_BYTES);
    cudaFuncSetAttribute(qz_mma_kernel,
                         cudaFuncAttributeMaxDynamicSharedMemorySize, QZ_SMEM_BYTES);

    pe_copy_kernel<<<(CNR * CD + 255) / 256, 256>>>(pe);
    pack_qkv_kernel<<<(CE * CE + 255) / 256, 256>>>(wq_w, wk_w, wv_w, wq_b, wk_b, wv_b);

    // fused QKV: M=4096, N=1536, K=512
    dim3 gq(1536 / 128, CM / 128);
    mma_gemm_kernel<128><<<gq, 256>>>(x, (const float*)pwqkv, (float*)pq, (float*)pk, (float*)pv,
                                      CM, 1536, CE, (const float*)pbqkv, nullptr, EPI_QKV);

    qz_mma_kernel<<<(CBH * CS) / 128, 256, QZ_SMEM_BYTES>>>(pe);

    dim3 gsc(CS / 128, CS / 128, CBH);
    scores_mma_kernel<<<gsc, 256, SC_SMEM_BYTES>>>(dist, dt, mask);

    softmax_kernel<<<CBH * CS, 256>>>(dt);

    dim3 gat(CS / 128, CBH);
    attn_mma_kernel<<<gat, 256, AT_SMEM_BYTES>>>();

    dim3 gwo(CE / 64, CM / 128);
    mma_gemm_kernel<64><<<gwo, 256>>>((const float*)pcc, wo_w, (float*)pt1, nullptr, nullptr,
                                      CM, CE, CE, wo_b, x, EPI_RESID);
    ln_kernel<<<CM, 256>>>((const float*)pt1, (float*)pao, ln1g, ln1b);

    dim3 gf1(CF / 128, CM / 128);
    mma_gemm_kernel<128><<<gf1, 256>>>((const float*)pao, w1, (float*)phid, nullptr, nullptr,
                                       CM, CF, CE, b1, nullptr, EPI_RELU);
    dim3 gf2(CE / 64, CM / 128);
    mma_gemm_kernel<64><<<gf2, 256>>>((const float*)phid, w2, (float*)pt2, nullptr, nullptr,
                                      CM, CE, CF, b2, (const float*)pao, EPI_RESID);
    ln_kernel<<<CM, 256>>>((const float*)pt2, out, ln2g, ln2b);
}

// round 6
// speedup vs baseline: 1.5388x; 1.1334x over previous
#include <cuda_runtime.h>
#include <cstdint>
#include <cstddef>

// Problem constants
#define CB 8
#define CS 512
#define CE 512
#define CH 8
#define CD 64
#define CP 64
#define CF 2048
#define CNR 129            // 2P+1
#define QZP 144            // padded qz row stride
#define CSR 192            // padded stride for bins / pos_emb (3 chunks of 64)
#define CBH (CB*CH)        // 64
#define CM (CB*CS)         // 4096

// ---------------- device scratch (zero-initialized .bss) ----------------------
__device__ __align__(16) float g_q[CBH*CS*CD];
__device__ __align__(16) float g_k[CBH*CS*CD];
__device__ __align__(16) float g_v[CBH*CS*CD];
__device__ __align__(16) float g_qz[(size_t)CBH*CS*QZP];
__device__ __align__(16) float g_w[CBH*CS*CS];          // scores -> aw (in place)
__device__ __align__(16) float g_s[CBH*CS*CSR];         // softmax bins (padded)
__device__ __align__(16) float g_pe[CSR*CD];            // padded pos_emb
__device__ __align__(16) float g_concat[CM*CE];
__device__ __align__(16) float g_t1[CM*CE];
__device__ __align__(16) float g_attnout[CM*CE];
__device__ __align__(16) float g_hidden[CM*CF];
__device__ __align__(16) float g_t2[CM*CE];
__device__ __align__(16) float g_wqkv[CE*3*CE];         // packed [512][1536]
__device__ __align__(16) float g_bqkv[3*CE];

enum { EPI_QKV = 0, EPI_RESID = 1, EPI_RELU = 2 };

__device__ __forceinline__ uint32_t f2tf(float f) {
    uint32_t u;
    asm("cvt.rna.tf32.f32 %0, %1;" : "=r"(u) : "f"(f));
    return u;
}

__device__ __forceinline__ void mma_tf32(float c[4], const uint32_t a[4],
                                         const uint32_t b[2]) {
    asm volatile(
        "mma.sync.aligned.m16n8k8.row.col.f32.tf32.tf32.f32 "
        "{%0,%1,%2,%3}, {%4,%5,%6,%7}, {%8,%9}, {%0,%1,%2,%3};\n"
        : "+f"(c[0]), "+f"(c[1]), "+f"(c[2]), "+f"(c[3])
        : "r"(a[0]), "r"(a[1]), "r"(a[2]), "r"(a[3]), "r"(b[0]), "r"(b[1]));
}

// ---------------- TF32 tensor-core GEMM: C = A(MxK)@B(KxN) + epilogue ---------
#define APITCH 20

template<int BN>
__global__ __launch_bounds__(256, 2) void mma_gemm_kernel(
    const float* __restrict__ A, const float* __restrict__ Bm,
    float* __restrict__ C, float* __restrict__ C2, float* __restrict__ C3,
    int M, int N, int K,
    const float* __restrict__ bias, const float* __restrict__ resid, int mode)
{
    constexpr int BPITCH = BN + 4;
    constexpr int NT = BN / 16;
    __shared__ uint32_t As[2][128 * APITCH];
    __shared__ uint32_t Bs[2][16 * BPITCH];

    const int tid = threadIdx.x;
    const int warp = tid >> 5;
    const int lane = tid & 31;
    const int gid = lane >> 2;
    const int tig = lane & 3;
    const int wy = warp >> 1;
    const int wx = warp & 1;
    const int bm = blockIdx.y * 128;
    const int bn = blockIdx.x * BN;

    const int ar = tid >> 1;
    const int ak = (tid & 1) << 3;
    const int br = tid >> 4;
    const int bc = (tid & 15) << 2;

    const float* Ap = A + (size_t)(bm + ar) * K + ak;
    const float* Bp = Bm + (size_t)br * N + bn + bc;

    float acc[2][NT][4];
#pragma unroll
    for (int mt = 0; mt < 2; mt++)
#pragma unroll
        for (int nt = 0; nt < NT; nt++)
#pragma unroll
            for (int r = 0; r < 4; r++) acc[mt][nt][r] = 0.0f;

    {
        float4 a0 = *(const float4*)(Ap + 0);
        float4 a1 = *(const float4*)(Ap + 4);
        uint4 ua0 = {f2tf(a0.x), f2tf(a0.y), f2tf(a0.z), f2tf(a0.w)};
        uint4 ua1 = {f2tf(a1.x), f2tf(a1.y), f2tf(a1.z), f2tf(a1.w)};
        *(uint4*)&As[0][ar * APITCH + ak] = ua0;
        *(uint4*)&As[0][ar * APITCH + ak + 4] = ua1;
        float4 b0 = *(const float4*)(Bp + 0);
        uint4 ub0 = {f2tf(b0.x), f2tf(b0.y), f2tf(b0.z), f2tf(b0.w)};
        *(uint4*)&Bs[0][br * BPITCH + bc] = ub0;
        if (BN == 128) {
            float4 b1 = *(const float4*)(Bp + 64);
            uint4 ub1 = {f2tf(b1.x), f2tf(b1.y), f2tf(b1.z), f2tf(b1.w)};
            *(uint4*)&Bs[0][br * BPITCH + bc + 64] = ub1;
        }
    }
    __syncthreads();

    for (int k0 = 0; k0 < K; k0 += 16) {
        const int buf = (k0 >> 4) & 1;
        const bool has_next = (k0 + 16) < K;
        float4 ra0, ra1, rb0, rb1;
        if (has_next) {
            ra0 = *(const float4*)(Ap + k0 + 16);
            ra1 = *(const float4*)(Ap + k0 + 20);
            rb0 = *(const float4*)(Bp + (size_t)(k0 + 16) * N);
            if (BN == 128) rb1 = *(const float4*)(Bp + (size_t)(k0 + 16) * N + 64);
        }

#pragma unroll
        for (int ks = 0; ks < 16; ks += 8) {
            uint32_t af[2][4];
#pragma unroll
            for (int mt = 0; mt < 2; mt++) {
                const int mrow = wy * 32 + mt * 16 + gid;
                af[mt][0] = As[buf][mrow * APITCH + ks + tig];
                af[mt][1] = As[buf][(mrow + 8) * APITCH + ks + tig];
                af[mt][2] = As[buf][mrow * APITCH + ks + tig + 4];
                af[mt][3] = As[buf][(mrow + 8) * APITCH + ks + tig + 4];
            }
            uint32_t bf[NT][2];
#pragma unroll
            for (int nt = 0; nt < NT; nt++) {
                const int nc = wx * (BN / 2) + nt * 8 + gid;
                bf[nt][0] = Bs[buf][(ks + tig) * BPITCH + nc];
                bf[nt][1] = Bs[buf][(ks + tig + 4) * BPITCH + nc];
            }
#pragma unroll
            for (int mt = 0; mt < 2; mt++)
#pragma unroll
                for (int nt = 0; nt < NT; nt++)
                    mma_tf32(acc[mt][nt], af[mt], bf[nt]);
        }

        if (has_next) {
            const int nb = buf ^ 1;
            uint4 ua0 = {f2tf(ra0.x), f2tf(ra0.y), f2tf(ra0.z), f2tf(ra0.w)};
            uint4 ua1 = {f2tf(ra1.x), f2tf(ra1.y), f2tf(ra1.z), f2tf(ra1.w)};
            *(uint4*)&As[nb][ar * APITCH + ak] = ua0;
            *(uint4*)&As[nb][ar * APITCH + ak + 4] = ua1;
            uint4 ub0 = {f2tf(rb0.x), f2tf(rb0.y), f2tf(rb0.z), f2tf(rb0.w)};
            *(uint4*)&Bs[nb][br * BPITCH + bc] = ub0;
            if (BN == 128) {
                uint4 ub1 = {f2tf(rb1.x), f2tf(rb1.y), f2tf(rb1.z), f2tf(rb1.w)};
                *(uint4*)&Bs[nb][br * BPITCH + bc + 64] = ub1;
            }
        }
        __syncthreads();
    }

#pragma unroll
    for (int mt = 0; mt < 2; mt++) {
#pragma unroll
        for (int nt = 0; nt < NT; nt++) {
            const int col = bn + wx * (BN / 2) + nt * 8 + 2 * tig;
            float bv0 = 0.0f, bv1 = 0.0f;
            if (bias) { bv0 = bias[col]; bv1 = bias[col + 1]; }
#pragma unroll
            for (int half = 0; half < 2; half++) {
                const int row = bm + wy * 32 + mt * 16 + gid + half * 8;
                float v0 = acc[mt][nt][half * 2 + 0] + bv0;
                float v1 = acc[mt][nt][half * 2 + 1] + bv1;
                if (mode == EPI_RESID) {
                    v0 += resid[(size_t)row * N + col];
                    v1 += resid[(size_t)row * N + col + 1];
                } else if (mode == EPI_RELU) {
                    v0 = fmaxf(v0, 0.0f);
                    v1 = fmaxf(v1, 0.0f);
                }
                float2 vv = {v0, v1};
                if (mode == EPI_QKV) {
                    const int b = row >> 9, ii = row & 511;
                    const int which = col >> 9;
                    const int cc = col & 511;
                    const int h = cc >> 6, d = cc & 63;
                    float* base = (which == 0) ? C : (which == 1) ? C2 : C3;
                    *(float2*)(base + (((size_t)(b * CH + h) * CS) + ii) * CD + d) = vv;
                } else {
                    *(float2*)(C + (size_t)row * N + col) = vv;
                }
            }
        }
    }
}

// ---------------- pack QKV weights/biases --------------------------------------
__global__ void pack_qkv_kernel(const float* __restrict__ wq, const float* __restrict__ wk,
                                const float* __restrict__ wv, const float* __restrict__ bq,
                                const float* __restrict__ bk, const float* __restrict__ bv)
{
    int idx = blockIdx.x * 256 + threadIdx.x;
    if (idx < CE * CE) {
        int r = idx >> 9, c = idx & 511;
        g_wqkv[(size_t)r * 1536 + c] = wq[idx];
        g_wqkv[(size_t)r * 1536 + 512 + c] = wk[idx];
        g_wqkv[(size_t)r * 1536 + 1024 + c] = wv[idx];
    }
    if (idx < CE) {
        g_bqkv[idx] = bq[idx];
        g_bqkv[512 + idx] = bk[idx];
        g_bqkv[1024 + idx] = bv[idx];
    }
}

// ---------------- pad pos_emb into g_pe ---------------------------------------
__global__ void pe_copy_kernel(const float* __restrict__ pe)
{
    int t = blockIdx.x * 256 + threadIdx.x;
    if (t < CNR * CD) g_pe[t] = pe[t];
}

// ---------------- qz (tensor, single tf32): (32768x64) @ (64x129->144) ---------
// dynamic smem (uint32): A[128*68], B[64*148]
#define QZ_A 0
#define QZ_B (128*68)
#define QZ_SMEM_BYTES ((128*68 + 64*148) * 4)

__global__ __launch_bounds__(256, 2) void qz_mma_kernel(const float* __restrict__ pe)
{
    extern __shared__ uint32_t sm[];
    uint32_t* Asm = sm + QZ_A;
    uint32_t* Bsm = sm + QZ_B;

    const int m0 = blockIdx.x << 7;
    const int tid = threadIdx.x;
    const int warp = tid >> 5;
    const int lane = tid & 31;
    const int gid = lane >> 2;
    const int tig = lane & 3;
    const int wy = warp >> 1;
    const int wx = warp & 1;

    for (int t = tid; t < 64 * 148; t += 256) Bsm[t] = 0u;
    __syncthreads();

#pragma unroll
    for (int l = 0; l < 8; l++) {
        const int idx = tid + (l << 8);
        const int r = idx >> 4;
        const int c = (idx & 15) << 2;
        float4 qv = *(const float4*)(g_q + (size_t)(m0 + r) * CD + c);
        uint4 ua = {f2tf(qv.x), f2tf(qv.y), f2tf(qv.z), f2tf(qv.w)};
        *(uint4*)&Asm[r*68 + c] = ua;
    }
    for (int t = tid; t < CNR * 16; t += 256) {
        const int n = t >> 4;
        const int k = (t & 15) << 2;
        float4 pv = *(const float4*)(pe + (size_t)n * CD + k);
        Bsm[(k+0)*148 + n] = f2tf(pv.x);
        Bsm[(k+1)*148 + n] = f2tf(pv.y);
        Bsm[(k+2)*148 + n] = f2tf(pv.z);
        Bsm[(k+3)*148 + n] = f2tf(pv.w);
    }
    __syncthreads();

    float acc[2][9][4];
#pragma unroll
    for (int mt = 0; mt < 2; mt++)
#pragma unroll
        for (int nt = 0; nt < 9; nt++)
#pragma unroll
            for (int r = 0; r < 4; r++) acc[mt][nt][r] = 0.0f;

#pragma unroll
    for (int ks = 0; ks < 64; ks += 8) {
        uint32_t af[2][4];
#pragma unroll
        for (int mt = 0; mt < 2; mt++) {
            const int mrow = wy * 32 + mt * 16 + gid;
            af[mt][0] = Asm[mrow*68 + ks + tig];
            af[mt][1] = Asm[(mrow+8)*68 + ks + tig];
            af[mt][2] = Asm[mrow*68 + ks + tig + 4];
            af[mt][3] = Asm[(mrow+8)*68 + ks + tig + 4];
        }
        uint32_t bf[9][2];
#pragma unroll
        for (int nt = 0; nt < 9; nt++) {
            const int nc = wx * 72 + nt * 8 + gid;
            bf[nt][0] = Bsm[(ks + tig)*148 + nc];
            bf[nt][1] = Bsm[(ks + tig + 4)*148 + nc];
        }
#pragma unroll
        for (int mt = 0; mt < 2; mt++)
#pragma unroll
            for (int nt = 0; nt < 9; nt++)
                mma_tf32(acc[mt][nt], af[mt], bf[nt]);
    }

#pragma unroll
    for (int mt = 0; mt < 2; mt++)
#pragma unroll
        for (int nt = 0; nt < 9; nt++) {
            const int col = wx * 72 + nt * 8 + 2 * tig;
#pragma unroll
            for (int half = 0; half < 2; half++) {
                const int row = m0 + wy * 32 + mt * 16 + gid + half * 8;
                float2 vv = {acc[mt][nt][half*2+0], acc[mt][nt][half*2+1]};
                *(float2*)&g_qz[(size_t)row * QZP + col] = vv;
            }
        }
}

// ---------------- scores (tensor, single tf32): 128x128 tile -------------------
// dynamic smem (uint32): Q[128*68], K[64*132], ints
#define SC_Q 0
#define SC_K (128*68)
#define SC_INT (128*68 + 64*132)
#define SC_SMEM_BYTES ((SC_INT + 3*128) * 4)

__global__ __launch_bounds__(256, 2) void scores_mma_kernel(
    const float* __restrict__ dist, const int* __restrict__ dt,
    const int* __restrict__ mask)
{
    extern __shared__ uint32_t sm[];
    uint32_t* Qs = sm + SC_Q;
    uint32_t* Ks = sm + SC_K;
    int* dti_s = (int*)(sm + SC_INT);
    int* dtj_s = dti_s + 128;
    int* mj_s = dtj_s + 128;

    const int bh = blockIdx.z;
    const int b = bh >> 3;
    const int i0 = blockIdx.y << 7;
    const int j0 = blockIdx.x << 7;
    const int tid = threadIdx.x;
    const int warp = tid >> 5;
    const int lane = tid & 31;
    const int gid = lane >> 2;
    const int tig = lane & 3;
    const int wy = warp >> 1;
    const int wx = warp & 1;

    const float* qb = g_q + (size_t)bh * CS * CD;
    const float* kb = g_k + (size_t)bh * CS * CD;

#pragma unroll
    for (int l = 0; l < 8; l++) {
        const int idx = tid + (l << 8);
        const int r = idx >> 4;
        const int c = (idx & 15) << 2;
        float4 qv = *(const float4*)(qb + (size_t)(i0 + r) * CD + c);
        float4 kv = *(const float4*)(kb + (size_t)(j0 + r) * CD + c);
        uint4 ua = {f2tf(qv.x), f2tf(qv.y), f2tf(qv.z), f2tf(qv.w)};
        *(uint4*)&Qs[r*68 + c] = ua;
        Ks[(c+0)*132 + r] = f2tf(kv.x);
        Ks[(c+1)*132 + r] = f2tf(kv.y);
        Ks[(c+2)*132 + r] = f2tf(kv.z);
        Ks[(c+3)*132 + r] = f2tf(kv.w);
    }
    if (tid < 128) {
        dti_s[tid] = dt[b * CS + i0 + tid];
        dtj_s[tid] = dt[b * CS + j0 + tid];
        mj_s[tid] = mask[b * CS + j0 + tid];
    }
    __syncthreads();

    float acc[2][8][4];
#pragma unroll
    for (int mt = 0; mt < 2; mt++)
#pragma unroll
        for (int nt = 0; nt < 8; nt++)
#pragma unroll
            for (int r = 0; r < 4; r++) acc[mt][nt][r] = 0.0f;

#pragma unroll
    for (int ks = 0; ks < 64; ks += 8) {
        uint32_t af[2][4];
#pragma unroll
        for (int mt = 0; mt < 2; mt++) {
            const int mrow = wy * 32 + mt * 16 + gid;
            af[mt][0] = Qs[mrow*68 + ks + tig];
            af[mt][1] = Qs[(mrow+8)*68 + ks + tig];
            af[mt][2] = Qs[mrow*68 + ks + tig + 4];
            af[mt][3] = Qs[(mrow+8)*68 + ks + tig + 4];
        }
        uint32_t bf[8][2];
#pragma unroll
        for (int nt = 0; nt < 8; nt++) {
            const int nc = wx * 64 + nt * 8 + gid;
            bf[nt][0] = Ks[(ks + tig)*132 + nc];
            bf[nt][1] = Ks[(ks + tig + 4)*132 + nc];
        }
#pragma unroll
        for (int mt = 0; mt < 2; mt++)
#pragma unroll
            for (int nt = 0; nt < 8; nt++)
                mma_tf32(acc[mt][nt], af[mt], bf[nt]);
    }

    // epilogue: qz gather + dist + mask
#pragma unroll
    for (int mt = 0; mt < 2; mt++) {
#pragma unroll
        for (int half = 0; half < 2; half++) {
            const int il = wy * 32 + mt * 16 + gid + half * 8;
            const int i = i0 + il;
            const int di = dti_s[il];
            const size_t qzrow = ((size_t)bh * CS + i) * QZP;
            const size_t drow = ((size_t)b * CS + i) * CS;
            const size_t wrow = ((size_t)bh * CS + i) * CS;
#pragma unroll
            for (int nt = 0; nt < 8; nt++) {
                const int jl = wx * 64 + nt * 8 + 2 * tig;
                float ov[2];
#pragma unroll
                for (int u = 0; u < 2; u++) {
                    const int jloc = jl + u;
                    int rel = min(max(dtj_s[jloc] - di, -CP), CP) + CP;
                    float v = (acc[mt][nt][half*2+u] + g_qz[qzrow + rel]) * 0.125f
                            + 0.6f * dist[drow + j0 + jloc];
                    if (mj_s[jloc] == 0) v = -1e9f;
                    ov[u] = v;
                }
                float2 st = {ov[0], ov[1]};
                *(float2*)&g_w[wrow + j0 + jl] = st;
            }
        }
    }
}

// ---------------- softmax + 129-bin histogram (shuffle reductions) -------------
__global__ __launch_bounds__(256) void softmax_kernel(const int* __restrict__ dt)
{
    const int row = blockIdx.x;           // bh*S + i
    const int bh = row >> 9;
    const int i = row & 511;
    const int b = bh >> 3;
    float* wr = g_w + (size_t)row * CS;
    const int tid = threadIdx.x;
    const int lane = tid & 31;
    const int wid = tid >> 5;

    __shared__ float wred[8];
    __shared__ float stat;
    __shared__ float bins[CNR];

    float2 v = *(const float2*)&wr[2 * tid];
    float m = fmaxf(v.x, v.y);
#pragma unroll
    for (int o = 16; o > 0; o >>= 1)
        m = fmaxf(m, __shfl_xor_sync(0xffffffffu, m, o));
    if (lane == 0) wred[wid] = m;
    if (tid < CNR) bins[tid] = 0.0f;
    __syncthreads();
    if (tid == 0) {
        float mm = wred[0];
#pragma unroll
        for (int k = 1; k < 8; k++) mm = fmaxf(mm, wred[k]);
        stat = mm;
    }
    __syncthreads();
    const float mx = stat;

    const float e0 = __expf(v.x - mx);
    const float e1 = __expf(v.y - mx);
    float s = e0 + e1;
#pragma unroll
    for (int o = 16; o > 0; o >>= 1)
        s += __shfl_xor_sync(0xffffffffu, s, o);
    if (lane == 0) wred[wid] = s;
    __syncthreads();
    if (tid == 0) {
        float ss = wred[0];
#pragma unroll
        for (int k = 1; k < 8; k++) ss += wred[k];
        stat = 1.0f / ss;
    }
    __syncthreads();
    const float inv = stat;

    const float a0 = e0 * inv, a1 = e1 * inv;
    float2 st = {a0, a1};
    *(float2*)&wr[2 * tid] = st;

    const int di = dt[b * CS + i];
    int2 dj = *(const int2*)&dt[b * CS + 2 * tid];
    int r0 = min(max(dj.x - di, -CP), CP) + CP;
    int r1 = min(max(dj.y - di, -CP), CP) + CP;
    atomicAdd(&bins[r0], a0);
    atomicAdd(&bins[r1], a1);
    __syncthreads();
    if (tid < CNR) g_s[(size_t)row * CSR + tid] = bins[tid];
}

// ---------------- attn (tensor, single-pass tf32): 128x64 tile -----------------
#define AT_A 0
#define AT_B (128*68)
#define AT_SMEM_BYTES ((128*68 + 64*68) * 4)

__global__ __launch_bounds__(256, 2) void attn_mma_kernel()
{
    extern __shared__ uint32_t sm[];
    uint32_t* Asm = sm + AT_A;
    uint32_t* Bsm = sm + AT_B;

    const int bh = blockIdx.y;
    const int b = bh >> 3, h = bh & 7;
    const int i0 = blockIdx.x << 7;
    const int tid = threadIdx.x;
    const int warp = tid >> 5;
    const int lane = tid & 31;
    const int gid = lane >> 2;
    const int tig = lane & 3;
    const int wy = warp >> 1;
    const int wx = warp & 1;

    const float* awb = g_w + (size_t)bh * CS * CS;
    const float* sb = g_s + (size_t)bh * CS * CSR;
    const float* vb = g_v + (size_t)bh * CS * CD;

    float acc[2][4][4];
#pragma unroll
    for (int mt = 0; mt < 2; mt++)
#pragma unroll
        for (int nt = 0; nt < 4; nt++)
#pragma unroll
            for (int r = 0; r < 4; r++) acc[mt][nt][r] = 0.0f;

    for (int c = 0; c < 11; c++) {
#pragma unroll
        for (int l = 0; l < 8; l++) {
            const int idx = tid + (l << 8);
            const int r = idx >> 4;
            const int cc = (idx & 15) << 2;
            float4 av;
            if (c < 8) av = *(const float4*)(awb + (size_t)(i0 + r) * CS + (c << 6) + cc);
            else       av = *(const float4*)(sb + (size_t)(i0 + r) * CSR + ((c - 8) << 6) + cc);
            uint4 ua = {f2tf(av.x), f2tf(av.y), f2tf(av.z), f2tf(av.w)};
            *(uint4*)&Asm[r*68 + cc] = ua;
        }
#pragma unroll
        for (int l = 0; l < 4; l++) {
            const int idx = tid + (l << 8);
            const int r = idx >> 4;
            const int cc = (idx & 15) << 2;
            float4 vv;
            if (c < 8) vv = *(const float4*)(vb + (size_t)((c << 6) + r) * CD + cc);
            else       vv = *(const float4*)(g_pe + (size_t)(((c - 8) << 6) + r) * CD + cc);
            uint4 ub = {f2tf(vv.x), f2tf(vv.y), f2tf(vv.z), f2tf(vv.w)};
            *(uint4*)&Bsm[r*68 + cc] = ub;
        }
        __syncthreads();

#pragma unroll
        for (int ks = 0; ks < 64; ks += 8) {
            uint32_t af[2][4];
#pragma unroll
            for (int mt = 0; mt < 2; mt++) {
                const int mrow = wy * 32 + mt * 16 + gid;
                af[mt][0] = Asm[mrow*68 + ks + tig];
                af[mt][1] = Asm[(mrow+8)*68 + ks + tig];
                af[mt][2] = Asm[mrow*68 + ks + tig + 4];
                af[mt][3] = Asm[(mrow+8)*68 + ks + tig + 4];
            }
            uint32_t bf[4][2];
#pragma unroll
            for (int nt = 0; nt < 4; nt++) {
                const int nc = wx * 32 + nt * 8 + gid;
                bf[nt][0] = Bsm[(ks + tig)*68 + nc];
                bf[nt][1] = Bsm[(ks + tig + 4)*68 + nc];
            }
#pragma unroll
            for (int mt = 0; mt < 2; mt++)
#pragma unroll
                for (int nt = 0; nt < 4; nt++)
                    mma_tf32(acc[mt][nt], af[mt], bf[nt]);
        }
        __syncthreads();
    }

#pragma unroll
    for (int mt = 0; mt < 2; mt++)
#pragma unroll
        for (int nt = 0; nt < 4; nt++) {
            const int col = wx * 32 + nt * 8 + 2 * tig;
#pragma unroll
            for (int half = 0; half < 2; half++) {
                const int row = wy * 32 + mt * 16 + gid + half * 8;
                float2 vv = {acc[mt][nt][half*2+0], acc[mt][nt][half*2+1]};
                *(float2*)&g_concat[(size_t)(b * CS + i0 + row) * CE + h * CD + col] = vv;
            }
        }
}

// ---------------- layernorm (row = 512) ---------------------------------------
__global__ __launch_bounds__(256) void ln_kernel(
    const float* __restrict__ in, float* __restrict__ out,
    const float* __restrict__ gg, const float* __restrict__ bb)
{
    const int row = blockIdx.x;
    const float* xr = in + (size_t)row * CE;
    const int tid = threadIdx.x;
    const int lane = tid & 31;
    const int wid = tid >> 5;
    __shared__ float wred[8];
    __shared__ float stat;

    float2 v = *(const float2*)&xr[2 * tid];
    float s = v.x + v.y;
#pragma unroll
    for (int o = 16; o > 0; o >>= 1) s += __shfl_xor_sync(0xffffffffu, s, o);
    if (lane == 0) wred[wid] = s;
    __syncthreads();
    if (tid == 0) {
        float ss = wred[0];
#pragma unroll
        for (int k = 1; k < 8; k++) ss += wred[k];
        stat = ss * (1.0f / CE);
    }
    __syncthreads();
    const float mu = stat;
    const float d0 = v.x - mu, d1 = v.y - mu;
    float q = d0 * d0 + d1 * d1;
#pragma unroll
    for (int o = 16; o > 0; o >>= 1) q += __shfl_xor_sync(0xffffffffu, q, o);
    if (lane == 0) wred[wid] = q;
    __syncthreads();
    if (tid == 0) {
        float qq = wred[0];
#pragma unroll
        for (int k = 1; k < 8; k++) qq += wred[k];
        stat = rsqrtf(qq * (1.0f / CE) + 1e-5f);
    }
    __syncthreads();
    const float rstd = stat;
    float2 gv = *(const float2*)&gg[2 * tid];
    float2 bv = *(const float2*)&bb[2 * tid];
    float2 ov = {d0 * rstd * gv.x + bv.x, d1 * rstd * gv.y + bv.y};
    *(float2*)&out[(size_t)row * CE + 2 * tid] = ov;
}

// ---------------- launch -------------------------------------------------------
extern "C" void kernel_launch(void* const* d_in, const int* in_sizes, int n_in,
                              void* d_out, int out_size)
{
    const float* x    = (const float*)d_in[0];
    const float* dist = (const float*)d_in[1];
    const int*   dt   = (const int*)d_in[2];
    const int*   mask = (const int*)d_in[3];
    const float* wq_w = (const float*)d_in[4];
    const float* wq_b = (const float*)d_in[5];
    const float* wk_w = (const float*)d_in[6];
    const float* wk_b = (const float*)d_in[7];
    const float* wv_w = (const float*)d_in[8];
    const float* wv_b = (const float*)d_in[9];
    const float* wo_w = (const float*)d_in[10];
    const float* wo_b = (const float*)d_in[11];
    const float* pe   = (const float*)d_in[12];
    const float* w1   = (const float*)d_in[13];
    const float* b1   = (const float*)d_in[14];
    const float* w2   = (const float*)d_in[15];
    const float* b2   = (const float*)d_in[16];
    const float* ln1g = (const float*)d_in[17];
    const float* ln1b = (const float*)d_in[18];
    const float* ln2g = (const float*)d_in[19];
    const float* ln2b = (const float*)d_in[20];
    float* out = (float*)d_out;

    void *pq, *pk, *pv, *pcc, *pt1, *pao, *phid, *pt2, *pwqkv, *pbqkv;
    cudaGetSymbolAddress(&pq, g_q);
    cudaGetSymbolAddress(&pk, g_k);
    cudaGetSymbolAddress(&pv, g_v);
    cudaGetSymbolAddress(&pcc, g_concat);
    cudaGetSymbolAddress(&pt1, g_t1);
    cudaGetSymbolAddress(&pao, g_attnout);
    cudaGetSymbolAddress(&phid, g_hidden);
    cudaGetSymbolAddress(&pt2, g_t2);
    cudaGetSymbolAddress(&pwqkv, g_wqkv);
    cudaGetSymbolAddress(&pbqkv, g_bqkv);

    cudaFuncSetAttribute(scores_mma_kernel,
                         cudaFuncAttributeMaxDynamicSharedMemorySize, SC_SMEM_BYTES);
    cudaFuncSetAttribute(attn_mma_kernel,
                         cudaFuncAttributeMaxDynamicSharedMemorySize, AT_SMEM_BYTES);
    cudaFuncSetAttribute(qz_mma_kernel,
                         cudaFuncAttributeMaxDynamicSharedMemorySize, QZ_SMEM_BYTES);

    pe_copy_kernel<<<(CNR * CD + 255) / 256, 256>>>(pe);
    pack_qkv_kernel<<<(CE * CE + 255) / 256, 256>>>(wq_w, wk_w, wv_w, wq_b, wk_b, wv_b);

    // fused QKV: M=4096, N=1536, K=512
    dim3 gq(1536 / 128, CM / 128);
    mma_gemm_kernel<128><<<gq, 256>>>(x, (const float*)pwqkv, (float*)pq, (float*)pk, (float*)pv,
                                      CM, 1536, CE, (const float*)pbqkv, nullptr, EPI_QKV);

    qz_mma_kernel<<<(CBH * CS) / 128, 256, QZ_SMEM_BYTES>>>(pe);

    dim3 gsc(CS / 128, CS / 128, CBH);
    scores_mma_kernel<<<gsc, 256, SC_SMEM_BYTES>>>(dist, dt, mask);

    softmax_kernel<<<CBH * CS, 256>>>(dt);

    dim3 gat(CS / 128, CBH);
    attn_mma_kernel<<<gat, 256, AT_SMEM_BYTES>>>();

    dim3 gwo(CE / 64, CM / 128);
    mma_gemm_kernel<64><<<gwo, 256>>>((const float*)pcc, wo_w, (float*)pt1, nullptr, nullptr,
                                      CM, CE, CE, wo_b, x, EPI_RESID);
    ln_kernel<<<CM, 256>>>((const float*)pt1, (float*)pao, ln1g, ln1b);

    dim3 gf1(CF / 128, CM / 128);
    mma_gemm_kernel<128><<<gf1, 256>>>((const float*)pao, w1, (float*)phid, nullptr, nullptr,
                                       CM, CF, CE, b1, nullptr, EPI_RELU);
    dim3 gf2(CE / 64, CM / 128);
    mma_gemm_kernel<64><<<gf2, 256>>>((const float*)phid, w2, (float*)pt2, nullptr, nullptr,
                                      CM, CE, CF, b2, (const float*)pao, EPI_RESID);
    ln_kernel<<<CM, 256>>>((const float*)pt2, out, ln2g, ln2b);
}

// round 7
// speedup vs baseline: 1.6073x; 1.0445x over previous
#include <cuda_runtime.h>
#include <cstdint>
#include <cstddef>

// Problem constants
#define CB 8
#define CS 512
#define CE 512
#define CH 8
#define CD 64
#define CP 64
#define CF 2048
#define CNR 129            // 2P+1
#define QZP 144            // padded qz row stride
#define CSR 192            // padded stride for bins / pos_emb (3 chunks of 64)
#define CBH (CB*CH)        // 64
#define CM (CB*CS)         // 4096

// ---------------- device scratch (zero-initialized .bss) ----------------------
__device__ __align__(16) float g_q[CBH*CS*CD];
__device__ __align__(16) float g_k[CBH*CS*CD];
__device__ __align__(16) float g_v[CBH*CS*CD];
__device__ __align__(16) float g_qz[(size_t)CBH*CS*QZP];
__device__ __align__(16) float g_w[CBH*CS*CS];          // scores -> aw (in place)
__device__ __align__(16) float g_s[CBH*CS*CSR];         // softmax bins (padded)
__device__ __align__(16) float g_pe[CSR*CD];            // padded pos_emb
__device__ __align__(16) float g_concat[CM*CE];
__device__ __align__(16) float g_t1[CM*CE];
__device__ __align__(16) float g_attnout[CM*CE];
__device__ __align__(16) float g_hidden[CM*CF];
__device__ __align__(16) float g_t2[CM*CE];
__device__ __align__(16) float g_wqkv[CE*3*CE];         // packed [512][1536]
__device__ __align__(16) float g_bqkv[3*CE];

enum { EPI_QKV = 0, EPI_RESID = 1, EPI_RELU = 2 };

__device__ __forceinline__ void mma_tf32(float c[4], const uint32_t a[4],
                                         const uint32_t b[2]) {
    asm volatile(
        "mma.sync.aligned.m16n8k8.row.col.f32.tf32.tf32.f32 "
        "{%0,%1,%2,%3}, {%4,%5,%6,%7}, {%8,%9}, {%0,%1,%2,%3};\n"
        : "+f"(c[0]), "+f"(c[1]), "+f"(c[2]), "+f"(c[3])
        : "r"(a[0]), "r"(a[1]), "r"(a[2]), "r"(a[3]), "r"(b[0]), "r"(b[1]));
}

__device__ __forceinline__ void cp16(uint32_t dst, const void* src) {
    asm volatile("cp.async.cg.shared.global [%0], [%1], 16;\n" :: "r"(dst), "l"(src));
}
__device__ __forceinline__ void cp_commit() {
    asm volatile("cp.async.commit_group;\n");
}
template<int N>
__device__ __forceinline__ void cp_wait() {
    asm volatile("cp.async.wait_group %0;\n" :: "n"(N));
}

// ---------------- TF32 tensor-core GEMM (cp.async 3-stage, raw fp32 bits) -----
#define APITCH 20
#define GEMM_NSTAGE 3

template<int BN>
__global__ __launch_bounds__(256, 2) void mma_gemm_kernel(
    const float* __restrict__ A, const float* __restrict__ Bm,
    float* __restrict__ C, float* __restrict__ C2, float* __restrict__ C3,
    int M, int N, int K,
    const float* __restrict__ bias, const float* __restrict__ resid, int mode)
{
    constexpr int BPITCH = BN + 4;
    constexpr int NT = BN / 16;
    constexpr int ASZ = 128 * APITCH;      // u32 per stage
    constexpr int BSZ = 16 * BPITCH;
    extern __shared__ uint32_t smem_u[];
    uint32_t* As = smem_u;                       // [3][ASZ]
    uint32_t* Bs = smem_u + GEMM_NSTAGE * ASZ;   // [3][BSZ]

    const int tid = threadIdx.x;
    const int warp = tid >> 5;
    const int lane = tid & 31;
    const int gid = lane >> 2;
    const int tig = lane & 3;
    const int wy = warp >> 1;
    const int wx = warp & 1;
    const int bm = blockIdx.y * 128;
    const int bn = blockIdx.x * BN;

    const int ar = tid >> 1;
    const int ak = (tid & 1) << 3;
    const int br = tid >> 4;
    const int bc = (tid & 15) << 2;

    const float* Ap = A + (size_t)(bm + ar) * K + ak;
    const float* Bp = Bm + (size_t)br * N + bn + bc;

    const uint32_t a_smem = (uint32_t)__cvta_generic_to_shared(As) + (ar * APITCH + ak) * 4;
    const uint32_t b_smem = (uint32_t)__cvta_generic_to_shared(Bs) + (br * BPITCH + bc) * 4;

    const int nk = K >> 4;

    float acc[2][NT][4];
#pragma unroll
    for (int mt = 0; mt < 2; mt++)
#pragma unroll
        for (int nt = 0; nt < NT; nt++)
#pragma unroll
            for (int r = 0; r < 4; r++) acc[mt][nt][r] = 0.0f;

    // prologue: stages 0,1
#pragma unroll
    for (int s = 0; s < 2; s++) {
        if (s < nk) {
            cp16(a_smem + s * ASZ * 4, Ap + (s << 4));
            cp16(a_smem + s * ASZ * 4 + 16, Ap + (s << 4) + 4);
            cp16(b_smem + s * BSZ * 4, Bp + (size_t)(s << 4) * N);
            if (BN == 128)
                cp16(b_smem + s * BSZ * 4 + 256, Bp + (size_t)(s << 4) * N + 64);
        }
        cp_commit();
    }

    for (int i = 0; i < nk; i++) {
        const int s2 = i + 2;
        if (s2 < nk) {
            const int bs = s2 % GEMM_NSTAGE;
            cp16(a_smem + bs * ASZ * 4, Ap + (s2 << 4));
            cp16(a_smem + bs * ASZ * 4 + 16, Ap + (s2 << 4) + 4);
            cp16(b_smem + bs * BSZ * 4, Bp + (size_t)(s2 << 4) * N);
            if (BN == 128)
                cp16(b_smem + bs * BSZ * 4 + 256, Bp + (size_t)(s2 << 4) * N + 64);
        }
        cp_commit();
        cp_wait<2>();
        __syncthreads();

        const int buf = i % GEMM_NSTAGE;
        const uint32_t* Ab = As + buf * ASZ;
        const uint32_t* Bb = Bs + buf * BSZ;
#pragma unroll
        for (int ks = 0; ks < 16; ks += 8) {
            uint32_t af[2][4];
#pragma unroll
            for (int mt = 0; mt < 2; mt++) {
                const int mrow = wy * 32 + mt * 16 + gid;
                af[mt][0] = Ab[mrow * APITCH + ks + tig];
                af[mt][1] = Ab[(mrow + 8) * APITCH + ks + tig];
                af[mt][2] = Ab[mrow * APITCH + ks + tig + 4];
                af[mt][3] = Ab[(mrow + 8) * APITCH + ks + tig + 4];
            }
            uint32_t bf[NT][2];
#pragma unroll
            for (int nt = 0; nt < NT; nt++) {
                const int nc = wx * (BN / 2) + nt * 8 + gid;
                bf[nt][0] = Bb[(ks + tig) * BPITCH + nc];
                bf[nt][1] = Bb[(ks + tig + 4) * BPITCH + nc];
            }
#pragma unroll
            for (int mt = 0; mt < 2; mt++)
#pragma unroll
                for (int nt = 0; nt < NT; nt++)
                    mma_tf32(acc[mt][nt], af[mt], bf[nt]);
        }
        __syncthreads();
    }

#pragma unroll
    for (int mt = 0; mt < 2; mt++) {
#pragma unroll
        for (int nt = 0; nt < NT; nt++) {
            const int col = bn + wx * (BN / 2) + nt * 8 + 2 * tig;
            float bv0 = 0.0f, bv1 = 0.0f;
            if (bias) { bv0 = bias[col]; bv1 = bias[col + 1]; }
#pragma unroll
            for (int half = 0; half < 2; half++) {
                const int row = bm + wy * 32 + mt * 16 + gid + half * 8;
                float v0 = acc[mt][nt][half * 2 + 0] + bv0;
                float v1 = acc[mt][nt][half * 2 + 1] + bv1;
                if (mode == EPI_RESID) {
                    v0 += resid[(size_t)row * N + col];
                    v1 += resid[(size_t)row * N + col + 1];
                } else if (mode == EPI_RELU) {
                    v0 = fmaxf(v0, 0.0f);
                    v1 = fmaxf(v1, 0.0f);
                }
                float2 vv = {v0, v1};
                if (mode == EPI_QKV) {
                    const int b = row >> 9, ii = row & 511;
                    const int which = col >> 9;
                    const int cc = col & 511;
                    const int h = cc >> 6, d = cc & 63;
                    float* base = (which == 0) ? C : (which == 1) ? C2 : C3;
                    *(float2*)(base + (((size_t)(b * CH + h) * CS) + ii) * CD + d) = vv;
                } else {
                    *(float2*)(C + (size_t)row * N + col) = vv;
                }
            }
        }
    }
}

#define GEMM_SMEM_BYTES(BN) (GEMM_NSTAGE * (128 * APITCH + 16 * ((BN) + 4)) * 4)

// ---------------- pack QKV weights/biases --------------------------------------
__global__ void pack_qkv_kernel(const float* __restrict__ wq, const float* __restrict__ wk,
                                const float* __restrict__ wv, const float* __restrict__ bq,
                                const float* __restrict__ bk, const float* __restrict__ bv)
{
    int idx = blockIdx.x * 256 + threadIdx.x;
    if (idx < CE * CE) {
        int r = idx >> 9, c = idx & 511;
        g_wqkv[(size_t)r * 1536 + c] = wq[idx];
        g_wqkv[(size_t)r * 1536 + 512 + c] = wk[idx];
        g_wqkv[(size_t)r * 1536 + 1024 + c] = wv[idx];
    }
    if (idx < CE) {
        g_bqkv[idx] = bq[idx];
        g_bqkv[512 + idx] = bk[idx];
        g_bqkv[1024 + idx] = bv[idx];
    }
}

// ---------------- pad pos_emb into g_pe ---------------------------------------
__global__ void pe_copy_kernel(const float* __restrict__ pe)
{
    int t = blockIdx.x * 256 + threadIdx.x;
    if (t < CNR * CD) g_pe[t] = pe[t];
}

// ---------------- qz (tensor, raw tf32): (32768x64) @ (64x129->144) ------------
#define QZ_A 0
#define QZ_B (128*68)
#define QZ_SMEM_BYTES ((128*68 + 64*148) * 4)

__global__ __launch_bounds__(256, 2) void qz_mma_kernel(const float* __restrict__ pe)
{
    extern __shared__ uint32_t sm[];
    uint32_t* Asm = sm + QZ_A;
    uint32_t* Bsm = sm + QZ_B;

    const int m0 = blockIdx.x << 7;
    const int tid = threadIdx.x;
    const int warp = tid >> 5;
    const int lane = tid & 31;
    const int gid = lane >> 2;
    const int tig = lane & 3;
    const int wy = warp >> 1;
    const int wx = warp & 1;

    for (int t = tid; t < 64 * 148; t += 256) Bsm[t] = 0u;
    __syncthreads();

#pragma unroll
    for (int l = 0; l < 8; l++) {
        const int idx = tid + (l << 8);
        const int r = idx >> 4;
        const int c = (idx & 15) << 2;
        float4 qv = *(const float4*)(g_q + (size_t)(m0 + r) * CD + c);
        uint4 ua = {__float_as_uint(qv.x), __float_as_uint(qv.y),
                    __float_as_uint(qv.z), __float_as_uint(qv.w)};
        *(uint4*)&Asm[r*68 + c] = ua;
    }
    for (int t = tid; t < CNR * 16; t += 256) {
        const int n = t >> 4;
        const int k = (t & 15) << 2;
        float4 pv = *(const float4*)(pe + (size_t)n * CD + k);
        Bsm[(k+0)*148 + n] = __float_as_uint(pv.x);
        Bsm[(k+1)*148 + n] = __float_as_uint(pv.y);
        Bsm[(k+2)*148 + n] = __float_as_uint(pv.z);
        Bsm[(k+3)*148 + n] = __float_as_uint(pv.w);
    }
    __syncthreads();

    float acc[2][9][4];
#pragma unroll
    for (int mt = 0; mt < 2; mt++)
#pragma unroll
        for (int nt = 0; nt < 9; nt++)
#pragma unroll
            for (int r = 0; r < 4; r++) acc[mt][nt][r] = 0.0f;

#pragma unroll
    for (int ks = 0; ks < 64; ks += 8) {
        uint32_t af[2][4];
#pragma unroll
        for (int mt = 0; mt < 2; mt++) {
            const int mrow = wy * 32 + mt * 16 + gid;
            af[mt][0] = Asm[mrow*68 + ks + tig];
            af[mt][1] = Asm[(mrow+8)*68 + ks + tig];
            af[mt][2] = Asm[mrow*68 + ks + tig + 4];
            af[mt][3] = Asm[(mrow+8)*68 + ks + tig + 4];
        }
        uint32_t bf[9][2];
#pragma unroll
        for (int nt = 0; nt < 9; nt++) {
            const int nc = wx * 72 + nt * 8 + gid;
            bf[nt][0] = Bsm[(ks + tig)*148 + nc];
            bf[nt][1] = Bsm[(ks + tig + 4)*148 + nc];
        }
#pragma unroll
        for (int mt = 0; mt < 2; mt++)
#pragma unroll
            for (int nt = 0; nt < 9; nt++)
                mma_tf32(acc[mt][nt], af[mt], bf[nt]);
    }

#pragma unroll
    for (int mt = 0; mt < 2; mt++)
#pragma unroll
        for (int nt = 0; nt < 9; nt++) {
            const int col = wx * 72 + nt * 8 + 2 * tig;
#pragma unroll
            for (int half = 0; half < 2; half++) {
                const int row = m0 + wy * 32 + mt * 16 + gid + half * 8;
                float2 vv = {acc[mt][nt][half*2+0], acc[mt][nt][half*2+1]};
                *(float2*)&g_qz[(size_t)row * QZP + col] = vv;
            }
        }
}

// ---------------- scores (tensor, raw tf32): 128x128 tile ----------------------
#define SC_Q 0
#define SC_K (128*68)
#define SC_INT (128*68 + 64*132)
#define SC_SMEM_BYTES ((SC_INT + 3*128) * 4)

__global__ __launch_bounds__(256, 2) void scores_mma_kernel(
    const float* __restrict__ dist, const int* __restrict__ dt,
    const int* __restrict__ mask)
{
    extern __shared__ uint32_t sm[];
    uint32_t* Qs = sm + SC_Q;
    uint32_t* Ks = sm + SC_K;
    int* dti_s = (int*)(sm + SC_INT);
    int* dtj_s = dti_s + 128;
    int* mj_s = dtj_s + 128;

    const int bh = blockIdx.z;
    const int b = bh >> 3;
    const int i0 = blockIdx.y << 7;
    const int j0 = blockIdx.x << 7;
    const int tid = threadIdx.x;
    const int warp = tid >> 5;
    const int lane = tid & 31;
    const int gid = lane >> 2;
    const int tig = lane & 3;
    const int wy = warp >> 1;
    const int wx = warp & 1;

    const float* qb = g_q + (size_t)bh * CS * CD;
    const float* kb = g_k + (size_t)bh * CS * CD;

#pragma unroll
    for (int l = 0; l < 8; l++) {
        const int idx = tid + (l << 8);
        const int r = idx >> 4;
        const int c = (idx & 15) << 2;
        float4 qv = *(const float4*)(qb + (size_t)(i0 + r) * CD + c);
        float4 kv = *(const float4*)(kb + (size_t)(j0 + r) * CD + c);
        uint4 ua = {__float_as_uint(qv.x), __float_as_uint(qv.y),
                    __float_as_uint(qv.z), __float_as_uint(qv.w)};
        *(uint4*)&Qs[r*68 + c] = ua;
        Ks[(c+0)*132 + r] = __float_as_uint(kv.x);
        Ks[(c+1)*132 + r] = __float_as_uint(kv.y);
        Ks[(c+2)*132 + r] = __float_as_uint(kv.z);
        Ks[(c+3)*132 + r] = __float_as_uint(kv.w);
    }
    if (tid < 128) {
        dti_s[tid] = dt[b * CS + i0 + tid];
        dtj_s[tid] = dt[b * CS + j0 + tid];
        mj_s[tid] = mask[b * CS + j0 + tid];
    }
    __syncthreads();

    float acc[2][8][4];
#pragma unroll
    for (int mt = 0; mt < 2; mt++)
#pragma unroll
        for (int nt = 0; nt < 8; nt++)
#pragma unroll
            for (int r = 0; r < 4; r++) acc[mt][nt][r] = 0.0f;

#pragma unroll
    for (int ks = 0; ks < 64; ks += 8) {
        uint32_t af[2][4];
#pragma unroll
        for (int mt = 0; mt < 2; mt++) {
            const int mrow = wy * 32 + mt * 16 + gid;
            af[mt][0] = Qs[mrow*68 + ks + tig];
            af[mt][1] = Qs[(mrow+8)*68 + ks + tig];
            af[mt][2] = Qs[mrow*68 + ks + tig + 4];
            af[mt][3] = Qs[(mrow+8)*68 + ks + tig + 4];
        }
        uint32_t bf[8][2];
#pragma unroll
        for (int nt = 0; nt < 8; nt++) {
            const int nc = wx * 64 + nt * 8 + gid;
            bf[nt][0] = Ks[(ks + tig)*132 + nc];
            bf[nt][1] = Ks[(ks + tig + 4)*132 + nc];
        }
#pragma unroll
        for (int mt = 0; mt < 2; mt++)
#pragma unroll
            for (int nt = 0; nt < 8; nt++)
                mma_tf32(acc[mt][nt], af[mt], bf[nt]);
    }

    // epilogue: qz gather + dist + mask
#pragma unroll
    for (int mt = 0; mt < 2; mt++) {
#pragma unroll
        for (int half = 0; half < 2; half++) {
            const int il = wy * 32 + mt * 16 + gid + half * 8;
            const int i = i0 + il;
            const int di = dti_s[il];
            const size_t qzrow = ((size_t)bh * CS + i) * QZP;
            const size_t drow = ((size_t)b * CS + i) * CS;
            const size_t wrow = ((size_t)bh * CS + i) * CS;
#pragma unroll
            for (int nt = 0; nt < 8; nt++) {
                const int jl = wx * 64 + nt * 8 + 2 * tig;
                float ov[2];
#pragma unroll
                for (int u = 0; u < 2; u++) {
                    const int jloc = jl + u;
                    int rel = min(max(dtj_s[jloc] - di, -CP), CP) + CP;
                    float v = (acc[mt][nt][half*2+u] + g_qz[qzrow + rel]) * 0.125f
                            + 0.6f * dist[drow + j0 + jloc];
                    if (mj_s[jloc] == 0) v = -1e9f;
                    ov[u] = v;
                }
                float2 st = {ov[0], ov[1]};
                *(float2*)&g_w[wrow + j0 + jl] = st;
            }
        }
    }
}

// ---------------- softmax + 129-bin histogram (shuffle reductions) -------------
__global__ __launch_bounds__(256) void softmax_kernel(const int* __restrict__ dt)
{
    const int row = blockIdx.x;           // bh*S + i
    const int bh = row >> 9;
    const int i = row & 511;
    const int b = bh >> 3;
    float* wr = g_w + (size_t)row * CS;
    const int tid = threadIdx.x;
    const int lane = tid & 31;
    const int wid = tid >> 5;

    __shared__ float wred[8];
    __shared__ float stat;
    __shared__ float bins[CNR];

    float2 v = *(const float2*)&wr[2 * tid];
    float m = fmaxf(v.x, v.y);
#pragma unroll
    for (int o = 16; o > 0; o >>= 1)
        m = fmaxf(m, __shfl_xor_sync(0xffffffffu, m, o));
    if (lane == 0) wred[wid] = m;
    if (tid < CNR) bins[tid] = 0.0f;
    __syncthreads();
    if (tid == 0) {
        float mm = wred[0];
#pragma unroll
        for (int k = 1; k < 8; k++) mm = fmaxf(mm, wred[k]);
        stat = mm;
    }
    __syncthreads();
    const float mx = stat;

    const float e0 = __expf(v.x - mx);
    const float e1 = __expf(v.y - mx);
    float s = e0 + e1;
#pragma unroll
    for (int o = 16; o > 0; o >>= 1)
        s += __shfl_xor_sync(0xffffffffu, s, o);
    if (lane == 0) wred[wid] = s;
    __syncthreads();
    if (tid == 0) {
        float ss = wred[0];
#pragma unroll
        for (int k = 1; k < 8; k++) ss += wred[k];
        stat = 1.0f / ss;
    }
    __syncthreads();
    const float inv = stat;

    const float a0 = e0 * inv, a1 = e1 * inv;
    float2 st = {a0, a1};
    *(float2*)&wr[2 * tid] = st;

    const int di = dt[b * CS + i];
    int2 dj = *(const int2*)&dt[b * CS + 2 * tid];
    int r0 = min(max(dj.x - di, -CP), CP) + CP;
    int r1 = min(max(dj.y - di, -CP), CP) + CP;
    atomicAdd(&bins[r0], a0);
    atomicAdd(&bins[r1], a1);
    __syncthreads();
    if (tid < CNR) g_s[(size_t)row * CSR + tid] = bins[tid];
}

// ---------------- attn (tensor, raw tf32): 128x64 tile -------------------------
#define AT_A 0
#define AT_B (128*68)
#define AT_SMEM_BYTES ((128*68 + 64*68) * 4)

__global__ __launch_bounds__(256, 2) void attn_mma_kernel()
{
    extern __shared__ uint32_t sm[];
    uint32_t* Asm = sm + AT_A;
    uint32_t* Bsm = sm + AT_B;

    const int bh = blockIdx.y;
    const int b = bh >> 3, h = bh & 7;
    const int i0 = blockIdx.x << 7;
    const int tid = threadIdx.x;
    const int warp = tid >> 5;
    const int lane = tid & 31;
    const int gid = lane >> 2;
    const int tig = lane & 3;
    const int wy = warp >> 1;
    const int wx = warp & 1;

    const float* awb = g_w + (size_t)bh * CS * CS;
    const float* sb = g_s + (size_t)bh * CS * CSR;
    const float* vb = g_v + (size_t)bh * CS * CD;

    float acc[2][4][4];
#pragma unroll
    for (int mt = 0; mt < 2; mt++)
#pragma unroll
        for (int nt = 0; nt < 4; nt++)
#pragma unroll
            for (int r = 0; r < 4; r++) acc[mt][nt][r] = 0.0f;

    for (int c = 0; c < 11; c++) {
#pragma unroll
        for (int l = 0; l < 8; l++) {
            const int idx = tid + (l << 8);
            const int r = idx >> 4;
            const int cc = (idx & 15) << 2;
            float4 av;
            if (c < 8) av = *(const float4*)(awb + (size_t)(i0 + r) * CS + (c << 6) + cc);
            else       av = *(const float4*)(sb + (size_t)(i0 + r) * CSR + ((c - 8) << 6) + cc);
            uint4 ua = {__float_as_uint(av.x), __float_as_uint(av.y),
                        __float_as_uint(av.z), __float_as_uint(av.w)};
            *(uint4*)&Asm[r*68 + cc] = ua;
        }
#pragma unroll
        for (int l = 0; l < 4; l++) {
            const int idx = tid + (l << 8);
            const int r = idx >> 4;
            const int cc = (idx & 15) << 2;
            float4 vv;
            if (c < 8) vv = *(const float4*)(vb + (size_t)((c << 6) + r) * CD + cc);
            else       vv = *(const float4*)(g_pe + (size_t)(((c - 8) << 6) + r) * CD + cc);
            uint4 ub = {__float_as_uint(vv.x), __float_as_uint(vv.y),
                        __float_as_uint(vv.z), __float_as_uint(vv.w)};
            *(uint4*)&Bsm[r*68 + cc] = ub;
        }
        __syncthreads();

#pragma unroll
        for (int ks = 0; ks < 64; ks += 8) {
            uint32_t af[2][4];
#pragma unroll
            for (int mt = 0; mt < 2; mt++) {
                const int mrow = wy * 32 + mt * 16 + gid;
                af[mt][0] = Asm[mrow*68 + ks + tig];
                af[mt][1] = Asm[(mrow+8)*68 + ks + tig];
                af[mt][2] = Asm[mrow*68 + ks + tig + 4];
                af[mt][3] = Asm[(mrow+8)*68 + ks + tig + 4];
            }
            uint32_t bf[4][2];
#pragma unroll
            for (int nt = 0; nt < 4; nt++) {
                const int nc = wx * 32 + nt * 8 + gid;
                bf[nt][0] = Bsm[(ks + tig)*68 + nc];
                bf[nt][1] = Bsm[(ks + tig + 4)*68 + nc];
            }
#pragma unroll
            for (int mt = 0; mt < 2; mt++)
#pragma unroll
                for (int nt = 0; nt < 4; nt++)
                    mma_tf32(acc[mt][nt], af[mt], bf[nt]);
        }
        __syncthreads();
    }

#pragma unroll
    for (int mt = 0; mt < 2; mt++)
#pragma unroll
        for (int nt = 0; nt < 4; nt++) {
            const int col = wx * 32 + nt * 8 + 2 * tig;
#pragma unroll
            for (int half = 0; half < 2; half++) {
                const int row = wy * 32 + mt * 16 + gid + half * 8;
                float2 vv = {acc[mt][nt][half*2+0], acc[mt][nt][half*2+1]};
                *(float2*)&g_concat[(size_t)(b * CS + i0 + row) * CE + h * CD + col] = vv;
            }
        }
}

// ---------------- layernorm (row = 512) ---------------------------------------
__global__ __launch_bounds__(256) void ln_kernel(
    const float* __restrict__ in, float* __restrict__ out,
    const float* __restrict__ gg, const float* __restrict__ bb)
{
    const int row = blockIdx.x;
    const float* xr = in + (size_t)row * CE;
    const int tid = threadIdx.x;
    const int lane = tid & 31;
    const int wid = tid >> 5;
    __shared__ float wred[8];
    __shared__ float stat;

    float2 v = *(const float2*)&xr[2 * tid];
    float s = v.x + v.y;
#pragma unroll
    for (int o = 16; o > 0; o >>= 1) s += __shfl_xor_sync(0xffffffffu, s, o);
    if (lane == 0) wred[wid] = s;
    __syncthreads();
    if (tid == 0) {
        float ss = wred[0];
#pragma unroll
        for (int k = 1; k < 8; k++) ss += wred[k];
        stat = ss * (1.0f / CE);
    }
    __syncthreads();
    const float mu = stat;
    const float d0 = v.x - mu, d1 = v.y - mu;
    float q = d0 * d0 + d1 * d1;
#pragma unroll
    for (int o = 16; o > 0; o >>= 1) q += __shfl_xor_sync(0xffffffffu, q, o);
    if (lane == 0) wred[wid] = q;
    __syncthreads();
    if (tid == 0) {
        float qq = wred[0];
#pragma unroll
        for (int k = 1; k < 8; k++) qq += wred[k];
        stat = rsqrtf(qq * (1.0f / CE) + 1e-5f);
    }
    __syncthreads();
    const float rstd = stat;
    float2 gv = *(const float2*)&gg[2 * tid];
    float2 bv = *(const float2*)&bb[2 * tid];
    float2 ov = {d0 * rstd * gv.x + bv.x, d1 * rstd * gv.y + bv.y};
    *(float2*)&out[(size_t)row * CE + 2 * tid] = ov;
}

// ---------------- launch -------------------------------------------------------
extern "C" void kernel_launch(void* const* d_in, const int* in_sizes, int n_in,
                              void* d_out, int out_size)
{
    const float* x    = (const float*)d_in[0];
    const float* dist = (const float*)d_in[1];
    const int*   dt   = (const int*)d_in[2];
    const int*   mask = (const int*)d_in[3];
    const float* wq_w = (const float*)d_in[4];
    const float* wq_b = (const float*)d_in[5];
    const float* wk_w = (const float*)d_in[6];
    const float* wk_b = (const float*)d_in[7];
    const float* wv_w = (const float*)d_in[8];
    const float* wv_b = (const float*)d_in[9];
    const float* wo_w = (const float*)d_in[10];
    const float* wo_b = (const float*)d_in[11];
    const float* pe   = (const float*)d_in[12];
    const float* w1   = (const float*)d_in[13];
    const float* b1   = (const float*)d_in[14];
    const float* w2   = (const float*)d_in[15];
    const float* b2   = (const float*)d_in[16];
    const float* ln1g = (const float*)d_in[17];
    const float* ln1b = (const float*)d_in[18];
    const float* ln2g = (const float*)d_in[19];
    const float* ln2b = (const float*)d_in[20];
    float* out = (float*)d_out;

    void *pq, *pk, *pv, *pcc, *pt1, *pao, *phid, *pt2, *pwqkv, *pbqkv;
    cudaGetSymbolAddress(&pq, g_q);
    cudaGetSymbolAddress(&pk, g_k);
    cudaGetSymbolAddress(&pv, g_v);
    cudaGetSymbolAddress(&pcc, g_concat);
    cudaGetSymbolAddress(&pt1, g_t1);
    cudaGetSymbolAddress(&pao, g_attnout);
    cudaGetSymbolAddress(&phid, g_hidden);
    cudaGetSymbolAddress(&pt2, g_t2);
    cudaGetSymbolAddress(&pwqkv, g_wqkv);
    cudaGetSymbolAddress(&pbqkv, g_bqkv);

    cudaFuncSetAttribute(scores_mma_kernel,
                         cudaFuncAttributeMaxDynamicSharedMemorySize, SC_SMEM_BYTES);
    cudaFuncSetAttribute(attn_mma_kernel,
                         cudaFuncAttributeMaxDynamicSharedMemorySize, AT_SMEM_BYTES);
    cudaFuncSetAttribute(qz_mma_kernel,
                         cudaFuncAttributeMaxDynamicSharedMemorySize, QZ_SMEM_BYTES);
    cudaFuncSetAttribute(mma_gemm_kernel<128>,
                         cudaFuncAttributeMaxDynamicSharedMemorySize, GEMM_SMEM_BYTES(128));
    cudaFuncSetAttribute(mma_gemm_kernel<64>,
                         cudaFuncAttributeMaxDynamicSharedMemorySize, GEMM_SMEM_BYTES(64));

    pe_copy_kernel<<<(CNR * CD + 255) / 256, 256>>>(pe);
    pack_qkv_kernel<<<(CE * CE + 255) / 256, 256>>>(wq_w, wk_w, wv_w, wq_b, wk_b, wv_b);

    // fused QKV: M=4096, N=1536, K=512
    dim3 gq(1536 / 128, CM / 128);
    mma_gemm_kernel<128><<<gq, 256, GEMM_SMEM_BYTES(128)>>>(
        x, (const float*)pwqkv, (float*)pq, (float*)pk, (float*)pv,
        CM, 1536, CE, (const float*)pbqkv, nullptr, EPI_QKV);

    qz_mma_kernel<<<(CBH * CS) / 128, 256, QZ_SMEM_BYTES>>>(pe);

    dim3 gsc(CS / 128, CS / 128, CBH);
    scores_mma_kernel<<<gsc, 256, SC_SMEM_BYTES>>>(dist, dt, mask);

    softmax_kernel<<<CBH * CS, 256>>>(dt);

    dim3 gat(CS / 128, CBH);
    attn_mma_kernel<<<gat, 256, AT_SMEM_BYTES>>>();

    dim3 gwo(CE / 64, CM / 128);
    mma_gemm_kernel<64><<<gwo, 256, GEMM_SMEM_BYTES(64)>>>(
        (const float*)pcc, wo_w, (float*)pt1, nullptr, nullptr,
        CM, CE, CE, wo_b, x, EPI_RESID);
    ln_kernel<<<CM, 256>>>((const float*)pt1, (float*)pao, ln1g, ln1b);

    dim3 gf1(CF / 128, CM / 128);
    mma_gemm_kernel<128><<<gf1, 256, GEMM_SMEM_BYTES(128)>>>(
        (const float*)pao, w1, (float*)phid, nullptr, nullptr,
        CM, CF, CE, b1, nullptr, EPI_RELU);
    dim3 gf2(CE / 64, CM / 128);
    mma_gemm_kernel<64><<<gf2, 256, GEMM_SMEM_BYTES(64)>>>(
        (const float*)phid, w2, (float*)pt2, nullptr, nullptr,
        CM, CE, CF, b2, (const float*)pao, EPI_RESID);
    ln_kernel<<<CM, 256>>>((const float*)pt2, out, ln2g, ln2b);
}

// round 8
// speedup vs baseline: 1.6485x; 1.0256x over previous
#include <cuda_runtime.h>
#include <cstdint>
#include <cstddef>

// Problem constants
#define CB 8
#define CS 512
#define CE 512
#define CH 8
#define CD 64
#define CP 64
#define CF 2048
#define CNR 129            // 2P+1
#define QZP 144            // padded qz row stride
#define CSR 192            // padded stride for bins / pos_emb (3 chunks of 64)
#define CBH (CB*CH)        // 64
#define CM (CB*CS)         // 4096

// ---------------- device scratch (zero-initialized .bss) ----------------------
__device__ __align__(16) float g_q[CBH*CS*CD];
__device__ __align__(16) float g_k[CBH*CS*CD];
__device__ __align__(16) float g_v[CBH*CS*CD];
__device__ __align__(16) float g_qz[(size_t)CBH*CS*QZP];
__device__ __align__(16) float g_w[CBH*CS*CS];          // scores -> aw (in place)
__device__ __align__(16) float g_s[CBH*CS*CSR];         // softmax bins (padded)
__device__ __align__(16) float g_pe[CSR*CD];            // padded pos_emb
__device__ __align__(16) float g_concat[CM*CE];
__device__ __align__(16) float g_t1[CM*CE];
__device__ __align__(16) float g_attnout[CM*CE];
__device__ __align__(16) float g_hidden[CM*CF];
__device__ __align__(16) float g_t2[CM*CE];
__device__ __align__(16) float g_wqkv[CE*3*CE];         // packed [512][1536]
__device__ __align__(16) float g_bqkv[3*CE];

enum { EPI_QKV = 0, EPI_RESID = 1, EPI_RELU = 2 };

__device__ __forceinline__ uint32_t f2tf(float f) {
    uint32_t u;
    asm("cvt.rna.tf32.f32 %0, %1;" : "=r"(u) : "f"(f));
    return u;
}

__device__ __forceinline__ void mma_tf32(float c[4], const uint32_t a[4],
                                         const uint32_t b[2]) {
    asm volatile(
        "mma.sync.aligned.m16n8k8.row.col.f32.tf32.tf32.f32 "
        "{%0,%1,%2,%3}, {%4,%5,%6,%7}, {%8,%9}, {%0,%1,%2,%3};\n"
        : "+f"(c[0]), "+f"(c[1]), "+f"(c[2]), "+f"(c[3])
        : "r"(a[0]), "r"(a[1]), "r"(a[2]), "r"(a[3]), "r"(b[0]), "r"(b[1]));
}

__device__ __forceinline__ void cp16(uint32_t dst, const void* src) {
    asm volatile("cp.async.cg.shared.global [%0], [%1], 16;\n" :: "r"(dst), "l"(src));
}
__device__ __forceinline__ void cp_commit() {
    asm volatile("cp.async.commit_group;\n");
}
template<int N>
__device__ __forceinline__ void cp_wait() {
    asm volatile("cp.async.wait_group %0;\n" :: "n"(N));
}

// ---------------- TF32 tensor-core GEMM (cp.async 4-stage, raw fp32 bits) -----
#define APITCH 20
#define GEMM_NSTAGE 4

template<int BN>
__global__ __launch_bounds__(256, 2) void mma_gemm_kernel(
    const float* __restrict__ A, const float* __restrict__ Bm,
    float* __restrict__ C, float* __restrict__ C2, float* __restrict__ C3,
    int M, int N, int K,
    const float* __restrict__ bias, const float* __restrict__ resid, int mode)
{
    constexpr int BPITCH = BN + 4;
    constexpr int NT = BN / 16;
    constexpr int ASZ = 128 * APITCH;      // u32 per stage
    constexpr int BSZ = 16 * BPITCH;
    extern __shared__ uint32_t smem_u[];
    uint32_t* As = smem_u;                       // [4][ASZ]
    uint32_t* Bs = smem_u + GEMM_NSTAGE * ASZ;   // [4][BSZ]

    const int tid = threadIdx.x;
    const int warp = tid >> 5;
    const int lane = tid & 31;
    const int gid = lane >> 2;
    const int tig = lane & 3;
    const int wy = warp >> 1;
    const int wx = warp & 1;
    const int bm = blockIdx.y * 128;
    const int bn = blockIdx.x * BN;

    const int ar = tid >> 1;
    const int ak = (tid & 1) << 3;
    const int br = tid >> 4;
    const int bc = (tid & 15) << 2;

    const float* Ap = A + (size_t)(bm + ar) * K + ak;
    const float* Bp = Bm + (size_t)br * N + bn + bc;

    const uint32_t a_smem = (uint32_t)__cvta_generic_to_shared(As) + (ar * APITCH + ak) * 4;
    const uint32_t b_smem = (uint32_t)__cvta_generic_to_shared(Bs) + (br * BPITCH + bc) * 4;

    const int nk = K >> 4;

    float acc[2][NT][4];
#pragma unroll
    for (int mt = 0; mt < 2; mt++)
#pragma unroll
        for (int nt = 0; nt < NT; nt++)
#pragma unroll
            for (int r = 0; r < 4; r++) acc[mt][nt][r] = 0.0f;

    // prologue: stages 0..2
#pragma unroll
    for (int s = 0; s < GEMM_NSTAGE - 1; s++) {
        if (s < nk) {
            cp16(a_smem + s * ASZ * 4, Ap + (s << 4));
            cp16(a_smem + s * ASZ * 4 + 16, Ap + (s << 4) + 4);
            cp16(b_smem + s * BSZ * 4, Bp + (size_t)(s << 4) * N);
            if (BN == 128)
                cp16(b_smem + s * BSZ * 4 + 256, Bp + (size_t)(s << 4) * N + 64);
        }
        cp_commit();
    }

    for (int i = 0; i < nk; i++) {
        const int s3 = i + GEMM_NSTAGE - 1;
        if (s3 < nk) {
            const int bs = s3 % GEMM_NSTAGE;
            cp16(a_smem + bs * ASZ * 4, Ap + (s3 << 4));
            cp16(a_smem + bs * ASZ * 4 + 16, Ap + (s3 << 4) + 4);
            cp16(b_smem + bs * BSZ * 4, Bp + (size_t)(s3 << 4) * N);
            if (BN == 128)
                cp16(b_smem + bs * BSZ * 4 + 256, Bp + (size_t)(s3 << 4) * N + 64);
        }
        cp_commit();
        cp_wait<GEMM_NSTAGE - 1>();
        __syncthreads();

        const int buf = i % GEMM_NSTAGE;
        const uint32_t* Ab = As + buf * ASZ;
        const uint32_t* Bb = Bs + buf * BSZ;
#pragma unroll
        for (int ks = 0; ks < 16; ks += 8) {
            uint32_t af[2][4];
#pragma unroll
            for (int mt = 0; mt < 2; mt++) {
                const int mrow = wy * 32 + mt * 16 + gid;
                af[mt][0] = Ab[mrow * APITCH + ks + tig];
                af[mt][1] = Ab[(mrow + 8) * APITCH + ks + tig];
                af[mt][2] = Ab[mrow * APITCH + ks + tig + 4];
                af[mt][3] = Ab[(mrow + 8) * APITCH + ks + tig + 4];
            }
            uint32_t bf[NT][2];
#pragma unroll
            for (int nt = 0; nt < NT; nt++) {
                const int nc = wx * (BN / 2) + nt * 8 + gid;
                bf[nt][0] = Bb[(ks + tig) * BPITCH + nc];
                bf[nt][1] = Bb[(ks + tig + 4) * BPITCH + nc];
            }
#pragma unroll
            for (int mt = 0; mt < 2; mt++)
#pragma unroll
                for (int nt = 0; nt < NT; nt++)
                    mma_tf32(acc[mt][nt], af[mt], bf[nt]);
        }
        __syncthreads();
    }

#pragma unroll
    for (int mt = 0; mt < 2; mt++) {
#pragma unroll
        for (int nt = 0; nt < NT; nt++) {
            const int col = bn + wx * (BN / 2) + nt * 8 + 2 * tig;
            float bv0 = 0.0f, bv1 = 0.0f;
            if (bias) { bv0 = bias[col]; bv1 = bias[col + 1]; }
#pragma unroll
            for (int half = 0; half < 2; half++) {
                const int row = bm + wy * 32 + mt * 16 + gid + half * 8;
                float v0 = acc[mt][nt][half * 2 + 0] + bv0;
                float v1 = acc[mt][nt][half * 2 + 1] + bv1;
                if (mode == EPI_RESID) {
                    v0 += resid[(size_t)row * N + col];
                    v1 += resid[(size_t)row * N + col + 1];
                } else if (mode == EPI_RELU) {
                    v0 = fmaxf(v0, 0.0f);
                    v1 = fmaxf(v1, 0.0f);
                }
                float2 vv = {v0, v1};
                if (mode == EPI_QKV) {
                    const int b = row >> 9, ii = row & 511;
                    const int which = col >> 9;
                    const int cc = col & 511;
                    const int h = cc >> 6, d = cc & 63;
                    float* base = (which == 0) ? C : (which == 1) ? C2 : C3;
                    *(float2*)(base + (((size_t)(b * CH + h) * CS) + ii) * CD + d) = vv;
                } else {
                    *(float2*)(C + (size_t)row * N + col) = vv;
                }
            }
        }
    }
}

#define GEMM_SMEM_BYTES(BN) (GEMM_NSTAGE * (128 * APITCH + 16 * ((BN) + 4)) * 4)

// ---------------- pack QKV weights/biases --------------------------------------
__global__ void pack_qkv_kernel(const float* __restrict__ wq, const float* __restrict__ wk,
                                const float* __restrict__ wv, const float* __restrict__ bq,
                                const float* __restrict__ bk, const float* __restrict__ bv)
{
    int idx = blockIdx.x * 256 + threadIdx.x;
    if (idx < CE * CE) {
        int r = idx >> 9, c = idx & 511;
        g_wqkv[(size_t)r * 1536 + c] = wq[idx];
        g_wqkv[(size_t)r * 1536 + 512 + c] = wk[idx];
        g_wqkv[(size_t)r * 1536 + 1024 + c] = wv[idx];
    }
    if (idx < CE) {
        g_bqkv[idx] = bq[idx];
        g_bqkv[512 + idx] = bk[idx];
        g_bqkv[1024 + idx] = bv[idx];
    }
}

// ---------------- pad pos_emb into g_pe ---------------------------------------
__global__ void pe_copy_kernel(const float* __restrict__ pe)
{
    int t = blockIdx.x * 256 + threadIdx.x;
    if (t < CNR * CD) g_pe[t] = pe[t];
}

// ---------------- qz (tensor, RN tf32): (32768x64) @ (64x129->144) -------------
#define QZ_A 0
#define QZ_B (128*68)
#define QZ_SMEM_BYTES ((128*68 + 64*148) * 4)

__global__ __launch_bounds__(256, 2) void qz_mma_kernel(const float* __restrict__ pe)
{
    extern __shared__ uint32_t sm[];
    uint32_t* Asm = sm + QZ_A;
    uint32_t* Bsm = sm + QZ_B;

    const int m0 = blockIdx.x << 7;
    const int tid = threadIdx.x;
    const int warp = tid >> 5;
    const int lane = tid & 31;
    const int gid = lane >> 2;
    const int tig = lane & 3;
    const int wy = warp >> 1;
    const int wx = warp & 1;

    for (int t = tid; t < 64 * 148; t += 256) Bsm[t] = 0u;
    __syncthreads();

#pragma unroll
    for (int l = 0; l < 8; l++) {
        const int idx = tid + (l << 8);
        const int r = idx >> 4;
        const int c = (idx & 15) << 2;
        float4 qv = *(const float4*)(g_q + (size_t)(m0 + r) * CD + c);
        uint4 ua = {f2tf(qv.x), f2tf(qv.y), f2tf(qv.z), f2tf(qv.w)};
        *(uint4*)&Asm[r*68 + c] = ua;
    }
    for (int t = tid; t < CNR * 16; t += 256) {
        const int n = t >> 4;
        const int k = (t & 15) << 2;
        float4 pv = *(const float4*)(pe + (size_t)n * CD + k);
        Bsm[(k+0)*148 + n] = f2tf(pv.x);
        Bsm[(k+1)*148 + n] = f2tf(pv.y);
        Bsm[(k+2)*148 + n] = f2tf(pv.z);
        Bsm[(k+3)*148 + n] = f2tf(pv.w);
    }
    __syncthreads();

    float acc[2][9][4];
#pragma unroll
    for (int mt = 0; mt < 2; mt++)
#pragma unroll
        for (int nt = 0; nt < 9; nt++)
#pragma unroll
            for (int r = 0; r < 4; r++) acc[mt][nt][r] = 0.0f;

#pragma unroll
    for (int ks = 0; ks < 64; ks += 8) {
        uint32_t af[2][4];
#pragma unroll
        for (int mt = 0; mt < 2; mt++) {
            const int mrow = wy * 32 + mt * 16 + gid;
            af[mt][0] = Asm[mrow*68 + ks + tig];
            af[mt][1] = Asm[(mrow+8)*68 + ks + tig];
            af[mt][2] = Asm[mrow*68 + ks + tig + 4];
            af[mt][3] = Asm[(mrow+8)*68 + ks + tig + 4];
        }
        uint32_t bf[9][2];
#pragma unroll
        for (int nt = 0; nt < 9; nt++) {
            const int nc = wx * 72 + nt * 8 + gid;
            bf[nt][0] = Bsm[(ks + tig)*148 + nc];
            bf[nt][1] = Bsm[(ks + tig + 4)*148 + nc];
        }
#pragma unroll
        for (int mt = 0; mt < 2; mt++)
#pragma unroll
            for (int nt = 0; nt < 9; nt++)
                mma_tf32(acc[mt][nt], af[mt], bf[nt]);
    }

#pragma unroll
    for (int mt = 0; mt < 2; mt++)
#pragma unroll
        for (int nt = 0; nt < 9; nt++) {
            const int col = wx * 72 + nt * 8 + 2 * tig;
#pragma unroll
            for (int half = 0; half < 2; half++) {
                const int row = m0 + wy * 32 + mt * 16 + gid + half * 8;
                float2 vv = {acc[mt][nt][half*2+0], acc[mt][nt][half*2+1]};
                *(float2*)&g_qz[(size_t)row * QZP + col] = vv;
            }
        }
}

// ---------------- scores (tensor, RN tf32): 128x128 tile -----------------------
#define SC_Q 0
#define SC_K (128*68)
#define SC_INT (128*68 + 64*132)
#define SC_SMEM_BYTES ((SC_INT + 3*128) * 4)

__global__ __launch_bounds__(256, 2) void scores_mma_kernel(
    const float* __restrict__ dist, const int* __restrict__ dt,
    const int* __restrict__ mask)
{
    extern __shared__ uint32_t sm[];
    uint32_t* Qs = sm + SC_Q;
    uint32_t* Ks = sm + SC_K;
    int* dti_s = (int*)(sm + SC_INT);
    int* dtj_s = dti_s + 128;
    int* mj_s = dtj_s + 128;

    const int bh = blockIdx.z;
    const int b = bh >> 3;
    const int i0 = blockIdx.y << 7;
    const int j0 = blockIdx.x << 7;
    const int tid = threadIdx.x;
    const int warp = tid >> 5;
    const int lane = tid & 31;
    const int gid = lane >> 2;
    const int tig = lane & 3;
    const int wy = warp >> 1;
    const int wx = warp & 1;

    const float* qb = g_q + (size_t)bh * CS * CD;
    const float* kb = g_k + (size_t)bh * CS * CD;

#pragma unroll
    for (int l = 0; l < 8; l++) {
        const int idx = tid + (l << 8);
        const int r = idx >> 4;
        const int c = (idx & 15) << 2;
        float4 qv = *(const float4*)(qb + (size_t)(i0 + r) * CD + c);
        float4 kv = *(const float4*)(kb + (size_t)(j0 + r) * CD + c);
        uint4 ua = {f2tf(qv.x), f2tf(qv.y), f2tf(qv.z), f2tf(qv.w)};
        *(uint4*)&Qs[r*68 + c] = ua;
        Ks[(c+0)*132 + r] = f2tf(kv.x);
        Ks[(c+1)*132 + r] = f2tf(kv.y);
        Ks[(c+2)*132 + r] = f2tf(kv.z);
        Ks[(c+3)*132 + r] = f2tf(kv.w);
    }
    if (tid < 128) {
        dti_s[tid] = dt[b * CS + i0 + tid];
        dtj_s[tid] = dt[b * CS + j0 + tid];
        mj_s[tid] = mask[b * CS + j0 + tid];
    }
    __syncthreads();

    float acc[2][8][4];
#pragma unroll
    for (int mt = 0; mt < 2; mt++)
#pragma unroll
        for (int nt = 0; nt < 8; nt++)
#pragma unroll
            for (int r = 0; r < 4; r++) acc[mt][nt][r] = 0.0f;

#pragma unroll
    for (int ks = 0; ks < 64; ks += 8) {
        uint32_t af[2][4];
#pragma unroll
        for (int mt = 0; mt < 2; mt++) {
            const int mrow = wy * 32 + mt * 16 + gid;
            af[mt][0] = Qs[mrow*68 + ks + tig];
            af[mt][1] = Qs[(mrow+8)*68 + ks + tig];
            af[mt][2] = Qs[mrow*68 + ks + tig + 4];
            af[mt][3] = Qs[(mrow+8)*68 + ks + tig + 4];
        }
        uint32_t bf[8][2];
#pragma unroll
        for (int nt = 0; nt < 8; nt++) {
            const int nc = wx * 64 + nt * 8 + gid;
            bf[nt][0] = Ks[(ks + tig)*132 + nc];
            bf[nt][1] = Ks[(ks + tig + 4)*132 + nc];
        }
#pragma unroll
        for (int mt = 0; mt < 2; mt++)
#pragma unroll
            for (int nt = 0; nt < 8; nt++)
                mma_tf32(acc[mt][nt], af[mt], bf[nt]);
    }

    // epilogue: qz gather + dist + mask
#pragma unroll
    for (int mt = 0; mt < 2; mt++) {
#pragma unroll
        for (int half = 0; half < 2; half++) {
            const int il = wy * 32 + mt * 16 + gid + half * 8;
            const int i = i0 + il;
            const int di = dti_s[il];
            const size_t qzrow = ((size_t)bh * CS + i) * QZP;
            const size_t drow = ((size_t)b * CS + i) * CS;
            const size_t wrow = ((size_t)bh * CS + i) * CS;
#pragma unroll
            for (int nt = 0; nt < 8; nt++) {
                const int jl = wx * 64 + nt * 8 + 2 * tig;
                float ov[2];
#pragma unroll
                for (int u = 0; u < 2; u++) {
                    const int jloc = jl + u;
                    int rel = min(max(dtj_s[jloc] - di, -CP), CP) + CP;
                    float v = (acc[mt][nt][half*2+u] + g_qz[qzrow + rel]) * 0.125f
                            + 0.6f * dist[drow + j0 + jloc];
                    if (mj_s[jloc] == 0) v = -1e9f;
                    ov[u] = v;
                }
                float2 st = {ov[0], ov[1]};
                *(float2*)&g_w[wrow + j0 + jl] = st;
            }
        }
    }
}

// ---------------- softmax + 129-bin histogram (shuffle reductions) -------------
__global__ __launch_bounds__(256) void softmax_kernel(const int* __restrict__ dt)
{
    const int row = blockIdx.x;           // bh*S + i
    const int bh = row >> 9;
    const int i = row & 511;
    const int b = bh >> 3;
    float* wr = g_w + (size_t)row * CS;
    const int tid = threadIdx.x;
    const int lane = tid & 31;
    const int wid = tid >> 5;

    __shared__ float wred[8];
    __shared__ float stat;
    __shared__ float bins[CNR];

    float2 v = *(const float2*)&wr[2 * tid];
    float m = fmaxf(v.x, v.y);
#pragma unroll
    for (int o = 16; o > 0; o >>= 1)
        m = fmaxf(m, __shfl_xor_sync(0xffffffffu, m, o));
    if (lane == 0) wred[wid] = m;
    if (tid < CNR) bins[tid] = 0.0f;
    __syncthreads();
    if (tid == 0) {
        float mm = wred[0];
#pragma unroll
        for (int k = 1; k < 8; k++) mm = fmaxf(mm, wred[k]);
        stat = mm;
    }
    __syncthreads();
    const float mx = stat;

    const float e0 = __expf(v.x - mx);
    const float e1 = __expf(v.y - mx);
    float s = e0 + e1;
#pragma unroll
    for (int o = 16; o > 0; o >>= 1)
        s += __shfl_xor_sync(0xffffffffu, s, o);
    if (lane == 0) wred[wid] = s;
    __syncthreads();
    if (tid == 0) {
        float ss = wred[0];
#pragma unroll
        for (int k = 1; k < 8; k++) ss += wred[k];
        stat = 1.0f / ss;
    }
    __syncthreads();
    const float inv = stat;

    const float a0 = e0 * inv, a1 = e1 * inv;
    float2 st = {a0, a1};
    *(float2*)&wr[2 * tid] = st;

    const int di = dt[b * CS + i];
    int2 dj = *(const int2*)&dt[b * CS + 2 * tid];
    int r0 = min(max(dj.x - di, -CP), CP) + CP;
    int r1 = min(max(dj.y - di, -CP), CP) + CP;
    atomicAdd(&bins[r0], a0);
    atomicAdd(&bins[r1], a1);
    __syncthreads();
    if (tid < CNR) g_s[(size_t)row * CSR + tid] = bins[tid];
}

// ---------------- attn (tensor, cp.async double-buffer): 128x64 tile -----------
// dynamic smem (uint32): A[2][128*68], B[2][64*68]
#define AT_ASZ (128*68)
#define AT_BSZ (64*68)
#define AT_SMEM_BYTES ((2*AT_ASZ + 2*AT_BSZ) * 4)

__global__ __launch_bounds__(256, 2) void attn_mma_kernel()
{
    extern __shared__ uint32_t sm[];
    uint32_t* Abuf = sm;                  // [2][AT_ASZ]
    uint32_t* Bbuf = sm + 2 * AT_ASZ;     // [2][AT_BSZ]

    const int bh = blockIdx.y;
    const int b = bh >> 3, h = bh & 7;
    const int i0 = blockIdx.x << 7;
    const int tid = threadIdx.x;
    const int warp = tid >> 5;
    const int lane = tid & 31;
    const int gid = lane >> 2;
    const int tig = lane & 3;
    const int wy = warp >> 1;
    const int wx = warp & 1;

    const float* awb = g_w + (size_t)bh * CS * CS;
    const float* sb = g_s + (size_t)bh * CS * CSR;
    const float* vb = g_v + (size_t)bh * CS * CD;

    const uint32_t a_base = (uint32_t)__cvta_generic_to_shared(Abuf);
    const uint32_t b_base = (uint32_t)__cvta_generic_to_shared(Bbuf);

    // per-thread staging coordinates
    const int a_r = tid >> 1;              // 0..127 (two float4 per row pair)
    const int a_c = (tid & 1) << 3;        // 0 or 8 -> two cp16 each covering 4
    const int b_r = tid >> 2;              // 0..63
    const int b_c = (tid & 3) << 2;        // 0,4,8,12 -> one cp16 covers 4; need 64 cols -> 4 cp16/row over 4 threads... 

    // A tile: 128 rows x 64 cols = 2048 float4; 256 threads x 8 cp16
    // B tile: 64 rows x 64 cols = 1024 float4; 256 threads x 4 cp16
    auto stage = [&](int c, int buf) {
        const uint32_t adst = a_base + buf * AT_ASZ * 4;
        const uint32_t bdst = b_base + buf * AT_BSZ * 4;
#pragma unroll
        for (int l = 0; l < 8; l++) {
            const int idx = tid + (l << 8);          // 0..2047
            const int r = idx >> 4;
            const int cc = (idx & 15) << 2;
            const float* src;
            if (c < 8) src = awb + (size_t)(i0 + r) * CS + (c << 6) + cc;
            else       src = sb + (size_t)(i0 + r) * CSR + ((c - 8) << 6) + cc;
            cp16(adst + (r * 68 + cc) * 4, src);
        }
#pragma unroll
        for (int l = 0; l < 4; l++) {
            const int idx = tid + (l << 8);          // 0..1023
            const int r = idx >> 4;
            const int cc = (idx & 15) << 2;
            const float* src;
            if (c < 8) src = vb + (size_t)((c << 6) + r) * CD + cc;
            else       src = g_pe + (size_t)(((c - 8) << 6) + r) * CD + cc;
            cp16(bdst + (r * 68 + cc) * 4, src);
        }
    };

    float acc[2][4][4];
#pragma unroll
    for (int mt = 0; mt < 2; mt++)
#pragma unroll
        for (int nt = 0; nt < 4; nt++)
#pragma unroll
            for (int r = 0; r < 4; r++) acc[mt][nt][r] = 0.0f;

    stage(0, 0);
    cp_commit();

    for (int c = 0; c < 11; c++) {
        if (c + 1 < 11) stage(c + 1, (c + 1) & 1);
        cp_commit();
        cp_wait<1>();
        __syncthreads();

        const uint32_t* Asm = Abuf + (c & 1) * AT_ASZ;
        const uint32_t* Bsm = Bbuf + (c & 1) * AT_BSZ;
#pragma unroll
        for (int ks = 0; ks < 64; ks += 8) {
            uint32_t af[2][4];
#pragma unroll
            for (int mt = 0; mt < 2; mt++) {
                const int mrow = wy * 32 + mt * 16 + gid;
                af[mt][0] = Asm[mrow*68 + ks + tig];
                af[mt][1] = Asm[(mrow+8)*68 + ks + tig];
                af[mt][2] = Asm[mrow*68 + ks + tig + 4];
                af[mt][3] = Asm[(mrow+8)*68 + ks + tig + 4];
            }
            uint32_t bf[4][2];
#pragma unroll
            for (int nt = 0; nt < 4; nt++) {
                const int nc = wx * 32 + nt * 8 + gid;
                bf[nt][0] = Bsm[(ks + tig)*68 + nc];
                bf[nt][1] = Bsm[(ks + tig + 4)*68 + nc];
            }
#pragma unroll
            for (int mt = 0; mt < 2; mt++)
#pragma unroll
                for (int nt = 0; nt < 4; nt++)
                    mma_tf32(acc[mt][nt], af[mt], bf[nt]);
        }
        __syncthreads();
    }

#pragma unroll
    for (int mt = 0; mt < 2; mt++)
#pragma unroll
        for (int nt = 0; nt < 4; nt++) {
            const int col = wx * 32 + nt * 8 + 2 * tig;
#pragma unroll
            for (int half = 0; half < 2; half++) {
                const int row = wy * 32 + mt * 16 + gid + half * 8;
                float2 vv = {acc[mt][nt][half*2+0], acc[mt][nt][half*2+1]};
                *(float2*)&g_concat[(size_t)(b * CS + i0 + row) * CE + h * CD + col] = vv;
            }
        }
}

// ---------------- layernorm (row = 512) ---------------------------------------
__global__ __launch_bounds__(256) void ln_kernel(
    const float* __restrict__ in, float* __restrict__ out,
    const float* __restrict__ gg, const float* __restrict__ bb)
{
    const int row = blockIdx.x;
    const float* xr = in + (size_t)row * CE;
    const int tid = threadIdx.x;
    const int lane = tid & 31;
    const int wid = tid >> 5;
    __shared__ float wred[8];
    __shared__ float stat;

    float2 v = *(const float2*)&xr[2 * tid];
    float s = v.x + v.y;
#pragma unroll
    for (int o = 16; o > 0; o >>= 1) s += __shfl_xor_sync(0xffffffffu, s, o);
    if (lane == 0) wred[wid] = s;
    __syncthreads();
    if (tid == 0) {
        float ss = wred[0];
#pragma unroll
        for (int k = 1; k < 8; k++) ss += wred[k];
        stat = ss * (1.0f / CE);
    }
    __syncthreads();
    const float mu = stat;
    const float d0 = v.x - mu, d1 = v.y - mu;
    float q = d0 * d0 + d1 * d1;
#pragma unroll
    for (int o = 16; o > 0; o >>= 1) q += __shfl_xor_sync(0xffffffffu, q, o);
    if (lane == 0) wred[wid] = q;
    __syncthreads();
    if (tid == 0) {
        float qq = wred[0];
#pragma unroll
        for (int k = 1; k < 8; k++) qq += wred[k];
        stat = rsqrtf(qq * (1.0f / CE) + 1e-5f);
    }
    __syncthreads();
    const float rstd = stat;
    float2 gv = *(const float2*)&gg[2 * tid];
    float2 bv = *(const float2*)&bb[2 * tid];
    float2 ov = {d0 * rstd * gv.x + bv.x, d1 * rstd * gv.y + bv.y};
    *(float2*)&out[(size_t)row * CE + 2 * tid] = ov;
}

// ---------------- launch -------------------------------------------------------
extern "C" void kernel_launch(void* const* d_in, const int* in_sizes, int n_in,
                              void* d_out, int out_size)
{
    const float* x    = (const float*)d_in[0];
    const float* dist = (const float*)d_in[1];
    const int*   dt   = (const int*)d_in[2];
    const int*   mask = (const int*)d_in[3];
    const float* wq_w = (const float*)d_in[4];
    const float* wq_b = (const float*)d_in[5];
    const float* wk_w = (const float*)d_in[6];
    const float* wk_b = (const float*)d_in[7];
    const float* wv_w = (const float*)d_in[8];
    const float* wv_b = (const float*)d_in[9];
    const float* wo_w = (const float*)d_in[10];
    const float* wo_b = (const float*)d_in[11];
    const float* pe   = (const float*)d_in[12];
    const float* w1   = (const float*)d_in[13];
    const float* b1   = (const float*)d_in[14];
    const float* w2   = (const float*)d_in[15];
    const float* b2   = (const float*)d_in[16];
    const float* ln1g = (const float*)d_in[17];
    const float* ln1b = (const float*)d_in[18];
    const float* ln2g = (const float*)d_in[19];
    const float* ln2b = (const float*)d_in[20];
    float* out = (float*)d_out;

    void *pq, *pk, *pv, *pcc, *pt1, *pao, *phid, *pt2, *pwqkv, *pbqkv;
    cudaGetSymbolAddress(&pq, g_q);
    cudaGetSymbolAddress(&pk, g_k);
    cudaGetSymbolAddress(&pv, g_v);
    cudaGetSymbolAddress(&pcc, g_concat);
    cudaGetSymbolAddress(&pt1, g_t1);
    cudaGetSymbolAddress(&pao, g_attnout);
    cudaGetSymbolAddress(&phid, g_hidden);
    cudaGetSymbolAddress(&pt2, g_t2);
    cudaGetSymbolAddress(&pwqkv, g_wqkv);
    cudaGetSymbolAddress(&pbqkv, g_bqkv);

    cudaFuncSetAttribute(scores_mma_kernel,
                         cudaFuncAttributeMaxDynamicSharedMemorySize, SC_SMEM_BYTES);
    cudaFuncSetAttribute(attn_mma_kernel,
                         cudaFuncAttributeMaxDynamicSharedMemorySize, AT_SMEM_BYTES);
    cudaFuncSetAttribute(qz_mma_kernel,
                         cudaFuncAttributeMaxDynamicSharedMemorySize, QZ_SMEM_BYTES);
    cudaFuncSetAttribute(mma_gemm_kernel<128>,
                         cudaFuncAttributeMaxDynamicSharedMemorySize, GEMM_SMEM_BYTES(128));
    cudaFuncSetAttribute(mma_gemm_kernel<64>,
                         cudaFuncAttributeMaxDynamicSharedMemorySize, GEMM_SMEM_BYTES(64));

    pe_copy_kernel<<<(CNR * CD + 255) / 256, 256>>>(pe);
    pack_qkv_kernel<<<(CE * CE + 255) / 256, 256>>>(wq_w, wk_w, wv_w, wq_b, wk_b, wv_b);

    // fused QKV: M=4096, N=1536, K=512
    dim3 gq(1536 / 128, CM / 128);
    mma_gemm_kernel<128><<<gq, 256, GEMM_SMEM_BYTES(128)>>>(
        x, (const float*)pwqkv, (float*)pq, (float*)pk, (float*)pv,
        CM, 1536, CE, (const float*)pbqkv, nullptr, EPI_QKV);

    qz_mma_kernel<<<(CBH * CS) / 128, 256, QZ_SMEM_BYTES>>>(pe);

    dim3 gsc(CS / 128, CS / 128, CBH);
    scores_mma_kernel<<<gsc, 256, SC_SMEM_BYTES>>>(dist, dt, mask);

    softmax_kernel<<<CBH * CS, 256>>>(dt);

    dim3 gat(CS / 128, CBH);
    attn_mma_kernel<<<gat, 256, AT_SMEM_BYTES>>>();

    dim3 gwo(CE / 64, CM / 128);
    mma_gemm_kernel<64><<<gwo, 256, GEMM_SMEM_BYTES(64)>>>(
        (const float*)pcc, wo_w, (float*)pt1, nullptr, nullptr,
        CM, CE, CE, wo_b, x, EPI_RESID);
    ln_kernel<<<CM, 256>>>((const float*)pt1, (float*)pao, ln1g, ln1b);

    dim3 gf1(CF / 128, CM / 128);
    mma_gemm_kernel<128><<<gf1, 256, GEMM_SMEM_BYTES(128)>>>(
        (const float*)pao, w1, (float*)phid, nullptr, nullptr,
        CM, CF, CE, b1, nullptr, EPI_RELU);
    dim3 gf2(CE / 64, CM / 128);
    mma_gemm_kernel<64><<<gf2, 256, GEMM_SMEM_BYTES(64)>>>(
        (const float*)phid, w2, (float*)pt2, nullptr, nullptr,
        CM, CE, CF, b2, (const float*)pao, EPI_RESID);
    ln_kernel<<<CM, 256>>>((const float*)pt2, out, ln2g, ln2b);
}

// round 9
// speedup vs baseline: 1.7476x; 1.0601x over previous
#include <cuda_runtime.h>
#include <cstdint>
#include <cstddef>

// Problem constants
#define CB 8
#define CS 512
#define CE 512
#define CH 8
#define CD 64
#define CP 64
#define CF 2048
#define CNR 129            // 2P+1
#define QZP 144            // padded qz row stride
#define CSR 192            // padded stride for bins / pos_emb (3 chunks of 64)
#define CBH (CB*CH)        // 64
#define CM (CB*CS)         // 4096

// ---------------- device scratch (zero-initialized .bss) ----------------------
__device__ __align__(16) float g_q[CBH*CS*CD];
__device__ __align__(16) float g_k[CBH*CS*CD];
__device__ __align__(16) float g_v[CBH*CS*CD];
__device__ __align__(16) float g_qz[(size_t)CBH*CS*QZP];
__device__ __align__(16) float g_w[CBH*CS*CS];          // scores -> aw (in place)
__device__ __align__(16) float g_s[CBH*CS*CSR];         // softmax bins (padded)
__device__ __align__(16) float g_pe[CSR*CD];            // padded pos_emb
__device__ __align__(16) float g_concat[CM*CE];         // rounded at write
__device__ __align__(16) float g_t1[CM*CE];
__device__ __align__(16) float g_attnout[CM*CE];        // fp32 (resid)
__device__ __align__(16) float g_attnout_r[CM*CE];      // RN-rounded (FFN1 A)
__device__ __align__(16) float g_hidden[CM*CF];         // rounded at write
__device__ __align__(16) float g_t2[CM*CE];
__device__ __align__(16) float g_wqkv[CE*3*CE];         // packed+rounded [512][1536]
__device__ __align__(16) float g_bqkv[3*CE];
__device__ __align__(16) float g_xr[CM*CE];             // rounded x
__device__ __align__(16) float g_wor[CE*CE];            // rounded wo
__device__ __align__(16) float g_w1r[CE*CF];            // rounded w1
__device__ __align__(16) float g_w2r[CF*CE];            // rounded w2

enum { EPI_QKV = 0, EPI_RESID = 1, EPI_RELU = 2 };

__device__ __forceinline__ uint32_t f2tf(float f) {
    uint32_t u;
    asm("cvt.rna.tf32.f32 %0, %1;" : "=r"(u) : "f"(f));
    return u;
}
__device__ __forceinline__ float roundtf(float f) {
    return __uint_as_float(f2tf(f));
}

__device__ __forceinline__ void mma_tf32(float c[4], const uint32_t a[4],
                                         const uint32_t b[2]) {
    asm volatile(
        "mma.sync.aligned.m16n8k8.row.col.f32.tf32.tf32.f32 "
        "{%0,%1,%2,%3}, {%4,%5,%6,%7}, {%8,%9}, {%0,%1,%2,%3};\n"
        : "+f"(c[0]), "+f"(c[1]), "+f"(c[2]), "+f"(c[3])
        : "r"(a[0]), "r"(a[1]), "r"(a[2]), "r"(a[3]), "r"(b[0]), "r"(b[1]));
}

__device__ __forceinline__ void cp16(uint32_t dst, const void* src) {
    asm volatile("cp.async.cg.shared.global [%0], [%1], 16;\n" :: "r"(dst), "l"(src));
}
__device__ __forceinline__ void cp_commit() {
    asm volatile("cp.async.commit_group;\n");
}
template<int N>
__device__ __forceinline__ void cp_wait() {
    asm volatile("cp.async.wait_group %0;\n" :: "n"(N));
}

// ---------------- TF32 tensor-core GEMM (cp.async 3-stage, BK=32) -------------
#define APITCH 36
#define GEMM_NSTAGE 3

template<int BN>
__global__ __launch_bounds__(256, 2) void mma_gemm_kernel(
    const float* __restrict__ A, const float* __restrict__ Bm,
    float* __restrict__ C, float* __restrict__ C2, float* __restrict__ C3,
    int M, int N, int K,
    const float* __restrict__ bias, const float* __restrict__ resid, int mode)
{
    constexpr int BPITCH = BN + 4;
    constexpr int NT = BN / 16;
    constexpr int ASZ = 128 * APITCH;      // u32 per stage (128x32 + pad)
    constexpr int BSZ = 32 * BPITCH;
    constexpr int NBL = (BN == 128) ? 4 : 2;
    extern __shared__ uint32_t smem_u[];
    uint32_t* As = smem_u;                       // [3][ASZ]
    uint32_t* Bs = smem_u + GEMM_NSTAGE * ASZ;   // [3][BSZ]

    const int tid = threadIdx.x;
    const int warp = tid >> 5;
    const int lane = tid & 31;
    const int gid = lane >> 2;
    const int tig = lane & 3;
    const int wy = warp >> 1;
    const int wx = warp & 1;
    const int bm = blockIdx.y * 128;
    const int bn = blockIdx.x * BN;

    const uint32_t a_base = (uint32_t)__cvta_generic_to_shared(As);
    const uint32_t b_base = (uint32_t)__cvta_generic_to_shared(Bs);

    const int nk = K >> 5;

    auto stageg = [&](int s) {
        const int bs = s % GEMM_NSTAGE;
        const uint32_t adst = a_base + bs * ASZ * 4;
        const uint32_t bdst = b_base + bs * BSZ * 4;
#pragma unroll
        for (int l = 0; l < 4; l++) {
            const int idx = tid + (l << 8);
            const int r = idx >> 3;
            const int c = (idx & 7) << 2;
            cp16(adst + (r * APITCH + c) * 4,
                 A + (size_t)(bm + r) * K + (s << 5) + c);
        }
#pragma unroll
        for (int l = 0; l < NBL; l++) {
            const int idx = tid + (l << 8);
            int r, c;
            if (BN == 128) { r = idx >> 5; c = (idx & 31) << 2; }
            else           { r = idx >> 4; c = (idx & 15) << 2; }
            cp16(bdst + (r * BPITCH + c) * 4,
                 Bm + (size_t)((s << 5) + r) * N + bn + c);
        }
    };

    float acc[2][NT][4];
#pragma unroll
    for (int mt = 0; mt < 2; mt++)
#pragma unroll
        for (int nt = 0; nt < NT; nt++)
#pragma unroll
            for (int r = 0; r < 4; r++) acc[mt][nt][r] = 0.0f;

    // prologue: stages 0,1
#pragma unroll
    for (int s = 0; s < GEMM_NSTAGE - 1; s++) {
        if (s < nk) stageg(s);
        cp_commit();
    }

    for (int i = 0; i < nk; i++) {
        const int sn = i + GEMM_NSTAGE - 1;
        if (sn < nk) stageg(sn);
        cp_commit();
        cp_wait<GEMM_NSTAGE - 1>();
        __syncthreads();

        const int buf = i % GEMM_NSTAGE;
        const uint32_t* Ab = As + buf * ASZ;
        const uint32_t* Bb = Bs + buf * BSZ;
#pragma unroll
        for (int ks = 0; ks < 32; ks += 8) {
            uint32_t af[2][4];
#pragma unroll
            for (int mt = 0; mt < 2; mt++) {
                const int mrow = wy * 32 + mt * 16 + gid;
                af[mt][0] = Ab[mrow * APITCH + ks + tig];
                af[mt][1] = Ab[(mrow + 8) * APITCH + ks + tig];
                af[mt][2] = Ab[mrow * APITCH + ks + tig + 4];
                af[mt][3] = Ab[(mrow + 8) * APITCH + ks + tig + 4];
            }
            uint32_t bf[NT][2];
#pragma unroll
            for (int nt = 0; nt < NT; nt++) {
                const int nc = wx * (BN / 2) + nt * 8 + gid;
                bf[nt][0] = Bb[(ks + tig) * BPITCH + nc];
                bf[nt][1] = Bb[(ks + tig + 4) * BPITCH + nc];
            }
#pragma unroll
            for (int mt = 0; mt < 2; mt++)
#pragma unroll
                for (int nt = 0; nt < NT; nt++)
                    mma_tf32(acc[mt][nt], af[mt], bf[nt]);
        }
        __syncthreads();
    }

#pragma unroll
    for (int mt = 0; mt < 2; mt++) {
#pragma unroll
        for (int nt = 0; nt < NT; nt++) {
            const int col = bn + wx * (BN / 2) + nt * 8 + 2 * tig;
            float bv0 = 0.0f, bv1 = 0.0f;
            if (bias) { bv0 = bias[col]; bv1 = bias[col + 1]; }
#pragma unroll
            for (int half = 0; half < 2; half++) {
                const int row = bm + wy * 32 + mt * 16 + gid + half * 8;
                float v0 = acc[mt][nt][half * 2 + 0] + bv0;
                float v1 = acc[mt][nt][half * 2 + 1] + bv1;
                if (mode == EPI_RESID) {
                    v0 += resid[(size_t)row * N + col];
                    v1 += resid[(size_t)row * N + col + 1];
                } else if (mode == EPI_RELU) {
                    v0 = roundtf(fmaxf(v0, 0.0f));   // RN for next GEMM
                    v1 = roundtf(fmaxf(v1, 0.0f));
                }
                float2 vv = {v0, v1};
                if (mode == EPI_QKV) {
                    const int b = row >> 9, ii = row & 511;
                    const int which = col >> 9;
                    const int cc = col & 511;
                    const int h = cc >> 6, d = cc & 63;
                    float* base = (which == 0) ? C : (which == 1) ? C2 : C3;
                    *(float2*)(base + (((size_t)(b * CH + h) * CS) + ii) * CD + d) = vv;
                } else {
                    *(float2*)(C + (size_t)row * N + col) = vv;
                }
            }
        }
    }
}

#define GEMM_SMEM_BYTES(BN) (GEMM_NSTAGE * (128 * APITCH + 32 * ((BN) + 4)) * 4)

// ---------------- round-copy (fp32 -> RN tf32 values) --------------------------
__global__ void round_copy_kernel(const float4* __restrict__ in,
                                  float4* __restrict__ out, int n4)
{
    int i = blockIdx.x * 256 + threadIdx.x;
    if (i < n4) {
        float4 v = in[i];
        v.x = roundtf(v.x); v.y = roundtf(v.y);
        v.z = roundtf(v.z); v.w = roundtf(v.w);
        out[i] = v;
    }
}

// ---------------- pack QKV weights/biases (rounded) ----------------------------
__global__ void pack_qkv_kernel(const float* __restrict__ wq, const float* __restrict__ wk,
                                const float* __restrict__ wv, const float* __restrict__ bq,
                                const float* __restrict__ bk, const float* __restrict__ bv)
{
    int idx = blockIdx.x * 256 + threadIdx.x;
    if (idx < CE * CE) {
        int r = idx >> 9, c = idx & 511;
        g_wqkv[(size_t)r * 1536 + c] = roundtf(wq[idx]);
        g_wqkv[(size_t)r * 1536 + 512 + c] = roundtf(wk[idx]);
        g_wqkv[(size_t)r * 1536 + 1024 + c] = roundtf(wv[idx]);
    }
    if (idx < CE) {
        g_bqkv[idx] = bq[idx];
        g_bqkv[512 + idx] = bk[idx];
        g_bqkv[1024 + idx] = bv[idx];
    }
}

// ---------------- pad pos_emb into g_pe ---------------------------------------
__global__ void pe_copy_kernel(const float* __restrict__ pe)
{
    int t = blockIdx.x * 256 + threadIdx.x;
    if (t < CNR * CD) g_pe[t] = pe[t];
}

// ---------------- qz (tensor, RN tf32): (32768x64) @ (64x129->144) -------------
#define QZ_A 0
#define QZ_B (128*68)
#define QZ_SMEM_BYTES ((128*68 + 64*148) * 4)

__global__ __launch_bounds__(256, 2) void qz_mma_kernel(const float* __restrict__ pe)
{
    extern __shared__ uint32_t sm[];
    uint32_t* Asm = sm + QZ_A;
    uint32_t* Bsm = sm + QZ_B;

    const int m0 = blockIdx.x << 7;
    const int tid = threadIdx.x;
    const int warp = tid >> 5;
    const int lane = tid & 31;
    const int gid = lane >> 2;
    const int tig = lane & 3;
    const int wy = warp >> 1;
    const int wx = warp & 1;

    for (int t = tid; t < 64 * 148; t += 256) Bsm[t] = 0u;
    __syncthreads();

#pragma unroll
    for (int l = 0; l < 8; l++) {
        const int idx = tid + (l << 8);
        const int r = idx >> 4;
        const int c = (idx & 15) << 2;
        float4 qv = *(const float4*)(g_q + (size_t)(m0 + r) * CD + c);
        uint4 ua = {f2tf(qv.x), f2tf(qv.y), f2tf(qv.z), f2tf(qv.w)};
        *(uint4*)&Asm[r*68 + c] = ua;
    }
    for (int t = tid; t < CNR * 16; t += 256) {
        const int n = t >> 4;
        const int k = (t & 15) << 2;
        float4 pv = *(const float4*)(pe + (size_t)n * CD + k);
        Bsm[(k+0)*148 + n] = f2tf(pv.x);
        Bsm[(k+1)*148 + n] = f2tf(pv.y);
        Bsm[(k+2)*148 + n] = f2tf(pv.z);
        Bsm[(k+3)*148 + n] = f2tf(pv.w);
    }
    __syncthreads();

    float acc[2][9][4];
#pragma unroll
    for (int mt = 0; mt < 2; mt++)
#pragma unroll
        for (int nt = 0; nt < 9; nt++)
#pragma unroll
            for (int r = 0; r < 4; r++) acc[mt][nt][r] = 0.0f;

#pragma unroll
    for (int ks = 0; ks < 64; ks += 8) {
        uint32_t af[2][4];
#pragma unroll
        for (int mt = 0; mt < 2; mt++) {
            const int mrow = wy * 32 + mt * 16 + gid;
            af[mt][0] = Asm[mrow*68 + ks + tig];
            af[mt][1] = Asm[(mrow+8)*68 + ks + tig];
            af[mt][2] = Asm[mrow*68 + ks + tig + 4];
            af[mt][3] = Asm[(mrow+8)*68 + ks + tig + 4];
        }
        uint32_t bf[9][2];
#pragma unroll
        for (int nt = 0; nt < 9; nt++) {
            const int nc = wx * 72 + nt * 8 + gid;
            bf[nt][0] = Bsm[(ks + tig)*148 + nc];
            bf[nt][1] = Bsm[(ks + tig + 4)*148 + nc];
        }
#pragma unroll
        for (int mt = 0; mt < 2; mt++)
#pragma unroll
            for (int nt = 0; nt < 9; nt++)
                mma_tf32(acc[mt][nt], af[mt], bf[nt]);
    }

#pragma unroll
    for (int mt = 0; mt < 2; mt++)
#pragma unroll
        for (int nt = 0; nt < 9; nt++) {
            const int col = wx * 72 + nt * 8 + 2 * tig;
#pragma unroll
            for (int half = 0; half < 2; half++) {
                const int row = m0 + wy * 32 + mt * 16 + gid + half * 8;
                float2 vv = {acc[mt][nt][half*2+0], acc[mt][nt][half*2+1]};
                *(float2*)&g_qz[(size_t)row * QZP + col] = vv;
            }
        }
}

// ---------------- scores (tensor, RN tf32): 128x128 tile -----------------------
#define SC_Q 0
#define SC_K (128*68)
#define SC_INT (128*68 + 64*132)
#define SC_SMEM_BYTES ((SC_INT + 3*128) * 4)

__global__ __launch_bounds__(256, 2) void scores_mma_kernel(
    const float* __restrict__ dist, const int* __restrict__ dt,
    const int* __restrict__ mask)
{
    extern __shared__ uint32_t sm[];
    uint32_t* Qs = sm + SC_Q;
    uint32_t* Ks = sm + SC_K;
    int* dti_s = (int*)(sm + SC_INT);
    int* dtj_s = dti_s + 128;
    int* mj_s = dtj_s + 128;

    const int bh = blockIdx.z;
    const int b = bh >> 3;
    const int i0 = blockIdx.y << 7;
    const int j0 = blockIdx.x << 7;
    const int tid = threadIdx.x;
    const int warp = tid >> 5;
    const int lane = tid & 31;
    const int gid = lane >> 2;
    const int tig = lane & 3;
    const int wy = warp >> 1;
    const int wx = warp & 1;

    const float* qb = g_q + (size_t)bh * CS * CD;
    const float* kb = g_k + (size_t)bh * CS * CD;

#pragma unroll
    for (int l = 0; l < 8; l++) {
        const int idx = tid + (l << 8);
        const int r = idx >> 4;
        const int c = (idx & 15) << 2;
        float4 qv = *(const float4*)(qb + (size_t)(i0 + r) * CD + c);
        float4 kv = *(const float4*)(kb + (size_t)(j0 + r) * CD + c);
        uint4 ua = {f2tf(qv.x), f2tf(qv.y), f2tf(qv.z), f2tf(qv.w)};
        *(uint4*)&Qs[r*68 + c] = ua;
        Ks[(c+0)*132 + r] = f2tf(kv.x);
        Ks[(c+1)*132 + r] = f2tf(kv.y);
        Ks[(c+2)*132 + r] = f2tf(kv.z);
        Ks[(c+3)*132 + r] = f2tf(kv.w);
    }
    if (tid < 128) {
        dti_s[tid] = dt[b * CS + i0 + tid];
        dtj_s[tid] = dt[b * CS + j0 + tid];
        mj_s[tid] = mask[b * CS + j0 + tid];
    }
    __syncthreads();

    float acc[2][8][4];
#pragma unroll
    for (int mt = 0; mt < 2; mt++)
#pragma unroll
        for (int nt = 0; nt < 8; nt++)
#pragma unroll
            for (int r = 0; r < 4; r++) acc[mt][nt][r] = 0.0f;

#pragma unroll
    for (int ks = 0; ks < 64; ks += 8) {
        uint32_t af[2][4];
#pragma unroll
        for (int mt = 0; mt < 2; mt++) {
            const int mrow = wy * 32 + mt * 16 + gid;
            af[mt][0] = Qs[mrow*68 + ks + tig];
            af[mt][1] = Qs[(mrow+8)*68 + ks + tig];
            af[mt][2] = Qs[mrow*68 + ks + tig + 4];
            af[mt][3] = Qs[(mrow+8)*68 + ks + tig + 4];
        }
        uint32_t bf[8][2];
#pragma unroll
        for (int nt = 0; nt < 8; nt++) {
            const int nc = wx * 64 + nt * 8 + gid;
            bf[nt][0] = Ks[(ks + tig)*132 + nc];
            bf[nt][1] = Ks[(ks + tig + 4)*132 + nc];
        }
#pragma unroll
        for (int mt = 0; mt < 2; mt++)
#pragma unroll
            for (int nt = 0; nt < 8; nt++)
                mma_tf32(acc[mt][nt], af[mt], bf[nt]);
    }

    // epilogue: qz gather + dist + mask
#pragma unroll
    for (int mt = 0; mt < 2; mt++) {
#pragma unroll
        for (int half = 0; half < 2; half++) {
            const int il = wy * 32 + mt * 16 + gid + half * 8;
            const int i = i0 + il;
            const int di = dti_s[il];
            const size_t qzrow = ((size_t)bh * CS + i) * QZP;
            const size_t drow = ((size_t)b * CS + i) * CS;
            const size_t wrow = ((size_t)bh * CS + i) * CS;
#pragma unroll
            for (int nt = 0; nt < 8; nt++) {
                const int jl = wx * 64 + nt * 8 + 2 * tig;
                float ov[2];
#pragma unroll
                for (int u = 0; u < 2; u++) {
                    const int jloc = jl + u;
                    int rel = min(max(dtj_s[jloc] - di, -CP), CP) + CP;
                    float v = (acc[mt][nt][half*2+u] + g_qz[qzrow + rel]) * 0.125f
                            + 0.6f * dist[drow + j0 + jloc];
                    if (mj_s[jloc] == 0) v = -1e9f;
                    ov[u] = v;
                }
                float2 st = {ov[0], ov[1]};
                *(float2*)&g_w[wrow + j0 + jl] = st;
            }
        }
    }
}

// ---------------- softmax + 129-bin histogram (shuffle reductions) -------------
__global__ __launch_bounds__(256) void softmax_kernel(const int* __restrict__ dt)
{
    const int row = blockIdx.x;           // bh*S + i
    const int bh = row >> 9;
    const int i = row & 511;
    const int b = bh >> 3;
    float* wr = g_w + (size_t)row * CS;
    const int tid = threadIdx.x;
    const int lane = tid & 31;
    const int wid = tid >> 5;

    __shared__ float wred[8];
    __shared__ float stat;
    __shared__ float bins[CNR];

    float2 v = *(const float2*)&wr[2 * tid];
    float m = fmaxf(v.x, v.y);
#pragma unroll
    for (int o = 16; o > 0; o >>= 1)
        m = fmaxf(m, __shfl_xor_sync(0xffffffffu, m, o));
    if (lane == 0) wred[wid] = m;
    if (tid < CNR) bins[tid] = 0.0f;
    __syncthreads();
    if (tid == 0) {
        float mm = wred[0];
#pragma unroll
        for (int k = 1; k < 8; k++) mm = fmaxf(mm, wred[k]);
        stat = mm;
    }
    __syncthreads();
    const float mx = stat;

    const float e0 = __expf(v.x - mx);
    const float e1 = __expf(v.y - mx);
    float s = e0 + e1;
#pragma unroll
    for (int o = 16; o > 0; o >>= 1)
        s += __shfl_xor_sync(0xffffffffu, s, o);
    if (lane == 0) wred[wid] = s;
    __syncthreads();
    if (tid == 0) {
        float ss = wred[0];
#pragma unroll
        for (int k = 1; k < 8; k++) ss += wred[k];
        stat = 1.0f / ss;
    }
    __syncthreads();
    const float inv = stat;

    const float a0 = e0 * inv, a1 = e1 * inv;
    float2 st = {a0, a1};
    *(float2*)&wr[2 * tid] = st;

    const int di = dt[b * CS + i];
    int2 dj = *(const int2*)&dt[b * CS + 2 * tid];
    int r0 = min(max(dj.x - di, -CP), CP) + CP;
    int r1 = min(max(dj.y - di, -CP), CP) + CP;
    atomicAdd(&bins[r0], a0);
    atomicAdd(&bins[r1], a1);
    __syncthreads();
    if (tid < CNR) g_s[(size_t)row * CSR + tid] = bins[tid];
}

// ---------------- attn (tensor, cp.async double-buffer): 128x64 tile -----------
#define AT_ASZ (128*68)
#define AT_BSZ (64*68)
#define AT_SMEM_BYTES ((2*AT_ASZ + 2*AT_BSZ) * 4)

__global__ __launch_bounds__(256, 2) void attn_mma_kernel()
{
    extern __shared__ uint32_t sm[];
    uint32_t* Abuf = sm;                  // [2][AT_ASZ]
    uint32_t* Bbuf = sm + 2 * AT_ASZ;     // [2][AT_BSZ]

    const int bh = blockIdx.y;
    const int b = bh >> 3, h = bh & 7;
    const int i0 = blockIdx.x << 7;
    const int tid = threadIdx.x;
    const int warp = tid >> 5;
    const int lane = tid & 31;
    const int gid = lane >> 2;
    const int tig = lane & 3;
    const int wy = warp >> 1;
    const int wx = warp & 1;

    const float* awb = g_w + (size_t)bh * CS * CS;
    const float* sb = g_s + (size_t)bh * CS * CSR;
    const float* vb = g_v + (size_t)bh * CS * CD;

    const uint32_t a_base = (uint32_t)__cvta_generic_to_shared(Abuf);
    const uint32_t b_base = (uint32_t)__cvta_generic_to_shared(Bbuf);

    auto stage = [&](int c, int buf) {
        const uint32_t adst = a_base + buf * AT_ASZ * 4;
        const uint32_t bdst = b_base + buf * AT_BSZ * 4;
#pragma unroll
        for (int l = 0; l < 8; l++) {
            const int idx = tid + (l << 8);
            const int r = idx >> 4;
            const int cc = (idx & 15) << 2;
            const float* src;
            if (c < 8) src = awb + (size_t)(i0 + r) * CS + (c << 6) + cc;
            else       src = sb + (size_t)(i0 + r) * CSR + ((c - 8) << 6) + cc;
            cp16(adst + (r * 68 + cc) * 4, src);
        }
#pragma unroll
        for (int l = 0; l < 4; l++) {
            const int idx = tid + (l << 8);
            const int r = idx >> 4;
            const int cc = (idx & 15) << 2;
            const float* src;
            if (c < 8) src = vb + (size_t)((c << 6) + r) * CD + cc;
            else       src = g_pe + (size_t)(((c - 8) << 6) + r) * CD + cc;
            cp16(bdst + (r * 68 + cc) * 4, src);
        }
    };

    float acc[2][4][4];
#pragma unroll
    for (int mt = 0; mt < 2; mt++)
#pragma unroll
        for (int nt = 0; nt < 4; nt++)
#pragma unroll
            for (int r = 0; r < 4; r++) acc[mt][nt][r] = 0.0f;

    stage(0, 0);
    cp_commit();

    for (int c = 0; c < 11; c++) {
        if (c + 1 < 11) stage(c + 1, (c + 1) & 1);
        cp_commit();
        cp_wait<1>();
        __syncthreads();

        const uint32_t* Asm = Abuf + (c & 1) * AT_ASZ;
        const uint32_t* Bsm = Bbuf + (c & 1) * AT_BSZ;
#pragma unroll
        for (int ks = 0; ks < 64; ks += 8) {
            uint32_t af[2][4];
#pragma unroll
            for (int mt = 0; mt < 2; mt++) {
                const int mrow = wy * 32 + mt * 16 + gid;
                af[mt][0] = Asm[mrow*68 + ks + tig];
                af[mt][1] = Asm[(mrow+8)*68 + ks + tig];
                af[mt][2] = Asm[mrow*68 + ks + tig + 4];
                af[mt][3] = Asm[(mrow+8)*68 + ks + tig + 4];
            }
            uint32_t bf[4][2];
#pragma unroll
            for (int nt = 0; nt < 4; nt++) {
                const int nc = wx * 32 + nt * 8 + gid;
                bf[nt][0] = Bsm[(ks + tig)*68 + nc];
                bf[nt][1] = Bsm[(ks + tig + 4)*68 + nc];
            }
#pragma unroll
            for (int mt = 0; mt < 2; mt++)
#pragma unroll
                for (int nt = 0; nt < 4; nt++)
                    mma_tf32(acc[mt][nt], af[mt], bf[nt]);
        }
        __syncthreads();
    }

#pragma unroll
    for (int mt = 0; mt < 2; mt++)
#pragma unroll
        for (int nt = 0; nt < 4; nt++) {
            const int col = wx * 32 + nt * 8 + 2 * tig;
#pragma unroll
            for (int half = 0; half < 2; half++) {
                const int row = wy * 32 + mt * 16 + gid + half * 8;
                float2 vv = {roundtf(acc[mt][nt][half*2+0]),
                             roundtf(acc[mt][nt][half*2+1])};   // RN for wo GEMM
                *(float2*)&g_concat[(size_t)(b * CS + i0 + row) * CE + h * CD + col] = vv;
            }
        }
}

// ---------------- layernorm (row = 512), optional rounded second output --------
__global__ __launch_bounds__(256) void ln_kernel(
    const float* __restrict__ in, float* __restrict__ out,
    float* __restrict__ out_r,
    const float* __restrict__ gg, const float* __restrict__ bb)
{
    const int row = blockIdx.x;
    const float* xr = in + (size_t)row * CE;
    const int tid = threadIdx.x;
    const int lane = tid & 31;
    const int wid = tid >> 5;
    __shared__ float wred[8];
    __shared__ float stat;

    float2 v = *(const float2*)&xr[2 * tid];
    float s = v.x + v.y;
#pragma unroll
    for (int o = 16; o > 0; o >>= 1) s += __shfl_xor_sync(0xffffffffu, s, o);
    if (lane == 0) wred[wid] = s;
    __syncthreads();
    if (tid == 0) {
        float ss = wred[0];
#pragma unroll
        for (int k = 1; k < 8; k++) ss += wred[k];
        stat = ss * (1.0f / CE);
    }
    __syncthreads();
    const float mu = stat;
    const float d0 = v.x - mu, d1 = v.y - mu;
    float q = d0 * d0 + d1 * d1;
#pragma unroll
    for (int o = 16; o > 0; o >>= 1) q += __shfl_xor_sync(0xffffffffu, q, o);
    if (lane == 0) wred[wid] = q;
    __syncthreads();
    if (tid == 0) {
        float qq = wred[0];
#pragma unroll
        for (int k = 1; k < 8; k++) qq += wred[k];
        stat = rsqrtf(qq * (1.0f / CE) + 1e-5f);
    }
    __syncthreads();
    const float rstd = stat;
    float2 gv = *(const float2*)&gg[2 * tid];
    float2 bv = *(const float2*)&bb[2 * tid];
    float2 ov = {d0 * rstd * gv.x + bv.x, d1 * rstd * gv.y + bv.y};
    *(float2*)&out[(size_t)row * CE + 2 * tid] = ov;
    if (out_r) {
        float2 orr = {roundtf(ov.x), roundtf(ov.y)};
        *(float2*)&out_r[(size_t)row * CE + 2 * tid] = orr;
    }
}

// ---------------- launch -------------------------------------------------------
extern "C" void kernel_launch(void* const* d_in, const int* in_sizes, int n_in,
                              void* d_out, int out_size)
{
    const float* x    = (const float*)d_in[0];
    const float* dist = (const float*)d_in[1];
    const int*   dt   = (const int*)d_in[2];
    const int*   mask = (const int*)d_in[3];
    const float* wq_w = (const float*)d_in[4];
    const float* wq_b = (const float*)d_in[5];
    const float* wk_w = (const float*)d_in[6];
    const float* wk_b = (const float*)d_in[7];
    const float* wv_w = (const float*)d_in[8];
    const float* wv_b = (const float*)d_in[9];
    const float* wo_w = (const float*)d_in[10];
    const float* wo_b = (const float*)d_in[11];
    const float* pe   = (const float*)d_in[12];
    const float* w1   = (const float*)d_in[13];
    const float* b1   = (const float*)d_in[14];
    const float* w2   = (const float*)d_in[15];
    const float* b2   = (const float*)d_in[16];
    const float* ln1g = (const float*)d_in[17];
    const float* ln1b = (const float*)d_in[18];
    const float* ln2g = (const float*)d_in[19];
    const float* ln2b = (const float*)d_in[20];
    float* out = (float*)d_out;

    void *pq, *pk, *pv, *pcc, *pt1, *pao, *paor, *phid, *pt2, *pwqkv, *pbqkv;
    void *pxr, *pwor, *pw1r, *pw2r;
    cudaGetSymbolAddress(&pq, g_q);
    cudaGetSymbolAddress(&pk, g_k);
    cudaGetSymbolAddress(&pv, g_v);
    cudaGetSymbolAddress(&pcc, g_concat);
    cudaGetSymbolAddress(&pt1, g_t1);
    cudaGetSymbolAddress(&pao, g_attnout);
    cudaGetSymbolAddress(&paor, g_attnout_r);
    cudaGetSymbolAddress(&phid, g_hidden);
    cudaGetSymbolAddress(&pt2, g_t2);
    cudaGetSymbolAddress(&pwqkv, g_wqkv);
    cudaGetSymbolAddress(&pbqkv, g_bqkv);
    cudaGetSymbolAddress(&pxr, g_xr);
    cudaGetSymbolAddress(&pwor, g_wor);
    cudaGetSymbolAddress(&pw1r, g_w1r);
    cudaGetSymbolAddress(&pw2r, g_w2r);

    cudaFuncSetAttribute(scores_mma_kernel,
                         cudaFuncAttributeMaxDynamicSharedMemorySize, SC_SMEM_BYTES);
    cudaFuncSetAttribute(attn_mma_kernel,
                         cudaFuncAttributeMaxDynamicSharedMemorySize, AT_SMEM_BYTES);
    cudaFuncSetAttribute(qz_mma_kernel,
                         cudaFuncAttributeMaxDynamicSharedMemorySize, QZ_SMEM_BYTES);
    cudaFuncSetAttribute(mma_gemm_kernel<128>,
                         cudaFuncAttributeMaxDynamicSharedMemorySize, GEMM_SMEM_BYTES(128));
    cudaFuncSetAttribute(mma_gemm_kernel<64>,
                         cudaFuncAttributeMaxDynamicSharedMemorySize, GEMM_SMEM_BYTES(64));

    pe_copy_kernel<<<(CNR * CD + 255) / 256, 256>>>(pe);
    pack_qkv_kernel<<<(CE * CE + 255) / 256, 256>>>(wq_w, wk_w, wv_w, wq_b, wk_b, wv_b);
    round_copy_kernel<<<(CM * CE / 4 + 255) / 256, 256>>>((const float4*)x, (float4*)pxr, CM * CE / 4);
    round_copy_kernel<<<(CE * CE / 4 + 255) / 256, 256>>>((const float4*)wo_w, (float4*)pwor, CE * CE / 4);
    round_copy_kernel<<<(CE * CF / 4 + 255) / 256, 256>>>((const float4*)w1, (float4*)pw1r, CE * CF / 4);
    round_copy_kernel<<<(CF * CE / 4 + 255) / 256, 256>>>((const float4*)w2, (float4*)pw2r, CF * CE / 4);

    // fused QKV: M=4096, N=1536, K=512
    dim3 gq(1536 / 128, CM / 128);
    mma_gemm_kernel<128><<<gq, 256, GEMM_SMEM_BYTES(128)>>>(
        (const float*)pxr, (const float*)pwqkv, (float*)pq, (float*)pk, (float*)pv,
        CM, 1536, CE, (const float*)pbqkv, nullptr, EPI_QKV);

    qz_mma_kernel<<<(CBH * CS) / 128, 256, QZ_SMEM_BYTES>>>(pe);

    dim3 gsc(CS / 128, CS / 128, CBH);
    scores_mma_kernel<<<gsc, 256, SC_SMEM_BYTES>>>(dist, dt, mask);

    softmax_kernel<<<CBH * CS, 256>>>(dt);

    dim3 gat(CS / 128, CBH);
    attn_mma_kernel<<<gat, 256, AT_SMEM_BYTES>>>();

    dim3 gwo(CE / 64, CM / 128);
    mma_gemm_kernel<64><<<gwo, 256, GEMM_SMEM_BYTES(64)>>>(
        (const float*)pcc, (const float*)pwor, (float*)pt1, nullptr, nullptr,
        CM, CE, CE, wo_b, x, EPI_RESID);
    ln_kernel<<<CM, 256>>>((const float*)pt1, (float*)pao, (float*)paor, ln1g, ln1b);

    dim3 gf1(CF / 128, CM / 128);
    mma_gemm_kernel<128><<<gf1, 256, GEMM_SMEM_BYTES(128)>>>(
        (const float*)paor, (const float*)pw1r, (float*)phid, nullptr, nullptr,
        CM, CF, CE, b1, nullptr, EPI_RELU);
    dim3 gf2(CE / 64, CM / 128);
    mma_gemm_kernel<64><<<gf2, 256, GEMM_SMEM_BYTES(64)>>>(
        (const float*)phid, (const float*)pw2r, (float*)pt2, nullptr, nullptr,
        CM, CE, CF, b2, (const float*)pao, EPI_RESID);
    ln_kernel<<<CM, 256>>>((const float*)pt2, out, nullptr, ln2g, ln2b);
}

// round 10
// speedup vs baseline: 2.2183x; 1.2693x over previous
#include <cuda_runtime.h>
#include <cstdint>
#include <cstddef>

// Problem constants
#define CB 8
#define CS 512
#define CE 512
#define CH 8
#define CD 64
#define CP 64
#define CF 2048
#define CNR 129            // 2P+1
#define CSR 192            // padded stride for bins / pos_emb (3 chunks of 64)
#define CBH (CB*CH)        // 64
#define CM (CB*CS)         // 4096

// ---------------- device scratch (zero-initialized .bss) ----------------------
__device__ __align__(16) float g_q[CBH*CS*CD];
__device__ __align__(16) float g_k[CBH*CS*CD];
__device__ __align__(16) float g_v[CBH*CS*CD];
__device__ __align__(16) float g_w[CBH*CS*CS];          // final aw
__device__ __align__(16) float g_s[CBH*CS*CSR];         // softmax bins (padded)
__device__ __align__(16) float g_pe[CSR*CD];            // padded pos_emb
__device__ __align__(16) float g_concat[CM*CE];         // rounded at write
__device__ __align__(16) float g_t1[CM*CE];
__device__ __align__(16) float g_attnout[CM*CE];        // fp32 (resid)
__device__ __align__(16) float g_attnout_r[CM*CE];      // RN-rounded (FFN1 A)
__device__ __align__(16) float g_hidden[CM*CF];         // rounded at write
__device__ __align__(16) float g_t2[CM*CE];
__device__ __align__(16) float g_wqkv[CE*3*CE];         // packed+rounded [512][1536]
__device__ __align__(16) float g_bqkv[3*CE];
__device__ __align__(16) float g_xr[CM*CE];             // rounded x
__device__ __align__(16) float g_wor[CE*CE];            // rounded wo
__device__ __align__(16) float g_w1r[CE*CF];            // rounded w1
__device__ __align__(16) float g_w2r[CF*CE];            // rounded w2

enum { EPI_QKV = 0, EPI_RESID = 1, EPI_RELU = 2 };

__device__ __forceinline__ uint32_t f2tf(float f) {
    uint32_t u;
    asm("cvt.rna.tf32.f32 %0, %1;" : "=r"(u) : "f"(f));
    return u;
}
__device__ __forceinline__ float roundtf(float f) {
    return __uint_as_float(f2tf(f));
}

__device__ __forceinline__ void mma_tf32(float c[4], const uint32_t a[4],
                                         const uint32_t b[2]) {
    asm volatile(
        "mma.sync.aligned.m16n8k8.row.col.f32.tf32.tf32.f32 "
        "{%0,%1,%2,%3}, {%4,%5,%6,%7}, {%8,%9}, {%0,%1,%2,%3};\n"
        : "+f"(c[0]), "+f"(c[1]), "+f"(c[2]), "+f"(c[3])
        : "r"(a[0]), "r"(a[1]), "r"(a[2]), "r"(a[3]), "r"(b[0]), "r"(b[1]));
}

__device__ __forceinline__ void cp16(uint32_t dst, const void* src) {
    asm volatile("cp.async.cg.shared.global [%0], [%1], 16;\n" :: "r"(dst), "l"(src));
}
__device__ __forceinline__ void cp_commit() {
    asm volatile("cp.async.commit_group;\n");
}
template<int N>
__device__ __forceinline__ void cp_wait() {
    asm volatile("cp.async.wait_group %0;\n" :: "n"(N));
}

// ---------------- TF32 tensor-core GEMM (cp.async 3-stage, BK=32) -------------
#define APITCH 36
#define GEMM_NSTAGE 3

template<int BN>
__global__ __launch_bounds__(256, 2) void mma_gemm_kernel(
    const float* __restrict__ A, const float* __restrict__ Bm,
    float* __restrict__ C, float* __restrict__ C2, float* __restrict__ C3,
    int M, int N, int K,
    const float* __restrict__ bias, const float* __restrict__ resid, int mode)
{
    constexpr int BPITCH = BN + 4;
    constexpr int NT = BN / 16;
    constexpr int ASZ = 128 * APITCH;
    constexpr int BSZ = 32 * BPITCH;
    constexpr int NBL = (BN == 128) ? 4 : 2;
    extern __shared__ uint32_t smem_u[];
    uint32_t* As = smem_u;
    uint32_t* Bs = smem_u + GEMM_NSTAGE * ASZ;

    const int tid = threadIdx.x;
    const int warp = tid >> 5;
    const int lane = tid & 31;
    const int gid = lane >> 2;
    const int tig = lane & 3;
    const int wy = warp >> 1;
    const int wx = warp & 1;
    const int bm = blockIdx.y * 128;
    const int bn = blockIdx.x * BN;

    const uint32_t a_base = (uint32_t)__cvta_generic_to_shared(As);
    const uint32_t b_base = (uint32_t)__cvta_generic_to_shared(Bs);

    const int nk = K >> 5;

    auto stageg = [&](int s) {
        const int bs = s % GEMM_NSTAGE;
        const uint32_t adst = a_base + bs * ASZ * 4;
        const uint32_t bdst = b_base + bs * BSZ * 4;
#pragma unroll
        for (int l = 0; l < 4; l++) {
            const int idx = tid + (l << 8);
            const int r = idx >> 3;
            const int c = (idx & 7) << 2;
            cp16(adst + (r * APITCH + c) * 4,
                 A + (size_t)(bm + r) * K + (s << 5) + c);
        }
#pragma unroll
        for (int l = 0; l < NBL; l++) {
            const int idx = tid + (l << 8);
            int r, c;
            if (BN == 128) { r = idx >> 5; c = (idx & 31) << 2; }
            else           { r = idx >> 4; c = (idx & 15) << 2; }
            cp16(bdst + (r * BPITCH + c) * 4,
                 Bm + (size_t)((s << 5) + r) * N + bn + c);
        }
    };

    float acc[2][NT][4];
#pragma unroll
    for (int mt = 0; mt < 2; mt++)
#pragma unroll
        for (int nt = 0; nt < NT; nt++)
#pragma unroll
            for (int r = 0; r < 4; r++) acc[mt][nt][r] = 0.0f;

#pragma unroll
    for (int s = 0; s < GEMM_NSTAGE - 1; s++) {
        if (s < nk) stageg(s);
        cp_commit();
    }

    for (int i = 0; i < nk; i++) {
        const int sn = i + GEMM_NSTAGE - 1;
        if (sn < nk) stageg(sn);
        cp_commit();
        cp_wait<GEMM_NSTAGE - 1>();
        __syncthreads();

        const int buf = i % GEMM_NSTAGE;
        const uint32_t* Ab = As + buf * ASZ;
        const uint32_t* Bb = Bs + buf * BSZ;
#pragma unroll
        for (int ks = 0; ks < 32; ks += 8) {
            uint32_t af[2][4];
#pragma unroll
            for (int mt = 0; mt < 2; mt++) {
                const int mrow = wy * 32 + mt * 16 + gid;
                af[mt][0] = Ab[mrow * APITCH + ks + tig];
                af[mt][1] = Ab[(mrow + 8) * APITCH + ks + tig];
                af[mt][2] = Ab[mrow * APITCH + ks + tig + 4];
                af[mt][3] = Ab[(mrow + 8) * APITCH + ks + tig + 4];
            }
            uint32_t bf[NT][2];
#pragma unroll
            for (int nt = 0; nt < NT; nt++) {
                const int nc = wx * (BN / 2) + nt * 8 + gid;
                bf[nt][0] = Bb[(ks + tig) * BPITCH + nc];
                bf[nt][1] = Bb[(ks + tig + 4) * BPITCH + nc];
            }
#pragma unroll
            for (int mt = 0; mt < 2; mt++)
#pragma unroll
                for (int nt = 0; nt < NT; nt++)
                    mma_tf32(acc[mt][nt], af[mt], bf[nt]);
        }
        __syncthreads();
    }

#pragma unroll
    for (int mt = 0; mt < 2; mt++) {
#pragma unroll
        for (int nt = 0; nt < NT; nt++) {
            const int col = bn + wx * (BN / 2) + nt * 8 + 2 * tig;
            float bv0 = 0.0f, bv1 = 0.0f;
            if (bias) { bv0 = bias[col]; bv1 = bias[col + 1]; }
#pragma unroll
            for (int half = 0; half < 2; half++) {
                const int row = bm + wy * 32 + mt * 16 + gid + half * 8;
                float v0 = acc[mt][nt][half * 2 + 0] + bv0;
                float v1 = acc[mt][nt][half * 2 + 1] + bv1;
                if (mode == EPI_RESID) {
                    v0 += resid[(size_t)row * N + col];
                    v1 += resid[(size_t)row * N + col + 1];
                } else if (mode == EPI_RELU) {
                    v0 = roundtf(fmaxf(v0, 0.0f));
                    v1 = roundtf(fmaxf(v1, 0.0f));
                }
                float2 vv = {v0, v1};
                if (mode == EPI_QKV) {
                    const int b = row >> 9, ii = row & 511;
                    const int which = col >> 9;
                    const int cc = col & 511;
                    const int h = cc >> 6, d = cc & 63;
                    float* base = (which == 0) ? C : (which == 1) ? C2 : C3;
                    *(float2*)(base + (((size_t)(b * CH + h) * CS) + ii) * CD + d) = vv;
                } else {
                    *(float2*)(C + (size_t)row * N + col) = vv;
                }
            }
        }
    }
}

#define GEMM_SMEM_BYTES(BN) (GEMM_NSTAGE * (128 * APITCH + 32 * ((BN) + 4)) * 4)

// ---------------- merged round-copy (4 arrays) ----------------------------------
__global__ void round4_kernel(const float4* __restrict__ s0, float4* __restrict__ d0, int n0,
                              const float4* __restrict__ s1, float4* __restrict__ d1, int n1,
                              const float4* __restrict__ s2, float4* __restrict__ d2, int n2,
                              const float4* __restrict__ s3, float4* __restrict__ d3, int n3)
{
    int i = blockIdx.x * 256 + threadIdx.x;
    const float4* s; float4* d;
    if (i < n0) { s = s0 + i; d = d0 + i; }
    else {
        i -= n0;
        if (i < n1) { s = s1 + i; d = d1 + i; }
        else {
            i -= n1;
            if (i < n2) { s = s2 + i; d = d2 + i; }
            else {
                i -= n2;
                if (i >= n3) return;
                s = s3 + i; d = d3 + i;
            }
        }
    }
    float4 v = *s;
    v.x = roundtf(v.x); v.y = roundtf(v.y);
    v.z = roundtf(v.z); v.w = roundtf(v.w);
    *d = v;
}

// ---------------- pack QKV weights/biases (rounded) ----------------------------
__global__ void pack_qkv_kernel(const float* __restrict__ wq, const float* __restrict__ wk,
                                const float* __restrict__ wv, const float* __restrict__ bq,
                                const float* __restrict__ bk, const float* __restrict__ bv)
{
    int idx = blockIdx.x * 256 + threadIdx.x;
    if (idx < CE * CE) {
        int r = idx >> 9, c = idx & 511;
        g_wqkv[(size_t)r * 1536 + c] = roundtf(wq[idx]);
        g_wqkv[(size_t)r * 1536 + 512 + c] = roundtf(wk[idx]);
        g_wqkv[(size_t)r * 1536 + 1024 + c] = roundtf(wv[idx]);
    }
    if (idx < CE) {
        g_bqkv[idx] = bq[idx];
        g_bqkv[512 + idx] = bk[idx];
        g_bqkv[1024 + idx] = bv[idx];
    }
}

// ---------------- pad pos_emb into g_pe ---------------------------------------
__global__ void pe_copy_kernel(const float* __restrict__ pe)
{
    int t = blockIdx.x * 256 + threadIdx.x;
    if (t < CNR * CD) g_pe[t] = pe[t];
}

// ---------------- FUSED qz + scores + softmax + bins ---------------------------
// block: 32 i-rows x full 512 j for one bh. 8 warps: wm = warp&1 (16-row half),
// wn = warp>>2... (warp>>1, 0..3) n-quarter.
// smem (u32 words):
#define FS_QW 0                               // Q: 32*68
#define FS_PEW (32*68)                        // PE 64*164 / K chunk 64*132 (aliased)
#define FS_QZW (FS_PEW + 64*164)              // qz: 32*132 (float)
#define FS_BINSW (FS_QZW + 32*132)            // bins: 32*132 (float)
#define FS_INTW (FS_BINSW + 32*132)           // dti 32, dtj 512, mj 512
#define FS_REDW (FS_INTW + 1056)              // red: 4*32 (float)
#define FS_SMEM_BYTES ((FS_REDW + 128) * 4)

__global__ __launch_bounds__(256, 2) void fused_scores_kernel(
    const float* __restrict__ dist, const int* __restrict__ dt,
    const int* __restrict__ mask, const float* __restrict__ pe)
{
    extern __shared__ uint32_t sm[];
    uint32_t* Qs = sm + FS_QW;
    uint32_t* PEs = sm + FS_PEW;            // reused as K-chunk buffer
    float* QZs = (float*)(sm + FS_QZW);
    float* bins = (float*)(sm + FS_BINSW);
    int* dti_s = (int*)(sm + FS_INTW);
    int* dtj_s = dti_s + 32;
    int* mj_s = dtj_s + 512;
    float* red = (float*)(sm + FS_REDW);    // [4][32]

    const int bh = blockIdx.y;
    const int b = bh >> 3;
    const int i0 = blockIdx.x << 5;         // 32 rows
    const int tid = threadIdx.x;
    const int warp = tid >> 5;
    const int lane = tid & 31;
    const int gid = lane >> 2;
    const int tig = lane & 3;
    const int wm = warp & 1;
    const int wn = warp >> 1;               // 0..3
    const int mrow = wm * 16 + gid;         // local row (and +8)

    const float* qb = g_q + (size_t)bh * CS * CD;
    const float* kb = g_k + (size_t)bh * CS * CD;

    // zero PE region and bins
    for (int t = tid; t < 64 * 164; t += 256) PEs[t] = 0u;
    for (int t = tid; t < 32 * 132; t += 256) bins[t] = 0.0f;

    // stage Q (32x64)
#pragma unroll
    for (int l = 0; l < 2; l++) {
        const int idx = tid + (l << 8);
        const int r = idx >> 4;
        const int c = (idx & 15) << 2;
        float4 qv = *(const float4*)(qb + (size_t)(i0 + r) * CD + c);
        uint4 ua = {f2tf(qv.x), f2tf(qv.y), f2tf(qv.z), f2tf(qv.w)};
        *(uint4*)&Qs[r * 68 + c] = ua;
    }
    if (tid < 32) dti_s[tid] = dt[b * CS + i0 + tid];
    {
        int2 dj = *(const int2*)&dt[b * CS + 2 * tid];
        dtj_s[2 * tid] = dj.x; dtj_s[2 * tid + 1] = dj.y;
        int2 mm = *(const int2*)&mask[b * CS + 2 * tid];
        mj_s[2 * tid] = mm.x; mj_s[2 * tid + 1] = mm.y;
    }
    __syncthreads();      // PE-zero complete before staging PE values

    // stage PE transposed [d][rel], pitch 164
    for (int t = tid; t < CNR * 16; t += 256) {
        const int n = t >> 4;
        const int k = (t & 15) << 2;
        float4 pv = *(const float4*)(pe + (size_t)n * CD + k);
        PEs[(k + 0) * 164 + n] = f2tf(pv.x);
        PEs[(k + 1) * 164 + n] = f2tf(pv.y);
        PEs[(k + 2) * 164 + n] = f2tf(pv.z);
        PEs[(k + 3) * 164 + n] = f2tf(pv.w);
    }
    __syncthreads();

    // ---- phase 1: qz tile = Q(32x64) @ PE^T (N padded to 160) -> QZs[32][132]
    {
        float qacc[5][4];
#pragma unroll
        for (int nt = 0; nt < 5; nt++)
#pragma unroll
            for (int r = 0; r < 4; r++) qacc[nt][r] = 0.0f;
#pragma unroll
        for (int ks = 0; ks < 64; ks += 8) {
            uint32_t af[4];
            af[0] = Qs[mrow * 68 + ks + tig];
            af[1] = Qs[(mrow + 8) * 68 + ks + tig];
            af[2] = Qs[mrow * 68 + ks + tig + 4];
            af[3] = Qs[(mrow + 8) * 68 + ks + tig + 4];
#pragma unroll
            for (int nt = 0; nt < 5; nt++) {
                const int nc = wn * 40 + nt * 8 + gid;
                uint32_t bf[2];
                bf[0] = PEs[(ks + tig) * 164 + nc];
                bf[1] = PEs[(ks + tig + 4) * 164 + nc];
                mma_tf32(qacc[nt], af, bf);
            }
        }
#pragma unroll
        for (int nt = 0; nt < 5; nt++) {
            const int col = wn * 40 + nt * 8 + 2 * tig;
            if (col <= 128) {
                QZs[mrow * 132 + col] = qacc[nt][0];
                QZs[mrow * 132 + col + 1] = qacc[nt][1];
                QZs[(mrow + 8) * 132 + col] = qacc[nt][2];
                QZs[(mrow + 8) * 132 + col + 1] = qacc[nt][3];
            }
        }
    }
    __syncthreads();

    // ---- phase 2: scores over 4 K-chunks, S kept in regs
    float sacc[4][4][4];
#pragma unroll
    for (int c = 0; c < 4; c++)
#pragma unroll
        for (int nt = 0; nt < 4; nt++)
#pragma unroll
            for (int r = 0; r < 4; r++) sacc[c][nt][r] = 0.0f;

#pragma unroll
    for (int ch = 0; ch < 4; ch++) {
        // stage K chunk (128 j) transposed [d][j], pitch 132 (reuses PE region)
#pragma unroll
        for (int l = 0; l < 8; l++) {
            const int idx = tid + (l << 8);
            const int jr = idx >> 4;
            const int c = (idx & 15) << 2;
            float4 kv = *(const float4*)(kb + (size_t)(ch * 128 + jr) * CD + c);
            PEs[(c + 0) * 132 + jr] = f2tf(kv.x);
            PEs[(c + 1) * 132 + jr] = f2tf(kv.y);
            PEs[(c + 2) * 132 + jr] = f2tf(kv.z);
            PEs[(c + 3) * 132 + jr] = f2tf(kv.w);
        }
        __syncthreads();

#pragma unroll
        for (int ks = 0; ks < 64; ks += 8) {
            uint32_t af[4];
            af[0] = Qs[mrow * 68 + ks + tig];
            af[1] = Qs[(mrow + 8) * 68 + ks + tig];
            af[2] = Qs[mrow * 68 + ks + tig + 4];
            af[3] = Qs[(mrow + 8) * 68 + ks + tig + 4];
#pragma unroll
            for (int nt = 0; nt < 4; nt++) {
                const int nc = wn * 32 + nt * 8 + gid;
                uint32_t bf[2];
                bf[0] = PEs[(ks + tig) * 132 + nc];
                bf[1] = PEs[(ks + tig + 4) * 132 + nc];
                mma_tf32(sacc[ch][nt], af, bf);
            }
        }

        // epilogue into regs: qz gather + dist + mask
#pragma unroll
        for (int half = 0; half < 2; half++) {
            const int il = mrow + half * 8;
            const int i = i0 + il;
            const int di = dti_s[il];
#pragma unroll
            for (int nt = 0; nt < 4; nt++) {
                const int jl = ch * 128 + wn * 32 + nt * 8 + 2 * tig;
                float2 dv = *(const float2*)&dist[((size_t)b * CS + i) * CS + jl];
#pragma unroll
                for (int u = 0; u < 2; u++) {
                    const int j = jl + u;
                    int rel = min(max(dtj_s[j] - di, -CP), CP) + CP;
                    float v = (sacc[ch][nt][half * 2 + u] + QZs[il * 132 + rel]) * 0.125f
                            + 0.6f * (u ? dv.y : dv.x);
                    if (mj_s[j] == 0) v = -1e9f;
                    sacc[ch][nt][half * 2 + u] = v;
                }
            }
        }
        __syncthreads();   // before restaging K
    }

    // ---- phase 3: softmax (two-pass over regs) + aw write + bins
    float mrow2[2];
#pragma unroll
    for (int half = 0; half < 2; half++) {
        float m = -1e30f;
#pragma unroll
        for (int c = 0; c < 4; c++)
#pragma unroll
            for (int nt = 0; nt < 4; nt++) {
                m = fmaxf(m, sacc[c][nt][half * 2]);
                m = fmaxf(m, sacc[c][nt][half * 2 + 1]);
            }
        m = fmaxf(m, __shfl_xor_sync(0xffffffffu, m, 1));
        m = fmaxf(m, __shfl_xor_sync(0xffffffffu, m, 2));
        mrow2[half] = m;
    }
    if (tig == 0) {
        red[wn * 32 + mrow] = mrow2[0];
        red[wn * 32 + mrow + 8] = mrow2[1];
    }
    __syncthreads();
#pragma unroll
    for (int half = 0; half < 2; half++) {
        const int r = mrow + half * 8;
        mrow2[half] = fmaxf(fmaxf(red[r], red[32 + r]), fmaxf(red[64 + r], red[96 + r]));
    }
    __syncthreads();   // red reuse

    float srow[2] = {0.0f, 0.0f};
#pragma unroll
    for (int half = 0; half < 2; half++) {
#pragma unroll
        for (int c = 0; c < 4; c++)
#pragma unroll
            for (int nt = 0; nt < 4; nt++) {
#pragma unroll
                for (int u = 0; u < 2; u++) {
                    float e = __expf(sacc[c][nt][half * 2 + u] - mrow2[half]);
                    sacc[c][nt][half * 2 + u] = e;
                    srow[half] += e;
                }
            }
        srow[half] += __shfl_xor_sync(0xffffffffu, srow[half], 1);
        srow[half] += __shfl_xor_sync(0xffffffffu, srow[half], 2);
    }
    if (tig == 0) {
        red[wn * 32 + mrow] = srow[0];
        red[wn * 32 + mrow + 8] = srow[1];
    }
    __syncthreads();
    float inv2[2];
#pragma unroll
    for (int half = 0; half < 2; half++) {
        const int r = mrow + half * 8;
        inv2[half] = 1.0f / (red[r] + red[32 + r] + red[64 + r] + red[96 + r]);
    }

    // aw write + bins atomics
#pragma unroll
    for (int half = 0; half < 2; half++) {
        const int il = mrow + half * 8;
        const int i = i0 + il;
        const int di = dti_s[il];
        const size_t wrow = ((size_t)bh * CS + i) * CS;
#pragma unroll
        for (int c = 0; c < 4; c++)
#pragma unroll
            for (int nt = 0; nt < 4; nt++) {
                const int jl = c * 128 + wn * 32 + nt * 8 + 2 * tig;
                const float a0 = sacc[c][nt][half * 2 + 0] * inv2[half];
                const float a1 = sacc[c][nt][half * 2 + 1] * inv2[half];
                float2 st = {a0, a1};
                *(float2*)&g_w[wrow + jl] = st;
                int r0 = min(max(dtj_s[jl] - di, -CP), CP) + CP;
                int r1 = min(max(dtj_s[jl + 1] - di, -CP), CP) + CP;
                atomicAdd(&bins[il * 132 + r0], a0);
                atomicAdd(&bins[il * 132 + r1], a1);
            }
    }
    __syncthreads();

    // write bins to g_s
    for (int t = tid; t < 32 * CNR; t += 256) {
        const int r = t / CNR;
        const int rel = t - r * CNR;
        g_s[((size_t)bh * CS + i0 + r) * CSR + rel] = bins[r * 132 + rel];
    }
}

// ---------------- attn (tensor, cp.async double-buffer): 128x64 tile -----------
#define AT_ASZ (128*68)
#define AT_BSZ (64*68)
#define AT_SMEM_BYTES ((2*AT_ASZ + 2*AT_BSZ) * 4)

__global__ __launch_bounds__(256, 2) void attn_mma_kernel()
{
    extern __shared__ uint32_t sm[];
    uint32_t* Abuf = sm;
    uint32_t* Bbuf = sm + 2 * AT_ASZ;

    const int bh = blockIdx.y;
    const int b = bh >> 3, h = bh & 7;
    const int i0 = blockIdx.x << 7;
    const int tid = threadIdx.x;
    const int warp = tid >> 5;
    const int lane = tid & 31;
    const int gid = lane >> 2;
    const int tig = lane & 3;
    const int wy = warp >> 1;
    const int wx = warp & 1;

    const float* awb = g_w + (size_t)bh * CS * CS;
    const float* sb = g_s + (size_t)bh * CS * CSR;
    const float* vb = g_v + (size_t)bh * CS * CD;

    const uint32_t a_base = (uint32_t)__cvta_generic_to_shared(Abuf);
    const uint32_t b_base = (uint32_t)__cvta_generic_to_shared(Bbuf);

    auto stage = [&](int c, int buf) {
        const uint32_t adst = a_base + buf * AT_ASZ * 4;
        const uint32_t bdst = b_base + buf * AT_BSZ * 4;
#pragma unroll
        for (int l = 0; l < 8; l++) {
            const int idx = tid + (l << 8);
            const int r = idx >> 4;
            const int cc = (idx & 15) << 2;
            const float* src;
            if (c < 8) src = awb + (size_t)(i0 + r) * CS + (c << 6) + cc;
            else       src = sb + (size_t)(i0 + r) * CSR + ((c - 8) << 6) + cc;
            cp16(adst + (r * 68 + cc) * 4, src);
        }
#pragma unroll
        for (int l = 0; l < 4; l++) {
            const int idx = tid + (l << 8);
            const int r = idx >> 4;
            const int cc = (idx & 15) << 2;
            const float* src;
            if (c < 8) src = vb + (size_t)((c << 6) + r) * CD + cc;
            else       src = g_pe + (size_t)(((c - 8) << 6) + r) * CD + cc;
            cp16(bdst + (r * 68 + cc) * 4, src);
        }
    };

    float acc[2][4][4];
#pragma unroll
    for (int mt = 0; mt < 2; mt++)
#pragma unroll
        for (int nt = 0; nt < 4; nt++)
#pragma unroll
            for (int r = 0; r < 4; r++) acc[mt][nt][r] = 0.0f;

    stage(0, 0);
    cp_commit();

    for (int c = 0; c < 11; c++) {
        if (c + 1 < 11) stage(c + 1, (c + 1) & 1);
        cp_commit();
        cp_wait<1>();
        __syncthreads();

        const uint32_t* Asm = Abuf + (c & 1) * AT_ASZ;
        const uint32_t* Bsm = Bbuf + (c & 1) * AT_BSZ;
#pragma unroll
        for (int ks = 0; ks < 64; ks += 8) {
            uint32_t af[2][4];
#pragma unroll
            for (int mt = 0; mt < 2; mt++) {
                const int mrow = wy * 32 + mt * 16 + gid;
                af[mt][0] = Asm[mrow*68 + ks + tig];
                af[mt][1] = Asm[(mrow+8)*68 + ks + tig];
                af[mt][2] = Asm[mrow*68 + ks + tig + 4];
                af[mt][3] = Asm[(mrow+8)*68 + ks + tig + 4];
            }
            uint32_t bf[4][2];
#pragma unroll
            for (int nt = 0; nt < 4; nt++) {
                const int nc = wx * 32 + nt * 8 + gid;
                bf[nt][0] = Bsm[(ks + tig)*68 + nc];
                bf[nt][1] = Bsm[(ks + tig + 4)*68 + nc];
            }
#pragma unroll
            for (int mt = 0; mt < 2; mt++)
#pragma unroll
                for (int nt = 0; nt < 4; nt++)
                    mma_tf32(acc[mt][nt], af[mt], bf[nt]);
        }
        __syncthreads();
    }

#pragma unroll
    for (int mt = 0; mt < 2; mt++)
#pragma unroll
        for (int nt = 0; nt < 4; nt++) {
            const int col = wx * 32 + nt * 8 + 2 * tig;
#pragma unroll
            for (int half = 0; half < 2; half++) {
                const int row = wy * 32 + mt * 16 + gid + half * 8;
                float2 vv = {roundtf(acc[mt][nt][half*2+0]),
                             roundtf(acc[mt][nt][half*2+1])};
                *(float2*)&g_concat[(size_t)(b * CS + i0 + row) * CE + h * CD + col] = vv;
            }
        }
}

// ---------------- layernorm (row = 512), optional rounded second output --------
__global__ __launch_bounds__(256) void ln_kernel(
    const float* __restrict__ in, float* __restrict__ out,
    float* __restrict__ out_r,
    const float* __restrict__ gg, const float* __restrict__ bb)
{
    const int row = blockIdx.x;
    const float* xr = in + (size_t)row * CE;
    const int tid = threadIdx.x;
    const int lane = tid & 31;
    const int wid = tid >> 5;
    __shared__ float wred[8];
    __shared__ float stat;

    float2 v = *(const float2*)&xr[2 * tid];
    float s = v.x + v.y;
#pragma unroll
    for (int o = 16; o > 0; o >>= 1) s += __shfl_xor_sync(0xffffffffu, s, o);
    if (lane == 0) wred[wid] = s;
    __syncthreads();
    if (tid == 0) {
        float ss = wred[0];
#pragma unroll
        for (int k = 1; k < 8; k++) ss += wred[k];
        stat = ss * (1.0f / CE);
    }
    __syncthreads();
    const float mu = stat;
    const float d0 = v.x - mu, d1 = v.y - mu;
    float q = d0 * d0 + d1 * d1;
#pragma unroll
    for (int o = 16; o > 0; o >>= 1) q += __shfl_xor_sync(0xffffffffu, q, o);
    if (lane == 0) wred[wid] = q;
    __syncthreads();
    if (tid == 0) {
        float qq = wred[0];
#pragma unroll
        for (int k = 1; k < 8; k++) qq += wred[k];
        stat = rsqrtf(qq * (1.0f / CE) + 1e-5f);
    }
    __syncthreads();
    const float rstd = stat;
    float2 gv = *(const float2*)&gg[2 * tid];
    float2 bv = *(const float2*)&bb[2 * tid];
    float2 ov = {d0 * rstd * gv.x + bv.x, d1 * rstd * gv.y + bv.y};
    *(float2*)&out[(size_t)row * CE + 2 * tid] = ov;
    if (out_r) {
        float2 orr = {roundtf(ov.x), roundtf(ov.y)};
        *(float2*)&out_r[(size_t)row * CE + 2 * tid] = orr;
    }
}

// ---------------- launch -------------------------------------------------------
extern "C" void kernel_launch(void* const* d_in, const int* in_sizes, int n_in,
                              void* d_out, int out_size)
{
    const float* x    = (const float*)d_in[0];
    const float* dist = (const float*)d_in[1];
    const int*   dt   = (const int*)d_in[2];
    const int*   mask = (const int*)d_in[3];
    const float* wq_w = (const float*)d_in[4];
    const float* wq_b = (const float*)d_in[5];
    const float* wk_w = (const float*)d_in[6];
    const float* wk_b = (const float*)d_in[7];
    const float* wv_w = (const float*)d_in[8];
    const float* wv_b = (const float*)d_in[9];
    const float* wo_w = (const float*)d_in[10];
    const float* wo_b = (const float*)d_in[11];
    const float* pe   = (const float*)d_in[12];
    const float* w1   = (const float*)d_in[13];
    const float* b1   = (const float*)d_in[14];
    const float* w2   = (const float*)d_in[15];
    const float* b2   = (const float*)d_in[16];
    const float* ln1g = (const float*)d_in[17];
    const float* ln1b = (const float*)d_in[18];
    const float* ln2g = (const float*)d_in[19];
    const float* ln2b = (const float*)d_in[20];
    float* out = (float*)d_out;

    void *pq, *pk, *pv, *pcc, *pt1, *pao, *paor, *phid, *pt2, *pwqkv, *pbqkv;
    void *pxr, *pwor, *pw1r, *pw2r;
    cudaGetSymbolAddress(&pq, g_q);
    cudaGetSymbolAddress(&pk, g_k);
    cudaGetSymbolAddress(&pv, g_v);
    cudaGetSymbolAddress(&pcc, g_concat);
    cudaGetSymbolAddress(&pt1, g_t1);
    cudaGetSymbolAddress(&pao, g_attnout);
    cudaGetSymbolAddress(&paor, g_attnout_r);
    cudaGetSymbolAddress(&phid, g_hidden);
    cudaGetSymbolAddress(&pt2, g_t2);
    cudaGetSymbolAddress(&pwqkv, g_wqkv);
    cudaGetSymbolAddress(&pbqkv, g_bqkv);
    cudaGetSymbolAddress(&pxr, g_xr);
    cudaGetSymbolAddress(&pwor, g_wor);
    cudaGetSymbolAddress(&pw1r, g_w1r);
    cudaGetSymbolAddress(&pw2r, g_w2r);

    cudaFuncSetAttribute(fused_scores_kernel,
                         cudaFuncAttributeMaxDynamicSharedMemorySize, FS_SMEM_BYTES);
    cudaFuncSetAttribute(attn_mma_kernel,
                         cudaFuncAttributeMaxDynamicSharedMemorySize, AT_SMEM_BYTES);
    cudaFuncSetAttribute(mma_gemm_kernel<128>,
                         cudaFuncAttributeMaxDynamicSharedMemorySize, GEMM_SMEM_BYTES(128));
    cudaFuncSetAttribute(mma_gemm_kernel<64>,
                         cudaFuncAttributeMaxDynamicSharedMemorySize, GEMM_SMEM_BYTES(64));

    pe_copy_kernel<<<(CNR * CD + 255) / 256, 256>>>(pe);
    pack_qkv_kernel<<<(CE * CE + 255) / 256, 256>>>(wq_w, wk_w, wv_w, wq_b, wk_b, wv_b);
    {
        const int n0 = CM * CE / 4, n1 = CE * CE / 4, n2 = CE * CF / 4, n3 = CF * CE / 4;
        const int ntot = n0 + n1 + n2 + n3;
        round4_kernel<<<(ntot + 255) / 256, 256>>>(
            (const float4*)x, (float4*)pxr, n0,
            (const float4*)wo_w, (float4*)pwor, n1,
            (const float4*)w1, (float4*)pw1r, n2,
            (const float4*)w2, (float4*)pw2r, n3);
    }

    // fused QKV: M=4096, N=1536, K=512
    dim3 gq(1536 / 128, CM / 128);
    mma_gemm_kernel<128><<<gq, 256, GEMM_SMEM_BYTES(128)>>>(
        (const float*)pxr, (const float*)pwqkv, (float*)pq, (float*)pk, (float*)pv,
        CM, 1536, CE, (const float*)pbqkv, nullptr, EPI_QKV);

    // fused qz + scores + softmax + bins
    dim3 gfs(CS / 32, CBH);
    fused_scores_kernel<<<gfs, 256, FS_SMEM_BYTES>>>(dist, dt, mask, pe);

    dim3 gat(CS / 128, CBH);
    attn_mma_kernel<<<gat, 256, AT_SMEM_BYTES>>>();

    dim3 gwo(CE / 64, CM / 128);
    mma_gemm_kernel<64><<<gwo, 256, GEMM_SMEM_BYTES(64)>>>(
        (const float*)pcc, (const float*)pwor, (float*)pt1, nullptr, nullptr,
        CM, CE, CE, wo_b, x, EPI_RESID);
    ln_kernel<<<CM, 256>>>((const float*)pt1, (float*)pao, (float*)paor, ln1g, ln1b);

    dim3 gf1(CF / 128, CM / 128);
    mma_gemm_kernel<128><<<gf1, 256, GEMM_SMEM_BYTES(128)>>>(
        (const float*)paor, (const float*)pw1r, (float*)phid, nullptr, nullptr,
        CM, CF, CE, b1, nullptr, EPI_RELU);
    dim3 gf2(CE / 64, CM / 128);
    mma_gemm_kernel<64><<<gf2, 256, GEMM_SMEM_BYTES(64)>>>(
        (const float*)phid, (const float*)pw2r, (float*)pt2, nullptr, nullptr,
        CM, CE, CF, b2, (const float*)pao, EPI_RESID);
    ln_kernel<<<CM, 256>>>((const float*)pt2, out, nullptr, ln2g, ln2b);
}

// round 11
// speedup vs baseline: 2.4272x; 1.0942x over previous
#include <cuda_runtime.h>
#include <cstdint>
#include <cstddef>

// Problem constants
#define CB 8
#define CS 512
#define CE 512
#define CH 8
#define CD 64
#define CP 64
#define CF 2048
#define CNR 129            // 2P+1
#define CSR 192            // padded stride for bins / pos_emb (3 chunks of 64)
#define CBH (CB*CH)        // 64
#define CM (CB*CS)         // 4096

// ---------------- device scratch (zero-initialized .bss) ----------------------
__device__ __align__(16) float g_q[CBH*CS*CD];
__device__ __align__(16) float g_k[CBH*CS*CD];
__device__ __align__(16) float g_v[CBH*CS*CD];
__device__ __align__(16) float g_w[CBH*CS*CS];          // final aw
__device__ __align__(16) float g_s[CBH*CS*CSR];         // softmax bins (padded)
__device__ __align__(16) float g_pe[CSR*CD];            // padded pos_emb
__device__ __align__(16) float g_concat[CM*CE];         // rounded at write
__device__ __align__(16) float g_t1[CM*CE];
__device__ __align__(16) float g_attnout[CM*CE];        // fp32 (resid)
__device__ __align__(16) float g_attnout_r[CM*CE];      // RN-rounded (FFN1 A)
__device__ __align__(16) float g_hidden[CM*CF];         // rounded at write
__device__ __align__(16) float g_t2[CM*CE];
__device__ __align__(16) float g_wqkv[CE*3*CE];         // packed+rounded [512][1536]
__device__ __align__(16) float g_bqkv[3*CE];
__device__ __align__(16) float g_xr[CM*CE];             // rounded x
__device__ __align__(16) float g_wor[CE*CE];            // rounded wo
__device__ __align__(16) float g_w1r[CE*CF];            // rounded w1
__device__ __align__(16) float g_w2r[CF*CE];            // rounded w2

enum { EPI_QKV = 0, EPI_RESID = 1, EPI_RELU = 2 };

__device__ __forceinline__ uint32_t f2tf(float f) {
    uint32_t u;
    asm("cvt.rna.tf32.f32 %0, %1;" : "=r"(u) : "f"(f));
    return u;
}
__device__ __forceinline__ float roundtf(float f) {
    return __uint_as_float(f2tf(f));
}

__device__ __forceinline__ void mma_tf32(float c[4], const uint32_t a[4],
                                         const uint32_t b[2]) {
    asm volatile(
        "mma.sync.aligned.m16n8k8.row.col.f32.tf32.tf32.f32 "
        "{%0,%1,%2,%3}, {%4,%5,%6,%7}, {%8,%9}, {%0,%1,%2,%3};\n"
        : "+f"(c[0]), "+f"(c[1]), "+f"(c[2]), "+f"(c[3])
        : "r"(a[0]), "r"(a[1]), "r"(a[2]), "r"(a[3]), "r"(b[0]), "r"(b[1]));
}

__device__ __forceinline__ void cp16(uint32_t dst, const void* src) {
    asm volatile("cp.async.cg.shared.global [%0], [%1], 16;\n" :: "r"(dst), "l"(src));
}
__device__ __forceinline__ void cp_commit() {
    asm volatile("cp.async.commit_group;\n");
}
template<int N>
__device__ __forceinline__ void cp_wait() {
    asm volatile("cp.async.wait_group %0;\n" :: "n"(N));
}

// ---------------- TF32 tensor-core GEMM (cp.async 3-stage, BK=32) -------------
// single barrier per mainloop iteration: wait -> sync -> issue -> compute
#define APITCH 36
#define GEMM_NSTAGE 3

template<int BN>
__global__ __launch_bounds__(256, 2) void mma_gemm_kernel(
    const float* __restrict__ A, const float* __restrict__ Bm,
    float* __restrict__ C, float* __restrict__ C2, float* __restrict__ C3,
    int M, int N, int K,
    const float* __restrict__ bias, const float* __restrict__ resid, int mode)
{
    constexpr int BPITCH = BN + 4;
    constexpr int NT = BN / 16;
    constexpr int ASZ = 128 * APITCH;
    constexpr int BSZ = 32 * BPITCH;
    constexpr int NBL = (BN == 128) ? 4 : 2;
    extern __shared__ uint32_t smem_u[];
    uint32_t* As = smem_u;
    uint32_t* Bs = smem_u + GEMM_NSTAGE * ASZ;

    const int tid = threadIdx.x;
    const int warp = tid >> 5;
    const int lane = tid & 31;
    const int gid = lane >> 2;
    const int tig = lane & 3;
    const int wy = warp >> 1;
    const int wx = warp & 1;
    const int bm = blockIdx.y * 128;
    const int bn = blockIdx.x * BN;

    const uint32_t a_base = (uint32_t)__cvta_generic_to_shared(As);
    const uint32_t b_base = (uint32_t)__cvta_generic_to_shared(Bs);

    const int nk = K >> 5;

    auto stageg = [&](int s) {
        const int bs = s % GEMM_NSTAGE;
        const uint32_t adst = a_base + bs * ASZ * 4;
        const uint32_t bdst = b_base + bs * BSZ * 4;
#pragma unroll
        for (int l = 0; l < 4; l++) {
            const int idx = tid + (l << 8);
            const int r = idx >> 3;
            const int c = (idx & 7) << 2;
            cp16(adst + (r * APITCH + c) * 4,
                 A + (size_t)(bm + r) * K + (s << 5) + c);
        }
#pragma unroll
        for (int l = 0; l < NBL; l++) {
            const int idx = tid + (l << 8);
            int r, c;
            if (BN == 128) { r = idx >> 5; c = (idx & 31) << 2; }
            else           { r = idx >> 4; c = (idx & 15) << 2; }
            cp16(bdst + (r * BPITCH + c) * 4,
                 Bm + (size_t)((s << 5) + r) * N + bn + c);
        }
    };

    float acc[2][NT][4];
#pragma unroll
    for (int mt = 0; mt < 2; mt++)
#pragma unroll
        for (int nt = 0; nt < NT; nt++)
#pragma unroll
            for (int r = 0; r < 4; r++) acc[mt][nt][r] = 0.0f;

    // prologue: stages 0,1
#pragma unroll
    for (int s = 0; s < GEMM_NSTAGE - 1; s++) {
        if (s < nk) stageg(s);
        cp_commit();
    }

    for (int i = 0; i < nk; i++) {
        cp_wait<1>();
        __syncthreads();
        if (i + 2 < nk) stageg(i + 2);
        cp_commit();

        const int buf = i % GEMM_NSTAGE;
        const uint32_t* Ab = As + buf * ASZ;
        const uint32_t* Bb = Bs + buf * BSZ;
#pragma unroll
        for (int ks = 0; ks < 32; ks += 8) {
            uint32_t af[2][4];
#pragma unroll
            for (int mt = 0; mt < 2; mt++) {
                const int mrow = wy * 32 + mt * 16 + gid;
                af[mt][0] = Ab[mrow * APITCH + ks + tig];
                af[mt][1] = Ab[(mrow + 8) * APITCH + ks + tig];
                af[mt][2] = Ab[mrow * APITCH + ks + tig + 4];
                af[mt][3] = Ab[(mrow + 8) * APITCH + ks + tig + 4];
            }
            uint32_t bf[NT][2];
#pragma unroll
            for (int nt = 0; nt < NT; nt++) {
                const int nc = wx * (BN / 2) + nt * 8 + gid;
                bf[nt][0] = Bb[(ks + tig) * BPITCH + nc];
                bf[nt][1] = Bb[(ks + tig + 4) * BPITCH + nc];
            }
#pragma unroll
            for (int mt = 0; mt < 2; mt++)
#pragma unroll
                for (int nt = 0; nt < NT; nt++)
                    mma_tf32(acc[mt][nt], af[mt], bf[nt]);
        }
    }

#pragma unroll
    for (int mt = 0; mt < 2; mt++) {
#pragma unroll
        for (int nt = 0; nt < NT; nt++) {
            const int col = bn + wx * (BN / 2) + nt * 8 + 2 * tig;
            float bv0 = 0.0f, bv1 = 0.0f;
            if (bias) { bv0 = bias[col]; bv1 = bias[col + 1]; }
#pragma unroll
            for (int half = 0; half < 2; half++) {
                const int row = bm + wy * 32 + mt * 16 + gid + half * 8;
                float v0 = acc[mt][nt][half * 2 + 0] + bv0;
                float v1 = acc[mt][nt][half * 2 + 1] + bv1;
                if (mode == EPI_RESID) {
                    v0 += resid[(size_t)row * N + col];
                    v1 += resid[(size_t)row * N + col + 1];
                } else if (mode == EPI_RELU) {
                    v0 = roundtf(fmaxf(v0, 0.0f));
                    v1 = roundtf(fmaxf(v1, 0.0f));
                }
                float2 vv = {v0, v1};
                if (mode == EPI_QKV) {
                    const int b = row >> 9, ii = row & 511;
                    const int which = col >> 9;
                    const int cc = col & 511;
                    const int h = cc >> 6, d = cc & 63;
                    float* base = (which == 0) ? C : (which == 1) ? C2 : C3;
                    *(float2*)(base + (((size_t)(b * CH + h) * CS) + ii) * CD + d) = vv;
                } else {
                    *(float2*)(C + (size_t)row * N + col) = vv;
                }
            }
        }
    }
}

#define GEMM_SMEM_BYTES(BN) (GEMM_NSTAGE * (128 * APITCH + 32 * ((BN) + 4)) * 4)

// ---------------- merged round-copy (4 arrays) ----------------------------------
__global__ void round4_kernel(const float4* __restrict__ s0, float4* __restrict__ d0, int n0,
                              const float4* __restrict__ s1, float4* __restrict__ d1, int n1,
                              const float4* __restrict__ s2, float4* __restrict__ d2, int n2,
                              const float4* __restrict__ s3, float4* __restrict__ d3, int n3)
{
    int i = blockIdx.x * 256 + threadIdx.x;
    const float4* s; float4* d;
    if (i < n0) { s = s0 + i; d = d0 + i; }
    else {
        i -= n0;
        if (i < n1) { s = s1 + i; d = d1 + i; }
        else {
            i -= n1;
            if (i < n2) { s = s2 + i; d = d2 + i; }
            else {
                i -= n2;
                if (i >= n3) return;
                s = s3 + i; d = d3 + i;
            }
        }
    }
    float4 v = *s;
    v.x = roundtf(v.x); v.y = roundtf(v.y);
    v.z = roundtf(v.z); v.w = roundtf(v.w);
    *d = v;
}

// ---------------- pack QKV weights/biases (rounded) ----------------------------
__global__ void pack_qkv_kernel(const float* __restrict__ wq, const float* __restrict__ wk,
                                const float* __restrict__ wv, const float* __restrict__ bq,
                                const float* __restrict__ bk, const float* __restrict__ bv)
{
    int idx = blockIdx.x * 256 + threadIdx.x;
    if (idx < CE * CE) {
        int r = idx >> 9, c = idx & 511;
        g_wqkv[(size_t)r * 1536 + c] = roundtf(wq[idx]);
        g_wqkv[(size_t)r * 1536 + 512 + c] = roundtf(wk[idx]);
        g_wqkv[(size_t)r * 1536 + 1024 + c] = roundtf(wv[idx]);
    }
    if (idx < CE) {
        g_bqkv[idx] = bq[idx];
        g_bqkv[512 + idx] = bk[idx];
        g_bqkv[1024 + idx] = bv[idx];
    }
}

// ---------------- pad pos_emb into g_pe ---------------------------------------
__global__ void pe_copy_kernel(const float* __restrict__ pe)
{
    int t = blockIdx.x * 256 + threadIdx.x;
    if (t < CNR * CD) g_pe[t] = pe[t];
}

// ---------------- FUSED qz + scores + softmax + bins (v2: cp.async) ------------
// block: 32 i-rows x full 512 j for one bh.
// K/PE stored NATURALLY ([row][d], pitch 68): mma .col B operand reads
// B[k][n] = buf[n*68 + k] -- conflict-free (68 mod 32 = 4).
// smem (u32 words):
#define FS_Q 0                       // 32*68 = 2176
#define FS_K 2176                    // 2 x 128*68 = 17408 (phase1: PE rows 0..159)
#define FS_QZ (2176 + 17408)         // 32*132 = 4224 (QZ; later bins)
#define FS_INT (FS_QZ + 4224)        // dti 32, dtj 512, mj 512
#define FS_RED (FS_INT + 1056)       // red: 4*32
#define FS_SMEM_BYTES ((FS_RED + 128) * 4)
#define FS_KBUF (128*68)

__global__ __launch_bounds__(256, 2) void fused_scores_kernel(
    const float* __restrict__ dist, const int* __restrict__ dt,
    const int* __restrict__ mask, const float* __restrict__ pe)
{
    extern __shared__ uint32_t sm[];
    uint32_t* Qs = sm + FS_Q;
    uint32_t* Kb = sm + FS_K;               // 2 buffers; phase1 = PE region
    float* QZs = (float*)(sm + FS_QZ);      // later: bins
    int* dti_s = (int*)(sm + FS_INT);
    int* dtj_s = dti_s + 32;
    int* mj_s = dtj_s + 512;
    float* red = (float*)(sm + FS_RED);

    const int bh = blockIdx.y;
    const int b = bh >> 3;
    const int i0 = blockIdx.x << 5;
    const int tid = threadIdx.x;
    const int warp = tid >> 5;
    const int lane = tid & 31;
    const int gid = lane >> 2;
    const int tig = lane & 3;
    const int wm = warp & 1;
    const int wn = warp >> 1;               // 0..3
    const int mrow = wm * 16 + gid;

    const float* qb = g_q + (size_t)bh * CS * CD;
    const float* kb = g_k + (size_t)bh * CS * CD;

    const uint32_t q_base = (uint32_t)__cvta_generic_to_shared(Qs);
    const uint32_t k_base = (uint32_t)__cvta_generic_to_shared(Kb);

    // zero PE pad rows 129..159
    for (int t = tid; t < 31 * 68; t += 256) Kb[129 * 68 + t] = 0u;
    // stage Q raw (32x64)
#pragma unroll
    for (int l = 0; l < 2; l++) {
        const int idx = tid + (l << 8);
        const int r = idx >> 4;
        const int c = (idx & 15) << 2;
        cp16(q_base + (r * 68 + c) * 4, qb + (size_t)(i0 + r) * CD + c);
    }
    // stage PE raw, natural layout rows 0..128
    for (int t = tid; t < CNR * 16; t += 256) {
        const int r = t >> 4;
        const int c = (t & 15) << 2;
        cp16(k_base + (r * 68 + c) * 4, pe + (size_t)r * CD + c);
    }
    cp_commit();

    if (tid < 32) dti_s[tid] = dt[b * CS + i0 + tid];
    {
        int2 dj = *(const int2*)&dt[b * CS + 2 * tid];
        dtj_s[2 * tid] = dj.x; dtj_s[2 * tid + 1] = dj.y;
        int2 mm = *(const int2*)&mask[b * CS + 2 * tid];
        mj_s[2 * tid] = mm.x; mj_s[2 * tid + 1] = mm.y;
    }
    cp_wait<0>();
    __syncthreads();

    // ---- phase 1: qz = Q(32x64) @ PE^T  (n = rel, padded to 160)
    float qacc[5][4];
#pragma unroll
    for (int nt = 0; nt < 5; nt++)
#pragma unroll
        for (int r = 0; r < 4; r++) qacc[nt][r] = 0.0f;
#pragma unroll
    for (int ks = 0; ks < 64; ks += 8) {
        uint32_t af[4];
        af[0] = Qs[mrow * 68 + ks + tig];
        af[1] = Qs[(mrow + 8) * 68 + ks + tig];
        af[2] = Qs[mrow * 68 + ks + tig + 4];
        af[3] = Qs[(mrow + 8) * 68 + ks + tig + 4];
#pragma unroll
        for (int nt = 0; nt < 5; nt++) {
            const int nc = wn * 40 + nt * 8 + gid;
            uint32_t bf[2];
            bf[0] = Kb[nc * 68 + ks + tig];
            bf[1] = Kb[nc * 68 + ks + tig + 4];
            mma_tf32(qacc[nt], af, bf);
        }
    }
    __syncthreads();   // all warps done with PE before chunk0 clobbers buf1

    // prefetch K chunk 0 -> buf1 (rows 128..255 region)
    {
        const uint32_t kdst = k_base + FS_KBUF * 4;   // buf1
#pragma unroll
        for (int l = 0; l < 8; l++) {
            const int idx = tid + (l << 8);
            const int r = idx >> 4;
            const int c = (idx & 15) << 2;
            cp16(kdst + (r * 68 + c) * 4, kb + (size_t)r * CD + c);
        }
        cp_commit();
    }

    // qz writeback to smem
#pragma unroll
    for (int nt = 0; nt < 5; nt++) {
        const int col = wn * 40 + nt * 8 + 2 * tig;
        if (col <= 128) {
            QZs[mrow * 132 + col] = qacc[nt][0];
            QZs[mrow * 132 + col + 1] = qacc[nt][1];
            QZs[(mrow + 8) * 132 + col] = qacc[nt][2];
            QZs[(mrow + 8) * 132 + col + 1] = qacc[nt][3];
        }
    }

    // ---- phase 2: scores over 4 K-chunks (double-buffered cp.async)
    float sacc[4][4][4];
#pragma unroll
    for (int c = 0; c < 4; c++)
#pragma unroll
        for (int nt = 0; nt < 4; nt++)
#pragma unroll
            for (int r = 0; r < 4; r++) sacc[c][nt][r] = 0.0f;

#pragma unroll
    for (int ch = 0; ch < 4; ch++) {
        cp_wait<0>();
        __syncthreads();    // chunk ch landed; QZ visible (ch=0); prev buf free
        if (ch < 3) {
            const uint32_t kdst = k_base + (((ch + 1) & 1) ^ 1) * FS_KBUF * 4;
#pragma unroll
            for (int l = 0; l < 8; l++) {
                const int idx = tid + (l << 8);
                const int r = idx >> 4;
                const int c = (idx & 15) << 2;
                cp16(kdst + (r * 68 + c) * 4,
                     kb + (size_t)((ch + 1) * 128 + r) * CD + c);
            }
        }
        cp_commit();

        const uint32_t* Kc = Kb + ((ch & 1) ^ 1) * FS_KBUF;
#pragma unroll
        for (int ks = 0; ks < 64; ks += 8) {
            uint32_t af[4];
            af[0] = Qs[mrow * 68 + ks + tig];
            af[1] = Qs[(mrow + 8) * 68 + ks + tig];
            af[2] = Qs[mrow * 68 + ks + tig + 4];
            af[3] = Qs[(mrow + 8) * 68 + ks + tig + 4];
#pragma unroll
            for (int nt = 0; nt < 4; nt++) {
                const int nc = wn * 32 + nt * 8 + gid;
                uint32_t bf[2];
                bf[0] = Kc[nc * 68 + ks + tig];
                bf[1] = Kc[nc * 68 + ks + tig + 4];
                mma_tf32(sacc[ch][nt], af, bf);
            }
        }

        // epilogue into regs: qz gather + dist + mask
#pragma unroll
        for (int half = 0; half < 2; half++) {
            const int il = mrow + half * 8;
            const int i = i0 + il;
            const int di = dti_s[il];
#pragma unroll
            for (int nt = 0; nt < 4; nt++) {
                const int jl = ch * 128 + wn * 32 + nt * 8 + 2 * tig;
                float2 dv = *(const float2*)&dist[((size_t)b * CS + i) * CS + jl];
#pragma unroll
                for (int u = 0; u < 2; u++) {
                    const int j = jl + u;
                    int rel = min(max(dtj_s[j] - di, -CP), CP) + CP;
                    float v = (sacc[ch][nt][half * 2 + u] + QZs[il * 132 + rel]) * 0.125f
                            + 0.6f * (u ? dv.y : dv.x);
                    if (mj_s[j] == 0) v = -1e9f;
                    sacc[ch][nt][half * 2 + u] = v;
                }
            }
        }
    }
    __syncthreads();   // all QZ gathers done (QZ region becomes bins)

    // ---- phase 3: softmax + aw write + bins
    float* bins = QZs;   // alias
    for (int t = tid; t < 32 * 132; t += 256) bins[t] = 0.0f;

    float mrow2[2];
#pragma unroll
    for (int half = 0; half < 2; half++) {
        float m = -1e30f;
#pragma unroll
        for (int c = 0; c < 4; c++)
#pragma unroll
            for (int nt = 0; nt < 4; nt++) {
                m = fmaxf(m, sacc[c][nt][half * 2]);
                m = fmaxf(m, sacc[c][nt][half * 2 + 1]);
            }
        m = fmaxf(m, __shfl_xor_sync(0xffffffffu, m, 1));
        m = fmaxf(m, __shfl_xor_sync(0xffffffffu, m, 2));
        mrow2[half] = m;
    }
    if (tig == 0) {
        red[wn * 32 + mrow] = mrow2[0];
        red[wn * 32 + mrow + 8] = mrow2[1];
    }
    __syncthreads();   // red + bins-zero visible
#pragma unroll
    for (int half = 0; half < 2; half++) {
        const int r = mrow + half * 8;
        mrow2[half] = fmaxf(fmaxf(red[r], red[32 + r]), fmaxf(red[64 + r], red[96 + r]));
    }
    __syncthreads();   // red reuse

    float srow[2] = {0.0f, 0.0f};
#pragma unroll
    for (int half = 0; half < 2; half++) {
#pragma unroll
        for (int c = 0; c < 4; c++)
#pragma unroll
            for (int nt = 0; nt < 4; nt++) {
#pragma unroll
                for (int u = 0; u < 2; u++) {
                    float e = __expf(sacc[c][nt][half * 2 + u] - mrow2[half]);
                    sacc[c][nt][half * 2 + u] = e;
                    srow[half] += e;
                }
            }
        srow[half] += __shfl_xor_sync(0xffffffffu, srow[half], 1);
        srow[half] += __shfl_xor_sync(0xffffffffu, srow[half], 2);
    }
    if (tig == 0) {
        red[wn * 32 + mrow] = srow[0];
        red[wn * 32 + mrow + 8] = srow[1];
    }
    __syncthreads();
    float inv2[2];
#pragma unroll
    for (int half = 0; half < 2; half++) {
        const int r = mrow + half * 8;
        inv2[half] = 1.0f / (red[r] + red[32 + r] + red[64 + r] + red[96 + r]);
    }

#pragma unroll
    for (int half = 0; half < 2; half++) {
        const int il = mrow + half * 8;
        const int i = i0 + il;
        const int di = dti_s[il];
        const size_t wrow = ((size_t)bh * CS + i) * CS;
#pragma unroll
        for (int c = 0; c < 4; c++)
#pragma unroll
            for (int nt = 0; nt < 4; nt++) {
                const int jl = c * 128 + wn * 32 + nt * 8 + 2 * tig;
                const float a0 = sacc[c][nt][half * 2 + 0] * inv2[half];
                const float a1 = sacc[c][nt][half * 2 + 1] * inv2[half];
                float2 st = {a0, a1};
                *(float2*)&g_w[wrow + jl] = st;
                int r0 = min(max(dtj_s[jl] - di, -CP), CP) + CP;
                int r1 = min(max(dtj_s[jl + 1] - di, -CP), CP) + CP;
                atomicAdd(&bins[il * 132 + r0], a0);
                atomicAdd(&bins[il * 132 + r1], a1);
            }
    }
    __syncthreads();

    for (int t = tid; t < 32 * CNR; t += 256) {
        const int r = t / CNR;
        const int rel = t - r * CNR;
        g_s[((size_t)bh * CS + i0 + r) * CSR + rel] = bins[r * 132 + rel];
    }
}

// ---------------- attn (tensor, cp.async double-buffer, single barrier) --------
#define AT_ASZ (128*68)
#define AT_BSZ (64*68)
#define AT_SMEM_BYTES ((2*AT_ASZ + 2*AT_BSZ) * 4)

__global__ __launch_bounds__(256, 2) void attn_mma_kernel()
{
    extern __shared__ uint32_t sm[];
    uint32_t* Abuf = sm;
    uint32_t* Bbuf = sm + 2 * AT_ASZ;

    const int bh = blockIdx.y;
    const int b = bh >> 3, h = bh & 7;
    const int i0 = blockIdx.x << 7;
    const int tid = threadIdx.x;
    const int warp = tid >> 5;
    const int lane = tid & 31;
    const int gid = lane >> 2;
    const int tig = lane & 3;
    const int wy = warp >> 1;
    const int wx = warp & 1;

    const float* awb = g_w + (size_t)bh * CS * CS;
    const float* sb = g_s + (size_t)bh * CS * CSR;
    const float* vb = g_v + (size_t)bh * CS * CD;

    const uint32_t a_base = (uint32_t)__cvta_generic_to_shared(Abuf);
    const uint32_t b_base = (uint32_t)__cvta_generic_to_shared(Bbuf);

    auto stage = [&](int c, int buf) {
        const uint32_t adst = a_base + buf * AT_ASZ * 4;
        const uint32_t bdst = b_base + buf * AT_BSZ * 4;
#pragma unroll
        for (int l = 0; l < 8; l++) {
            const int idx = tid + (l << 8);
            const int r = idx >> 4;
            const int cc = (idx & 15) << 2;
            const float* src;
            if (c < 8) src = awb + (size_t)(i0 + r) * CS + (c << 6) + cc;
            else       src = sb + (size_t)(i0 + r) * CSR + ((c - 8) << 6) + cc;
            cp16(adst + (r * 68 + cc) * 4, src);
        }
#pragma unroll
        for (int l = 0; l < 4; l++) {
            const int idx = tid + (l << 8);
            const int r = idx >> 4;
            const int cc = (idx & 15) << 2;
            const float* src;
            if (c < 8) src = vb + (size_t)((c << 6) + r) * CD + cc;
            else       src = g_pe + (size_t)(((c - 8) << 6) + r) * CD + cc;
            cp16(bdst + (r * 68 + cc) * 4, src);
        }
    };

    float acc[2][4][4];
#pragma unroll
    for (int mt = 0; mt < 2; mt++)
#pragma unroll
        for (int nt = 0; nt < 4; nt++)
#pragma unroll
            for (int r = 0; r < 4; r++) acc[mt][nt][r] = 0.0f;

    stage(0, 0);
    cp_commit();

    for (int c = 0; c < 11; c++) {
        cp_wait<0>();
        __syncthreads();
        if (c + 1 < 11) stage(c + 1, (c + 1) & 1);
        cp_commit();

        const uint32_t* Asm = Abuf + (c & 1) * AT_ASZ;
        const uint32_t* Bsm = Bbuf + (c & 1) * AT_BSZ;
#pragma unroll
        for (int ks = 0; ks < 64; ks += 8) {
            uint32_t af[2][4];
#pragma unroll
            for (int mt = 0; mt < 2; mt++) {
                const int mrow = wy * 32 + mt * 16 + gid;
                af[mt][0] = Asm[mrow*68 + ks + tig];
                af[mt][1] = Asm[(mrow+8)*68 + ks + tig];
                af[mt][2] = Asm[mrow*68 + ks + tig + 4];
                af[mt][3] = Asm[(mrow+8)*68 + ks + tig + 4];
            }
            uint32_t bf[4][2];
#pragma unroll
            for (int nt = 0; nt < 4; nt++) {
                const int nc = wx * 32 + nt * 8 + gid;
                bf[nt][0] = Bsm[(ks + tig)*68 + nc];
                bf[nt][1] = Bsm[(ks + tig + 4)*68 + nc];
            }
#pragma unroll
            for (int mt = 0; mt < 2; mt++)
#pragma unroll
                for (int nt = 0; nt < 4; nt++)
                    mma_tf32(acc[mt][nt], af[mt], bf[nt]);
        }
    }

#pragma unroll
    for (int mt = 0; mt < 2; mt++)
#pragma unroll
        for (int nt = 0; nt < 4; nt++) {
            const int col = wx * 32 + nt * 8 + 2 * tig;
#pragma unroll
            for (int half = 0; half < 2; half++) {
                const int row = wy * 32 + mt * 16 + gid + half * 8;
                float2 vv = {roundtf(acc[mt][nt][half*2+0]),
                             roundtf(acc[mt][nt][half*2+1])};
                *(float2*)&g_concat[(size_t)(b * CS + i0 + row) * CE + h * CD + col] = vv;
            }
        }
}

// ---------------- layernorm (row = 512), optional rounded second output --------
__global__ __launch_bounds__(256) void ln_kernel(
    const float* __restrict__ in, float* __restrict__ out,
    float* __restrict__ out_r,
    const float* __restrict__ gg, const float* __restrict__ bb)
{
    const int row = blockIdx.x;
    const float* xr = in + (size_t)row * CE;
    const int tid = threadIdx.x;
    const int lane = tid & 31;
    const int wid = tid >> 5;
    __shared__ float wred[8];
    __shared__ float stat;

    float2 v = *(const float2*)&xr[2 * tid];
    float s = v.x + v.y;
#pragma unroll
    for (int o = 16; o > 0; o >>= 1) s += __shfl_xor_sync(0xffffffffu, s, o);
    if (lane == 0) wred[wid] = s;
    __syncthreads();
    if (tid == 0) {
        float ss = wred[0];
#pragma unroll
        for (int k = 1; k < 8; k++) ss += wred[k];
        stat = ss * (1.0f / CE);
    }
    __syncthreads();
    const float mu = stat;
    const float d0 = v.x - mu, d1 = v.y - mu;
    float q = d0 * d0 + d1 * d1;
#pragma unroll
    for (int o = 16; o > 0; o >>= 1) q += __shfl_xor_sync(0xffffffffu, q, o);
    if (lane == 0) wred[wid] = q;
    __syncthreads();
    if (tid == 0) {
        float qq = wred[0];
#pragma unroll
        for (int k = 1; k < 8; k++) qq += wred[k];
        stat = rsqrtf(qq * (1.0f / CE) + 1e-5f);
    }
    __syncthreads();
    const float rstd = stat;
    float2 gv = *(const float2*)&gg[2 * tid];
    float2 bv = *(const float2*)&bb[2 * tid];
    float2 ov = {d0 * rstd * gv.x + bv.x, d1 * rstd * gv.y + bv.y};
    *(float2*)&out[(size_t)row * CE + 2 * tid] = ov;
    if (out_r) {
        float2 orr = {roundtf(ov.x), roundtf(ov.y)};
        *(float2*)&out_r[(size_t)row * CE + 2 * tid] = orr;
    }
}

// ---------------- launch -------------------------------------------------------
extern "C" void kernel_launch(void* const* d_in, const int* in_sizes, int n_in,
                              void* d_out, int out_size)
{
    const float* x    = (const float*)d_in[0];
    const float* dist = (const float*)d_in[1];
    const int*   dt   = (const int*)d_in[2];
    const int*   mask = (const int*)d_in[3];
    const float* wq_w = (const float*)d_in[4];
    const float* wq_b = (const float*)d_in[5];
    const float* wk_w = (const float*)d_in[6];
    const float* wk_b = (const float*)d_in[7];
    const float* wv_w = (const float*)d_in[8];
    const float* wv_b = (const float*)d_in[9];
    const float* wo_w = (const float*)d_in[10];
    const float* wo_b = (const float*)d_in[11];
    const float* pe   = (const float*)d_in[12];
    const float* w1   = (const float*)d_in[13];
    const float* b1   = (const float*)d_in[14];
    const float* w2   = (const float*)d_in[15];
    const float* b2   = (const float*)d_in[16];
    const float* ln1g = (const float*)d_in[17];
    const float* ln1b = (const float*)d_in[18];
    const float* ln2g = (const float*)d_in[19];
    const float* ln2b = (const float*)d_in[20];
    float* out = (float*)d_out;

    void *pq, *pk, *pv, *pcc, *pt1, *pao, *paor, *phid, *pt2, *pwqkv, *pbqkv;
    void *pxr, *pwor, *pw1r, *pw2r;
    cudaGetSymbolAddress(&pq, g_q);
    cudaGetSymbolAddress(&pk, g_k);
    cudaGetSymbolAddress(&pv, g_v);
    cudaGetSymbolAddress(&pcc, g_concat);
    cudaGetSymbolAddress(&pt1, g_t1);
    cudaGetSymbolAddress(&pao, g_attnout);
    cudaGetSymbolAddress(&paor, g_attnout_r);
    cudaGetSymbolAddress(&phid, g_hidden);
    cudaGetSymbolAddress(&pt2, g_t2);
    cudaGetSymbolAddress(&pwqkv, g_wqkv);
    cudaGetSymbolAddress(&pbqkv, g_bqkv);
    cudaGetSymbolAddress(&pxr, g_xr);
    cudaGetSymbolAddress(&pwor, g_wor);
    cudaGetSymbolAddress(&pw1r, g_w1r);
    cudaGetSymbolAddress(&pw2r, g_w2r);

    cudaFuncSetAttribute(fused_scores_kernel,
                         cudaFuncAttributeMaxDynamicSharedMemorySize, FS_SMEM_BYTES);
    cudaFuncSetAttribute(attn_mma_kernel,
                         cudaFuncAttributeMaxDynamicSharedMemorySize, AT_SMEM_BYTES);
    cudaFuncSetAttribute(mma_gemm_kernel<128>,
                         cudaFuncAttributeMaxDynamicSharedMemorySize, GEMM_SMEM_BYTES(128));
    cudaFuncSetAttribute(mma_gemm_kernel<64>,
                         cudaFuncAttributeMaxDynamicSharedMemorySize, GEMM_SMEM_BYTES(64));

    pe_copy_kernel<<<(CNR * CD + 255) / 256, 256>>>(pe);
    pack_qkv_kernel<<<(CE * CE + 255) / 256, 256>>>(wq_w, wk_w, wv_w, wq_b, wk_b, wv_b);
    {
        const int n0 = CM * CE / 4, n1 = CE * CE / 4, n2 = CE * CF / 4, n3 = CF * CE / 4;
        const int ntot = n0 + n1 + n2 + n3;
        round4_kernel<<<(ntot + 255) / 256, 256>>>(
            (const float4*)x, (float4*)pxr, n0,
            (const float4*)wo_w, (float4*)pwor, n1,
            (const float4*)w1, (float4*)pw1r, n2,
            (const float4*)w2, (float4*)pw2r, n3);
    }

    // fused QKV: M=4096, N=1536, K=512
    dim3 gq(1536 / 128, CM / 128);
    mma_gemm_kernel<128><<<gq, 256, GEMM_SMEM_BYTES(128)>>>(
        (const float*)pxr, (const float*)pwqkv, (float*)pq, (float*)pk, (float*)pv,
        CM, 1536, CE, (const float*)pbqkv, nullptr, EPI_QKV);

    // fused qz + scores + softmax + bins
    dim3 gfs(CS / 32, CBH);
    fused_scores_kernel<<<gfs, 256, FS_SMEM_BYTES>>>(dist, dt, mask, pe);

    dim3 gat(CS / 128, CBH);
    attn_mma_kernel<<<gat, 256, AT_SMEM_BYTES>>>();

    dim3 gwo(CE / 64, CM / 128);
    mma_gemm_kernel<64><<<gwo, 256, GEMM_SMEM_BYTES(64)>>>(
        (const float*)pcc, (const float*)pwor, (float*)pt1, nullptr, nullptr,
        CM, CE, CE, wo_b, x, EPI_RESID);
    ln_kernel<<<CM, 256>>>((const float*)pt1, (float*)pao, (float*)paor, ln1g, ln1b);

    dim3 gf1(CF / 128, CM / 128);
    mma_gemm_kernel<128><<<gf1, 256, GEMM_SMEM_BYTES(128)>>>(
        (const float*)paor, (const float*)pw1r, (float*)phid, nullptr, nullptr,
        CM, CF, CE, b1, nullptr, EPI_RELU);
    dim3 gf2(CE / 64, CM / 128);
    mma_gemm_kernel<64><<<gf2, 256, GEMM_SMEM_BYTES(64)>>>(
        (const float*)phid, (const float*)pw2r, (float*)pt2, nullptr, nullptr,
        CM, CE, CF, b2, (const float*)pao, EPI_RESID);
    ln_kernel<<<CM, 256>>>((const float*)pt2, out, nullptr, ln2g, ln2b);
}

// round 12
// speedup vs baseline: 2.4377x; 1.0044x over previous
#include <cuda_runtime.h>
#include <cstdint>
#include <cstddef>

// Problem constants
#define CB 8
#define CS 512
#define CE 512
#define CH 8
#define CD 64
#define CP 64
#define CF 2048
#define CNR 129            // 2P+1
#define CSR 192            // padded rows for pos_emb
#define CBH (CB*CH)        // 64
#define CM (CB*CS)         // 4096

// ---------------- device scratch (zero-initialized .bss) ----------------------
__device__ __align__(16) float g_q[CBH*CS*CD];
__device__ __align__(16) float g_k[CBH*CS*CD];
__device__ __align__(16) float g_v[CBH*CS*CD];
__device__ __align__(16) float g_pe[CSR*CD];            // padded pos_emb (rows >=129 zero)
__device__ __align__(16) float g_concat[CM*CE];         // rounded at write
__device__ __align__(16) float g_t1[CM*CE];
__device__ __align__(16) float g_attnout[CM*CE];        // fp32 (resid)
__device__ __align__(16) float g_attnout_r[CM*CE];      // RN-rounded (FFN1 A)
__device__ __align__(16) float g_hidden[CM*CF];         // rounded at write
__device__ __align__(16) float g_t2[CM*CE];
__device__ __align__(16) float g_wqkv[CE*3*CE];         // packed+rounded [512][1536]
__device__ __align__(16) float g_bqkv[3*CE];
__device__ __align__(16) float g_xr[CM*CE];             // rounded x
__device__ __align__(16) float g_wor[CE*CE];            // rounded wo
__device__ __align__(16) float g_w1r[CE*CF];            // rounded w1
__device__ __align__(16) float g_w2r[CF*CE];            // rounded w2

enum { EPI_QKV = 0, EPI_RESID = 1, EPI_RELU = 2 };

__device__ __forceinline__ uint32_t f2tf(float f) {
    uint32_t u;
    asm("cvt.rna.tf32.f32 %0, %1;" : "=r"(u) : "f"(f));
    return u;
}
__device__ __forceinline__ float roundtf(float f) {
    return __uint_as_float(f2tf(f));
}

__device__ __forceinline__ void mma_tf32(float c[4], const uint32_t a[4],
                                         const uint32_t b[2]) {
    asm volatile(
        "mma.sync.aligned.m16n8k8.row.col.f32.tf32.tf32.f32 "
        "{%0,%1,%2,%3}, {%4,%5,%6,%7}, {%8,%9}, {%0,%1,%2,%3};\n"
        : "+f"(c[0]), "+f"(c[1]), "+f"(c[2]), "+f"(c[3])
        : "r"(a[0]), "r"(a[1]), "r"(a[2]), "r"(a[3]), "r"(b[0]), "r"(b[1]));
}

__device__ __forceinline__ void cp16(uint32_t dst, const void* src) {
    asm volatile("cp.async.cg.shared.global [%0], [%1], 16;\n" :: "r"(dst), "l"(src));
}
__device__ __forceinline__ void cp_commit() {
    asm volatile("cp.async.commit_group;\n");
}
template<int N>
__device__ __forceinline__ void cp_wait() {
    asm volatile("cp.async.wait_group %0;\n" :: "n"(N));
}

// ---------------- TF32 tensor-core GEMM (cp.async 3-stage, BK=32) -------------
#define APITCH 36
#define GEMM_NSTAGE 3

template<int BN>
__global__ __launch_bounds__(256, 2) void mma_gemm_kernel(
    const float* __restrict__ A, const float* __restrict__ Bm,
    float* __restrict__ C, float* __restrict__ C2, float* __restrict__ C3,
    int M, int N, int K,
    const float* __restrict__ bias, const float* __restrict__ resid, int mode)
{
    constexpr int BPITCH = BN + 4;
    constexpr int NT = BN / 16;
    constexpr int ASZ = 128 * APITCH;
    constexpr int BSZ = 32 * BPITCH;
    constexpr int NBL = (BN == 128) ? 4 : 2;
    extern __shared__ uint32_t smem_u[];
    uint32_t* As = smem_u;
    uint32_t* Bs = smem_u + GEMM_NSTAGE * ASZ;

    const int tid = threadIdx.x;
    const int warp = tid >> 5;
    const int lane = tid & 31;
    const int gid = lane >> 2;
    const int tig = lane & 3;
    const int wy = warp >> 1;
    const int wx = warp & 1;
    const int bm = blockIdx.y * 128;
    const int bn = blockIdx.x * BN;

    const uint32_t a_base = (uint32_t)__cvta_generic_to_shared(As);
    const uint32_t b_base = (uint32_t)__cvta_generic_to_shared(Bs);

    const int nk = K >> 5;

    auto stageg = [&](int s) {
        const int bs = s % GEMM_NSTAGE;
        const uint32_t adst = a_base + bs * ASZ * 4;
        const uint32_t bdst = b_base + bs * BSZ * 4;
#pragma unroll
        for (int l = 0; l < 4; l++) {
            const int idx = tid + (l << 8);
            const int r = idx >> 3;
            const int c = (idx & 7) << 2;
            cp16(adst + (r * APITCH + c) * 4,
                 A + (size_t)(bm + r) * K + (s << 5) + c);
        }
#pragma unroll
        for (int l = 0; l < NBL; l++) {
            const int idx = tid + (l << 8);
            int r, c;
            if (BN == 128) { r = idx >> 5; c = (idx & 31) << 2; }
            else           { r = idx >> 4; c = (idx & 15) << 2; }
            cp16(bdst + (r * BPITCH + c) * 4,
                 Bm + (size_t)((s << 5) + r) * N + bn + c);
        }
    };

    float acc[2][NT][4];
#pragma unroll
    for (int mt = 0; mt < 2; mt++)
#pragma unroll
        for (int nt = 0; nt < NT; nt++)
#pragma unroll
            for (int r = 0; r < 4; r++) acc[mt][nt][r] = 0.0f;

#pragma unroll
    for (int s = 0; s < GEMM_NSTAGE - 1; s++) {
        if (s < nk) stageg(s);
        cp_commit();
    }

    for (int i = 0; i < nk; i++) {
        cp_wait<1>();
        __syncthreads();
        if (i + 2 < nk) stageg(i + 2);
        cp_commit();

        const int buf = i % GEMM_NSTAGE;
        const uint32_t* Ab = As + buf * ASZ;
        const uint32_t* Bb = Bs + buf * BSZ;
#pragma unroll
        for (int ks = 0; ks < 32; ks += 8) {
            uint32_t af[2][4];
#pragma unroll
            for (int mt = 0; mt < 2; mt++) {
                const int mrow = wy * 32 + mt * 16 + gid;
                af[mt][0] = Ab[mrow * APITCH + ks + tig];
                af[mt][1] = Ab[(mrow + 8) * APITCH + ks + tig];
                af[mt][2] = Ab[mrow * APITCH + ks + tig + 4];
                af[mt][3] = Ab[(mrow + 8) * APITCH + ks + tig + 4];
            }
            uint32_t bf[NT][2];
#pragma unroll
            for (int nt = 0; nt < NT; nt++) {
                const int nc = wx * (BN / 2) + nt * 8 + gid;
                bf[nt][0] = Bb[(ks + tig) * BPITCH + nc];
                bf[nt][1] = Bb[(ks + tig + 4) * BPITCH + nc];
            }
#pragma unroll
            for (int mt = 0; mt < 2; mt++)
#pragma unroll
                for (int nt = 0; nt < NT; nt++)
                    mma_tf32(acc[mt][nt], af[mt], bf[nt]);
        }
    }

#pragma unroll
    for (int mt = 0; mt < 2; mt++) {
#pragma unroll
        for (int nt = 0; nt < NT; nt++) {
            const int col = bn + wx * (BN / 2) + nt * 8 + 2 * tig;
            float bv0 = 0.0f, bv1 = 0.0f;
            if (bias) { bv0 = bias[col]; bv1 = bias[col + 1]; }
#pragma unroll
            for (int half = 0; half < 2; half++) {
                const int row = bm + wy * 32 + mt * 16 + gid + half * 8;
                float v0 = acc[mt][nt][half * 2 + 0] + bv0;
                float v1 = acc[mt][nt][half * 2 + 1] + bv1;
                if (mode == EPI_RESID) {
                    v0 += resid[(size_t)row * N + col];
                    v1 += resid[(size_t)row * N + col + 1];
                } else if (mode == EPI_RELU) {
                    v0 = roundtf(fmaxf(v0, 0.0f));
                    v1 = roundtf(fmaxf(v1, 0.0f));
                }
                float2 vv = {v0, v1};
                if (mode == EPI_QKV) {
                    const int b = row >> 9, ii = row & 511;
                    const int which = col >> 9;
                    const int cc = col & 511;
                    const int h = cc >> 6, d = cc & 63;
                    float* base = (which == 0) ? C : (which == 1) ? C2 : C3;
                    *(float2*)(base + (((size_t)(b * CH + h) * CS) + ii) * CD + d) = vv;
                } else {
                    *(float2*)(C + (size_t)row * N + col) = vv;
                }
            }
        }
    }
}

#define GEMM_SMEM_BYTES(BN) (GEMM_NSTAGE * (128 * APITCH + 32 * ((BN) + 4)) * 4)

// ---------------- merged round-copy (4 arrays) ----------------------------------
__global__ void round4_kernel(const float4* __restrict__ s0, float4* __restrict__ d0, int n0,
                              const float4* __restrict__ s1, float4* __restrict__ d1, int n1,
                              const float4* __restrict__ s2, float4* __restrict__ d2, int n2,
                              const float4* __restrict__ s3, float4* __restrict__ d3, int n3)
{
    int i = blockIdx.x * 256 + threadIdx.x;
    const float4* s; float4* d;
    if (i < n0) { s = s0 + i; d = d0 + i; }
    else {
        i -= n0;
        if (i < n1) { s = s1 + i; d = d1 + i; }
        else {
            i -= n1;
            if (i < n2) { s = s2 + i; d = d2 + i; }
            else {
                i -= n2;
                if (i >= n3) return;
                s = s3 + i; d = d3 + i;
            }
        }
    }
    float4 v = *s;
    v.x = roundtf(v.x); v.y = roundtf(v.y);
    v.z = roundtf(v.z); v.w = roundtf(v.w);
    *d = v;
}

// ---------------- pack QKV weights/biases (rounded) ----------------------------
__global__ void pack_qkv_kernel(const float* __restrict__ wq, const float* __restrict__ wk,
                                const float* __restrict__ wv, const float* __restrict__ bq,
                                const float* __restrict__ bk, const float* __restrict__ bv)
{
    int idx = blockIdx.x * 256 + threadIdx.x;
    if (idx < CE * CE) {
        int r = idx >> 9, c = idx & 511;
        g_wqkv[(size_t)r * 1536 + c] = roundtf(wq[idx]);
        g_wqkv[(size_t)r * 1536 + 512 + c] = roundtf(wk[idx]);
        g_wqkv[(size_t)r * 1536 + 1024 + c] = roundtf(wv[idx]);
    }
    if (idx < CE) {
        g_bqkv[idx] = bq[idx];
        g_bqkv[512 + idx] = bk[idx];
        g_bqkv[1024 + idx] = bv[idx];
    }
}

// ---------------- pad pos_emb into g_pe ---------------------------------------
__global__ void pe_copy_kernel(const float* __restrict__ pe)
{
    int t = blockIdx.x * 256 + threadIdx.x;
    if (t < CNR * CD) g_pe[t] = pe[t];
}

// ---------------- FULLY FUSED attention: qz+scores+softmax+bins+aw@V+bins@PE ---
// block: 32 i-rows x full 512 j for one bh. 8 warps: wm = warp&1, wn = warp>>1.
// smem (u32 words):
#define FS_Q 0                 // Q: 32*68 = 2176 (dead after phase 2; AW reuses [0,4224))
#define FS_K 4224              // 2 x 128*68 = 17408 (PE phase1 / K / V / PE chunks)
#define FS_QZ 21632            // 32*132 = 4224 (QZ; later bins)
#define FS_INT 25856           // dti 32, dtj 512, mj 512 = 1056
#define FS_RED 26912           // 128
#define FS_SMEM_BYTES (27040 * 4)
#define FS_KBUF (128*68)

__global__ __launch_bounds__(256, 2) void fused_attn_kernel(
    const float* __restrict__ dist, const int* __restrict__ dt,
    const int* __restrict__ mask)
{
    extern __shared__ uint32_t sm[];
    uint32_t* Qs = sm + FS_Q;
    float* AW = (float*)(sm + FS_Q);        // phase 5 alias (32*132)
    uint32_t* Kb = sm + FS_K;
    float* QZs = (float*)(sm + FS_QZ);      // later bins
    int* dti_s = (int*)(sm + FS_INT);
    int* dtj_s = dti_s + 32;
    int* mj_s = dtj_s + 512;
    float* red = (float*)(sm + FS_RED);

    const int bh = blockIdx.y;
    const int b = bh >> 3, h = bh & 7;
    const int i0 = blockIdx.x << 5;
    const int tid = threadIdx.x;
    const int warp = tid >> 5;
    const int lane = tid & 31;
    const int gid = lane >> 2;
    const int tig = lane & 3;
    const int wm = warp & 1;
    const int wn = warp >> 1;               // 0..3
    const int mrow = wm * 16 + gid;

    const float* qb = g_q + (size_t)bh * CS * CD;
    const float* kb = g_k + (size_t)bh * CS * CD;
    const float* vb = g_v + (size_t)bh * CS * CD;

    const uint32_t q_base = (uint32_t)__cvta_generic_to_shared(Qs);
    const uint32_t k_base = (uint32_t)__cvta_generic_to_shared(Kb);

    // ---- phase 0: stage Q + PE (g_pe rows 0..159; rows >=129 are zero)
#pragma unroll
    for (int l = 0; l < 2; l++) {
        const int idx = tid + (l << 8);
        const int r = idx >> 4;
        const int c = (idx & 15) << 2;
        cp16(q_base + (r * 68 + c) * 4, qb + (size_t)(i0 + r) * CD + c);
    }
    for (int t = tid; t < 160 * 16; t += 256) {
        const int r = t >> 4;
        const int c = (t & 15) << 2;
        cp16(k_base + (r * 68 + c) * 4, g_pe + (size_t)r * CD + c);
    }
    cp_commit();

    if (tid < 32) dti_s[tid] = dt[b * CS + i0 + tid];
    {
        int2 dj = *(const int2*)&dt[b * CS + 2 * tid];
        dtj_s[2 * tid] = dj.x; dtj_s[2 * tid + 1] = dj.y;
        int2 mm = *(const int2*)&mask[b * CS + 2 * tid];
        mj_s[2 * tid] = mm.x; mj_s[2 * tid + 1] = mm.y;
    }
    cp_wait<0>();
    __syncthreads();

    // ---- phase 1: qz = Q(32x64) @ PE^T (n padded to 160) -> QZs[32][132]
    {
        float qacc[5][4];
#pragma unroll
        for (int nt = 0; nt < 5; nt++)
#pragma unroll
            for (int r = 0; r < 4; r++) qacc[nt][r] = 0.0f;
#pragma unroll
        for (int ks = 0; ks < 64; ks += 8) {
            uint32_t af[4];
            af[0] = Qs[mrow * 68 + ks + tig];
            af[1] = Qs[(mrow + 8) * 68 + ks + tig];
            af[2] = Qs[mrow * 68 + ks + tig + 4];
            af[3] = Qs[(mrow + 8) * 68 + ks + tig + 4];
#pragma unroll
            for (int nt = 0; nt < 5; nt++) {
                const int nc = wn * 40 + nt * 8 + gid;
                uint32_t bf[2];
                bf[0] = Kb[nc * 68 + ks + tig];
                bf[1] = Kb[nc * 68 + ks + tig + 4];
                mma_tf32(qacc[nt], af, bf);
            }
        }
        __syncthreads();   // PE reads done before K chunk0 clobbers Kb

        // stage K chunk 0 -> buf0
#pragma unroll
        for (int l = 0; l < 8; l++) {
            const int idx = tid + (l << 8);
            const int r = idx >> 4;
            const int c = (idx & 15) << 2;
            cp16(k_base + (r * 68 + c) * 4, kb + (size_t)r * CD + c);
        }
        cp_commit();

        // qz writeback
#pragma unroll
        for (int nt = 0; nt < 5; nt++) {
            const int col = wn * 40 + nt * 8 + 2 * tig;
            if (col <= 128) {
                QZs[mrow * 132 + col] = qacc[nt][0];
                QZs[mrow * 132 + col + 1] = qacc[nt][1];
                QZs[(mrow + 8) * 132 + col] = qacc[nt][2];
                QZs[(mrow + 8) * 132 + col + 1] = qacc[nt][3];
            }
        }
    }

    // ---- phase 2: scores over 4 K-chunks (double-buffered)
    float sacc[4][4][4];
#pragma unroll
    for (int c = 0; c < 4; c++)
#pragma unroll
        for (int nt = 0; nt < 4; nt++)
#pragma unroll
            for (int r = 0; r < 4; r++) sacc[c][nt][r] = 0.0f;

#pragma unroll
    for (int ch = 0; ch < 4; ch++) {
        cp_wait<0>();
        __syncthreads();
        if (ch < 3) {
            const uint32_t kdst = k_base + (((ch + 1) & 1)) * FS_KBUF * 4;
#pragma unroll
            for (int l = 0; l < 8; l++) {
                const int idx = tid + (l << 8);
                const int r = idx >> 4;
                const int c = (idx & 15) << 2;
                cp16(kdst + (r * 68 + c) * 4,
                     kb + (size_t)((ch + 1) * 128 + r) * CD + c);
            }
        }
        cp_commit();

        const uint32_t* Kc = Kb + (ch & 1) * FS_KBUF;
#pragma unroll
        for (int ks = 0; ks < 64; ks += 8) {
            uint32_t af[4];
            af[0] = Qs[mrow * 68 + ks + tig];
            af[1] = Qs[(mrow + 8) * 68 + ks + tig];
            af[2] = Qs[mrow * 68 + ks + tig + 4];
            af[3] = Qs[(mrow + 8) * 68 + ks + tig + 4];
#pragma unroll
            for (int nt = 0; nt < 4; nt++) {
                const int nc = wn * 32 + nt * 8 + gid;
                uint32_t bf[2];
                bf[0] = Kc[nc * 68 + ks + tig];
                bf[1] = Kc[nc * 68 + ks + tig + 4];
                mma_tf32(sacc[ch][nt], af, bf);
            }
        }

#pragma unroll
        for (int half = 0; half < 2; half++) {
            const int il = mrow + half * 8;
            const int i = i0 + il;
            const int di = dti_s[il];
#pragma unroll
            for (int nt = 0; nt < 4; nt++) {
                const int jl = ch * 128 + wn * 32 + nt * 8 + 2 * tig;
                float2 dv = *(const float2*)&dist[((size_t)b * CS + i) * CS + jl];
#pragma unroll
                for (int u = 0; u < 2; u++) {
                    const int j = jl + u;
                    int rel = min(max(dtj_s[j] - di, -CP), CP) + CP;
                    float v = (sacc[ch][nt][half * 2 + u] + QZs[il * 132 + rel]) * 0.125f
                            + 0.6f * (u ? dv.y : dv.x);
                    if (mj_s[j] == 0) v = -1e9f;
                    sacc[ch][nt][half * 2 + u] = v;
                }
            }
        }
    }
    __syncthreads();   // QZ gathers done; QZ region becomes bins

    // ---- phase 3: softmax in regs + bins
    float* bins = QZs;
    for (int t = tid; t < 32 * 132; t += 256) bins[t] = 0.0f;

    float mrow2[2];
#pragma unroll
    for (int half = 0; half < 2; half++) {
        float m = -1e30f;
#pragma unroll
        for (int c = 0; c < 4; c++)
#pragma unroll
            for (int nt = 0; nt < 4; nt++) {
                m = fmaxf(m, sacc[c][nt][half * 2]);
                m = fmaxf(m, sacc[c][nt][half * 2 + 1]);
            }
        m = fmaxf(m, __shfl_xor_sync(0xffffffffu, m, 1));
        m = fmaxf(m, __shfl_xor_sync(0xffffffffu, m, 2));
        mrow2[half] = m;
    }
    if (tig == 0) {
        red[wn * 32 + mrow] = mrow2[0];
        red[wn * 32 + mrow + 8] = mrow2[1];
    }
    __syncthreads();
#pragma unroll
    for (int half = 0; half < 2; half++) {
        const int r = mrow + half * 8;
        mrow2[half] = fmaxf(fmaxf(red[r], red[32 + r]), fmaxf(red[64 + r], red[96 + r]));
    }
    __syncthreads();

    float srow[2] = {0.0f, 0.0f};
#pragma unroll
    for (int half = 0; half < 2; half++) {
#pragma unroll
        for (int c = 0; c < 4; c++)
#pragma unroll
            for (int nt = 0; nt < 4; nt++)
#pragma unroll
                for (int u = 0; u < 2; u++) {
                    float e = __expf(sacc[c][nt][half * 2 + u] - mrow2[half]);
                    sacc[c][nt][half * 2 + u] = e;
                    srow[half] += e;
                }
        srow[half] += __shfl_xor_sync(0xffffffffu, srow[half], 1);
        srow[half] += __shfl_xor_sync(0xffffffffu, srow[half], 2);
    }
    if (tig == 0) {
        red[wn * 32 + mrow] = srow[0];
        red[wn * 32 + mrow + 8] = srow[1];
    }
    __syncthreads();
    float inv2[2];
#pragma unroll
    for (int half = 0; half < 2; half++) {
        const int r = mrow + half * 8;
        inv2[half] = 1.0f / (red[r] + red[32 + r] + red[64 + r] + red[96 + r]);
    }

    // normalize in regs + bins atomics
#pragma unroll
    for (int half = 0; half < 2; half++) {
        const int il = mrow + half * 8;
        const int di = dti_s[il];
#pragma unroll
        for (int c = 0; c < 4; c++)
#pragma unroll
            for (int nt = 0; nt < 4; nt++) {
                const int jl = c * 128 + wn * 32 + nt * 8 + 2 * tig;
                float a0 = sacc[c][nt][half * 2 + 0] * inv2[half];
                float a1 = sacc[c][nt][half * 2 + 1] * inv2[half];
                sacc[c][nt][half * 2 + 0] = a0;
                sacc[c][nt][half * 2 + 1] = a1;
                int r0 = min(max(dtj_s[jl] - di, -CP), CP) + CP;
                int r1 = min(max(dtj_s[jl + 1] - di, -CP), CP) + CP;
                atomicAdd(&bins[il * 132 + r0], a0);
                atomicAdd(&bins[il * 132 + r1], a1);
            }
    }
    __syncthreads();   // bins complete; Q region now dead -> AW

    // ---- phase 5: out = aw @ V + bins @ PE
    float oacc[2][4];
#pragma unroll
    for (int nt = 0; nt < 2; nt++)
#pragma unroll
        for (int r = 0; r < 4; r++) oacc[nt][r] = 0.0f;

    // stage V chunk 0 -> buf0
#pragma unroll
    for (int l = 0; l < 8; l++) {
        const int idx = tid + (l << 8);
        const int r = idx >> 4;
        const int c = (idx & 15) << 2;
        cp16(k_base + (r * 68 + c) * 4, vb + (size_t)r * CD + c);
    }
    cp_commit();

#pragma unroll
    for (int ch = 0; ch < 4; ch++) {
        // write aw chunk into AW [32][132]
#pragma unroll
        for (int half = 0; half < 2; half++) {
            const int il = mrow + half * 8;
#pragma unroll
            for (int nt = 0; nt < 4; nt++) {
                const int jloc = wn * 32 + nt * 8 + 2 * tig;
                float2 st = {sacc[ch][nt][half * 2 + 0], sacc[ch][nt][half * 2 + 1]};
                *(float2*)&AW[il * 132 + jloc] = st;
            }
        }
        cp_wait<0>();
        __syncthreads();   // V ch landed + AW visible
        if (ch < 3) {
            const uint32_t vdst = k_base + ((ch + 1) & 1) * FS_KBUF * 4;
#pragma unroll
            for (int l = 0; l < 8; l++) {
                const int idx = tid + (l << 8);
                const int r = idx >> 4;
                const int c = (idx & 15) << 2;
                cp16(vdst + (r * 68 + c) * 4,
                     vb + (size_t)((ch + 1) * 128 + r) * CD + c);
            }
        }
        cp_commit();

        const uint32_t* Vc = Kb + (ch & 1) * FS_KBUF;
        const uint32_t* AWu = (const uint32_t*)AW;
#pragma unroll
        for (int ks = 0; ks < 128; ks += 8) {
            uint32_t af[4];
            af[0] = AWu[mrow * 132 + ks + tig];
            af[1] = AWu[(mrow + 8) * 132 + ks + tig];
            af[2] = AWu[mrow * 132 + ks + tig + 4];
            af[3] = AWu[(mrow + 8) * 132 + ks + tig + 4];
#pragma unroll
            for (int nt = 0; nt < 2; nt++) {
                const int nc = wn * 16 + nt * 8 + gid;
                uint32_t bf[2];
                bf[0] = Vc[(ks + tig) * 68 + nc];
                bf[1] = Vc[(ks + tig + 4) * 68 + nc];
                mma_tf32(oacc[nt], af, bf);
            }
        }
        __syncthreads();   // AW free for next chunk
    }

    // PE part: 3 chunks of 64 k; A = bins (pitch 132, zeros/garbage*0 beyond 128)
    {
        // stage PE chunk 0 -> buf0 (V3 was buf1)
#pragma unroll
        for (int l = 0; l < 4; l++) {
            const int idx = tid + (l << 8);
            const int r = idx >> 4;
            const int c = (idx & 15) << 2;
            cp16(k_base + (r * 68 + c) * 4, g_pe + (size_t)r * CD + c);
        }
        cp_commit();

        const uint32_t* binsu = (const uint32_t*)bins;
#pragma unroll
        for (int pch = 0; pch < 3; pch++) {
            cp_wait<0>();
            __syncthreads();
            if (pch < 2) {
                const uint32_t pdst = k_base + ((pch + 1) & 1) * FS_KBUF * 4;
#pragma unroll
                for (int l = 0; l < 4; l++) {
                    const int idx = tid + (l << 8);
                    const int r = idx >> 4;
                    const int c = (idx & 15) << 2;
                    cp16(pdst + (r * 68 + c) * 4,
                         g_pe + (size_t)((pch + 1) * 64 + r) * CD + c);
                }
            }
            cp_commit();

            const uint32_t* Pc = Kb + (pch & 1) * FS_KBUF;
#pragma unroll
            for (int ks = 0; ks < 64; ks += 8) {
                const int kk = pch * 64 + ks;
                uint32_t af[4];
                af[0] = binsu[mrow * 132 + kk + tig];
                af[1] = binsu[(mrow + 8) * 132 + kk + tig];
                af[2] = binsu[mrow * 132 + kk + tig + 4];
                af[3] = binsu[(mrow + 8) * 132 + kk + tig + 4];
#pragma unroll
                for (int nt = 0; nt < 2; nt++) {
                    const int nc = wn * 16 + nt * 8 + gid;
                    uint32_t bf[2];
                    bf[0] = Pc[(ks + tig) * 68 + nc];
                    bf[1] = Pc[(ks + tig + 4) * 68 + nc];
                    mma_tf32(oacc[nt], af, bf);
                }
            }
        }
    }

    // epilogue: write g_concat (rounded)
#pragma unroll
    for (int nt = 0; nt < 2; nt++) {
        const int col = h * CD + wn * 16 + nt * 8 + 2 * tig;
#pragma unroll
        for (int half = 0; half < 2; half++) {
            const int row = i0 + mrow + half * 8;
            float2 vv = {roundtf(oacc[nt][half * 2 + 0]),
                         roundtf(oacc[nt][half * 2 + 1])};
            *(float2*)&g_concat[(size_t)(b * CS + row) * CE + col] = vv;
        }
    }
}

// ---------------- layernorm (row = 512), optional rounded second output --------
__global__ __launch_bounds__(256) void ln_kernel(
    const float* __restrict__ in, float* __restrict__ out,
    float* __restrict__ out_r,
    const float* __restrict__ gg, const float* __restrict__ bb)
{
    const int row = blockIdx.x;
    const float* xr = in + (size_t)row * CE;
    const int tid = threadIdx.x;
    const int lane = tid & 31;
    const int wid = tid >> 5;
    __shared__ float wred[8];
    __shared__ float stat;

    float2 v = *(const float2*)&xr[2 * tid];
    float s = v.x + v.y;
#pragma unroll
    for (int o = 16; o > 0; o >>= 1) s += __shfl_xor_sync(0xffffffffu, s, o);
    if (lane == 0) wred[wid] = s;
    __syncthreads();
    if (tid == 0) {
        float ss = wred[0];
#pragma unroll
        for (int k = 1; k < 8; k++) ss += wred[k];
        stat = ss * (1.0f / CE);
    }
    __syncthreads();
    const float mu = stat;
    const float d0 = v.x - mu, d1 = v.y - mu;
    float q = d0 * d0 + d1 * d1;
#pragma unroll
    for (int o = 16; o > 0; o >>= 1) q += __shfl_xor_sync(0xffffffffu, q, o);
    if (lane == 0) wred[wid] = q;
    __syncthreads();
    if (tid == 0) {
        float qq = wred[0];
#pragma unroll
        for (int k = 1; k < 8; k++) qq += wred[k];
        stat = rsqrtf(qq * (1.0f / CE) + 1e-5f);
    }
    __syncthreads();
    const float rstd = stat;
    float2 gv = *(const float2*)&gg[2 * tid];
    float2 bv = *(const float2*)&bb[2 * tid];
    float2 ov = {d0 * rstd * gv.x + bv.x, d1 * rstd * gv.y + bv.y};
    *(float2*)&out[(size_t)row * CE + 2 * tid] = ov;
    if (out_r) {
        float2 orr = {roundtf(ov.x), roundtf(ov.y)};
        *(float2*)&out_r[(size_t)row * CE + 2 * tid] = orr;
    }
}

// ---------------- launch -------------------------------------------------------
extern "C" void kernel_launch(void* const* d_in, const int* in_sizes, int n_in,
                              void* d_out, int out_size)
{
    const float* x    = (const float*)d_in[0];
    const float* dist = (const float*)d_in[1];
    const int*   dt   = (const int*)d_in[2];
    const int*   mask = (const int*)d_in[3];
    const float* wq_w = (const float*)d_in[4];
    const float* wq_b = (const float*)d_in[5];
    const float* wk_w = (const float*)d_in[6];
    const float* wk_b = (const float*)d_in[7];
    const float* wv_w = (const float*)d_in[8];
    const float* wv_b = (const float*)d_in[9];
    const float* wo_w = (const float*)d_in[10];
    const float* wo_b = (const float*)d_in[11];
    const float* pe   = (const float*)d_in[12];
    const float* w1   = (const float*)d_in[13];
    const float* b1   = (const float*)d_in[14];
    const float* w2   = (const float*)d_in[15];
    const float* b2   = (const float*)d_in[16];
    const float* ln1g = (const float*)d_in[17];
    const float* ln1b = (const float*)d_in[18];
    const float* ln2g = (const float*)d_in[19];
    const float* ln2b = (const float*)d_in[20];
    float* out = (float*)d_out;

    void *pq, *pk, *pv, *pcc, *pt1, *pao, *paor, *phid, *pt2, *pwqkv, *pbqkv;
    void *pxr, *pwor, *pw1r, *pw2r;
    cudaGetSymbolAddress(&pq, g_q);
    cudaGetSymbolAddress(&pk, g_k);
    cudaGetSymbolAddress(&pv, g_v);
    cudaGetSymbolAddress(&pcc, g_concat);
    cudaGetSymbolAddress(&pt1, g_t1);
    cudaGetSymbolAddress(&pao, g_attnout);
    cudaGetSymbolAddress(&paor, g_attnout_r);
    cudaGetSymbolAddress(&phid, g_hidden);
    cudaGetSymbolAddress(&pt2, g_t2);
    cudaGetSymbolAddress(&pwqkv, g_wqkv);
    cudaGetSymbolAddress(&pbqkv, g_bqkv);
    cudaGetSymbolAddress(&pxr, g_xr);
    cudaGetSymbolAddress(&pwor, g_wor);
    cudaGetSymbolAddress(&pw1r, g_w1r);
    cudaGetSymbolAddress(&pw2r, g_w2r);

    cudaFuncSetAttribute(fused_attn_kernel,
                         cudaFuncAttributeMaxDynamicSharedMemorySize, FS_SMEM_BYTES);
    cudaFuncSetAttribute(mma_gemm_kernel<128>,
                         cudaFuncAttributeMaxDynamicSharedMemorySize, GEMM_SMEM_BYTES(128));
    cudaFuncSetAttribute(mma_gemm_kernel<64>,
                         cudaFuncAttributeMaxDynamicSharedMemorySize, GEMM_SMEM_BYTES(64));

    pe_copy_kernel<<<(CNR * CD + 255) / 256, 256>>>(pe);
    pack_qkv_kernel<<<(CE * CE + 255) / 256, 256>>>(wq_w, wk_w, wv_w, wq_b, wk_b, wv_b);
    {
        const int n0 = CM * CE / 4, n1 = CE * CE / 4, n2 = CE * CF / 4, n3 = CF * CE / 4;
        const int ntot = n0 + n1 + n2 + n3;
        round4_kernel<<<(ntot + 255) / 256, 256>>>(
            (const float4*)x, (float4*)pxr, n0,
            (const float4*)wo_w, (float4*)pwor, n1,
            (const float4*)w1, (float4*)pw1r, n2,
            (const float4*)w2, (float4*)pw2r, n3);
    }

    // fused QKV: M=4096, N=1536, K=512
    dim3 gq(1536 / 128, CM / 128);
    mma_gemm_kernel<128><<<gq, 256, GEMM_SMEM_BYTES(128)>>>(
        (const float*)pxr, (const float*)pwqkv, (float*)pq, (float*)pk, (float*)pv,
        CM, 1536, CE, (const float*)pbqkv, nullptr, EPI_QKV);

    // fully fused attention -> g_concat
    dim3 gfs(CS / 32, CBH);
    fused_attn_kernel<<<gfs, 256, FS_SMEM_BYTES>>>(dist, dt, mask);

    dim3 gwo(CE / 64, CM / 128);
    mma_gemm_kernel<64><<<gwo, 256, GEMM_SMEM_BYTES(64)>>>(
        (const float*)pcc, (const float*)pwor, (float*)pt1, nullptr, nullptr,
        CM, CE, CE, wo_b, x, EPI_RESID);
    ln_kernel<<<CM, 256>>>((const float*)pt1, (float*)pao, (float*)paor, ln1g, ln1b);

    dim3 gf1(CF / 128, CM / 128);
    mma_gemm_kernel<128><<<gf1, 256, GEMM_SMEM_BYTES(128)>>>(
        (const float*)paor, (const float*)pw1r, (float*)phid, nullptr, nullptr,
        CM, CF, CE, b1, nullptr, EPI_RELU);
    dim3 gf2(CE / 64, CM / 128);
    mma_gemm_kernel<64><<<gf2, 256, GEMM_SMEM_BYTES(64)>>>(
        (const float*)phid, (const float*)pw2r, (float*)pt2, nullptr, nullptr,
        CM, CE, CF, b2, (const float*)pao, EPI_RESID);
    ln_kernel<<<CM, 256>>>((const float*)pt2, out, nullptr, ln2g, ln2b);
}

// round 13
// speedup vs baseline: 2.5043x; 1.0273x over previous
#include <cuda_runtime.h>
#include <cstdint>
#include <cstddef>

// Problem constants
#define CB 8
#define CS 512
#define CE 512
#define CH 8
#define CD 64
#define CP 64
#define CF 2048
#define CNR 129            // 2P+1
#define CSR 192            // padded rows for pos_emb
#define CBH (CB*CH)        // 64
#define CM (CB*CS)         // 4096

// ---------------- device scratch (zero-initialized .bss) ----------------------
__device__ __align__(16) float g_q[CBH*CS*CD];
__device__ __align__(16) float g_k[CBH*CS*CD];
__device__ __align__(16) float g_v[CBH*CS*CD];
__device__ __align__(16) float g_pe[CSR*CD];            // padded pos_emb (rows >=129 zero)
__device__ __align__(16) float g_concat[CM*CE];         // rounded at write
__device__ __align__(16) float g_t1[CM*CE];
__device__ __align__(16) float g_attnout[CM*CE];        // fp32 (resid)
__device__ __align__(16) float g_attnout_r[CM*CE];      // RN-rounded (FFN1 A)
__device__ __align__(16) float g_hidden[CM*CF];         // rounded at write
__device__ __align__(16) float g_t2[CM*CE];             // FFN2 partial 0
__device__ __align__(16) float g_t2b[CM*CE];            // FFN2 partial 1
__device__ __align__(16) float g_wqkv[CE*3*CE];         // packed+rounded [512][1536]
__device__ __align__(16) float g_bqkv[3*CE];
__device__ __align__(16) float g_xr[CM*CE];             // rounded x
__device__ __align__(16) float g_wor[CE*CE];            // rounded wo
__device__ __align__(16) float g_w1r[CE*CF];            // rounded w1
__device__ __align__(16) float g_w2r[CF*CE];            // rounded w2

enum { EPI_QKV = 0, EPI_RESID = 1, EPI_RELU = 2, EPI_NONE = 3 };

__device__ __forceinline__ uint32_t f2tf(float f) {
    uint32_t u;
    asm("cvt.rna.tf32.f32 %0, %1;" : "=r"(u) : "f"(f));
    return u;
}
__device__ __forceinline__ float roundtf(float f) {
    return __uint_as_float(f2tf(f));
}

__device__ __forceinline__ void mma_tf32(float c[4], const uint32_t a[4],
                                         const uint32_t b[2]) {
    asm volatile(
        "mma.sync.aligned.m16n8k8.row.col.f32.tf32.tf32.f32 "
        "{%0,%1,%2,%3}, {%4,%5,%6,%7}, {%8,%9}, {%0,%1,%2,%3};\n"
        : "+f"(c[0]), "+f"(c[1]), "+f"(c[2]), "+f"(c[3])
        : "r"(a[0]), "r"(a[1]), "r"(a[2]), "r"(a[3]), "r"(b[0]), "r"(b[1]));
}

__device__ __forceinline__ void cp16(uint32_t dst, const void* src) {
    asm volatile("cp.async.cg.shared.global [%0], [%1], 16;\n" :: "r"(dst), "l"(src));
}
__device__ __forceinline__ void cp_commit() {
    asm volatile("cp.async.commit_group;\n");
}
template<int N>
__device__ __forceinline__ void cp_wait() {
    asm volatile("cp.async.wait_group %0;\n" :: "n"(N));
}

// ---------------- TF32 tensor-core GEMM (cp.async 3-stage, BK=32) -------------
// supports split-K via gridDim.z (EPI_NONE writes partial to C / C2 by z)
#define APITCH 36
#define GEMM_NSTAGE 3

template<int BN>
__global__ __launch_bounds__(256, 2) void mma_gemm_kernel(
    const float* __restrict__ A, const float* __restrict__ Bm,
    float* __restrict__ C, float* __restrict__ C2, float* __restrict__ C3,
    int M, int N, int K, int Kstride,
    const float* __restrict__ bias, const float* __restrict__ resid, int mode)
{
    constexpr int BPITCH = BN + 4;
    constexpr int NT = BN / 16;
    constexpr int ASZ = 128 * APITCH;
    constexpr int BSZ = 32 * BPITCH;
    constexpr int CPR = BN / 4;            // float4 chunks per B row
    constexpr int NBL = CPR / 8;           // B cp16 per thread per stage
    extern __shared__ uint32_t smem_u[];
    uint32_t* As = smem_u;
    uint32_t* Bs = smem_u + GEMM_NSTAGE * ASZ;

    const int tid = threadIdx.x;
    const int warp = tid >> 5;
    const int lane = tid & 31;
    const int gid = lane >> 2;
    const int tig = lane & 3;
    const int wy = warp >> 1;
    const int wx = warp & 1;
    const int bm = blockIdx.y * 128;
    const int bn = blockIdx.x * BN;
    const int koff = blockIdx.z * K;

    const uint32_t a_base = (uint32_t)__cvta_generic_to_shared(As);
    const uint32_t b_base = (uint32_t)__cvta_generic_to_shared(Bs);

    const int nk = K >> 5;

    auto stageg = [&](int s) {
        const int bs = s % GEMM_NSTAGE;
        const uint32_t adst = a_base + bs * ASZ * 4;
        const uint32_t bdst = b_base + bs * BSZ * 4;
#pragma unroll
        for (int l = 0; l < 4; l++) {
            const int idx = tid + (l << 8);
            const int r = idx >> 3;
            const int c = (idx & 7) << 2;
            cp16(adst + (r * APITCH + c) * 4,
                 A + (size_t)(bm + r) * Kstride + koff + (s << 5) + c);
        }
#pragma unroll
        for (int l = 0; l < NBL; l++) {
            const int idx = tid + (l << 8);
            const int r = idx / CPR;
            const int c = (idx % CPR) << 2;
            cp16(bdst + (r * BPITCH + c) * 4,
                 Bm + (size_t)(koff + (s << 5) + r) * N + bn + c);
        }
    };

    float acc[2][NT][4];
#pragma unroll
    for (int mt = 0; mt < 2; mt++)
#pragma unroll
        for (int nt = 0; nt < NT; nt++)
#pragma unroll
            for (int r = 0; r < 4; r++) acc[mt][nt][r] = 0.0f;

#pragma unroll
    for (int s = 0; s < GEMM_NSTAGE - 1; s++) {
        if (s < nk) stageg(s);
        cp_commit();
    }

    for (int i = 0; i < nk; i++) {
        cp_wait<1>();
        __syncthreads();
        if (i + 2 < nk) stageg(i + 2);
        cp_commit();

        const int buf = i % GEMM_NSTAGE;
        const uint32_t* Ab = As + buf * ASZ;
        const uint32_t* Bb = Bs + buf * BSZ;
#pragma unroll
        for (int ks = 0; ks < 32; ks += 8) {
            uint32_t af[2][4];
#pragma unroll
            for (int mt = 0; mt < 2; mt++) {
                const int mrow = wy * 32 + mt * 16 + gid;
                af[mt][0] = Ab[mrow * APITCH + ks + tig];
                af[mt][1] = Ab[(mrow + 8) * APITCH + ks + tig];
                af[mt][2] = Ab[mrow * APITCH + ks + tig + 4];
                af[mt][3] = Ab[(mrow + 8) * APITCH + ks + tig + 4];
            }
            uint32_t bf[NT][2];
#pragma unroll
            for (int nt = 0; nt < NT; nt++) {
                const int nc = wx * (BN / 2) + nt * 8 + gid;
                bf[nt][0] = Bb[(ks + tig) * BPITCH + nc];
                bf[nt][1] = Bb[(ks + tig + 4) * BPITCH + nc];
            }
#pragma unroll
            for (int mt = 0; mt < 2; mt++)
#pragma unroll
                for (int nt = 0; nt < NT; nt++)
                    mma_tf32(acc[mt][nt], af[mt], bf[nt]);
        }
    }

    float* Csel = (mode == EPI_NONE && blockIdx.z) ? C2 : C;
#pragma unroll
    for (int mt = 0; mt < 2; mt++) {
#pragma unroll
        for (int nt = 0; nt < NT; nt++) {
            const int col = bn + wx * (BN / 2) + nt * 8 + 2 * tig;
            float bv0 = 0.0f, bv1 = 0.0f;
            if (bias) { bv0 = bias[col]; bv1 = bias[col + 1]; }
#pragma unroll
            for (int half = 0; half < 2; half++) {
                const int row = bm + wy * 32 + mt * 16 + gid + half * 8;
                float v0 = acc[mt][nt][half * 2 + 0] + bv0;
                float v1 = acc[mt][nt][half * 2 + 1] + bv1;
                if (mode == EPI_RESID) {
                    v0 += resid[(size_t)row * N + col];
                    v1 += resid[(size_t)row * N + col + 1];
                } else if (mode == EPI_RELU) {
                    v0 = roundtf(fmaxf(v0, 0.0f));
                    v1 = roundtf(fmaxf(v1, 0.0f));
                }
                float2 vv = {v0, v1};
                if (mode == EPI_QKV) {
                    const int b = row >> 9, ii = row & 511;
                    const int which = col >> 9;
                    const int cc = col & 511;
                    const int h = cc >> 6, d = cc & 63;
                    float* base = (which == 0) ? C : (which == 1) ? C2 : C3;
                    *(float2*)(base + (((size_t)(b * CH + h) * CS) + ii) * CD + d) = vv;
                } else {
                    *(float2*)(Csel + (size_t)row * N + col) = vv;
                }
            }
        }
    }
}

#define GEMM_SMEM_BYTES(BN) (GEMM_NSTAGE * (128 * APITCH + 32 * ((BN) + 4)) * 4)

// ---------------- merged round-copy (4 arrays) ----------------------------------
__global__ void round4_kernel(const float4* __restrict__ s0, float4* __restrict__ d0, int n0,
                              const float4* __restrict__ s1, float4* __restrict__ d1, int n1,
                              const float4* __restrict__ s2, float4* __restrict__ d2, int n2,
                              const float4* __restrict__ s3, float4* __restrict__ d3, int n3)
{
    int i = blockIdx.x * 256 + threadIdx.x;
    const float4* s; float4* d;
    if (i < n0) { s = s0 + i; d = d0 + i; }
    else {
        i -= n0;
        if (i < n1) { s = s1 + i; d = d1 + i; }
        else {
            i -= n1;
            if (i < n2) { s = s2 + i; d = d2 + i; }
            else {
                i -= n2;
                if (i >= n3) return;
                s = s3 + i; d = d3 + i;
            }
        }
    }
    float4 v = *s;
    v.x = roundtf(v.x); v.y = roundtf(v.y);
    v.z = roundtf(v.z); v.w = roundtf(v.w);
    *d = v;
}

// ---------------- pack QKV weights/biases (rounded) ----------------------------
__global__ void pack_qkv_kernel(const float* __restrict__ wq, const float* __restrict__ wk,
                                const float* __restrict__ wv, const float* __restrict__ bq,
                                const float* __restrict__ bk, const float* __restrict__ bv)
{
    int idx = blockIdx.x * 256 + threadIdx.x;
    if (idx < CE * CE) {
        int r = idx >> 9, c = idx & 511;
        g_wqkv[(size_t)r * 1536 + c] = roundtf(wq[idx]);
        g_wqkv[(size_t)r * 1536 + 512 + c] = roundtf(wk[idx]);
        g_wqkv[(size_t)r * 1536 + 1024 + c] = roundtf(wv[idx]);
    }
    if (idx < CE) {
        g_bqkv[idx] = bq[idx];
        g_bqkv[512 + idx] = bk[idx];
        g_bqkv[1024 + idx] = bv[idx];
    }
}

// ---------------- pad pos_emb into g_pe ---------------------------------------
__global__ void pe_copy_kernel(const float* __restrict__ pe)
{
    int t = blockIdx.x * 256 + threadIdx.x;
    if (t < CNR * CD) g_pe[t] = pe[t];
}

// ---------------- FULLY FUSED attention: qz+scores+softmax+bins+aw@V+bins@PE ---
#define FS_Q 0
#define FS_K 4224
#define FS_QZ 21632
#define FS_INT 25856
#define FS_RED 26912
#define FS_SMEM_BYTES (27040 * 4)
#define FS_KBUF (128*68)

__global__ __launch_bounds__(256, 2) void fused_attn_kernel(
    const float* __restrict__ dist, const int* __restrict__ dt,
    const int* __restrict__ mask)
{
    extern __shared__ uint32_t sm[];
    uint32_t* Qs = sm + FS_Q;
    float* AW = (float*)(sm + FS_Q);
    uint32_t* Kb = sm + FS_K;
    float* QZs = (float*)(sm + FS_QZ);
    int* dti_s = (int*)(sm + FS_INT);
    int* dtj_s = dti_s + 32;
    int* mj_s = dtj_s + 512;
    float* red = (float*)(sm + FS_RED);

    const int bh = blockIdx.y;
    const int b = bh >> 3, h = bh & 7;
    const int i0 = blockIdx.x << 5;
    const int tid = threadIdx.x;
    const int warp = tid >> 5;
    const int lane = tid & 31;
    const int gid = lane >> 2;
    const int tig = lane & 3;
    const int wm = warp & 1;
    const int wn = warp >> 1;
    const int mrow = wm * 16 + gid;

    const float* qb = g_q + (size_t)bh * CS * CD;
    const float* kb = g_k + (size_t)bh * CS * CD;
    const float* vb = g_v + (size_t)bh * CS * CD;

    const uint32_t q_base = (uint32_t)__cvta_generic_to_shared(Qs);
    const uint32_t k_base = (uint32_t)__cvta_generic_to_shared(Kb);

#pragma unroll
    for (int l = 0; l < 2; l++) {
        const int idx = tid + (l << 8);
        const int r = idx >> 4;
        const int c = (idx & 15) << 2;
        cp16(q_base + (r * 68 + c) * 4, qb + (size_t)(i0 + r) * CD + c);
    }
    for (int t = tid; t < 160 * 16; t += 256) {
        const int r = t >> 4;
        const int c = (t & 15) << 2;
        cp16(k_base + (r * 68 + c) * 4, g_pe + (size_t)r * CD + c);
    }
    cp_commit();

    if (tid < 32) dti_s[tid] = dt[b * CS + i0 + tid];
    {
        int2 dj = *(const int2*)&dt[b * CS + 2 * tid];
        dtj_s[2 * tid] = dj.x; dtj_s[2 * tid + 1] = dj.y;
        int2 mm = *(const int2*)&mask[b * CS + 2 * tid];
        mj_s[2 * tid] = mm.x; mj_s[2 * tid + 1] = mm.y;
    }
    cp_wait<0>();
    __syncthreads();

    {
        float qacc[5][4];
#pragma unroll
        for (int nt = 0; nt < 5; nt++)
#pragma unroll
            for (int r = 0; r < 4; r++) qacc[nt][r] = 0.0f;
#pragma unroll
        for (int ks = 0; ks < 64; ks += 8) {
            uint32_t af[4];
            af[0] = Qs[mrow * 68 + ks + tig];
            af[1] = Qs[(mrow + 8) * 68 + ks + tig];
            af[2] = Qs[mrow * 68 + ks + tig + 4];
            af[3] = Qs[(mrow + 8) * 68 + ks + tig + 4];
#pragma unroll
            for (int nt = 0; nt < 5; nt++) {
                const int nc = wn * 40 + nt * 8 + gid;
                uint32_t bf[2];
                bf[0] = Kb[nc * 68 + ks + tig];
                bf[1] = Kb[nc * 68 + ks + tig + 4];
                mma_tf32(qacc[nt], af, bf);
            }
        }
        __syncthreads();

#pragma unroll
        for (int l = 0; l < 8; l++) {
            const int idx = tid + (l << 8);
            const int r = idx >> 4;
            const int c = (idx & 15) << 2;
            cp16(k_base + (r * 68 + c) * 4, kb + (size_t)r * CD + c);
        }
        cp_commit();

#pragma unroll
        for (int nt = 0; nt < 5; nt++) {
            const int col = wn * 40 + nt * 8 + 2 * tig;
            if (col <= 128) {
                QZs[mrow * 132 + col] = qacc[nt][0];
                QZs[mrow * 132 + col + 1] = qacc[nt][1];
                QZs[(mrow + 8) * 132 + col] = qacc[nt][2];
                QZs[(mrow + 8) * 132 + col + 1] = qacc[nt][3];
            }
        }
    }

    float sacc[4][4][4];
#pragma unroll
    for (int c = 0; c < 4; c++)
#pragma unroll
        for (int nt = 0; nt < 4; nt++)
#pragma unroll
            for (int r = 0; r < 4; r++) sacc[c][nt][r] = 0.0f;

#pragma unroll
    for (int ch = 0; ch < 4; ch++) {
        cp_wait<0>();
        __syncthreads();
        if (ch < 3) {
            const uint32_t kdst = k_base + (((ch + 1) & 1)) * FS_KBUF * 4;
#pragma unroll
            for (int l = 0; l < 8; l++) {
                const int idx = tid + (l << 8);
                const int r = idx >> 4;
                const int c = (idx & 15) << 2;
                cp16(kdst + (r * 68 + c) * 4,
                     kb + (size_t)((ch + 1) * 128 + r) * CD + c);
            }
        }
        cp_commit();

        const uint32_t* Kc = Kb + (ch & 1) * FS_KBUF;
#pragma unroll
        for (int ks = 0; ks < 64; ks += 8) {
            uint32_t af[4];
            af[0] = Qs[mrow * 68 + ks + tig];
            af[1] = Qs[(mrow + 8) * 68 + ks + tig];
            af[2] = Qs[mrow * 68 + ks + tig + 4];
            af[3] = Qs[(mrow + 8) * 68 + ks + tig + 4];
#pragma unroll
            for (int nt = 0; nt < 4; nt++) {
                const int nc = wn * 32 + nt * 8 + gid;
                uint32_t bf[2];
                bf[0] = Kc[nc * 68 + ks + tig];
                bf[1] = Kc[nc * 68 + ks + tig + 4];
                mma_tf32(sacc[ch][nt], af, bf);
            }
        }

#pragma unroll
        for (int half = 0; half < 2; half++) {
            const int il = mrow + half * 8;
            const int i = i0 + il;
            const int di = dti_s[il];
#pragma unroll
            for (int nt = 0; nt < 4; nt++) {
                const int jl = ch * 128 + wn * 32 + nt * 8 + 2 * tig;
                float2 dv = *(const float2*)&dist[((size_t)b * CS + i) * CS + jl];
#pragma unroll
                for (int u = 0; u < 2; u++) {
                    const int j = jl + u;
                    int rel = min(max(dtj_s[j] - di, -CP), CP) + CP;
                    float v = (sacc[ch][nt][half * 2 + u] + QZs[il * 132 + rel]) * 0.125f
                            + 0.6f * (u ? dv.y : dv.x);
                    if (mj_s[j] == 0) v = -1e9f;
                    sacc[ch][nt][half * 2 + u] = v;
                }
            }
        }
    }
    __syncthreads();

    float* bins = QZs;
    for (int t = tid; t < 32 * 132; t += 256) bins[t] = 0.0f;

    float mrow2[2];
#pragma unroll
    for (int half = 0; half < 2; half++) {
        float m = -1e30f;
#pragma unroll
        for (int c = 0; c < 4; c++)
#pragma unroll
            for (int nt = 0; nt < 4; nt++) {
                m = fmaxf(m, sacc[c][nt][half * 2]);
                m = fmaxf(m, sacc[c][nt][half * 2 + 1]);
            }
        m = fmaxf(m, __shfl_xor_sync(0xffffffffu, m, 1));
        m = fmaxf(m, __shfl_xor_sync(0xffffffffu, m, 2));
        mrow2[half] = m;
    }
    if (tig == 0) {
        red[wn * 32 + mrow] = mrow2[0];
        red[wn * 32 + mrow + 8] = mrow2[1];
    }
    __syncthreads();
#pragma unroll
    for (int half = 0; half < 2; half++) {
        const int r = mrow + half * 8;
        mrow2[half] = fmaxf(fmaxf(red[r], red[32 + r]), fmaxf(red[64 + r], red[96 + r]));
    }
    __syncthreads();

    float srow[2] = {0.0f, 0.0f};
#pragma unroll
    for (int half = 0; half < 2; half++) {
#pragma unroll
        for (int c = 0; c < 4; c++)
#pragma unroll
            for (int nt = 0; nt < 4; nt++)
#pragma unroll
                for (int u = 0; u < 2; u++) {
                    float e = __expf(sacc[c][nt][half * 2 + u] - mrow2[half]);
                    sacc[c][nt][half * 2 + u] = e;
                    srow[half] += e;
                }
        srow[half] += __shfl_xor_sync(0xffffffffu, srow[half], 1);
        srow[half] += __shfl_xor_sync(0xffffffffu, srow[half], 2);
    }
    if (tig == 0) {
        red[wn * 32 + mrow] = srow[0];
        red[wn * 32 + mrow + 8] = srow[1];
    }
    __syncthreads();
    float inv2[2];
#pragma unroll
    for (int half = 0; half < 2; half++) {
        const int r = mrow + half * 8;
        inv2[half] = 1.0f / (red[r] + red[32 + r] + red[64 + r] + red[96 + r]);
    }

#pragma unroll
    for (int half = 0; half < 2; half++) {
        const int il = mrow + half * 8;
        const int di = dti_s[il];
#pragma unroll
        for (int c = 0; c < 4; c++)
#pragma unroll
            for (int nt = 0; nt < 4; nt++) {
                const int jl = c * 128 + wn * 32 + nt * 8 + 2 * tig;
                float a0 = sacc[c][nt][half * 2 + 0] * inv2[half];
                float a1 = sacc[c][nt][half * 2 + 1] * inv2[half];
                sacc[c][nt][half * 2 + 0] = a0;
                sacc[c][nt][half * 2 + 1] = a1;
                int r0 = min(max(dtj_s[jl] - di, -CP), CP) + CP;
                int r1 = min(max(dtj_s[jl + 1] - di, -CP), CP) + CP;
                atomicAdd(&bins[il * 132 + r0], a0);
                atomicAdd(&bins[il * 132 + r1], a1);
            }
    }
    __syncthreads();

    float oacc[2][4];
#pragma unroll
    for (int nt = 0; nt < 2; nt++)
#pragma unroll
        for (int r = 0; r < 4; r++) oacc[nt][r] = 0.0f;

#pragma unroll
    for (int l = 0; l < 8; l++) {
        const int idx = tid + (l << 8);
        const int r = idx >> 4;
        const int c = (idx & 15) << 2;
        cp16(k_base + (r * 68 + c) * 4, vb + (size_t)r * CD + c);
    }
    cp_commit();

#pragma unroll
    for (int ch = 0; ch < 4; ch++) {
#pragma unroll
        for (int half = 0; half < 2; half++) {
            const int il = mrow + half * 8;
#pragma unroll
            for (int nt = 0; nt < 4; nt++) {
                const int jloc = wn * 32 + nt * 8 + 2 * tig;
                float2 st = {sacc[ch][nt][half * 2 + 0], sacc[ch][nt][half * 2 + 1]};
                *(float2*)&AW[il * 132 + jloc] = st;
            }
        }
        cp_wait<0>();
        __syncthreads();
        if (ch < 3) {
            const uint32_t vdst = k_base + ((ch + 1) & 1) * FS_KBUF * 4;
#pragma unroll
            for (int l = 0; l < 8; l++) {
                const int idx = tid + (l << 8);
                const int r = idx >> 4;
                const int c = (idx & 15) << 2;
                cp16(vdst + (r * 68 + c) * 4,
                     vb + (size_t)((ch + 1) * 128 + r) * CD + c);
            }
        }
        cp_commit();

        const uint32_t* Vc = Kb + (ch & 1) * FS_KBUF;
        const uint32_t* AWu = (const uint32_t*)AW;
#pragma unroll
        for (int ks = 0; ks < 128; ks += 8) {
            uint32_t af[4];
            af[0] = AWu[mrow * 132 + ks + tig];
            af[1] = AWu[(mrow + 8) * 132 + ks + tig];
            af[2] = AWu[mrow * 132 + ks + tig + 4];
            af[3] = AWu[(mrow + 8) * 132 + ks + tig + 4];
#pragma unroll
            for (int nt = 0; nt < 2; nt++) {
                const int nc = wn * 16 + nt * 8 + gid;
                uint32_t bf[2];
                bf[0] = Vc[(ks + tig) * 68 + nc];
                bf[1] = Vc[(ks + tig + 4) * 68 + nc];
                mma_tf32(oacc[nt], af, bf);
            }
        }
        __syncthreads();
    }

    {
#pragma unroll
        for (int l = 0; l < 4; l++) {
            const int idx = tid + (l << 8);
            const int r = idx >> 4;
            const int c = (idx & 15) << 2;
            cp16(k_base + (r * 68 + c) * 4, g_pe + (size_t)r * CD + c);
        }
        cp_commit();

        const uint32_t* binsu = (const uint32_t*)bins;
#pragma unroll
        for (int pch = 0; pch < 3; pch++) {
            cp_wait<0>();
            __syncthreads();
            if (pch < 2) {
                const uint32_t pdst = k_base + ((pch + 1) & 1) * FS_KBUF * 4;
#pragma unroll
                for (int l = 0; l < 4; l++) {
                    const int idx = tid + (l << 8);
                    const int r = idx >> 4;
                    const int c = (idx & 15) << 2;
                    cp16(pdst + (r * 68 + c) * 4,
                         g_pe + (size_t)((pch + 1) * 64 + r) * CD + c);
                }
            }
            cp_commit();

            const uint32_t* Pc = Kb + (pch & 1) * FS_KBUF;
#pragma unroll
            for (int ks = 0; ks < 64; ks += 8) {
                const int kk = pch * 64 + ks;
                uint32_t af[4];
                af[0] = binsu[mrow * 132 + kk + tig];
                af[1] = binsu[(mrow + 8) * 132 + kk + tig];
                af[2] = binsu[mrow * 132 + kk + tig + 4];
                af[3] = binsu[(mrow + 8) * 132 + kk + tig + 4];
#pragma unroll
                for (int nt = 0; nt < 2; nt++) {
                    const int nc = wn * 16 + nt * 8 + gid;
                    uint32_t bf[2];
                    bf[0] = Pc[(ks + tig) * 68 + nc];
                    bf[1] = Pc[(ks + tig + 4) * 68 + nc];
                    mma_tf32(oacc[nt], af, bf);
                }
            }
        }
    }

#pragma unroll
    for (int nt = 0; nt < 2; nt++) {
        const int col = h * CD + wn * 16 + nt * 8 + 2 * tig;
#pragma unroll
        for (int half = 0; half < 2; half++) {
            const int row = i0 + mrow + half * 8;
            float2 vv = {roundtf(oacc[nt][half * 2 + 0]),
                         roundtf(oacc[nt][half * 2 + 1])};
            *(float2*)&g_concat[(size_t)(b * CS + row) * CE + col] = vv;
        }
    }
}

// ---------------- layernorm: in (+ in2 + addv + resid) -> LN -------------------
__global__ __launch_bounds__(256) void ln_kernel(
    const float* __restrict__ in, const float* __restrict__ in2,
    const float* __restrict__ addv, const float* __restrict__ resid,
    float* __restrict__ out, float* __restrict__ out_r,
    const float* __restrict__ gg, const float* __restrict__ bb)
{
    const int row = blockIdx.x;
    const int tid = threadIdx.x;
    const int lane = tid & 31;
    const int wid = tid >> 5;
    __shared__ float wred[8];
    __shared__ float stat;

    float2 v = *(const float2*)&in[(size_t)row * CE + 2 * tid];
    if (in2) {
        float2 v2 = *(const float2*)&in2[(size_t)row * CE + 2 * tid];
        v.x += v2.x; v.y += v2.y;
    }
    if (addv) {
        float2 av = *(const float2*)&addv[2 * tid];
        v.x += av.x; v.y += av.y;
    }
    if (resid) {
        float2 rv = *(const float2*)&resid[(size_t)row * CE + 2 * tid];
        v.x += rv.x; v.y += rv.y;
    }
    float s = v.x + v.y;
#pragma unroll
    for (int o = 16; o > 0; o >>= 1) s += __shfl_xor_sync(0xffffffffu, s, o);
    if (lane == 0) wred[wid] = s;
    __syncthreads();
    if (tid == 0) {
        float ss = wred[0];
#pragma unroll
        for (int k = 1; k < 8; k++) ss += wred[k];
        stat = ss * (1.0f / CE);
    }
    __syncthreads();
    const float mu = stat;
    const float d0 = v.x - mu, d1 = v.y - mu;
    float q = d0 * d0 + d1 * d1;
#pragma unroll
    for (int o = 16; o > 0; o >>= 1) q += __shfl_xor_sync(0xffffffffu, q, o);
    if (lane == 0) wred[wid] = q;
    __syncthreads();
    if (tid == 0) {
        float qq = wred[0];
#pragma unroll
        for (int k = 1; k < 8; k++) qq += wred[k];
        stat = rsqrtf(qq * (1.0f / CE) + 1e-5f);
    }
    __syncthreads();
    const float rstd = stat;
    float2 gv = *(const float2*)&gg[2 * tid];
    float2 bv = *(const float2*)&bb[2 * tid];
    float2 ov = {d0 * rstd * gv.x + bv.x, d1 * rstd * gv.y + bv.y};
    *(float2*)&out[(size_t)row * CE + 2 * tid] = ov;
    if (out_r) {
        float2 orr = {roundtf(ov.x), roundtf(ov.y)};
        *(float2*)&out_r[(size_t)row * CE + 2 * tid] = orr;
    }
}

// ---------------- launch -------------------------------------------------------
extern "C" void kernel_launch(void* const* d_in, const int* in_sizes, int n_in,
                              void* d_out, int out_size)
{
    const float* x    = (const float*)d_in[0];
    const float* dist = (const float*)d_in[1];
    const int*   dt   = (const int*)d_in[2];
    const int*   mask = (const int*)d_in[3];
    const float* wq_w = (const float*)d_in[4];
    const float* wq_b = (const float*)d_in[5];
    const float* wk_w = (const float*)d_in[6];
    const float* wk_b = (const float*)d_in[7];
    const float* wv_w = (const float*)d_in[8];
    const float* wv_b = (const float*)d_in[9];
    const float* wo_w = (const float*)d_in[10];
    const float* wo_b = (const float*)d_in[11];
    const float* pe   = (const float*)d_in[12];
    const float* w1   = (const float*)d_in[13];
    const float* b1   = (const float*)d_in[14];
    const float* w2   = (const float*)d_in[15];
    const float* b2   = (const float*)d_in[16];
    const float* ln1g = (const float*)d_in[17];
    const float* ln1b = (const float*)d_in[18];
    const float* ln2g = (const float*)d_in[19];
    const float* ln2b = (const float*)d_in[20];
    float* out = (float*)d_out;

    void *pq, *pk, *pv, *pcc, *pt1, *pao, *paor, *phid, *pt2, *pt2b, *pwqkv, *pbqkv;
    void *pxr, *pwor, *pw1r, *pw2r;
    cudaGetSymbolAddress(&pq, g_q);
    cudaGetSymbolAddress(&pk, g_k);
    cudaGetSymbolAddress(&pv, g_v);
    cudaGetSymbolAddress(&pcc, g_concat);
    cudaGetSymbolAddress(&pt1, g_t1);
    cudaGetSymbolAddress(&pao, g_attnout);
    cudaGetSymbolAddress(&paor, g_attnout_r);
    cudaGetSymbolAddress(&phid, g_hidden);
    cudaGetSymbolAddress(&pt2, g_t2);
    cudaGetSymbolAddress(&pt2b, g_t2b);
    cudaGetSymbolAddress(&pwqkv, g_wqkv);
    cudaGetSymbolAddress(&pbqkv, g_bqkv);
    cudaGetSymbolAddress(&pxr, g_xr);
    cudaGetSymbolAddress(&pwor, g_wor);
    cudaGetSymbolAddress(&pw1r, g_w1r);
    cudaGetSymbolAddress(&pw2r, g_w2r);

    cudaFuncSetAttribute(fused_attn_kernel,
                         cudaFuncAttributeMaxDynamicSharedMemorySize, FS_SMEM_BYTES);
    cudaFuncSetAttribute(mma_gemm_kernel<128>,
                         cudaFuncAttributeMaxDynamicSharedMemorySize, GEMM_SMEM_BYTES(128));
    cudaFuncSetAttribute(mma_gemm_kernel<96>,
                         cudaFuncAttributeMaxDynamicSharedMemorySize, GEMM_SMEM_BYTES(96));
    cudaFuncSetAttribute(mma_gemm_kernel<64>,
                         cudaFuncAttributeMaxDynamicSharedMemorySize, GEMM_SMEM_BYTES(64));

    pe_copy_kernel<<<(CNR * CD + 255) / 256, 256>>>(pe);
    pack_qkv_kernel<<<(CE * CE + 255) / 256, 256>>>(wq_w, wk_w, wv_w, wq_b, wk_b, wv_b);
    {
        const int n0 = CM * CE / 4, n1 = CE * CE / 4, n2 = CE * CF / 4, n3 = CF * CE / 4;
        const int ntot = n0 + n1 + n2 + n3;
        round4_kernel<<<(ntot + 255) / 256, 256>>>(
            (const float4*)x, (float4*)pxr, n0,
            (const float4*)wo_w, (float4*)pwor, n1,
            (const float4*)w1, (float4*)pw1r, n2,
            (const float4*)w2, (float4*)pw2r, n3);
    }

    // fused QKV: M=4096, N=1536, K=512 (BN=96: 512 tiles, better wave fill)
    dim3 gq(1536 / 96, CM / 128);
    mma_gemm_kernel<96><<<gq, 256, GEMM_SMEM_BYTES(96)>>>(
        (const float*)pxr, (const float*)pwqkv, (float*)pq, (float*)pk, (float*)pv,
        CM, 1536, CE, CE, (const float*)pbqkv, nullptr, EPI_QKV);

    // fully fused attention -> g_concat
    dim3 gfs(CS / 32, CBH);
    fused_attn_kernel<<<gfs, 256, FS_SMEM_BYTES>>>(dist, dt, mask);

    dim3 gwo(CE / 64, CM / 128);
    mma_gemm_kernel<64><<<gwo, 256, GEMM_SMEM_BYTES(64)>>>(
        (const float*)pcc, (const float*)pwor, (float*)pt1, nullptr, nullptr,
        CM, CE, CE, CE, wo_b, x, EPI_RESID);
    ln_kernel<<<CM, 256>>>((const float*)pt1, nullptr, nullptr, nullptr,
                           (float*)pao, (float*)paor, ln1g, ln1b);

    dim3 gf1(CF / 128, CM / 128);
    mma_gemm_kernel<128><<<gf1, 256, GEMM_SMEM_BYTES(128)>>>(
        (const float*)paor, (const float*)pw1r, (float*)phid, nullptr, nullptr,
        CM, CF, CE, CE, b1, nullptr, EPI_RELU);

    // FFN2 split-K=2, BN=128: grid (4, 32, 2), partials -> t2 / t2b
    dim3 gf2(CE / 128, CM / 128, 2);
    mma_gemm_kernel<128><<<gf2, 256, GEMM_SMEM_BYTES(128)>>>(
        (const float*)phid, (const float*)pw2r, (float*)pt2, (float*)pt2b, nullptr,
        CM, CE, CF / 2, CF, nullptr, nullptr, EPI_NONE);

    // ln2 fuses partial reduce + bias + residual
    ln_kernel<<<CM, 256>>>((const float*)pt2, (const float*)pt2b, b2, (const float*)pao,
                           out, nullptr, ln2g, ln2b);
}

// round 14
// speedup vs baseline: 2.5904x; 1.0343x over previous
#include <cuda_runtime.h>
#include <cstdint>
#include <cstddef>

// Problem constants
#define CB 8
#define CS 512
#define CE 512
#define CH 8
#define CD 64
#define CP 64
#define CF 2048
#define CNR 129            // 2P+1
#define CSR 192            // padded rows for pos_emb
#define CBH (CB*CH)        // 64
#define CM (CB*CS)         // 4096

// ---------------- device scratch (zero-initialized .bss) ----------------------
__device__ __align__(16) float g_q[CBH*CS*CD];
__device__ __align__(16) float g_k[CBH*CS*CD];
__device__ __align__(16) float g_v[CBH*CS*CD];
__device__ __align__(16) float g_pe[CSR*CD];            // padded pos_emb (rows >=129 zero)
__device__ __align__(16) float g_concat[CM*CE];         // rounded at write
__device__ __align__(16) float g_t1[CM*CE];
__device__ __align__(16) float g_attnout[CM*CE];        // fp32 (resid)
__device__ __align__(16) float g_attnout_r[CM*CE];      // RN-rounded (FFN1 A)
__device__ __align__(16) float g_hidden[CM*CF];         // rounded at write
__device__ __align__(16) float g_t2[CM*CE];             // split-K partial 0
__device__ __align__(16) float g_t2b[CM*CE];            // split-K partial 1
__device__ __align__(16) float g_wqkv[CE*3*CE];         // packed+rounded [512][1536]
__device__ __align__(16) float g_bqkv[3*CE];
__device__ __align__(16) float g_xr[CM*CE];             // rounded x
__device__ __align__(16) float g_wor[CE*CE];            // rounded wo
__device__ __align__(16) float g_w1r[CE*CF];            // rounded w1
__device__ __align__(16) float g_w2r[CF*CE];            // rounded w2

enum { EPI_QKV = 0, EPI_RESID = 1, EPI_RELU = 2, EPI_NONE = 3 };

__device__ __forceinline__ uint32_t f2tf(float f) {
    uint32_t u;
    asm("cvt.rna.tf32.f32 %0, %1;" : "=r"(u) : "f"(f));
    return u;
}
__device__ __forceinline__ float roundtf(float f) {
    return __uint_as_float(f2tf(f));
}

__device__ __forceinline__ void mma_tf32(float c[4], const uint32_t a[4],
                                         const uint32_t b[2]) {
    asm volatile(
        "mma.sync.aligned.m16n8k8.row.col.f32.tf32.tf32.f32 "
        "{%0,%1,%2,%3}, {%4,%5,%6,%7}, {%8,%9}, {%0,%1,%2,%3};\n"
        : "+f"(c[0]), "+f"(c[1]), "+f"(c[2]), "+f"(c[3])
        : "r"(a[0]), "r"(a[1]), "r"(a[2]), "r"(a[3]), "r"(b[0]), "r"(b[1]));
}

__device__ __forceinline__ void cp16(uint32_t dst, const void* src) {
    asm volatile("cp.async.cg.shared.global [%0], [%1], 16;\n" :: "r"(dst), "l"(src));
}
__device__ __forceinline__ void cp_commit() {
    asm volatile("cp.async.commit_group;\n");
}
template<int N>
__device__ __forceinline__ void cp_wait() {
    asm volatile("cp.async.wait_group %0;\n" :: "n"(N));
}

// ---------------- TF32 tensor-core GEMM (cp.async 3-stage, BK=32) -------------
// supports split-K via gridDim.z (EPI_NONE writes partial to C / C2 by z)
#define APITCH 36
#define GEMM_NSTAGE 3

template<int BN>
__global__ __launch_bounds__(256, 2) void mma_gemm_kernel(
    const float* __restrict__ A, const float* __restrict__ Bm,
    float* __restrict__ C, float* __restrict__ C2, float* __restrict__ C3,
    int M, int N, int K, int Kstride,
    const float* __restrict__ bias, const float* __restrict__ resid, int mode)
{
    constexpr int BPITCH = BN + 4;
    constexpr int NT = BN / 16;
    constexpr int ASZ = 128 * APITCH;
    constexpr int BSZ = 32 * BPITCH;
    constexpr int CPR = BN / 4;
    constexpr int NBL = CPR / 8;
    extern __shared__ uint32_t smem_u[];
    uint32_t* As = smem_u;
    uint32_t* Bs = smem_u + GEMM_NSTAGE * ASZ;

    const int tid = threadIdx.x;
    const int warp = tid >> 5;
    const int lane = tid & 31;
    const int gid = lane >> 2;
    const int tig = lane & 3;
    const int wy = warp >> 1;
    const int wx = warp & 1;
    const int bm = blockIdx.y * 128;
    const int bn = blockIdx.x * BN;
    const int koff = blockIdx.z * K;

    const uint32_t a_base = (uint32_t)__cvta_generic_to_shared(As);
    const uint32_t b_base = (uint32_t)__cvta_generic_to_shared(Bs);

    const int nk = K >> 5;

    auto stageg = [&](int s) {
        const int bs = s % GEMM_NSTAGE;
        const uint32_t adst = a_base + bs * ASZ * 4;
        const uint32_t bdst = b_base + bs * BSZ * 4;
#pragma unroll
        for (int l = 0; l < 4; l++) {
            const int idx = tid + (l << 8);
            const int r = idx >> 3;
            const int c = (idx & 7) << 2;
            cp16(adst + (r * APITCH + c) * 4,
                 A + (size_t)(bm + r) * Kstride + koff + (s << 5) + c);
        }
#pragma unroll
        for (int l = 0; l < NBL; l++) {
            const int idx = tid + (l << 8);
            const int r = idx / CPR;
            const int c = (idx % CPR) << 2;
            cp16(bdst + (r * BPITCH + c) * 4,
                 Bm + (size_t)(koff + (s << 5) + r) * N + bn + c);
        }
    };

    float acc[2][NT][4];
#pragma unroll
    for (int mt = 0; mt < 2; mt++)
#pragma unroll
        for (int nt = 0; nt < NT; nt++)
#pragma unroll
            for (int r = 0; r < 4; r++) acc[mt][nt][r] = 0.0f;

#pragma unroll
    for (int s = 0; s < GEMM_NSTAGE - 1; s++) {
        if (s < nk) stageg(s);
        cp_commit();
    }

    for (int i = 0; i < nk; i++) {
        cp_wait<1>();
        __syncthreads();
        if (i + 2 < nk) stageg(i + 2);
        cp_commit();

        const int buf = i % GEMM_NSTAGE;
        const uint32_t* Ab = As + buf * ASZ;
        const uint32_t* Bb = Bs + buf * BSZ;
#pragma unroll
        for (int ks = 0; ks < 32; ks += 8) {
            uint32_t af[2][4];
#pragma unroll
            for (int mt = 0; mt < 2; mt++) {
                const int mrow = wy * 32 + mt * 16 + gid;
                af[mt][0] = Ab[mrow * APITCH + ks + tig];
                af[mt][1] = Ab[(mrow + 8) * APITCH + ks + tig];
                af[mt][2] = Ab[mrow * APITCH + ks + tig + 4];
                af[mt][3] = Ab[(mrow + 8) * APITCH + ks + tig + 4];
            }
            uint32_t bf[NT][2];
#pragma unroll
            for (int nt = 0; nt < NT; nt++) {
                const int nc = wx * (BN / 2) + nt * 8 + gid;
                bf[nt][0] = Bb[(ks + tig) * BPITCH + nc];
                bf[nt][1] = Bb[(ks + tig + 4) * BPITCH + nc];
            }
#pragma unroll
            for (int mt = 0; mt < 2; mt++)
#pragma unroll
                for (int nt = 0; nt < NT; nt++)
                    mma_tf32(acc[mt][nt], af[mt], bf[nt]);
        }
    }

    float* Csel = (mode == EPI_NONE && blockIdx.z) ? C2 : C;
#pragma unroll
    for (int mt = 0; mt < 2; mt++) {
#pragma unroll
        for (int nt = 0; nt < NT; nt++) {
            const int col = bn + wx * (BN / 2) + nt * 8 + 2 * tig;
            float bv0 = 0.0f, bv1 = 0.0f;
            if (bias) { bv0 = bias[col]; bv1 = bias[col + 1]; }
#pragma unroll
            for (int half = 0; half < 2; half++) {
                const int row = bm + wy * 32 + mt * 16 + gid + half * 8;
                float v0 = acc[mt][nt][half * 2 + 0] + bv0;
                float v1 = acc[mt][nt][half * 2 + 1] + bv1;
                if (mode == EPI_RESID) {
                    v0 += resid[(size_t)row * N + col];
                    v1 += resid[(size_t)row * N + col + 1];
                } else if (mode == EPI_RELU) {
                    v0 = roundtf(fmaxf(v0, 0.0f));
                    v1 = roundtf(fmaxf(v1, 0.0f));
                }
                float2 vv = {v0, v1};
                if (mode == EPI_QKV) {
                    const int b = row >> 9, ii = row & 511;
                    const int which = col >> 9;
                    const int cc = col & 511;
                    const int h = cc >> 6, d = cc & 63;
                    float* base = (which == 0) ? C : (which == 1) ? C2 : C3;
                    *(float2*)(base + (((size_t)(b * CH + h) * CS) + ii) * CD + d) = vv;
                } else {
                    *(float2*)(Csel + (size_t)row * N + col) = vv;
                }
            }
        }
    }
}

#define GEMM_SMEM_BYTES(BN) (GEMM_NSTAGE * (128 * APITCH + 32 * ((BN) + 4)) * 4)

// ---------------- merged round-copy (4 arrays) ----------------------------------
__global__ void round4_kernel(const float4* __restrict__ s0, float4* __restrict__ d0, int n0,
                              const float4* __restrict__ s1, float4* __restrict__ d1, int n1,
                              const float4* __restrict__ s2, float4* __restrict__ d2, int n2,
                              const float4* __restrict__ s3, float4* __restrict__ d3, int n3)
{
    int i = blockIdx.x * 256 + threadIdx.x;
    const float4* s; float4* d;
    if (i < n0) { s = s0 + i; d = d0 + i; }
    else {
        i -= n0;
        if (i < n1) { s = s1 + i; d = d1 + i; }
        else {
            i -= n1;
            if (i < n2) { s = s2 + i; d = d2 + i; }
            else {
                i -= n2;
                if (i >= n3) return;
                s = s3 + i; d = d3 + i;
            }
        }
    }
    float4 v = *s;
    v.x = roundtf(v.x); v.y = roundtf(v.y);
    v.z = roundtf(v.z); v.w = roundtf(v.w);
    *d = v;
}

// ---------------- pack QKV weights/biases (rounded) ----------------------------
__global__ void pack_qkv_kernel(const float* __restrict__ wq, const float* __restrict__ wk,
                                const float* __restrict__ wv, const float* __restrict__ bq,
                                const float* __restrict__ bk, const float* __restrict__ bv)
{
    int idx = blockIdx.x * 256 + threadIdx.x;
    if (idx < CE * CE) {
        int r = idx >> 9, c = idx & 511;
        g_wqkv[(size_t)r * 1536 + c] = roundtf(wq[idx]);
        g_wqkv[(size_t)r * 1536 + 512 + c] = roundtf(wk[idx]);
        g_wqkv[(size_t)r * 1536 + 1024 + c] = roundtf(wv[idx]);
    }
    if (idx < CE) {
        g_bqkv[idx] = bq[idx];
        g_bqkv[512 + idx] = bk[idx];
        g_bqkv[1024 + idx] = bv[idx];
    }
}

// ---------------- pad pos_emb into g_pe ---------------------------------------
__global__ void pe_copy_kernel(const float* __restrict__ pe)
{
    int t = blockIdx.x * 256 + threadIdx.x;
    if (t < CNR * CD) g_pe[t] = pe[t];
}

// ---------------- FULLY FUSED attention ----------------------------------------
#define FS_Q 0
#define FS_K 4224
#define FS_QZ 21632
#define FS_INT 25856
#define FS_RED 26912
#define FS_SMEM_BYTES (27040 * 4)
#define FS_KBUF (128*68)

__global__ __launch_bounds__(256, 2) void fused_attn_kernel(
    const float* __restrict__ dist, const int* __restrict__ dt,
    const int* __restrict__ mask)
{
    extern __shared__ uint32_t sm[];
    uint32_t* Qs = sm + FS_Q;
    float* AW = (float*)(sm + FS_Q);
    uint32_t* Kb = sm + FS_K;
    float* QZs = (float*)(sm + FS_QZ);
    int* dti_s = (int*)(sm + FS_INT);
    int* dtj_s = dti_s + 32;
    int* mj_s = dtj_s + 512;
    float* red = (float*)(sm + FS_RED);

    const int bh = blockIdx.y;
    const int b = bh >> 3, h = bh & 7;
    const int i0 = blockIdx.x << 5;
    const int tid = threadIdx.x;
    const int warp = tid >> 5;
    const int lane = tid & 31;
    const int gid = lane >> 2;
    const int tig = lane & 3;
    const int wm = warp & 1;
    const int wn = warp >> 1;
    const int mrow = wm * 16 + gid;

    const float* qb = g_q + (size_t)bh * CS * CD;
    const float* kb = g_k + (size_t)bh * CS * CD;
    const float* vb = g_v + (size_t)bh * CS * CD;

    const uint32_t q_base = (uint32_t)__cvta_generic_to_shared(Qs);
    const uint32_t k_base = (uint32_t)__cvta_generic_to_shared(Kb);

#pragma unroll
    for (int l = 0; l < 2; l++) {
        const int idx = tid + (l << 8);
        const int r = idx >> 4;
        const int c = (idx & 15) << 2;
        cp16(q_base + (r * 68 + c) * 4, qb + (size_t)(i0 + r) * CD + c);
    }
    for (int t = tid; t < 160 * 16; t += 256) {
        const int r = t >> 4;
        const int c = (t & 15) << 2;
        cp16(k_base + (r * 68 + c) * 4, g_pe + (size_t)r * CD + c);
    }
    cp_commit();

    if (tid < 32) dti_s[tid] = dt[b * CS + i0 + tid];
    {
        int2 dj = *(const int2*)&dt[b * CS + 2 * tid];
        dtj_s[2 * tid] = dj.x; dtj_s[2 * tid + 1] = dj.y;
        int2 mm = *(const int2*)&mask[b * CS + 2 * tid];
        mj_s[2 * tid] = mm.x; mj_s[2 * tid + 1] = mm.y;
    }
    cp_wait<0>();
    __syncthreads();

    // ---- phase 1: qz
    {
        float qacc[5][4];
#pragma unroll
        for (int nt = 0; nt < 5; nt++)
#pragma unroll
            for (int r = 0; r < 4; r++) qacc[nt][r] = 0.0f;
#pragma unroll
        for (int ks = 0; ks < 64; ks += 8) {
            uint32_t af[4];
            af[0] = Qs[mrow * 68 + ks + tig];
            af[1] = Qs[(mrow + 8) * 68 + ks + tig];
            af[2] = Qs[mrow * 68 + ks + tig + 4];
            af[3] = Qs[(mrow + 8) * 68 + ks + tig + 4];
#pragma unroll
            for (int nt = 0; nt < 5; nt++) {
                const int nc = wn * 40 + nt * 8 + gid;
                uint32_t bf[2];
                bf[0] = Kb[nc * 68 + ks + tig];
                bf[1] = Kb[nc * 68 + ks + tig + 4];
                mma_tf32(qacc[nt], af, bf);
            }
        }
        __syncthreads();

#pragma unroll
        for (int l = 0; l < 8; l++) {
            const int idx = tid + (l << 8);
            const int r = idx >> 4;
            const int c = (idx & 15) << 2;
            cp16(k_base + (r * 68 + c) * 4, kb + (size_t)r * CD + c);
        }
        cp_commit();

#pragma unroll
        for (int nt = 0; nt < 5; nt++) {
            const int col = wn * 40 + nt * 8 + 2 * tig;
            if (col <= 128) {
                QZs[mrow * 132 + col] = qacc[nt][0];
                QZs[mrow * 132 + col + 1] = qacc[nt][1];
                QZs[(mrow + 8) * 132 + col] = qacc[nt][2];
                QZs[(mrow + 8) * 132 + col + 1] = qacc[nt][3];
            }
        }
    }

    // ---- phase 2: scores
    float sacc[4][4][4];
#pragma unroll
    for (int c = 0; c < 4; c++)
#pragma unroll
        for (int nt = 0; nt < 4; nt++)
#pragma unroll
            for (int r = 0; r < 4; r++) sacc[c][nt][r] = 0.0f;

#pragma unroll
    for (int ch = 0; ch < 4; ch++) {
        cp_wait<0>();
        __syncthreads();
        if (ch < 3) {
            const uint32_t kdst = k_base + (((ch + 1) & 1)) * FS_KBUF * 4;
#pragma unroll
            for (int l = 0; l < 8; l++) {
                const int idx = tid + (l << 8);
                const int r = idx >> 4;
                const int c = (idx & 15) << 2;
                cp16(kdst + (r * 68 + c) * 4,
                     kb + (size_t)((ch + 1) * 128 + r) * CD + c);
            }
        }
        cp_commit();

        const uint32_t* Kc = Kb + (ch & 1) * FS_KBUF;
#pragma unroll
        for (int ks = 0; ks < 64; ks += 8) {
            uint32_t af[4];
            af[0] = Qs[mrow * 68 + ks + tig];
            af[1] = Qs[(mrow + 8) * 68 + ks + tig];
            af[2] = Qs[mrow * 68 + ks + tig + 4];
            af[3] = Qs[(mrow + 8) * 68 + ks + tig + 4];
#pragma unroll
            for (int nt = 0; nt < 4; nt++) {
                const int nc = wn * 32 + nt * 8 + gid;
                uint32_t bf[2];
                bf[0] = Kc[nc * 68 + ks + tig];
                bf[1] = Kc[nc * 68 + ks + tig + 4];
                mma_tf32(sacc[ch][nt], af, bf);
            }
        }

#pragma unroll
        for (int half = 0; half < 2; half++) {
            const int il = mrow + half * 8;
            const int i = i0 + il;
            const int di = dti_s[il];
#pragma unroll
            for (int nt = 0; nt < 4; nt++) {
                const int jl = ch * 128 + wn * 32 + nt * 8 + 2 * tig;
                float2 dv = *(const float2*)&dist[((size_t)b * CS + i) * CS + jl];
#pragma unroll
                for (int u = 0; u < 2; u++) {
                    const int j = jl + u;
                    int rel = min(max(dtj_s[j] - di, -CP), CP) + CP;
                    float v = (sacc[ch][nt][half * 2 + u] + QZs[il * 132 + rel]) * 0.125f
                            + 0.6f * (u ? dv.y : dv.x);
                    if (mj_s[j] == 0) v = -1e9f;
                    sacc[ch][nt][half * 2 + u] = v;
                }
            }
        }
    }
    __syncthreads();

    // ---- phase 3: softmax + bins
    float* bins = QZs;
    for (int t = tid; t < 32 * 132; t += 256) bins[t] = 0.0f;

    float mrw[2];
#pragma unroll
    for (int half = 0; half < 2; half++) {
        float m = -1e30f;
#pragma unroll
        for (int c = 0; c < 4; c++)
#pragma unroll
            for (int nt = 0; nt < 4; nt++) {
                m = fmaxf(m, sacc[c][nt][half * 2]);
                m = fmaxf(m, sacc[c][nt][half * 2 + 1]);
            }
        m = fmaxf(m, __shfl_xor_sync(0xffffffffu, m, 1));
        m = fmaxf(m, __shfl_xor_sync(0xffffffffu, m, 2));
        mrw[half] = m;
    }
    if (tig == 0) {
        red[wn * 32 + mrow] = mrw[0];
        red[wn * 32 + mrow + 8] = mrw[1];
    }
    __syncthreads();
#pragma unroll
    for (int half = 0; half < 2; half++) {
        const int r = mrow + half * 8;
        mrw[half] = fmaxf(fmaxf(red[r], red[32 + r]), fmaxf(red[64 + r], red[96 + r]));
    }
    __syncthreads();

    float srow[2] = {0.0f, 0.0f};
#pragma unroll
    for (int half = 0; half < 2; half++) {
#pragma unroll
        for (int c = 0; c < 4; c++)
#pragma unroll
            for (int nt = 0; nt < 4; nt++)
#pragma unroll
                for (int u = 0; u < 2; u++) {
                    float e = __expf(sacc[c][nt][half * 2 + u] - mrw[half]);
                    sacc[c][nt][half * 2 + u] = e;
                    srow[half] += e;
                }
        srow[half] += __shfl_xor_sync(0xffffffffu, srow[half], 1);
        srow[half] += __shfl_xor_sync(0xffffffffu, srow[half], 2);
    }
    if (tig == 0) {
        red[wn * 32 + mrow] = srow[0];
        red[wn * 32 + mrow + 8] = srow[1];
    }
    __syncthreads();
    float inv2[2];
#pragma unroll
    for (int half = 0; half < 2; half++) {
        const int r = mrow + half * 8;
        inv2[half] = 1.0f / (red[r] + red[32 + r] + red[64 + r] + red[96 + r]);
    }

#pragma unroll
    for (int half = 0; half < 2; half++) {
        const int il = mrow + half * 8;
        const int di = dti_s[il];
#pragma unroll
        for (int c = 0; c < 4; c++)
#pragma unroll
            for (int nt = 0; nt < 4; nt++) {
                const int jl = c * 128 + wn * 32 + nt * 8 + 2 * tig;
                float a0 = sacc[c][nt][half * 2 + 0] * inv2[half];
                float a1 = sacc[c][nt][half * 2 + 1] * inv2[half];
                sacc[c][nt][half * 2 + 0] = a0;
                sacc[c][nt][half * 2 + 1] = a1;
                int r0 = min(max(dtj_s[jl] - di, -CP), CP) + CP;
                int r1 = min(max(dtj_s[jl + 1] - di, -CP), CP) + CP;
                atomicAdd(&bins[il * 132 + r0], a0);
                atomicAdd(&bins[il * 132 + r1], a1);
            }
    }
    __syncthreads();

    // ---- phase 5: out = aw @ V + bins @ PE (2-way k-split across warp halves)
    const int wk = warp >> 2;        // k-half
    const int wq = warp & 3;
    const int wm2 = wq >> 1;         // m-half
    const int wn2 = wq & 1;          // n-half
    const int mrow2 = wm2 * 16 + gid;

    float oacc[4][4];
#pragma unroll
    for (int nt = 0; nt < 4; nt++)
#pragma unroll
        for (int r = 0; r < 4; r++) oacc[nt][r] = 0.0f;

#pragma unroll
    for (int l = 0; l < 8; l++) {
        const int idx = tid + (l << 8);
        const int r = idx >> 4;
        const int c = (idx & 15) << 2;
        cp16(k_base + (r * 68 + c) * 4, vb + (size_t)r * CD + c);
    }
    cp_commit();

#pragma unroll
    for (int ch = 0; ch < 4; ch++) {
        // stage aw chunk into AW (original wm/wn mapping)
#pragma unroll
        for (int half = 0; half < 2; half++) {
            const int il = mrow + half * 8;
#pragma unroll
            for (int nt = 0; nt < 4; nt++) {
                const int jloc = wn * 32 + nt * 8 + 2 * tig;
                float2 st = {sacc[ch][nt][half * 2 + 0], sacc[ch][nt][half * 2 + 1]};
                *(float2*)&AW[il * 132 + jloc] = st;
            }
        }
        cp_wait<0>();
        __syncthreads();
        if (ch < 3) {
            const uint32_t vdst = k_base + ((ch + 1) & 1) * FS_KBUF * 4;
#pragma unroll
            for (int l = 0; l < 8; l++) {
                const int idx = tid + (l << 8);
                const int r = idx >> 4;
                const int c = (idx & 15) << 2;
                cp16(vdst + (r * 68 + c) * 4,
                     vb + (size_t)((ch + 1) * 128 + r) * CD + c);
            }
        }
        cp_commit();

        const uint32_t* Vc = Kb + (ch & 1) * FS_KBUF;
        const uint32_t* AWu = (const uint32_t*)AW;
#pragma unroll
        for (int ks = 0; ks < 64; ks += 8) {
            const int kk = wk * 64 + ks;
            uint32_t af[4];
            af[0] = AWu[mrow2 * 132 + kk + tig];
            af[1] = AWu[(mrow2 + 8) * 132 + kk + tig];
            af[2] = AWu[mrow2 * 132 + kk + tig + 4];
            af[3] = AWu[(mrow2 + 8) * 132 + kk + tig + 4];
#pragma unroll
            for (int nt = 0; nt < 4; nt++) {
                const int nc = wn2 * 32 + nt * 8 + gid;
                uint32_t bf[2];
                bf[0] = Vc[(kk + tig) * 68 + nc];
                bf[1] = Vc[(kk + tig + 4) * 68 + nc];
                mma_tf32(oacc[nt], af, bf);
            }
        }
        __syncthreads();
    }

    // PE part (k-split: each warp-half does 32 of each 64-chunk)
    {
#pragma unroll
        for (int l = 0; l < 4; l++) {
            const int idx = tid + (l << 8);
            const int r = idx >> 4;
            const int c = (idx & 15) << 2;
            cp16(k_base + (r * 68 + c) * 4, g_pe + (size_t)r * CD + c);
        }
        cp_commit();

        const uint32_t* binsu = (const uint32_t*)bins;
#pragma unroll
        for (int pch = 0; pch < 3; pch++) {
            cp_wait<0>();
            __syncthreads();
            if (pch < 2) {
                const uint32_t pdst = k_base + ((pch + 1) & 1) * FS_KBUF * 4;
#pragma unroll
                for (int l = 0; l < 4; l++) {
                    const int idx = tid + (l << 8);
                    const int r = idx >> 4;
                    const int c = (idx & 15) << 2;
                    cp16(pdst + (r * 68 + c) * 4,
                         g_pe + (size_t)((pch + 1) * 64 + r) * CD + c);
                }
            }
            cp_commit();

            const uint32_t* Pc = Kb + (pch & 1) * FS_KBUF;
#pragma unroll
            for (int ks = 0; ks < 32; ks += 8) {
                const int kl = wk * 32 + ks;          // within 64-chunk
                const int kk = pch * 64 + kl;         // bins k index
                uint32_t af[4];
                af[0] = binsu[mrow2 * 132 + kk + tig];
                af[1] = binsu[(mrow2 + 8) * 132 + kk + tig];
                af[2] = binsu[mrow2 * 132 + kk + tig + 4];
                af[3] = binsu[(mrow2 + 8) * 132 + kk + tig + 4];
#pragma unroll
                for (int nt = 0; nt < 4; nt++) {
                    const int nc = wn2 * 32 + nt * 8 + gid;
                    uint32_t bf[2];
                    bf[0] = Pc[(kl + tig) * 68 + nc];
                    bf[1] = Pc[(kl + tig + 4) * 68 + nc];
                    mma_tf32(oacc[nt], af, bf);
                }
            }
        }
    }
    __syncthreads();   // AW/bins reads done

    // cross-k reduction via AW region, then epilogue from wk=0 warps
    float* redk = AW;   // 2048 floats needed, 4224 available
    if (wk == 1) {
#pragma unroll
        for (int nt = 0; nt < 4; nt++) {
            float4 p = {oacc[nt][0], oacc[nt][1], oacc[nt][2], oacc[nt][3]};
            *(float4*)&redk[(wq * 4 + nt) * 128 + lane * 4] = p;
        }
    }
    __syncthreads();
    if (wk == 0) {
#pragma unroll
        for (int nt = 0; nt < 4; nt++) {
            float4 p = *(const float4*)&redk[(wq * 4 + nt) * 128 + lane * 4];
            oacc[nt][0] += p.x; oacc[nt][1] += p.y;
            oacc[nt][2] += p.z; oacc[nt][3] += p.w;
        }
#pragma unroll
        for (int nt = 0; nt < 4; nt++) {
            const int col = h * CD + wn2 * 32 + nt * 8 + 2 * tig;
#pragma unroll
            for (int half = 0; half < 2; half++) {
                const int row = i0 + mrow2 + half * 8;
                float2 vv = {roundtf(oacc[nt][half * 2 + 0]),
                             roundtf(oacc[nt][half * 2 + 1])};
                *(float2*)&g_concat[(size_t)(b * CS + row) * CE + col] = vv;
            }
        }
    }
}

// ---------------- layernorm: in (+ in2 + addv + resid) -> LN -------------------
__global__ __launch_bounds__(256) void ln_kernel(
    const float* __restrict__ in, const float* __restrict__ in2,
    const float* __restrict__ addv, const float* __restrict__ resid,
    float* __restrict__ out, float* __restrict__ out_r,
    const float* __restrict__ gg, const float* __restrict__ bb)
{
    const int row = blockIdx.x;
    const int tid = threadIdx.x;
    const int lane = tid & 31;
    const int wid = tid >> 5;
    __shared__ float wred[8];
    __shared__ float stat;

    float2 v = *(const float2*)&in[(size_t)row * CE + 2 * tid];
    if (in2) {
        float2 v2 = *(const float2*)&in2[(size_t)row * CE + 2 * tid];
        v.x += v2.x; v.y += v2.y;
    }
    if (addv) {
        float2 av = *(const float2*)&addv[2 * tid];
        v.x += av.x; v.y += av.y;
    }
    if (resid) {
        float2 rv = *(const float2*)&resid[(size_t)row * CE + 2 * tid];
        v.x += rv.x; v.y += rv.y;
    }
    float s = v.x + v.y;
#pragma unroll
    for (int o = 16; o > 0; o >>= 1) s += __shfl_xor_sync(0xffffffffu, s, o);
    if (lane == 0) wred[wid] = s;
    __syncthreads();
    if (tid == 0) {
        float ss = wred[0];
#pragma unroll
        for (int k = 1; k < 8; k++) ss += wred[k];
        stat = ss * (1.0f / CE);
    }
    __syncthreads();
    const float mu = stat;
    const float d0 = v.x - mu, d1 = v.y - mu;
    float q = d0 * d0 + d1 * d1;
#pragma unroll
    for (int o = 16; o > 0; o >>= 1) q += __shfl_xor_sync(0xffffffffu, q, o);
    if (lane == 0) wred[wid] = q;
    __syncthreads();
    if (tid == 0) {
        float qq = wred[0];
#pragma unroll
        for (int k = 1; k < 8; k++) qq += wred[k];
        stat = rsqrtf(qq * (1.0f / CE) + 1e-5f);
    }
    __syncthreads();
    const float rstd = stat;
    float2 gv = *(const float2*)&gg[2 * tid];
    float2 bv = *(const float2*)&bb[2 * tid];
    float2 ov = {d0 * rstd * gv.x + bv.x, d1 * rstd * gv.y + bv.y};
    *(float2*)&out[(size_t)row * CE + 2 * tid] = ov;
    if (out_r) {
        float2 orr = {roundtf(ov.x), roundtf(ov.y)};
        *(float2*)&out_r[(size_t)row * CE + 2 * tid] = orr;
    }
}

// ---------------- launch -------------------------------------------------------
extern "C" void kernel_launch(void* const* d_in, const int* in_sizes, int n_in,
                              void* d_out, int out_size)
{
    const float* x    = (const float*)d_in[0];
    const float* dist = (const float*)d_in[1];
    const int*   dt   = (const int*)d_in[2];
    const int*   mask = (const int*)d_in[3];
    const float* wq_w = (const float*)d_in[4];
    const float* wq_b = (const float*)d_in[5];
    const float* wk_w = (const float*)d_in[6];
    const float* wk_b = (const float*)d_in[7];
    const float* wv_w = (const float*)d_in[8];
    const float* wv_b = (const float*)d_in[9];
    const float* wo_w = (const float*)d_in[10];
    const float* wo_b = (const float*)d_in[11];
    const float* pe   = (const float*)d_in[12];
    const float* w1   = (const float*)d_in[13];
    const float* b1   = (const float*)d_in[14];
    const float* w2   = (const float*)d_in[15];
    const float* b2   = (const float*)d_in[16];
    const float* ln1g = (const float*)d_in[17];
    const float* ln1b = (const float*)d_in[18];
    const float* ln2g = (const float*)d_in[19];
    const float* ln2b = (const float*)d_in[20];
    float* out = (float*)d_out;

    void *pq, *pk, *pv, *pcc, *pt1, *pao, *paor, *phid, *pt2, *pt2b, *pwqkv, *pbqkv;
    void *pxr, *pwor, *pw1r, *pw2r;
    cudaGetSymbolAddress(&pq, g_q);
    cudaGetSymbolAddress(&pk, g_k);
    cudaGetSymbolAddress(&pv, g_v);
    cudaGetSymbolAddress(&pcc, g_concat);
    cudaGetSymbolAddress(&pt1, g_t1);
    cudaGetSymbolAddress(&pao, g_attnout);
    cudaGetSymbolAddress(&paor, g_attnout_r);
    cudaGetSymbolAddress(&phid, g_hidden);
    cudaGetSymbolAddress(&pt2, g_t2);
    cudaGetSymbolAddress(&pt2b, g_t2b);
    cudaGetSymbolAddress(&pwqkv, g_wqkv);
    cudaGetSymbolAddress(&pbqkv, g_bqkv);
    cudaGetSymbolAddress(&pxr, g_xr);
    cudaGetSymbolAddress(&pwor, g_wor);
    cudaGetSymbolAddress(&pw1r, g_w1r);
    cudaGetSymbolAddress(&pw2r, g_w2r);

    cudaFuncSetAttribute(fused_attn_kernel,
                         cudaFuncAttributeMaxDynamicSharedMemorySize, FS_SMEM_BYTES);
    cudaFuncSetAttribute(mma_gemm_kernel<128>,
                         cudaFuncAttributeMaxDynamicSharedMemorySize, GEMM_SMEM_BYTES(128));

    pe_copy_kernel<<<(CNR * CD + 255) / 256, 256>>>(pe);
    pack_qkv_kernel<<<(CE * CE + 255) / 256, 256>>>(wq_w, wk_w, wv_w, wq_b, wk_b, wv_b);
    {
        const int n0 = CM * CE / 4, n1 = CE * CE / 4, n2 = CE * CF / 4, n3 = CF * CE / 4;
        const int ntot = n0 + n1 + n2 + n3;
        round4_kernel<<<(ntot + 255) / 256, 256>>>(
            (const float4*)x, (float4*)pxr, n0,
            (const float4*)wo_w, (float4*)pwor, n1,
            (const float4*)w1, (float4*)pw1r, n2,
            (const float4*)w2, (float4*)pw2r, n3);
    }

    // fused QKV: M=4096, N=1536, K=512 (BN=128)
    dim3 gq(1536 / 128, CM / 128);
    mma_gemm_kernel<128><<<gq, 256, GEMM_SMEM_BYTES(128)>>>(
        (const float*)pxr, (const float*)pwqkv, (float*)pq, (float*)pk, (float*)pv,
        CM, 1536, CE, CE, (const float*)pbqkv, nullptr, EPI_QKV);

    // fully fused attention -> g_concat
    dim3 gfs(CS / 32, CBH);
    fused_attn_kernel<<<gfs, 256, FS_SMEM_BYTES>>>(dist, dt, mask);

    // wo: split-K=2, BN=128 -> partials t1/t2b; reduce + bias + resid in ln1
    dim3 gwo(CE / 128, CM / 128, 2);
    mma_gemm_kernel<128><<<gwo, 256, GEMM_SMEM_BYTES(128)>>>(
        (const float*)pcc, (const float*)pwor, (float*)pt1, (float*)pt2b, nullptr,
        CM, CE, CE / 2, CE, nullptr, nullptr, EPI_NONE);
    ln_kernel<<<CM, 256>>>((const float*)pt1, (const float*)pt2b, wo_b, x,
                           (float*)pao, (float*)paor, ln1g, ln1b);

    dim3 gf1(CF / 128, CM / 128);
    mma_gemm_kernel<128><<<gf1, 256, GEMM_SMEM_BYTES(128)>>>(
        (const float*)paor, (const float*)pw1r, (float*)phid, nullptr, nullptr,
        CM, CF, CE, CE, b1, nullptr, EPI_RELU);

    // FFN2 split-K=2, BN=128: partials -> t2 / t2b
    dim3 gf2(CE / 128, CM / 128, 2);
    mma_gemm_kernel<128><<<gf2, 256, GEMM_SMEM_BYTES(128)>>>(
        (const float*)phid, (const float*)pw2r, (float*)pt2, (float*)pt2b, nullptr,
        CM, CE, CF / 2, CF, nullptr, nullptr, EPI_NONE);

    // ln2 fuses partial reduce + bias + residual
    ln_kernel<<<CM, 256>>>((const float*)pt2, (const float*)pt2b, b2, (const float*)pao,
                           out, nullptr, ln2g, ln2b);
}

// round 15
// speedup vs baseline: 2.6211x; 1.0119x over previous
#include <cuda_runtime.h>
#include <cstdint>
#include <cstddef>

// Problem constants
#define CB 8
#define CS 512
#define CE 512
#define CH 8
#define CD 64
#define CP 64
#define CF 2048
#define CNR 129            // 2P+1
#define CSR 192            // padded rows for pos_emb
#define CBH (CB*CH)        // 64
#define CM (CB*CS)         // 4096

// ---------------- device scratch (zero-initialized .bss) ----------------------
__device__ __align__(16) float g_q[CBH*CS*CD];
__device__ __align__(16) float g_k[CBH*CS*CD];
__device__ __align__(16) float g_v[CBH*CS*CD];
__device__ __align__(16) float g_pe[CSR*CD];            // padded pos_emb (rows >=129 zero)
__device__ __align__(16) float g_concat[CM*CE];         // rounded at write
__device__ __align__(16) float g_t1[CM*CE];
__device__ __align__(16) float g_attnout[CM*CE];        // fp32 (resid)
__device__ __align__(16) float g_attnout_r[CM*CE];      // RN-rounded (FFN1 A)
__device__ __align__(16) float g_hidden[CM*CF];         // rounded at write
__device__ __align__(16) float g_t2[CM*CE];             // split-K partial 0
__device__ __align__(16) float g_t2b[CM*CE];            // split-K partial 1
__device__ __align__(16) float g_wqkv[CE*3*CE];         // packed+rounded [512][1536]
__device__ __align__(16) float g_bqkv[3*CE];
__device__ __align__(16) float g_wor[CE*CE];            // rounded wo
__device__ __align__(16) float g_w1r[CE*CF];            // rounded w1
__device__ __align__(16) float g_w2r[CF*CE];            // rounded w2

enum { EPI_QKV = 0, EPI_RESID = 1, EPI_RELU = 2, EPI_NONE = 3 };

__device__ __forceinline__ uint32_t f2tf(float f) {
    uint32_t u;
    asm("cvt.rna.tf32.f32 %0, %1;" : "=r"(u) : "f"(f));
    return u;
}
__device__ __forceinline__ float roundtf(float f) {
    return __uint_as_float(f2tf(f));
}

__device__ __forceinline__ void mma_tf32(float c[4], const uint32_t a[4],
                                         const uint32_t b[2]) {
    asm volatile(
        "mma.sync.aligned.m16n8k8.row.col.f32.tf32.tf32.f32 "
        "{%0,%1,%2,%3}, {%4,%5,%6,%7}, {%8,%9}, {%0,%1,%2,%3};\n"
        : "+f"(c[0]), "+f"(c[1]), "+f"(c[2]), "+f"(c[3])
        : "r"(a[0]), "r"(a[1]), "r"(a[2]), "r"(a[3]), "r"(b[0]), "r"(b[1]));
}

__device__ __forceinline__ void cp16(uint32_t dst, const void* src) {
    asm volatile("cp.async.cg.shared.global [%0], [%1], 16;\n" :: "r"(dst), "l"(src));
}
__device__ __forceinline__ void cp_commit() {
    asm volatile("cp.async.commit_group;\n");
}
template<int N>
__device__ __forceinline__ void cp_wait() {
    asm volatile("cp.async.wait_group %0;\n" :: "n"(N));
}

// ---------------- TF32 tensor-core GEMM (cp.async 3-stage, BK=32) -------------
#define APITCH 36
#define GEMM_NSTAGE 3

template<int BN>
__global__ __launch_bounds__(256, 2) void mma_gemm_kernel(
    const float* __restrict__ A, const float* __restrict__ Bm,
    float* __restrict__ C, float* __restrict__ C2, float* __restrict__ C3,
    int M, int N, int K, int Kstride,
    const float* __restrict__ bias, const float* __restrict__ resid, int mode)
{
    constexpr int BPITCH = BN + 4;
    constexpr int NT = BN / 16;
    constexpr int ASZ = 128 * APITCH;
    constexpr int BSZ = 32 * BPITCH;
    constexpr int CPR = BN / 4;
    constexpr int NBL = CPR / 8;
    extern __shared__ uint32_t smem_u[];
    uint32_t* As = smem_u;
    uint32_t* Bs = smem_u + GEMM_NSTAGE * ASZ;

    const int tid = threadIdx.x;
    const int warp = tid >> 5;
    const int lane = tid & 31;
    const int gid = lane >> 2;
    const int tig = lane & 3;
    const int wy = warp >> 1;
    const int wx = warp & 1;
    const int bm = blockIdx.y * 128;
    const int bn = blockIdx.x * BN;
    const int koff = blockIdx.z * K;

    const uint32_t a_base = (uint32_t)__cvta_generic_to_shared(As);
    const uint32_t b_base = (uint32_t)__cvta_generic_to_shared(Bs);

    const int nk = K >> 5;

    auto stageg = [&](int s) {
        const int bs = s % GEMM_NSTAGE;
        const uint32_t adst = a_base + bs * ASZ * 4;
        const uint32_t bdst = b_base + bs * BSZ * 4;
#pragma unroll
        for (int l = 0; l < 4; l++) {
            const int idx = tid + (l << 8);
            const int r = idx >> 3;
            const int c = (idx & 7) << 2;
            cp16(adst + (r * APITCH + c) * 4,
                 A + (size_t)(bm + r) * Kstride + koff + (s << 5) + c);
        }
#pragma unroll
        for (int l = 0; l < NBL; l++) {
            const int idx = tid + (l << 8);
            const int r = idx / CPR;
            const int c = (idx % CPR) << 2;
            cp16(bdst + (r * BPITCH + c) * 4,
                 Bm + (size_t)(koff + (s << 5) + r) * N + bn + c);
        }
    };

    float acc[2][NT][4];
#pragma unroll
    for (int mt = 0; mt < 2; mt++)
#pragma unroll
        for (int nt = 0; nt < NT; nt++)
#pragma unroll
            for (int r = 0; r < 4; r++) acc[mt][nt][r] = 0.0f;

#pragma unroll
    for (int s = 0; s < GEMM_NSTAGE - 1; s++) {
        if (s < nk) stageg(s);
        cp_commit();
    }

    for (int i = 0; i < nk; i++) {
        cp_wait<1>();
        __syncthreads();
        if (i + 2 < nk) stageg(i + 2);
        cp_commit();

        const int buf = i % GEMM_NSTAGE;
        const uint32_t* Ab = As + buf * ASZ;
        const uint32_t* Bb = Bs + buf * BSZ;
#pragma unroll
        for (int ks = 0; ks < 32; ks += 8) {
            uint32_t af[2][4];
#pragma unroll
            for (int mt = 0; mt < 2; mt++) {
                const int mrow = wy * 32 + mt * 16 + gid;
                af[mt][0] = Ab[mrow * APITCH + ks + tig];
                af[mt][1] = Ab[(mrow + 8) * APITCH + ks + tig];
                af[mt][2] = Ab[mrow * APITCH + ks + tig + 4];
                af[mt][3] = Ab[(mrow + 8) * APITCH + ks + tig + 4];
            }
            uint32_t bf[NT][2];
#pragma unroll
            for (int nt = 0; nt < NT; nt++) {
                const int nc = wx * (BN / 2) + nt * 8 + gid;
                bf[nt][0] = Bb[(ks + tig) * BPITCH + nc];
                bf[nt][1] = Bb[(ks + tig + 4) * BPITCH + nc];
            }
#pragma unroll
            for (int mt = 0; mt < 2; mt++)
#pragma unroll
                for (int nt = 0; nt < NT; nt++)
                    mma_tf32(acc[mt][nt], af[mt], bf[nt]);
        }
    }

    float* Csel = (mode == EPI_NONE && blockIdx.z) ? C2 : C;
#pragma unroll
    for (int mt = 0; mt < 2; mt++) {
#pragma unroll
        for (int nt = 0; nt < NT; nt++) {
            const int col = bn + wx * (BN / 2) + nt * 8 + 2 * tig;
            float bv0 = 0.0f, bv1 = 0.0f;
            if (bias) { bv0 = bias[col]; bv1 = bias[col + 1]; }
#pragma unroll
            for (int half = 0; half < 2; half++) {
                const int row = bm + wy * 32 + mt * 16 + gid + half * 8;
                float v0 = acc[mt][nt][half * 2 + 0] + bv0;
                float v1 = acc[mt][nt][half * 2 + 1] + bv1;
                if (mode == EPI_RESID) {
                    v0 += resid[(size_t)row * N + col];
                    v1 += resid[(size_t)row * N + col + 1];
                } else if (mode == EPI_RELU) {
                    v0 = roundtf(fmaxf(v0, 0.0f));
                    v1 = roundtf(fmaxf(v1, 0.0f));
                }
                float2 vv = {v0, v1};
                if (mode == EPI_QKV) {
                    const int b = row >> 9, ii = row & 511;
                    const int which = col >> 9;
                    const int cc = col & 511;
                    const int h = cc >> 6, d = cc & 63;
                    float* base = (which == 0) ? C : (which == 1) ? C2 : C3;
                    *(float2*)(base + (((size_t)(b * CH + h) * CS) + ii) * CD + d) = vv;
                } else {
                    *(float2*)(Csel + (size_t)row * N + col) = vv;
                }
            }
        }
    }
}

#define GEMM_SMEM_BYTES(BN) (GEMM_NSTAGE * (128 * APITCH + 32 * ((BN) + 4)) * 4)

// ---------------- merged round-copy (3 weight arrays) --------------------------
__global__ void round3_kernel(const float4* __restrict__ s1, float4* __restrict__ d1, int n1,
                              const float4* __restrict__ s2, float4* __restrict__ d2, int n2,
                              const float4* __restrict__ s3, float4* __restrict__ d3, int n3)
{
    int i = blockIdx.x * 256 + threadIdx.x;
    const float4* s; float4* d;
    if (i < n1) { s = s1 + i; d = d1 + i; }
    else {
        i -= n1;
        if (i < n2) { s = s2 + i; d = d2 + i; }
        else {
            i -= n2;
            if (i >= n3) return;
            s = s3 + i; d = d3 + i;
        }
    }
    float4 v = *s;
    v.x = roundtf(v.x); v.y = roundtf(v.y);
    v.z = roundtf(v.z); v.w = roundtf(v.w);
    *d = v;
}

// ---------------- pack QKV weights/biases (rounded) + pe copy ------------------
__global__ void pack_qkv_kernel(const float* __restrict__ wq, const float* __restrict__ wk,
                                const float* __restrict__ wv, const float* __restrict__ bq,
                                const float* __restrict__ bk, const float* __restrict__ bv,
                                const float* __restrict__ pe)
{
    int idx = blockIdx.x * 256 + threadIdx.x;
    if (idx < CE * CE) {
        int r = idx >> 9, c = idx & 511;
        g_wqkv[(size_t)r * 1536 + c] = roundtf(wq[idx]);
        g_wqkv[(size_t)r * 1536 + 512 + c] = roundtf(wk[idx]);
        g_wqkv[(size_t)r * 1536 + 1024 + c] = roundtf(wv[idx]);
    }
    if (idx < CE) {
        g_bqkv[idx] = bq[idx];
        g_bqkv[512 + idx] = bk[idx];
        g_bqkv[1024 + idx] = bv[idx];
    }
    if (idx < CNR * CD) g_pe[idx] = pe[idx];
}

// ---------------- FULLY FUSED attention ----------------------------------------
#define FS_Q 0
#define FS_K 4224
#define FS_QZ 21632
#define FS_INT 25856
#define FS_RED 26912
#define FS_SMEM_BYTES (27040 * 4)
#define FS_KBUF (128*68)

__global__ __launch_bounds__(256, 2) void fused_attn_kernel(
    const float* __restrict__ dist, const int* __restrict__ dt,
    const int* __restrict__ mask)
{
    extern __shared__ uint32_t sm[];
    uint32_t* Qs = sm + FS_Q;
    float* AW = (float*)(sm + FS_Q);
    uint32_t* Kb = sm + FS_K;
    float* QZs = (float*)(sm + FS_QZ);
    int* dti_s = (int*)(sm + FS_INT);
    int* dtj_s = dti_s + 32;
    int* mj_s = dtj_s + 512;
    float* red = (float*)(sm + FS_RED);

    const int bh = blockIdx.y;
    const int b = bh >> 3, h = bh & 7;
    const int i0 = blockIdx.x << 5;
    const int tid = threadIdx.x;
    const int warp = tid >> 5;
    const int lane = tid & 31;
    const int gid = lane >> 2;
    const int tig = lane & 3;
    const int wm = warp & 1;
    const int wn = warp >> 1;
    const int mrow = wm * 16 + gid;

    const float* qb = g_q + (size_t)bh * CS * CD;
    const float* kb = g_k + (size_t)bh * CS * CD;
    const float* vb = g_v + (size_t)bh * CS * CD;

    const uint32_t q_base = (uint32_t)__cvta_generic_to_shared(Qs);
    const uint32_t k_base = (uint32_t)__cvta_generic_to_shared(Kb);

#pragma unroll
    for (int l = 0; l < 2; l++) {
        const int idx = tid + (l << 8);
        const int r = idx >> 4;
        const int c = (idx & 15) << 2;
        cp16(q_base + (r * 68 + c) * 4, qb + (size_t)(i0 + r) * CD + c);
    }
    for (int t = tid; t < 160 * 16; t += 256) {
        const int r = t >> 4;
        const int c = (t & 15) << 2;
        cp16(k_base + (r * 68 + c) * 4, g_pe + (size_t)r * CD + c);
    }
    cp_commit();

    if (tid < 32) dti_s[tid] = dt[b * CS + i0 + tid];
    {
        int2 dj = *(const int2*)&dt[b * CS + 2 * tid];
        dtj_s[2 * tid] = dj.x; dtj_s[2 * tid + 1] = dj.y;
        int2 mm = *(const int2*)&mask[b * CS + 2 * tid];
        mj_s[2 * tid] = mm.x; mj_s[2 * tid + 1] = mm.y;
    }
    cp_wait<0>();
    __syncthreads();

    // ---- phase 1: qz
    {
        float qacc[5][4];
#pragma unroll
        for (int nt = 0; nt < 5; nt++)
#pragma unroll
            for (int r = 0; r < 4; r++) qacc[nt][r] = 0.0f;
#pragma unroll
        for (int ks = 0; ks < 64; ks += 8) {
            uint32_t af[4];
            af[0] = Qs[mrow * 68 + ks + tig];
            af[1] = Qs[(mrow + 8) * 68 + ks + tig];
            af[2] = Qs[mrow * 68 + ks + tig + 4];
            af[3] = Qs[(mrow + 8) * 68 + ks + tig + 4];
#pragma unroll
            for (int nt = 0; nt < 5; nt++) {
                const int nc = wn * 40 + nt * 8 + gid;
                uint32_t bf[2];
                bf[0] = Kb[nc * 68 + ks + tig];
                bf[1] = Kb[nc * 68 + ks + tig + 4];
                mma_tf32(qacc[nt], af, bf);
            }
        }
        __syncthreads();

#pragma unroll
        for (int l = 0; l < 8; l++) {
            const int idx = tid + (l << 8);
            const int r = idx >> 4;
            const int c = (idx & 15) << 2;
            cp16(k_base + (r * 68 + c) * 4, kb + (size_t)r * CD + c);
        }
        cp_commit();

#pragma unroll
        for (int nt = 0; nt < 5; nt++) {
            const int col = wn * 40 + nt * 8 + 2 * tig;
            if (col <= 128) {
                QZs[mrow * 132 + col] = qacc[nt][0];
                QZs[mrow * 132 + col + 1] = qacc[nt][1];
                QZs[(mrow + 8) * 132 + col] = qacc[nt][2];
                QZs[(mrow + 8) * 132 + col + 1] = qacc[nt][3];
            }
        }
    }

    // ---- phase 2: scores (dist prefetched into regs before MMA)
    float sacc[4][4][4];
#pragma unroll
    for (int c = 0; c < 4; c++)
#pragma unroll
        for (int nt = 0; nt < 4; nt++)
#pragma unroll
            for (int r = 0; r < 4; r++) sacc[c][nt][r] = 0.0f;

#pragma unroll
    for (int ch = 0; ch < 4; ch++) {
        cp_wait<0>();
        __syncthreads();
        if (ch < 3) {
            const uint32_t kdst = k_base + (((ch + 1) & 1)) * FS_KBUF * 4;
#pragma unroll
            for (int l = 0; l < 8; l++) {
                const int idx = tid + (l << 8);
                const int r = idx >> 4;
                const int c = (idx & 15) << 2;
                cp16(kdst + (r * 68 + c) * 4,
                     kb + (size_t)((ch + 1) * 128 + r) * CD + c);
            }
        }
        cp_commit();

        // prefetch dist for this chunk (LDG overlaps the MMAs below)
        float2 dv[2][4];
#pragma unroll
        for (int half = 0; half < 2; half++) {
            const int i = i0 + mrow + half * 8;
#pragma unroll
            for (int nt = 0; nt < 4; nt++) {
                const int jl = ch * 128 + wn * 32 + nt * 8 + 2 * tig;
                dv[half][nt] = *(const float2*)&dist[((size_t)b * CS + i) * CS + jl];
            }
        }

        const uint32_t* Kc = Kb + (ch & 1) * FS_KBUF;
#pragma unroll
        for (int ks = 0; ks < 64; ks += 8) {
            uint32_t af[4];
            af[0] = Qs[mrow * 68 + ks + tig];
            af[1] = Qs[(mrow + 8) * 68 + ks + tig];
            af[2] = Qs[mrow * 68 + ks + tig + 4];
            af[3] = Qs[(mrow + 8) * 68 + ks + tig + 4];
#pragma unroll
            for (int nt = 0; nt < 4; nt++) {
                const int nc = wn * 32 + nt * 8 + gid;
                uint32_t bf[2];
                bf[0] = Kc[nc * 68 + ks + tig];
                bf[1] = Kc[nc * 68 + ks + tig + 4];
                mma_tf32(sacc[ch][nt], af, bf);
            }
        }

#pragma unroll
        for (int half = 0; half < 2; half++) {
            const int il = mrow + half * 8;
            const int di = dti_s[il];
#pragma unroll
            for (int nt = 0; nt < 4; nt++) {
                const int jl = ch * 128 + wn * 32 + nt * 8 + 2 * tig;
#pragma unroll
                for (int u = 0; u < 2; u++) {
                    const int j = jl + u;
                    int rel = min(max(dtj_s[j] - di, -CP), CP) + CP;
                    float v = (sacc[ch][nt][half * 2 + u] + QZs[il * 132 + rel]) * 0.125f
                            + 0.6f * (u ? dv[half][nt].y : dv[half][nt].x);
                    if (mj_s[j] == 0) v = -1e9f;
                    sacc[ch][nt][half * 2 + u] = v;
                }
            }
        }
    }
    __syncthreads();

    // ---- phase 3: softmax + bins
    float* bins = QZs;
    for (int t = tid; t < 32 * 132; t += 256) bins[t] = 0.0f;

    float mrw[2];
#pragma unroll
    for (int half = 0; half < 2; half++) {
        float m = -1e30f;
#pragma unroll
        for (int c = 0; c < 4; c++)
#pragma unroll
            for (int nt = 0; nt < 4; nt++) {
                m = fmaxf(m, sacc[c][nt][half * 2]);
                m = fmaxf(m, sacc[c][nt][half * 2 + 1]);
            }
        m = fmaxf(m, __shfl_xor_sync(0xffffffffu, m, 1));
        m = fmaxf(m, __shfl_xor_sync(0xffffffffu, m, 2));
        mrw[half] = m;
    }
    if (tig == 0) {
        red[wn * 32 + mrow] = mrw[0];
        red[wn * 32 + mrow + 8] = mrw[1];
    }
    __syncthreads();
#pragma unroll
    for (int half = 0; half < 2; half++) {
        const int r = mrow + half * 8;
        mrw[half] = fmaxf(fmaxf(red[r], red[32 + r]), fmaxf(red[64 + r], red[96 + r]));
    }
    __syncthreads();

    float srow[2] = {0.0f, 0.0f};
#pragma unroll
    for (int half = 0; half < 2; half++) {
#pragma unroll
        for (int c = 0; c < 4; c++)
#pragma unroll
            for (int nt = 0; nt < 4; nt++)
#pragma unroll
                for (int u = 0; u < 2; u++) {
                    float e = __expf(sacc[c][nt][half * 2 + u] - mrw[half]);
                    sacc[c][nt][half * 2 + u] = e;
                    srow[half] += e;
                }
        srow[half] += __shfl_xor_sync(0xffffffffu, srow[half], 1);
        srow[half] += __shfl_xor_sync(0xffffffffu, srow[half], 2);
    }
    if (tig == 0) {
        red[wn * 32 + mrow] = srow[0];
        red[wn * 32 + mrow + 8] = srow[1];
    }
    __syncthreads();
    float inv2[2];
#pragma unroll
    for (int half = 0; half < 2; half++) {
        const int r = mrow + half * 8;
        inv2[half] = 1.0f / (red[r] + red[32 + r] + red[64 + r] + red[96 + r]);
    }

#pragma unroll
    for (int half = 0; half < 2; half++) {
        const int il = mrow + half * 8;
        const int di = dti_s[il];
#pragma unroll
        for (int c = 0; c < 4; c++)
#pragma unroll
            for (int nt = 0; nt < 4; nt++) {
                const int jl = c * 128 + wn * 32 + nt * 8 + 2 * tig;
                float a0 = sacc[c][nt][half * 2 + 0] * inv2[half];
                float a1 = sacc[c][nt][half * 2 + 1] * inv2[half];
                sacc[c][nt][half * 2 + 0] = a0;
                sacc[c][nt][half * 2 + 1] = a1;
                int r0 = min(max(dtj_s[jl] - di, -CP), CP) + CP;
                int r1 = min(max(dtj_s[jl + 1] - di, -CP), CP) + CP;
                atomicAdd(&bins[il * 132 + r0], a0);
                atomicAdd(&bins[il * 132 + r1], a1);
            }
    }
    __syncthreads();

    // ---- phase 5: out = aw @ V + bins @ PE (2-way k-split across warp halves)
    const int wk = warp >> 2;
    const int wq = warp & 3;
    const int wm2 = wq >> 1;
    const int wn2 = wq & 1;
    const int mrow2 = wm2 * 16 + gid;

    float oacc[4][4];
#pragma unroll
    for (int nt = 0; nt < 4; nt++)
#pragma unroll
        for (int r = 0; r < 4; r++) oacc[nt][r] = 0.0f;

#pragma unroll
    for (int l = 0; l < 8; l++) {
        const int idx = tid + (l << 8);
        const int r = idx >> 4;
        const int c = (idx & 15) << 2;
        cp16(k_base + (r * 68 + c) * 4, vb + (size_t)r * CD + c);
    }
    cp_commit();

#pragma unroll
    for (int ch = 0; ch < 4; ch++) {
#pragma unroll
        for (int half = 0; half < 2; half++) {
            const int il = mrow + half * 8;
#pragma unroll
            for (int nt = 0; nt < 4; nt++) {
                const int jloc = wn * 32 + nt * 8 + 2 * tig;
                float2 st = {sacc[ch][nt][half * 2 + 0], sacc[ch][nt][half * 2 + 1]};
                *(float2*)&AW[il * 132 + jloc] = st;
            }
        }
        cp_wait<0>();
        __syncthreads();
        if (ch < 3) {
            const uint32_t vdst = k_base + ((ch + 1) & 1) * FS_KBUF * 4;
#pragma unroll
            for (int l = 0; l < 8; l++) {
                const int idx = tid + (l << 8);
                const int r = idx >> 4;
                const int c = (idx & 15) << 2;
                cp16(vdst + (r * 68 + c) * 4,
                     vb + (size_t)((ch + 1) * 128 + r) * CD + c);
            }
        }
        cp_commit();

        const uint32_t* Vc = Kb + (ch & 1) * FS_KBUF;
        const uint32_t* AWu = (const uint32_t*)AW;
#pragma unroll
        for (int ks = 0; ks < 64; ks += 8) {
            const int kk = wk * 64 + ks;
            uint32_t af[4];
            af[0] = AWu[mrow2 * 132 + kk + tig];
            af[1] = AWu[(mrow2 + 8) * 132 + kk + tig];
            af[2] = AWu[mrow2 * 132 + kk + tig + 4];
            af[3] = AWu[(mrow2 + 8) * 132 + kk + tig + 4];
#pragma unroll
            for (int nt = 0; nt < 4; nt++) {
                const int nc = wn2 * 32 + nt * 8 + gid;
                uint32_t bf[2];
                bf[0] = Vc[(kk + tig) * 68 + nc];
                bf[1] = Vc[(kk + tig + 4) * 68 + nc];
                mma_tf32(oacc[nt], af, bf);
            }
        }
        __syncthreads();
    }

    // PE part (k-split)
    {
#pragma unroll
        for (int l = 0; l < 4; l++) {
            const int idx = tid + (l << 8);
            const int r = idx >> 4;
            const int c = (idx & 15) << 2;
            cp16(k_base + (r * 68 + c) * 4, g_pe + (size_t)r * CD + c);
        }
        cp_commit();

        const uint32_t* binsu = (const uint32_t*)bins;
#pragma unroll
        for (int pch = 0; pch < 3; pch++) {
            cp_wait<0>();
            __syncthreads();
            if (pch < 2) {
                const uint32_t pdst = k_base + ((pch + 1) & 1) * FS_KBUF * 4;
#pragma unroll
                for (int l = 0; l < 4; l++) {
                    const int idx = tid + (l << 8);
                    const int r = idx >> 4;
                    const int c = (idx & 15) << 2;
                    cp16(pdst + (r * 68 + c) * 4,
                         g_pe + (size_t)((pch + 1) * 64 + r) * CD + c);
                }
            }
            cp_commit();

            const uint32_t* Pc = Kb + (pch & 1) * FS_KBUF;
#pragma unroll
            for (int ks = 0; ks < 32; ks += 8) {
                const int kl = wk * 32 + ks;
                const int kk = pch * 64 + kl;
                uint32_t af[4];
                af[0] = binsu[mrow2 * 132 + kk + tig];
                af[1] = binsu[(mrow2 + 8) * 132 + kk + tig];
                af[2] = binsu[mrow2 * 132 + kk + tig + 4];
                af[3] = binsu[(mrow2 + 8) * 132 + kk + tig + 4];
#pragma unroll
                for (int nt = 0; nt < 4; nt++) {
                    const int nc = wn2 * 32 + nt * 8 + gid;
                    uint32_t bf[2];
                    bf[0] = Pc[(kl + tig) * 68 + nc];
                    bf[1] = Pc[(kl + tig + 4) * 68 + nc];
                    mma_tf32(oacc[nt], af, bf);
                }
            }
        }
    }
    __syncthreads();

    float* redk = AW;
    if (wk == 1) {
#pragma unroll
        for (int nt = 0; nt < 4; nt++) {
            float4 p = {oacc[nt][0], oacc[nt][1], oacc[nt][2], oacc[nt][3]};
            *(float4*)&redk[(wq * 4 + nt) * 128 + lane * 4] = p;
        }
    }
    __syncthreads();
    if (wk == 0) {
#pragma unroll
        for (int nt = 0; nt < 4; nt++) {
            float4 p = *(const float4*)&redk[(wq * 4 + nt) * 128 + lane * 4];
            oacc[nt][0] += p.x; oacc[nt][1] += p.y;
            oacc[nt][2] += p.z; oacc[nt][3] += p.w;
        }
#pragma unroll
        for (int nt = 0; nt < 4; nt++) {
            const int col = h * CD + wn2 * 32 + nt * 8 + 2 * tig;
#pragma unroll
            for (int half = 0; half < 2; half++) {
                const int row = i0 + mrow2 + half * 8;
                float2 vv = {roundtf(oacc[nt][half * 2 + 0]),
                             roundtf(oacc[nt][half * 2 + 1])};
                *(float2*)&g_concat[(size_t)(b * CS + row) * CE + col] = vv;
            }
        }
    }
}

// ---------------- layernorm: in (+ in2 + addv + resid) -> LN -------------------
__global__ __launch_bounds__(256) void ln_kernel(
    const float* __restrict__ in, const float* __restrict__ in2,
    const float* __restrict__ addv, const float* __restrict__ resid,
    float* __restrict__ out, float* __restrict__ out_r,
    const float* __restrict__ gg, const float* __restrict__ bb)
{
    const int row = blockIdx.x;
    const int tid = threadIdx.x;
    const int lane = tid & 31;
    const int wid = tid >> 5;
    __shared__ float wred[8];
    __shared__ float stat;

    float2 v = *(const float2*)&in[(size_t)row * CE + 2 * tid];
    if (in2) {
        float2 v2 = *(const float2*)&in2[(size_t)row * CE + 2 * tid];
        v.x += v2.x; v.y += v2.y;
    }
    if (addv) {
        float2 av = *(const float2*)&addv[2 * tid];
        v.x += av.x; v.y += av.y;
    }
    if (resid) {
        float2 rv = *(const float2*)&resid[(size_t)row * CE + 2 * tid];
        v.x += rv.x; v.y += rv.y;
    }
    float s = v.x + v.y;
#pragma unroll
    for (int o = 16; o > 0; o >>= 1) s += __shfl_xor_sync(0xffffffffu, s, o);
    if (lane == 0) wred[wid] = s;
    __syncthreads();
    if (tid == 0) {
        float ss = wred[0];
#pragma unroll
        for (int k = 1; k < 8; k++) ss += wred[k];
        stat = ss * (1.0f / CE);
    }
    __syncthreads();
    const float mu = stat;
    const float d0 = v.x - mu, d1 = v.y - mu;
    float q = d0 * d0 + d1 * d1;
#pragma unroll
    for (int o = 16; o > 0; o >>= 1) q += __shfl_xor_sync(0xffffffffu, q, o);
    if (lane == 0) wred[wid] = q;
    __syncthreads();
    if (tid == 0) {
        float qq = wred[0];
#pragma unroll
        for (int k = 1; k < 8; k++) qq += wred[k];
        stat = rsqrtf(qq * (1.0f / CE) + 1e-5f);
    }
    __syncthreads();
    const float rstd = stat;
    float2 gv = *(const float2*)&gg[2 * tid];
    float2 bv = *(const float2*)&bb[2 * tid];
    float2 ov = {d0 * rstd * gv.x + bv.x, d1 * rstd * gv.y + bv.y};
    *(float2*)&out[(size_t)row * CE + 2 * tid] = ov;
    if (out_r) {
        float2 orr = {roundtf(ov.x), roundtf(ov.y)};
        *(float2*)&out_r[(size_t)row * CE + 2 * tid] = orr;
    }
}

// ---------------- launch -------------------------------------------------------
extern "C" void kernel_launch(void* const* d_in, const int* in_sizes, int n_in,
                              void* d_out, int out_size)
{
    const float* x    = (const float*)d_in[0];
    const float* dist = (const float*)d_in[1];
    const int*   dt   = (const int*)d_in[2];
    const int*   mask = (const int*)d_in[3];
    const float* wq_w = (const float*)d_in[4];
    const float* wq_b = (const float*)d_in[5];
    const float* wk_w = (const float*)d_in[6];
    const float* wk_b = (const float*)d_in[7];
    const float* wv_w = (const float*)d_in[8];
    const float* wv_b = (const float*)d_in[9];
    const float* wo_w = (const float*)d_in[10];
    const float* wo_b = (const float*)d_in[11];
    const float* pe   = (const float*)d_in[12];
    const float* w1   = (const float*)d_in[13];
    const float* b1   = (const float*)d_in[14];
    const float* w2   = (const float*)d_in[15];
    const float* b2   = (const float*)d_in[16];
    const float* ln1g = (const float*)d_in[17];
    const float* ln1b = (const float*)d_in[18];
    const float* ln2g = (const float*)d_in[19];
    const float* ln2b = (const float*)d_in[20];
    float* out = (float*)d_out;

    void *pq, *pk, *pv, *pcc, *pt1, *pao, *paor, *phid, *pt2, *pt2b, *pwqkv, *pbqkv;
    void *pwor, *pw1r, *pw2r;
    cudaGetSymbolAddress(&pq, g_q);
    cudaGetSymbolAddress(&pk, g_k);
    cudaGetSymbolAddress(&pv, g_v);
    cudaGetSymbolAddress(&pcc, g_concat);
    cudaGetSymbolAddress(&pt1, g_t1);
    cudaGetSymbolAddress(&pao, g_attnout);
    cudaGetSymbolAddress(&paor, g_attnout_r);
    cudaGetSymbolAddress(&phid, g_hidden);
    cudaGetSymbolAddress(&pt2, g_t2);
    cudaGetSymbolAddress(&pt2b, g_t2b);
    cudaGetSymbolAddress(&pwqkv, g_wqkv);
    cudaGetSymbolAddress(&pbqkv, g_bqkv);
    cudaGetSymbolAddress(&pwor, g_wor);
    cudaGetSymbolAddress(&pw1r, g_w1r);
    cudaGetSymbolAddress(&pw2r, g_w2r);

    cudaFuncSetAttribute(fused_attn_kernel,
                         cudaFuncAttributeMaxDynamicSharedMemorySize, FS_SMEM_BYTES);
    cudaFuncSetAttribute(mma_gemm_kernel<128>,
                         cudaFuncAttributeMaxDynamicSharedMemorySize, GEMM_SMEM_BYTES(128));

    pack_qkv_kernel<<<(CE * CE + 255) / 256, 256>>>(wq_w, wk_w, wv_w, wq_b, wk_b, wv_b, pe);
    {
        const int n1 = CE * CE / 4, n2 = CE * CF / 4, n3 = CF * CE / 4;
        const int ntot = n1 + n2 + n3;
        round3_kernel<<<(ntot + 255) / 256, 256>>>(
            (const float4*)wo_w, (float4*)pwor, n1,
            (const float4*)w1, (float4*)pw1r, n2,
            (const float4*)w2, (float4*)pw2r, n3);
    }

    // fused QKV: M=4096, N=1536, K=512 (A = raw x, RZ truncation in HW)
    dim3 gq(1536 / 128, CM / 128);
    mma_gemm_kernel<128><<<gq, 256, GEMM_SMEM_BYTES(128)>>>(
        x, (const float*)pwqkv, (float*)pq, (float*)pk, (float*)pv,
        CM, 1536, CE, CE, (const float*)pbqkv, nullptr, EPI_QKV);

    // fully fused attention -> g_concat
    dim3 gfs(CS / 32, CBH);
    fused_attn_kernel<<<gfs, 256, FS_SMEM_BYTES>>>(dist, dt, mask);

    // wo: split-K=2 -> partials t1/t2b; reduce + bias + resid in ln1
    dim3 gwo(CE / 128, CM / 128, 2);
    mma_gemm_kernel<128><<<gwo, 256, GEMM_SMEM_BYTES(128)>>>(
        (const float*)pcc, (const float*)pwor, (float*)pt1, (float*)pt2b, nullptr,
        CM, CE, CE / 2, CE, nullptr, nullptr, EPI_NONE);
    ln_kernel<<<CM, 256>>>((const float*)pt1, (const float*)pt2b, wo_b, x,
                           (float*)pao, (float*)paor, ln1g, ln1b);

    dim3 gf1(CF / 128, CM / 128);
    mma_gemm_kernel<128><<<gf1, 256, GEMM_SMEM_BYTES(128)>>>(
        (const float*)paor, (const float*)pw1r, (float*)phid, nullptr, nullptr,
        CM, CF, CE, CE, b1, nullptr, EPI_RELU);

    // FFN2 split-K=2: partials -> t2 / t2b
    dim3 gf2(CE / 128, CM / 128, 2);
    mma_gemm_kernel<128><<<gf2, 256, GEMM_SMEM_BYTES(128)>>>(
        (const float*)phid, (const float*)pw2r, (float*)pt2, (float*)pt2b, nullptr,
        CM, CE, CF / 2, CF, nullptr, nullptr, EPI_NONE);

    ln_kernel<<<CM, 256>>>((const float*)pt2, (const float*)pt2b, b2, (const float*)pao,
                           out, nullptr, ln2g, ln2b);
}